// round 2
// baseline (speedup 1.0000x reference)
#include <cuda_runtime.h>
#include <math.h>

#define BATCH   131072
#define DIM     64
#define QD      32
#define NLAYERS 6
#define HF      128
#define HH      256
#define DTC     0.05f

// ---------------------------------------------------------------------------
// Scratch (static __device__ arrays -- the sanctioned alloc-free workaround)
// ---------------------------------------------------------------------------
__device__ float g_z   [BATCH * DIM];   // flow-forward output s = [q,p] (base point)
__device__ float g_zk  [BATCH * DIM];   // current RK4 stage input
__device__ float g_grad[BATCH * DIM];   // grad H accumulation
__device__ float g_acc [BATCH * DIM];   // RK4 weighted sum of dz
__device__ float g_h1  [BATCH * HH];    // softplus(a1) buffer
__device__ float g_g2  [BATCH * HH];    // g2 buffer
__device__ float g_g1  [BATCH * HH];    // g1 buffer
__device__ float g_kW1t[DIM * HH];
__device__ float g_kW2t[HH * HH];
__device__ float g_vW1t[QD * HH];
__device__ float g_vW2t[HH * HH];
__device__ float g_M   [DIM * DIM];

__device__ __forceinline__ float softplusf(float x) {
    return fmaxf(x, 0.f) + log1pf(expf(-fabsf(x)));
}

// ---------------------------------------------------------------------------
// Prep: transpose (out[c*R+r] = in[r*C+c])
// ---------------------------------------------------------------------------
__global__ void transpose_k(const float* __restrict__ in, float* __restrict__ out,
                            int R, int C) {
    int idx = blockIdx.x * 256 + threadIdx.x;
    if (idx < R * C) {
        int r = idx / C, c = idx % C;
        out[c * R + r] = in[idx];
    }
}

// ---------------------------------------------------------------------------
// Prep: M = (A - A^T) - L L^T,  L = tril(Lp,-1) + diag(softplus(diag(Lp)))
// ---------------------------------------------------------------------------
__global__ void build_M_k(const float* __restrict__ A, const float* __restrict__ Lp,
                          float* __restrict__ M) {
    __shared__ float L[DIM * DIM];
    int t = threadIdx.x;
    for (int idx = t; idx < DIM * DIM; idx += 256) {
        int i = idx >> 6, j = idx & 63;
        float v;
        if (i > j)       v = Lp[idx];
        else if (i == j) v = softplusf(Lp[idx]);
        else             v = 0.f;
        L[idx] = v;
    }
    __syncthreads();
    for (int idx = t; idx < DIM * DIM; idx += 256) {
        int i = idx >> 6, j = idx & 63;
        float s = 0.f;
        #pragma unroll 8
        for (int k = 0; k < DIM; k++) s += L[i * DIM + k] * L[j * DIM + k];
        M[idx] = A[i * DIM + j] - A[j * DIM + i] - s;
    }
}

// ---------------------------------------------------------------------------
// Fused RealNVP coupling layer (forward or inverse), one thread per row.
// Layer weights staged in SMEM; two passes (s-MLP then t-MLP) reuse the same
// 33KB of static SMEM.
// ---------------------------------------------------------------------------
__global__ __launch_bounds__(256)
void flow_layer_k(float* __restrict__ z,
                  const float* __restrict__ sW1, const float* __restrict__ sb1,
                  const float* __restrict__ sW2, const float* __restrict__ sb2,
                  const float* __restrict__ tW1, const float* __restrict__ tb1,
                  const float* __restrict__ tW2, const float* __restrict__ tb2,
                  int layer, int inverse) {
    __shared__ float W1s[HF * QD];   // [hidden][in]  (row contiguous)
    __shared__ float W2s[QD * HF];   // [out][hidden] (natural layout, broadcast reads)
    __shared__ float b1s[HF];
    __shared__ float b2s[QD];

    const int parity = layer & 1;
    const int tid    = threadIdx.x;
    const size_t b   = (size_t)blockIdx.x * 256 + tid;
    float* zrow      = z + b * DIM;
    const int coff   = parity ? QD : 0;   // conditioning half
    const int moff   = parity ? 0  : QD;  // modified half

    float cond[QD];
    #pragma unroll
    for (int i = 0; i < QD; i += 4) {
        float4 v = *reinterpret_cast<const float4*>(zrow + coff + i);
        cond[i] = v.x; cond[i+1] = v.y; cond[i+2] = v.z; cond[i+3] = v.w;
    }

    const float* lsW1 = sW1 + (size_t)layer * HF * QD;
    const float* lsb1 = sb1 + (size_t)layer * HF;
    const float* lsW2 = sW2 + (size_t)layer * QD * HF;
    const float* lsb2 = sb2 + (size_t)layer * QD;
    const float* ltW1 = tW1 + (size_t)layer * HF * QD;
    const float* ltb1 = tb1 + (size_t)layer * HF;
    const float* ltW2 = tW2 + (size_t)layer * QD * HF;
    const float* ltb2 = tb2 + (size_t)layer * QD;

    // ---- pass 1: s-MLP ----
    #pragma unroll
    for (int r = 0; r < 4; r++) {
        int lin = r * 256 + tid;
        *reinterpret_cast<float4*>(&W1s[lin * 4]) =
            *reinterpret_cast<const float4*>(lsW1 + lin * 4);
        *reinterpret_cast<float4*>(&W2s[lin * 4]) =
            *reinterpret_cast<const float4*>(lsW2 + lin * 4);
    }
    if (tid < HF) b1s[tid] = lsb1[tid];
    if (tid < QD) b2s[tid] = lsb2[tid];
    __syncthreads();

    float sacc[QD];
    #pragma unroll
    for (int n = 0; n < QD; n++) sacc[n] = b2s[n];
    #pragma unroll 2
    for (int j = 0; j < HF; j++) {
        float hsum = b1s[j];
        const float4* w4 = reinterpret_cast<const float4*>(&W1s[j * QD]);
        #pragma unroll
        for (int kk = 0; kk < QD / 4; kk++) {
            float4 w = w4[kk];
            hsum = fmaf(cond[kk*4+0], w.x, hsum);
            hsum = fmaf(cond[kk*4+1], w.y, hsum);
            hsum = fmaf(cond[kk*4+2], w.z, hsum);
            hsum = fmaf(cond[kk*4+3], w.w, hsum);
        }
        hsum = fmaxf(hsum, 0.f);
        #pragma unroll
        for (int n = 0; n < QD; n++) sacc[n] = fmaf(hsum, W2s[n * HF + j], sacc[n]);
    }
    __syncthreads();

    // ---- pass 2: t-MLP (reuse smem) ----
    #pragma unroll
    for (int r = 0; r < 4; r++) {
        int lin = r * 256 + tid;
        *reinterpret_cast<float4*>(&W1s[lin * 4]) =
            *reinterpret_cast<const float4*>(ltW1 + lin * 4);
        *reinterpret_cast<float4*>(&W2s[lin * 4]) =
            *reinterpret_cast<const float4*>(ltW2 + lin * 4);
    }
    if (tid < HF) b1s[tid] = ltb1[tid];
    if (tid < QD) b2s[tid] = ltb2[tid];
    __syncthreads();

    float tacc[QD];
    #pragma unroll
    for (int n = 0; n < QD; n++) tacc[n] = b2s[n];
    #pragma unroll 2
    for (int j = 0; j < HF; j++) {
        float hsum = b1s[j];
        const float4* w4 = reinterpret_cast<const float4*>(&W1s[j * QD]);
        #pragma unroll
        for (int kk = 0; kk < QD / 4; kk++) {
            float4 w = w4[kk];
            hsum = fmaf(cond[kk*4+0], w.x, hsum);
            hsum = fmaf(cond[kk*4+1], w.y, hsum);
            hsum = fmaf(cond[kk*4+2], w.z, hsum);
            hsum = fmaf(cond[kk*4+3], w.w, hsum);
        }
        hsum = fmaxf(hsum, 0.f);
        #pragma unroll
        for (int n = 0; n < QD; n++) tacc[n] = fmaf(hsum, W2s[n * HF + j], tacc[n]);
    }

    // ---- affine update of the other half ----
    float xo[QD];
    #pragma unroll
    for (int i = 0; i < QD; i += 4) {
        float4 v = *reinterpret_cast<const float4*>(zrow + moff + i);
        xo[i] = v.x; xo[i+1] = v.y; xo[i+2] = v.z; xo[i+3] = v.w;
    }
    #pragma unroll
    for (int n = 0; n < QD; n++) {
        float s = tanhf(sacc[n]);
        float t = tacc[n];
        xo[n] = inverse ? (xo[n] - t) * expf(-s) : fmaf(xo[n], expf(s), t);
    }
    #pragma unroll
    for (int i = 0; i < QD; i += 4) {
        float4 v = make_float4(xo[i], xo[i+1], xo[i+2], xo[i+3]);
        *reinterpret_cast<float4*>(zrow + moff + i) = v;
    }
}

// ---------------------------------------------------------------------------
// Tiled SGEMM: C[B,N] = epilogue(A[B,K] @ W[K,N])
//   BM=128, BK=32, TM=8; BN/TN in {64/4, 32/2}; 256 threads.
// Epilogues:
//   EPI_SP     : softplus(acc + bias[n])
//   EPI_G2     : bias2[n] * sigmoid(acc + bias[n])
//   EPI_MULSIG : acc * (1 - exp(-aux[row,n]))    (aux = stored softplus)
//   EPI_STORE  : acc
//   EPI_ADDTO  : C += acc
// ---------------------------------------------------------------------------
#define EPI_SP     0
#define EPI_G2     1
#define EPI_MULSIG 2
#define EPI_STORE  3
#define EPI_ADDTO  4

template<int BN, int TN, int EPI>
__global__ __launch_bounds__(256)
void gemm_k(const float* __restrict__ A, int lda,
            const float* __restrict__ W, int ldw,
            const float* __restrict__ bias,
            const float* __restrict__ bias2,
            const float* __restrict__ aux,
            float* __restrict__ C, int ldc, int K) {
    constexpr int BM = 128, BK = 32, TM = 8;
    __shared__ float As[BK][BM + 1];
    __shared__ float Ws[BK][BN];

    const int tid  = threadIdx.x;
    const int tx   = tid % (BN / TN);
    const int ty   = tid / (BN / TN);
    const int row0 = blockIdx.x * BM;
    const int col0 = blockIdx.y * BN;

    float acc[TM][TN];
    #pragma unroll
    for (int i = 0; i < TM; i++)
        #pragma unroll
        for (int j = 0; j < TN; j++) acc[i][j] = 0.f;

    for (int k0 = 0; k0 < K; k0 += BK) {
        // stage A tile (transposed into As[k][m])
        #pragma unroll
        for (int r = 0; r < 4; r++) {
            int lin = r * 256 + tid;
            int m = lin >> 3, k4 = lin & 7;
            float4 v = *reinterpret_cast<const float4*>(
                A + (size_t)(row0 + m) * lda + k0 + k4 * 4);
            As[k4*4+0][m] = v.x; As[k4*4+1][m] = v.y;
            As[k4*4+2][m] = v.z; As[k4*4+3][m] = v.w;
        }
        // stage W tile
        constexpr int WIT = (BK * BN / 4) / 256;
        #pragma unroll
        for (int r = 0; r < WIT; r++) {
            int lin = r * 256 + tid;
            int n4 = lin % (BN / 4), k = lin / (BN / 4);
            *reinterpret_cast<float4*>(&Ws[k][n4 * 4]) =
                *reinterpret_cast<const float4*>(W + (size_t)(k0 + k) * ldw + col0 + n4 * 4);
        }
        __syncthreads();

        #pragma unroll
        for (int k = 0; k < BK; k++) {
            float rm[TM], rn[TN];
            #pragma unroll
            for (int i = 0; i < TM; i++) rm[i] = As[k][ty * TM + i];
            #pragma unroll
            for (int j = 0; j < TN; j++) rn[j] = Ws[k][tx * TN + j];
            #pragma unroll
            for (int i = 0; i < TM; i++)
                #pragma unroll
                for (int j = 0; j < TN; j++) acc[i][j] = fmaf(rm[i], rn[j], acc[i][j]);
        }
        __syncthreads();
    }

    #pragma unroll
    for (int i = 0; i < TM; i++) {
        const int row = row0 + ty * TM + i;
        #pragma unroll
        for (int j = 0; j < TN; j++) {
            const int n = col0 + tx * TN + j;
            float v = acc[i][j];
            if (EPI == EPI_SP) {
                v = softplusf(v + bias[n]);
            } else if (EPI == EPI_G2) {
                float a = v + bias[n];
                v = bias2[n] / (1.f + expf(-a));
            } else if (EPI == EPI_MULSIG) {
                v *= (1.f - expf(-aux[(size_t)row * HH + n]));
            } else if (EPI == EPI_ADDTO) {
                v += C[(size_t)row * ldc + n];
            }
            C[(size_t)row * ldc + n] = v;
        }
    }
}

// ---------------------------------------------------------------------------
// dz = M @ gradH (per row), dp += u*Bc, RK4 bookkeeping.
// stage<3: znext = zbase + c*DT*dz ; stage 3: znext = zbase + DT/6 * acc_total
// ---------------------------------------------------------------------------
__global__ __launch_bounds__(256)
void dyn_combine_k(const float* __restrict__ grad, const float* __restrict__ u,
                   const float* __restrict__ Bc, const float* __restrict__ Mg,
                   const float* __restrict__ zbase, float* __restrict__ acc,
                   float* __restrict__ znext, int stage) {
    __shared__ float Ms[DIM * DIM];
    __shared__ float Bcs[QD];
    for (int i = threadIdx.x; i < DIM * DIM; i += 256) Ms[i] = Mg[i];
    if (threadIdx.x < QD) Bcs[threadIdx.x] = Bc[threadIdx.x];
    __syncthreads();

    const size_t b = (size_t)blockIdx.x * 256 + threadIdx.x;
    float g[DIM];
    #pragma unroll
    for (int i = 0; i < DIM; i += 4) {
        float4 v = *reinterpret_cast<const float4*>(grad + b * DIM + i);
        g[i] = v.x; g[i+1] = v.y; g[i+2] = v.z; g[i+3] = v.w;
    }
    const float ub = u[b];
    const float w  = (stage == 1 || stage == 2) ? 2.f : 1.f;
    const float cn = (stage == 2) ? DTC : (0.5f * DTC);

    #pragma unroll 2
    for (int i = 0; i < DIM; i++) {
        float v = 0.f;
        const float4* m4 = reinterpret_cast<const float4*>(&Ms[i * DIM]);
        #pragma unroll
        for (int j = 0; j < DIM / 4; j++) {
            float4 m = m4[j];
            v = fmaf(m.x, g[4*j+0], v); v = fmaf(m.y, g[4*j+1], v);
            v = fmaf(m.z, g[4*j+2], v); v = fmaf(m.w, g[4*j+3], v);
        }
        if (i >= QD) v = fmaf(ub, Bcs[i - QD], v);
        float a = (stage == 0 ? 0.f : acc[b * DIM + i]) + w * v;
        acc[b * DIM + i] = a;
        znext[b * DIM + i] = (stage < 3) ? fmaf(cn, v, zbase[b * DIM + i])
                                         : fmaf(DTC / 6.f, a, zbase[b * DIM + i]);
    }
}

// ---------------------------------------------------------------------------
// Host orchestration
// ---------------------------------------------------------------------------
extern "C" void kernel_launch(void* const* d_in, const int* in_sizes, int n_in,
                              void* d_out, int out_size) {
    const float* h    = (const float*)d_in[0];
    const float* u    = (const float*)d_in[1];
    const float* sW1  = (const float*)d_in[2];
    const float* sb1  = (const float*)d_in[3];
    const float* sW2  = (const float*)d_in[4];
    const float* sb2  = (const float*)d_in[5];
    const float* tW1  = (const float*)d_in[6];
    const float* tb1  = (const float*)d_in[7];
    const float* tW2  = (const float*)d_in[8];
    const float* tb2  = (const float*)d_in[9];
    const float* kW1  = (const float*)d_in[10];
    const float* kb1  = (const float*)d_in[11];
    const float* kW2  = (const float*)d_in[12];
    const float* kb2  = (const float*)d_in[13];
    const float* kW3  = (const float*)d_in[14];
    const float* vW1  = (const float*)d_in[16];
    const float* vb1  = (const float*)d_in[17];
    const float* vW2  = (const float*)d_in[18];
    const float* vb2  = (const float*)d_in[19];
    const float* vW3  = (const float*)d_in[20];
    const float* A    = (const float*)d_in[22];
    const float* Lp   = (const float*)d_in[23];
    const float* Bc   = (const float*)d_in[24];
    float* out = (float*)d_out;

    float *z, *zk, *grad, *acc, *h1, *gg2, *gg1, *kW1t, *kW2t, *vW1t, *vW2t, *Mp;
    cudaGetSymbolAddress((void**)&z,    g_z);
    cudaGetSymbolAddress((void**)&zk,   g_zk);
    cudaGetSymbolAddress((void**)&grad, g_grad);
    cudaGetSymbolAddress((void**)&acc,  g_acc);
    cudaGetSymbolAddress((void**)&h1,   g_h1);
    cudaGetSymbolAddress((void**)&gg2,  g_g2);
    cudaGetSymbolAddress((void**)&gg1,  g_g1);
    cudaGetSymbolAddress((void**)&kW1t, g_kW1t);
    cudaGetSymbolAddress((void**)&kW2t, g_kW2t);
    cudaGetSymbolAddress((void**)&vW1t, g_vW1t);
    cudaGetSymbolAddress((void**)&vW2t, g_vW2t);
    cudaGetSymbolAddress((void**)&Mp,   g_M);

    // prep: transposes + M (cheap, deterministic, per-call)
    transpose_k<<<(HH * DIM + 255) / 256, 256>>>(kW1, kW1t, HH, DIM);
    transpose_k<<<(HH * HH  + 255) / 256, 256>>>(kW2, kW2t, HH, HH);
    transpose_k<<<(HH * QD  + 255) / 256, 256>>>(vW1, vW1t, HH, QD);
    transpose_k<<<(HH * HH  + 255) / 256, 256>>>(vW2, vW2t, HH, HH);
    build_M_k<<<1, 256>>>(A, Lp, Mp);

    // s = flow_fwd(h)
    cudaMemcpyAsync(z, h, (size_t)BATCH * DIM * sizeof(float),
                    cudaMemcpyDeviceToDevice, 0);
    for (int l = 0; l < NLAYERS; l++)
        flow_layer_k<<<BATCH / 256, 256>>>(z, sW1, sb1, sW2, sb2,
                                           tW1, tb1, tW2, tb2, l, 0);
    cudaMemcpyAsync(zk, z, (size_t)BATCH * DIM * sizeof(float),
                    cudaMemcpyDeviceToDevice, 0);

    dim3 gN(BATCH / 128, HH / 64);  // N=256
    dim3 g1(BATCH / 128, 1);        // N<=64

    for (int st = 0; st < 4; st++) {
        // T-network gradient
        gemm_k<64, 4, EPI_SP>    <<<gN, 256>>>(zk,  DIM, kW1t, HH, kb1, 0, 0, h1,  HH, DIM);
        gemm_k<64, 4, EPI_G2>    <<<gN, 256>>>(h1,  HH,  kW2t, HH, kb2, kW3, 0, gg2, HH, HH);
        gemm_k<64, 4, EPI_MULSIG><<<gN, 256>>>(gg2, HH,  kW2,  HH, 0, 0, h1, gg1, HH, HH);
        gemm_k<64, 4, EPI_STORE> <<<g1, 256>>>(gg1, HH,  kW1,  DIM, 0, 0, 0, grad, DIM, HH);
        // V-network gradient (input = q = first 32 cols of zk)
        gemm_k<64, 4, EPI_SP>    <<<gN, 256>>>(zk,  DIM, vW1t, HH, vb1, 0, 0, h1,  HH, QD);
        gemm_k<64, 4, EPI_G2>    <<<gN, 256>>>(h1,  HH,  vW2t, HH, vb2, vW3, 0, gg2, HH, HH);
        gemm_k<64, 4, EPI_MULSIG><<<gN, 256>>>(gg2, HH,  vW2,  HH, 0, 0, h1, gg1, HH, HH);
        gemm_k<32, 2, EPI_ADDTO> <<<g1, 256>>>(gg1, HH,  vW1,  QD, 0, 0, 0, grad, DIM, HH);
        // dz = M @ grad ; dp += u*Bc ; RK4 update
        dyn_combine_k<<<BATCH / 256, 256>>>(grad, u, Bc, Mp, z, acc,
                                            (st < 3) ? zk : out, st);
    }

    // h_next = flow_inv(z_next) in place on the output buffer
    for (int l = NLAYERS - 1; l >= 0; l--)
        flow_layer_k<<<BATCH / 256, 256>>>(out, sW1, sb1, sW2, sb2,
                                           tW1, tb1, tW2, tb2, l, 1);
}

// round 3
// speedup vs baseline: 1.0003x; 1.0003x over previous
#include <cuda_runtime.h>
#include <math.h>

#define BATCH   131072
#define DIM     64
#define QD      32
#define NLAYERS 6
#define HF      128
#define HH      256
#define DTC     0.05f

// ---------------------------------------------------------------------------
// Scratch (static __device__ arrays -- the sanctioned alloc-free workaround)
// ---------------------------------------------------------------------------
__device__ float g_z   [BATCH * DIM];   // flow-forward output s = [q,p] (base point)
__device__ float g_zk  [BATCH * DIM];   // current RK4 stage input
__device__ float g_grad[BATCH * DIM];   // grad H accumulation
__device__ float g_acc [BATCH * DIM];   // RK4 weighted sum of dz
__device__ float g_h1  [BATCH * HH];    // softplus(a1) buffer
__device__ float g_g2  [BATCH * HH];    // g2 buffer
__device__ float g_g1  [BATCH * HH];    // g1 buffer
__device__ float g_kW1t[DIM * HH];
__device__ float g_kW2t[HH * HH];
__device__ float g_vW1t[QD * HH];
__device__ float g_vW2t[HH * HH];
__device__ float g_M   [DIM * DIM];

__device__ __forceinline__ float softplusf(float x) {
    return fmaxf(x, 0.f) + log1pf(expf(-fabsf(x)));
}

// ---------------------------------------------------------------------------
// Prep: transpose (out[c*R+r] = in[r*C+c])
// ---------------------------------------------------------------------------
__global__ void transpose_k(const float* __restrict__ in, float* __restrict__ out,
                            int R, int C) {
    int idx = blockIdx.x * 256 + threadIdx.x;
    if (idx < R * C) {
        int r = idx / C, c = idx % C;
        out[c * R + r] = in[idx];
    }
}

// ---------------------------------------------------------------------------
// Prep: M = (A - A^T) - L L^T,  L = tril(Lp,-1) + diag(softplus(diag(Lp)))
// ---------------------------------------------------------------------------
__global__ void build_M_k(const float* __restrict__ A, const float* __restrict__ Lp,
                          float* __restrict__ M) {
    __shared__ float L[DIM * DIM];
    int t = threadIdx.x;
    for (int idx = t; idx < DIM * DIM; idx += 256) {
        int i = idx >> 6, j = idx & 63;
        float v;
        if (i > j)       v = Lp[idx];
        else if (i == j) v = softplusf(Lp[idx]);
        else             v = 0.f;
        L[idx] = v;
    }
    __syncthreads();
    for (int idx = t; idx < DIM * DIM; idx += 256) {
        int i = idx >> 6, j = idx & 63;
        float s = 0.f;
        #pragma unroll 8
        for (int k = 0; k < DIM; k++) s += L[i * DIM + k] * L[j * DIM + k];
        M[idx] = A[i * DIM + j] - A[j * DIM + i] - s;
    }
}

// ---------------------------------------------------------------------------
// Fused RealNVP coupling layer (forward or inverse), one thread per row.
// Layer weights staged in SMEM; two passes (s-MLP then t-MLP) reuse the same
// 33KB of static SMEM.
// ---------------------------------------------------------------------------
__global__ __launch_bounds__(256)
void flow_layer_k(float* __restrict__ z,
                  const float* __restrict__ sW1, const float* __restrict__ sb1,
                  const float* __restrict__ sW2, const float* __restrict__ sb2,
                  const float* __restrict__ tW1, const float* __restrict__ tb1,
                  const float* __restrict__ tW2, const float* __restrict__ tb2,
                  int layer, int inverse) {
    __shared__ float W1s[HF * QD];   // [hidden][in]  (row contiguous)
    __shared__ float W2s[QD * HF];   // [out][hidden] (natural layout, broadcast reads)
    __shared__ float b1s[HF];
    __shared__ float b2s[QD];

    const int parity = layer & 1;
    const int tid    = threadIdx.x;
    const size_t b   = (size_t)blockIdx.x * 256 + tid;
    float* zrow      = z + b * DIM;
    const int coff   = parity ? QD : 0;   // conditioning half
    const int moff   = parity ? 0  : QD;  // modified half

    float cond[QD];
    #pragma unroll
    for (int i = 0; i < QD; i += 4) {
        float4 v = *reinterpret_cast<const float4*>(zrow + coff + i);
        cond[i] = v.x; cond[i+1] = v.y; cond[i+2] = v.z; cond[i+3] = v.w;
    }

    const float* lsW1 = sW1 + (size_t)layer * HF * QD;
    const float* lsb1 = sb1 + (size_t)layer * HF;
    const float* lsW2 = sW2 + (size_t)layer * QD * HF;
    const float* lsb2 = sb2 + (size_t)layer * QD;
    const float* ltW1 = tW1 + (size_t)layer * HF * QD;
    const float* ltb1 = tb1 + (size_t)layer * HF;
    const float* ltW2 = tW2 + (size_t)layer * QD * HF;
    const float* ltb2 = tb2 + (size_t)layer * QD;

    // ---- pass 1: s-MLP ----
    #pragma unroll
    for (int r = 0; r < 4; r++) {
        int lin = r * 256 + tid;
        *reinterpret_cast<float4*>(&W1s[lin * 4]) =
            *reinterpret_cast<const float4*>(lsW1 + lin * 4);
        *reinterpret_cast<float4*>(&W2s[lin * 4]) =
            *reinterpret_cast<const float4*>(lsW2 + lin * 4);
    }
    if (tid < HF) b1s[tid] = lsb1[tid];
    if (tid < QD) b2s[tid] = lsb2[tid];
    __syncthreads();

    float sacc[QD];
    #pragma unroll
    for (int n = 0; n < QD; n++) sacc[n] = b2s[n];
    #pragma unroll 2
    for (int j = 0; j < HF; j++) {
        float hsum = b1s[j];
        const float4* w4 = reinterpret_cast<const float4*>(&W1s[j * QD]);
        #pragma unroll
        for (int kk = 0; kk < QD / 4; kk++) {
            float4 w = w4[kk];
            hsum = fmaf(cond[kk*4+0], w.x, hsum);
            hsum = fmaf(cond[kk*4+1], w.y, hsum);
            hsum = fmaf(cond[kk*4+2], w.z, hsum);
            hsum = fmaf(cond[kk*4+3], w.w, hsum);
        }
        hsum = fmaxf(hsum, 0.f);
        #pragma unroll
        for (int n = 0; n < QD; n++) sacc[n] = fmaf(hsum, W2s[n * HF + j], sacc[n]);
    }
    __syncthreads();

    // ---- pass 2: t-MLP (reuse smem) ----
    #pragma unroll
    for (int r = 0; r < 4; r++) {
        int lin = r * 256 + tid;
        *reinterpret_cast<float4*>(&W1s[lin * 4]) =
            *reinterpret_cast<const float4*>(ltW1 + lin * 4);
        *reinterpret_cast<float4*>(&W2s[lin * 4]) =
            *reinterpret_cast<const float4*>(ltW2 + lin * 4);
    }
    if (tid < HF) b1s[tid] = ltb1[tid];
    if (tid < QD) b2s[tid] = ltb2[tid];
    __syncthreads();

    float tacc[QD];
    #pragma unroll
    for (int n = 0; n < QD; n++) tacc[n] = b2s[n];
    #pragma unroll 2
    for (int j = 0; j < HF; j++) {
        float hsum = b1s[j];
        const float4* w4 = reinterpret_cast<const float4*>(&W1s[j * QD]);
        #pragma unroll
        for (int kk = 0; kk < QD / 4; kk++) {
            float4 w = w4[kk];
            hsum = fmaf(cond[kk*4+0], w.x, hsum);
            hsum = fmaf(cond[kk*4+1], w.y, hsum);
            hsum = fmaf(cond[kk*4+2], w.z, hsum);
            hsum = fmaf(cond[kk*4+3], w.w, hsum);
        }
        hsum = fmaxf(hsum, 0.f);
        #pragma unroll
        for (int n = 0; n < QD; n++) tacc[n] = fmaf(hsum, W2s[n * HF + j], tacc[n]);
    }

    // ---- affine update of the other half ----
    float xo[QD];
    #pragma unroll
    for (int i = 0; i < QD; i += 4) {
        float4 v = *reinterpret_cast<const float4*>(zrow + moff + i);
        xo[i] = v.x; xo[i+1] = v.y; xo[i+2] = v.z; xo[i+3] = v.w;
    }
    #pragma unroll
    for (int n = 0; n < QD; n++) {
        float s = tanhf(sacc[n]);
        float t = tacc[n];
        xo[n] = inverse ? (xo[n] - t) * expf(-s) : fmaf(xo[n], expf(s), t);
    }
    #pragma unroll
    for (int i = 0; i < QD; i += 4) {
        float4 v = make_float4(xo[i], xo[i+1], xo[i+2], xo[i+3]);
        *reinterpret_cast<float4*>(zrow + moff + i) = v;
    }
}

// ---------------------------------------------------------------------------
// Tiled SGEMM: C[B,N] = epilogue(A[B,K] @ W[K,N])
//   BM=128, BK=32, TM=8; BN/TN in {64/4, 32/2}; 256 threads.
// Epilogues:
//   EPI_SP     : softplus(acc + bias[n])
//   EPI_G2     : bias2[n] * sigmoid(acc + bias[n])
//   EPI_MULSIG : acc * (1 - exp(-aux[row,n]))    (aux = stored softplus)
//   EPI_STORE  : acc
//   EPI_ADDTO  : C += acc
// ---------------------------------------------------------------------------
#define EPI_SP     0
#define EPI_G2     1
#define EPI_MULSIG 2
#define EPI_STORE  3
#define EPI_ADDTO  4

template<int BN, int TN, int EPI>
__global__ __launch_bounds__(256)
void gemm_k(const float* __restrict__ A, int lda,
            const float* __restrict__ W, int ldw,
            const float* __restrict__ bias,
            const float* __restrict__ bias2,
            const float* __restrict__ aux,
            float* __restrict__ C, int ldc, int K) {
    constexpr int BM = 128, BK = 32, TM = 8;
    __shared__ float As[BK][BM + 1];
    __shared__ float Ws[BK][BN];

    const int tid  = threadIdx.x;
    const int tx   = tid % (BN / TN);
    const int ty   = tid / (BN / TN);
    const int row0 = blockIdx.x * BM;
    const int col0 = blockIdx.y * BN;

    float acc[TM][TN];
    #pragma unroll
    for (int i = 0; i < TM; i++)
        #pragma unroll
        for (int j = 0; j < TN; j++) acc[i][j] = 0.f;

    for (int k0 = 0; k0 < K; k0 += BK) {
        // stage A tile (transposed into As[k][m])
        #pragma unroll
        for (int r = 0; r < 4; r++) {
            int lin = r * 256 + tid;
            int m = lin >> 3, k4 = lin & 7;
            float4 v = *reinterpret_cast<const float4*>(
                A + (size_t)(row0 + m) * lda + k0 + k4 * 4);
            As[k4*4+0][m] = v.x; As[k4*4+1][m] = v.y;
            As[k4*4+2][m] = v.z; As[k4*4+3][m] = v.w;
        }
        // stage W tile
        constexpr int WIT = (BK * BN / 4) / 256;
        #pragma unroll
        for (int r = 0; r < WIT; r++) {
            int lin = r * 256 + tid;
            int n4 = lin % (BN / 4), k = lin / (BN / 4);
            *reinterpret_cast<float4*>(&Ws[k][n4 * 4]) =
                *reinterpret_cast<const float4*>(W + (size_t)(k0 + k) * ldw + col0 + n4 * 4);
        }
        __syncthreads();

        #pragma unroll
        for (int k = 0; k < BK; k++) {
            float rm[TM], rn[TN];
            #pragma unroll
            for (int i = 0; i < TM; i++) rm[i] = As[k][ty * TM + i];
            #pragma unroll
            for (int j = 0; j < TN; j++) rn[j] = Ws[k][tx * TN + j];
            #pragma unroll
            for (int i = 0; i < TM; i++)
                #pragma unroll
                for (int j = 0; j < TN; j++) acc[i][j] = fmaf(rm[i], rn[j], acc[i][j]);
        }
        __syncthreads();
    }

    #pragma unroll
    for (int i = 0; i < TM; i++) {
        const int row = row0 + ty * TM + i;
        #pragma unroll
        for (int j = 0; j < TN; j++) {
            const int n = col0 + tx * TN + j;
            float v = acc[i][j];
            if (EPI == EPI_SP) {
                v = softplusf(v + bias[n]);
            } else if (EPI == EPI_G2) {
                float a = v + bias[n];
                v = bias2[n] / (1.f + expf(-a));
            } else if (EPI == EPI_MULSIG) {
                v *= (1.f - expf(-aux[(size_t)row * HH + n]));
            } else if (EPI == EPI_ADDTO) {
                v += C[(size_t)row * ldc + n];
            }
            C[(size_t)row * ldc + n] = v;
        }
    }
}

// ---------------------------------------------------------------------------
// dz = M @ gradH (per row), dp += u*Bc, RK4 bookkeeping.
// stage<3: znext = zbase + c*DT*dz ; stage 3: znext = zbase + DT/6 * acc_total
// ---------------------------------------------------------------------------
__global__ __launch_bounds__(256)
void dyn_combine_k(const float* __restrict__ grad, const float* __restrict__ u,
                   const float* __restrict__ Bc, const float* __restrict__ Mg,
                   const float* __restrict__ zbase, float* __restrict__ acc,
                   float* __restrict__ znext, int stage) {
    __shared__ float Ms[DIM * DIM];
    __shared__ float Bcs[QD];
    for (int i = threadIdx.x; i < DIM * DIM; i += 256) Ms[i] = Mg[i];
    if (threadIdx.x < QD) Bcs[threadIdx.x] = Bc[threadIdx.x];
    __syncthreads();

    const size_t b = (size_t)blockIdx.x * 256 + threadIdx.x;
    float g[DIM];
    #pragma unroll
    for (int i = 0; i < DIM; i += 4) {
        float4 v = *reinterpret_cast<const float4*>(grad + b * DIM + i);
        g[i] = v.x; g[i+1] = v.y; g[i+2] = v.z; g[i+3] = v.w;
    }
    const float ub = u[b];
    const float w  = (stage == 1 || stage == 2) ? 2.f : 1.f;
    const float cn = (stage == 2) ? DTC : (0.5f * DTC);

    #pragma unroll 2
    for (int i = 0; i < DIM; i++) {
        float v = 0.f;
        const float4* m4 = reinterpret_cast<const float4*>(&Ms[i * DIM]);
        #pragma unroll
        for (int j = 0; j < DIM / 4; j++) {
            float4 m = m4[j];
            v = fmaf(m.x, g[4*j+0], v); v = fmaf(m.y, g[4*j+1], v);
            v = fmaf(m.z, g[4*j+2], v); v = fmaf(m.w, g[4*j+3], v);
        }
        if (i >= QD) v = fmaf(ub, Bcs[i - QD], v);
        float a = (stage == 0 ? 0.f : acc[b * DIM + i]) + w * v;
        acc[b * DIM + i] = a;
        znext[b * DIM + i] = (stage < 3) ? fmaf(cn, v, zbase[b * DIM + i])
                                         : fmaf(DTC / 6.f, a, zbase[b * DIM + i]);
    }
}

// ---------------------------------------------------------------------------
// Host orchestration
// ---------------------------------------------------------------------------
extern "C" void kernel_launch(void* const* d_in, const int* in_sizes, int n_in,
                              void* d_out, int out_size) {
    const float* h    = (const float*)d_in[0];
    const float* u    = (const float*)d_in[1];
    const float* sW1  = (const float*)d_in[2];
    const float* sb1  = (const float*)d_in[3];
    const float* sW2  = (const float*)d_in[4];
    const float* sb2  = (const float*)d_in[5];
    const float* tW1  = (const float*)d_in[6];
    const float* tb1  = (const float*)d_in[7];
    const float* tW2  = (const float*)d_in[8];
    const float* tb2  = (const float*)d_in[9];
    const float* kW1  = (const float*)d_in[10];
    const float* kb1  = (const float*)d_in[11];
    const float* kW2  = (const float*)d_in[12];
    const float* kb2  = (const float*)d_in[13];
    const float* kW3  = (const float*)d_in[14];
    const float* vW1  = (const float*)d_in[16];
    const float* vb1  = (const float*)d_in[17];
    const float* vW2  = (const float*)d_in[18];
    const float* vb2  = (const float*)d_in[19];
    const float* vW3  = (const float*)d_in[20];
    const float* A    = (const float*)d_in[22];
    const float* Lp   = (const float*)d_in[23];
    const float* Bc   = (const float*)d_in[24];
    float* out = (float*)d_out;

    float *z, *zk, *grad, *acc, *h1, *gg2, *gg1, *kW1t, *kW2t, *vW1t, *vW2t, *Mp;
    cudaGetSymbolAddress((void**)&z,    g_z);
    cudaGetSymbolAddress((void**)&zk,   g_zk);
    cudaGetSymbolAddress((void**)&grad, g_grad);
    cudaGetSymbolAddress((void**)&acc,  g_acc);
    cudaGetSymbolAddress((void**)&h1,   g_h1);
    cudaGetSymbolAddress((void**)&gg2,  g_g2);
    cudaGetSymbolAddress((void**)&gg1,  g_g1);
    cudaGetSymbolAddress((void**)&kW1t, g_kW1t);
    cudaGetSymbolAddress((void**)&kW2t, g_kW2t);
    cudaGetSymbolAddress((void**)&vW1t, g_vW1t);
    cudaGetSymbolAddress((void**)&vW2t, g_vW2t);
    cudaGetSymbolAddress((void**)&Mp,   g_M);

    // prep: transposes + M (cheap, deterministic, per-call)
    transpose_k<<<(HH * DIM + 255) / 256, 256>>>(kW1, kW1t, HH, DIM);
    transpose_k<<<(HH * HH  + 255) / 256, 256>>>(kW2, kW2t, HH, HH);
    transpose_k<<<(HH * QD  + 255) / 256, 256>>>(vW1, vW1t, HH, QD);
    transpose_k<<<(HH * HH  + 255) / 256, 256>>>(vW2, vW2t, HH, HH);
    build_M_k<<<1, 256>>>(A, Lp, Mp);

    // s = flow_fwd(h)
    cudaMemcpyAsync(z, h, (size_t)BATCH * DIM * sizeof(float),
                    cudaMemcpyDeviceToDevice, 0);
    for (int l = 0; l < NLAYERS; l++)
        flow_layer_k<<<BATCH / 256, 256>>>(z, sW1, sb1, sW2, sb2,
                                           tW1, tb1, tW2, tb2, l, 0);
    cudaMemcpyAsync(zk, z, (size_t)BATCH * DIM * sizeof(float),
                    cudaMemcpyDeviceToDevice, 0);

    dim3 gN(BATCH / 128, HH / 64);  // N=256
    dim3 g1(BATCH / 128, 1);        // N<=64

    for (int st = 0; st < 4; st++) {
        // T-network gradient
        gemm_k<64, 4, EPI_SP>    <<<gN, 256>>>(zk,  DIM, kW1t, HH, kb1, 0, 0, h1,  HH, DIM);
        gemm_k<64, 4, EPI_G2>    <<<gN, 256>>>(h1,  HH,  kW2t, HH, kb2, kW3, 0, gg2, HH, HH);
        gemm_k<64, 4, EPI_MULSIG><<<gN, 256>>>(gg2, HH,  kW2,  HH, 0, 0, h1, gg1, HH, HH);
        gemm_k<64, 4, EPI_STORE> <<<g1, 256>>>(gg1, HH,  kW1,  DIM, 0, 0, 0, grad, DIM, HH);
        // V-network gradient (input = q = first 32 cols of zk)
        gemm_k<64, 4, EPI_SP>    <<<gN, 256>>>(zk,  DIM, vW1t, HH, vb1, 0, 0, h1,  HH, QD);
        gemm_k<64, 4, EPI_G2>    <<<gN, 256>>>(h1,  HH,  vW2t, HH, vb2, vW3, 0, gg2, HH, HH);
        gemm_k<64, 4, EPI_MULSIG><<<gN, 256>>>(gg2, HH,  vW2,  HH, 0, 0, h1, gg1, HH, HH);
        gemm_k<32, 2, EPI_ADDTO> <<<g1, 256>>>(gg1, HH,  vW1,  QD, 0, 0, 0, grad, DIM, HH);
        // dz = M @ grad ; dp += u*Bc ; RK4 update
        dyn_combine_k<<<BATCH / 256, 256>>>(grad, u, Bc, Mp, z, acc,
                                            (st < 3) ? zk : out, st);
    }

    // h_next = flow_inv(z_next) in place on the output buffer
    for (int l = NLAYERS - 1; l >= 0; l--)
        flow_layer_k<<<BATCH / 256, 256>>>(out, sW1, sb1, sW2, sb2,
                                           tW1, tb1, tW2, tb2, l, 1);
}

// round 6
// speedup vs baseline: 2.2404x; 2.2397x over previous
#include <cuda_runtime.h>
#include <cuda_bf16.h>
#include <math.h>
#include <cstdint>

#define BATCH   131072
#define DIM     64
#define QD      32
#define NLAYERS 6
#define HF      128
#define HH      256
#define DTC     0.05f

// ===========================================================================
// Scratch (static __device__ arrays)
// ===========================================================================
__device__ __align__(16) float g_z   [BATCH * DIM];
__device__ __align__(16) float g_acc [BATCH * DIM];
__device__ __align__(16) float g_dzT [BATCH * DIM];
__device__ __align__(16) float g_dzV [BATCH * DIM];
__device__ __align__(16) __nv_bfloat16 g_zk [BATCH * DIM];
__device__ __align__(16) __nv_bfloat16 g_h1T[BATCH * HH];
__device__ __align__(16) __nv_bfloat16 g_h1V[BATCH * HH];
__device__ __align__(16) __nv_bfloat16 g_g2T[BATCH * HH];
__device__ __align__(16) __nv_bfloat16 g_g2V[BATCH * HH];
__device__ __align__(16) __nv_bfloat16 g_g1T[BATCH * HH];
__device__ __align__(16) __nv_bfloat16 g_g1V[BATCH * HH];
// bf16 weight images, plain row-major [N][K]
__device__ __align__(16) __nv_bfloat16 g_Bk1 [HH * 64];
__device__ __align__(16) __nv_bfloat16 g_Bv1 [HH * 64];
__device__ __align__(16) __nv_bfloat16 g_Bk2 [HH * HH];
__device__ __align__(16) __nv_bfloat16 g_Bv2 [HH * HH];
__device__ __align__(16) __nv_bfloat16 g_Bk2t[HH * HH];
__device__ __align__(16) __nv_bfloat16 g_Bv2t[HH * HH];
__device__ __align__(16) __nv_bfloat16 g_BkM [64 * HH];
__device__ __align__(16) __nv_bfloat16 g_BvM [64 * HH];
__device__ float g_M[DIM * DIM];

__device__ __forceinline__ float softplusf(float x) {
    return fmaxf(x, 0.f) + log1pf(expf(-fabsf(x)));
}

__device__ __forceinline__ uint32_t smem_u32(const void* p) {
    uint32_t a;
    asm("{ .reg .u64 t; cvta.to.shared.u64 t, %1; cvt.u32.u64 %0, t; }"
        : "=r"(a) : "l"(p));
    return a;
}

__device__ __forceinline__ uint32_t lds32(uint32_t addr) {
    uint32_t v;
    asm("ld.shared.b32 %0, [%1];" : "=r"(v) : "r"(addr));
    return v;
}

__device__ __forceinline__ void mma16816(float* c, uint32_t a0, uint32_t a1,
                                         uint32_t a2, uint32_t a3,
                                         uint32_t b0, uint32_t b1) {
    asm volatile(
        "mma.sync.aligned.m16n8k16.row.col.f32.bf16.bf16.f32 "
        "{%0,%1,%2,%3},{%4,%5,%6,%7},{%8,%9},{%0,%1,%2,%3};"
        : "+f"(c[0]), "+f"(c[1]), "+f"(c[2]), "+f"(c[3])
        : "r"(a0), "r"(a1), "r"(a2), "r"(a3), "r"(b0), "r"(b1));
}

// ===========================================================================
// Prep kernels
// ===========================================================================
__global__ void build_M_k(const float* __restrict__ A, const float* __restrict__ Lp,
                          float* __restrict__ M) {
    __shared__ float L[DIM * DIM];
    int t = threadIdx.x;
    for (int idx = t; idx < DIM * DIM; idx += 256) {
        int i = idx >> 6, j = idx & 63;
        float v;
        if (i > j)       v = Lp[idx];
        else if (i == j) v = softplusf(Lp[idx]);
        else             v = 0.f;
        L[idx] = v;
    }
    __syncthreads();
    for (int idx = t; idx < DIM * DIM; idx += 256) {
        int i = idx >> 6, j = idx & 63;
        float s = 0.f;
        #pragma unroll 8
        for (int k = 0; k < DIM; k++) s += L[i * DIM + k] * L[j * DIM + k];
        M[idx] = A[i * DIM + j] - A[j * DIM + i] - s;
    }
}

// dst[r*K+k] = transpose ? src[k*srcld + r] : (k < srcld ? src[r*srcld + k] : 0)
__global__ void pack_k(const float* __restrict__ src, __nv_bfloat16* __restrict__ dst,
                       int R, int K, int srcld, int transpose) {
    int idx = blockIdx.x * 256 + threadIdx.x;
    if (idx >= R * K) return;
    int r = idx / K, k = idx % K;
    float v = transpose ? src[(size_t)k * srcld + r]
                        : ((k < srcld) ? src[(size_t)r * srcld + k] : 0.f);
    dst[idx] = __float2bfloat16(v);
}

// dst[i*256+k] = sum_{n<nc} W1[k*nc+n] * M[i*64+n]   ([64 rows][256 cols])
__global__ void pack_BM_k(const float* __restrict__ W1, int nc,
                          const float* __restrict__ M, __nv_bfloat16* __restrict__ dst) {
    int idx = blockIdx.x * 256 + threadIdx.x;
    if (idx >= 64 * HH) return;
    int i = idx >> 8, k = idx & 255;
    float s = 0.f;
    for (int n = 0; n < nc; n++) s += W1[k * nc + n] * M[i * 64 + n];
    dst[idx] = __float2bfloat16(s);
}

__global__ void f2bf_k(const float* __restrict__ s, __nv_bfloat16* __restrict__ d) {
    int i = blockIdx.x * 256 + threadIdx.x;
    float4 v = reinterpret_cast<const float4*>(s)[i];
    __nv_bfloat162 a; a.x = __float2bfloat16(v.x); a.y = __float2bfloat16(v.y);
    __nv_bfloat162 b; b.x = __float2bfloat16(v.z); b.y = __float2bfloat16(v.w);
    reinterpret_cast<__nv_bfloat162*>(d)[2 * i]     = a;
    reinterpret_cast<__nv_bfloat162*>(d)[2 * i + 1] = b;
}

// ===========================================================================
// Warp-MMA bf16 GEMM: C[128-tile, N] = epi( A[B,K] @ W[N,K]^T )
//   CTA tile 128 x BN, full K in smem (row pad +8 elems -> stride = 4 banks
//   mod 32 -> the (t/4, t%4) fragment gather rotates conflict-free).
//   Fragments gathered with plain ld.shared.b32 (4B-aligned by construction;
//   no ldmatrix, no 16B alignment hazard).
//   8 warps: 4 (M) x 2 (N); warp tile 32 x BN/2.
//   EPI 0: softplus(x + bias[n]) -> bf16     EPI 1: w3[n]*sigmoid(x+bias) -> bf16
//   EPI 2: x * (1 - exp(-aux))   -> bf16     EPI 3: x -> fp32
//   blockIdx.z selects the (T, V) operand set.
// ===========================================================================
template<int K, int BN, int EPI>
__global__ __launch_bounds__(256)
void gemm_mma(const __nv_bfloat16* __restrict__ A0, const __nv_bfloat16* __restrict__ A1,
              const __nv_bfloat16* __restrict__ B0, const __nv_bfloat16* __restrict__ B1,
              const float* __restrict__ bias0, const float* __restrict__ bias1,
              const float* __restrict__ w30,  const float* __restrict__ w31,
              const __nv_bfloat16* __restrict__ aux0, const __nv_bfloat16* __restrict__ aux1,
              void* __restrict__ C0, void* __restrict__ C1, int Nld) {
    constexpr int LDE = K + 8;           // padded bf16 elements per smem row
    extern __shared__ __align__(16) char smraw[];
    __nv_bfloat16* smA = reinterpret_cast<__nv_bfloat16*>(smraw);   // 128 x LDE
    __nv_bfloat16* smB = smA + 128 * LDE;                           // BN  x LDE

    const int tid = threadIdx.x, wid = tid >> 5, lane = tid & 31;
    const int zi = blockIdx.z;
    const __nv_bfloat16* A   = zi ? A1 : A0;
    const __nv_bfloat16* Bw  = zi ? B1 : B0;
    const float* bia         = zi ? bias1 : bias0;
    const float* w3          = zi ? w31 : w30;
    const __nv_bfloat16* aux = zi ? aux1 : aux0;
    char* Cc                 = (char*)(zi ? C1 : C0);

    const size_t row0 = (size_t)blockIdx.x * 128;
    const int    col0 = blockIdx.y * BN;

    // ---- stage A [128, K] and W [BN, K] (row-major, padded rows) ----
    constexpr int ASEG = K / 8;          // uint4 segments per row
    #pragma unroll 4
    for (int c = tid; c < 128 * ASEG; c += 256) {
        int r = c / ASEG, s = c % ASEG;
        *reinterpret_cast<uint4*>(smA + r * LDE + s * 8) =
            *reinterpret_cast<const uint4*>(A + (row0 + r) * K + s * 8);
    }
    #pragma unroll 4
    for (int c = tid; c < BN * ASEG; c += 256) {
        int r = c / ASEG, s = c % ASEG;
        *reinterpret_cast<uint4*>(smB + r * LDE + s * 8) =
            *reinterpret_cast<const uint4*>(Bw + (size_t)(col0 + r) * K + s * 8);
    }
    __syncthreads();

    const int wm = wid & 3;              // 0..3  -> 32-row strip
    const int wn = wid >> 2;             // 0..1  -> BN/2-col strip
    constexpr int WN = BN / 2;
    constexpr int NT = WN / 8;           // n8-tiles per warp
    const int g = lane >> 2;             // 0..7
    const int j = lane & 3;              // 0..3

    float acc[2][NT][4];
    #pragma unroll
    for (int mt = 0; mt < 2; mt++)
        #pragma unroll
        for (int nt = 0; nt < NT; nt++)
            #pragma unroll
            for (int i = 0; i < 4; i++) acc[mt][nt][i] = 0.f;

    // per-lane base byte addresses (k0 = 0)
    const uint32_t sA = smem_u32(smA), sB = smem_u32(smB);
    uint32_t aBase[2];
    #pragma unroll
    for (int mt = 0; mt < 2; mt++)
        aBase[mt] = sA + (uint32_t)(((wm * 32 + mt * 16 + g) * LDE + 2 * j) * 2);
    uint32_t bBase[NT];
    #pragma unroll
    for (int nt = 0; nt < NT; nt++)
        bBase[nt] = sB + (uint32_t)(((wn * WN + nt * 8 + g) * LDE + 2 * j) * 2);

    constexpr uint32_t ROW8 = (uint32_t)(8 * LDE * 2);   // +8 rows (bytes)

    #pragma unroll 4
    for (int kc = 0; kc < K / 16; kc++) {
        const uint32_t kb = (uint32_t)(kc * 32);         // +16 k elems (bytes)
        uint32_t a[2][4];
        #pragma unroll
        for (int mt = 0; mt < 2; mt++) {
            a[mt][0] = lds32(aBase[mt] + kb);
            a[mt][1] = lds32(aBase[mt] + kb + ROW8);
            a[mt][2] = lds32(aBase[mt] + kb + 16);
            a[mt][3] = lds32(aBase[mt] + kb + ROW8 + 16);
        }
        uint32_t b[NT][2];
        #pragma unroll
        for (int nt = 0; nt < NT; nt++) {
            b[nt][0] = lds32(bBase[nt] + kb);
            b[nt][1] = lds32(bBase[nt] + kb + 16);
        }
        #pragma unroll
        for (int mt = 0; mt < 2; mt++)
            #pragma unroll
            for (int nt = 0; nt < NT; nt++)
                mma16816(acc[mt][nt], a[mt][0], a[mt][1], a[mt][2], a[mt][3],
                         b[nt][0], b[nt][1]);
    }

    // ---- epilogue straight from fragments ----
    #pragma unroll
    for (int mt = 0; mt < 2; mt++) {
        const size_t r0 = row0 + wm * 32 + mt * 16 + (lane >> 2);
        const size_t r1 = r0 + 8;
        #pragma unroll
        for (int nt = 0; nt < NT; nt++) {
            const int gc = col0 + wn * WN + nt * 8 + (lane & 3) * 2;
            float v0 = acc[mt][nt][0], v1 = acc[mt][nt][1];
            float v2 = acc[mt][nt][2], v3 = acc[mt][nt][3];
            if (EPI == 3) {
                *reinterpret_cast<float2*>((float*)Cc + r0 * Nld + gc) =
                    make_float2(v0, v1);
                *reinterpret_cast<float2*>((float*)Cc + r1 * Nld + gc) =
                    make_float2(v2, v3);
            } else {
                if (EPI == 0) {
                    float b0 = bia[gc], b1 = bia[gc + 1];
                    v0 = softplusf(v0 + b0); v1 = softplusf(v1 + b1);
                    v2 = softplusf(v2 + b0); v3 = softplusf(v3 + b1);
                } else if (EPI == 1) {
                    float b0 = bia[gc], b1 = bia[gc + 1];
                    float s0 = w3[gc], s1 = w3[gc + 1];
                    v0 = s0 / (1.f + expf(-(v0 + b0)));
                    v1 = s1 / (1.f + expf(-(v1 + b1)));
                    v2 = s0 / (1.f + expf(-(v2 + b0)));
                    v3 = s1 / (1.f + expf(-(v3 + b1)));
                } else if (EPI == 2) {
                    __nv_bfloat162 h0 = *reinterpret_cast<const __nv_bfloat162*>(
                        aux + r0 * HH + gc);
                    __nv_bfloat162 h1 = *reinterpret_cast<const __nv_bfloat162*>(
                        aux + r1 * HH + gc);
                    v0 *= (1.f - expf(-__bfloat162float(h0.x)));
                    v1 *= (1.f - expf(-__bfloat162float(h0.y)));
                    v2 *= (1.f - expf(-__bfloat162float(h1.x)));
                    v3 *= (1.f - expf(-__bfloat162float(h1.y)));
                }
                __nv_bfloat162 o0; o0.x = __float2bfloat16(v0); o0.y = __float2bfloat16(v1);
                __nv_bfloat162 o1; o1.x = __float2bfloat16(v2); o1.y = __float2bfloat16(v3);
                *reinterpret_cast<__nv_bfloat162*>(
                    (__nv_bfloat16*)Cc + r0 * Nld + gc) = o0;
                *reinterpret_cast<__nv_bfloat162*>(
                    (__nv_bfloat16*)Cc + r1 * Nld + gc) = o1;
            }
        }
    }
}

// ===========================================================================
// RK4 elementwise combine
// ===========================================================================
__global__ __launch_bounds__(256)
void rk4_k(const float* __restrict__ dzT, const float* __restrict__ dzV,
           const float* __restrict__ u, const float* __restrict__ Bc,
           const float* __restrict__ z, float* __restrict__ acc,
           __nv_bfloat16* __restrict__ zk, float* __restrict__ out, int stage) {
    size_t idx = (size_t)blockIdx.x * 256 + threadIdx.x;
    int col = (int)(idx & 63);
    size_t row = idx >> 6;
    float dz = dzT[idx] + dzV[idx];
    if (col >= QD) dz += u[row] * Bc[col - QD];
    float w = (stage == 1 || stage == 2) ? 2.f : 1.f;
    float a = (stage == 0 ? 0.f : acc[idx]) + w * dz;
    acc[idx] = a;
    if (stage < 3) {
        float cn = (stage == 2) ? DTC : 0.5f * DTC;
        zk[idx] = __float2bfloat16(fmaf(cn, dz, z[idx]));
    } else {
        out[idx] = fmaf(DTC / 6.f, a, z[idx]);
    }
}

// ===========================================================================
// Fused RealNVP coupling layer (fp32, proven)
// ===========================================================================
__global__ __launch_bounds__(256)
void flow_layer_k(float* __restrict__ z,
                  const float* __restrict__ sW1, const float* __restrict__ sb1,
                  const float* __restrict__ sW2, const float* __restrict__ sb2,
                  const float* __restrict__ tW1, const float* __restrict__ tb1,
                  const float* __restrict__ tW2, const float* __restrict__ tb2,
                  int layer, int inverse) {
    __shared__ float W1s[HF * QD];
    __shared__ float W2s[QD * HF];
    __shared__ float b1s[HF];
    __shared__ float b2s[QD];

    const int parity = layer & 1;
    const int tid    = threadIdx.x;
    const size_t b   = (size_t)blockIdx.x * 256 + tid;
    float* zrow      = z + b * DIM;
    const int coff   = parity ? QD : 0;
    const int moff   = parity ? 0  : QD;

    float cond[QD];
    #pragma unroll
    for (int i = 0; i < QD; i += 4) {
        float4 v = *reinterpret_cast<const float4*>(zrow + coff + i);
        cond[i] = v.x; cond[i+1] = v.y; cond[i+2] = v.z; cond[i+3] = v.w;
    }

    const float* lsW1 = sW1 + (size_t)layer * HF * QD;
    const float* lsb1 = sb1 + (size_t)layer * HF;
    const float* lsW2 = sW2 + (size_t)layer * QD * HF;
    const float* lsb2 = sb2 + (size_t)layer * QD;
    const float* ltW1 = tW1 + (size_t)layer * HF * QD;
    const float* ltb1 = tb1 + (size_t)layer * HF;
    const float* ltW2 = tW2 + (size_t)layer * QD * HF;
    const float* ltb2 = tb2 + (size_t)layer * QD;

    #pragma unroll
    for (int r = 0; r < 4; r++) {
        int lin = r * 256 + tid;
        *reinterpret_cast<float4*>(&W1s[lin * 4]) =
            *reinterpret_cast<const float4*>(lsW1 + lin * 4);
        *reinterpret_cast<float4*>(&W2s[lin * 4]) =
            *reinterpret_cast<const float4*>(lsW2 + lin * 4);
    }
    if (tid < HF) b1s[tid] = lsb1[tid];
    if (tid < QD) b2s[tid] = lsb2[tid];
    __syncthreads();

    float sacc[QD];
    #pragma unroll
    for (int n = 0; n < QD; n++) sacc[n] = b2s[n];
    #pragma unroll 2
    for (int j = 0; j < HF; j++) {
        float hsum = b1s[j];
        const float4* w4 = reinterpret_cast<const float4*>(&W1s[j * QD]);
        #pragma unroll
        for (int kk = 0; kk < QD / 4; kk++) {
            float4 w = w4[kk];
            hsum = fmaf(cond[kk*4+0], w.x, hsum);
            hsum = fmaf(cond[kk*4+1], w.y, hsum);
            hsum = fmaf(cond[kk*4+2], w.z, hsum);
            hsum = fmaf(cond[kk*4+3], w.w, hsum);
        }
        hsum = fmaxf(hsum, 0.f);
        #pragma unroll
        for (int n = 0; n < QD; n++) sacc[n] = fmaf(hsum, W2s[n * HF + j], sacc[n]);
    }
    __syncthreads();

    #pragma unroll
    for (int r = 0; r < 4; r++) {
        int lin = r * 256 + tid;
        *reinterpret_cast<float4*>(&W1s[lin * 4]) =
            *reinterpret_cast<const float4*>(ltW1 + lin * 4);
        *reinterpret_cast<float4*>(&W2s[lin * 4]) =
            *reinterpret_cast<const float4*>(ltW2 + lin * 4);
    }
    if (tid < HF) b1s[tid] = ltb1[tid];
    if (tid < QD) b2s[tid] = ltb2[tid];
    __syncthreads();

    float tacc[QD];
    #pragma unroll
    for (int n = 0; n < QD; n++) tacc[n] = b2s[n];
    #pragma unroll 2
    for (int j = 0; j < HF; j++) {
        float hsum = b1s[j];
        const float4* w4 = reinterpret_cast<const float4*>(&W1s[j * QD]);
        #pragma unroll
        for (int kk = 0; kk < QD / 4; kk++) {
            float4 w = w4[kk];
            hsum = fmaf(cond[kk*4+0], w.x, hsum);
            hsum = fmaf(cond[kk*4+1], w.y, hsum);
            hsum = fmaf(cond[kk*4+2], w.z, hsum);
            hsum = fmaf(cond[kk*4+3], w.w, hsum);
        }
        hsum = fmaxf(hsum, 0.f);
        #pragma unroll
        for (int n = 0; n < QD; n++) tacc[n] = fmaf(hsum, W2s[n * HF + j], tacc[n]);
    }

    float xo[QD];
    #pragma unroll
    for (int i = 0; i < QD; i += 4) {
        float4 v = *reinterpret_cast<const float4*>(zrow + moff + i);
        xo[i] = v.x; xo[i+1] = v.y; xo[i+2] = v.z; xo[i+3] = v.w;
    }
    #pragma unroll
    for (int n = 0; n < QD; n++) {
        float s = tanhf(sacc[n]);
        float t = tacc[n];
        xo[n] = inverse ? (xo[n] - t) * expf(-s) : fmaf(xo[n], expf(s), t);
    }
    #pragma unroll
    for (int i = 0; i < QD; i += 4) {
        float4 v = make_float4(xo[i], xo[i+1], xo[i+2], xo[i+3]);
        *reinterpret_cast<float4*>(zrow + moff + i) = v;
    }
}

// ===========================================================================
// Host orchestration
// ===========================================================================
extern "C" void kernel_launch(void* const* d_in, const int* in_sizes, int n_in,
                              void* d_out, int out_size) {
    const float* h    = (const float*)d_in[0];
    const float* u    = (const float*)d_in[1];
    const float* sW1  = (const float*)d_in[2];
    const float* sb1  = (const float*)d_in[3];
    const float* sW2  = (const float*)d_in[4];
    const float* sb2  = (const float*)d_in[5];
    const float* tW1  = (const float*)d_in[6];
    const float* tb1  = (const float*)d_in[7];
    const float* tW2  = (const float*)d_in[8];
    const float* tb2  = (const float*)d_in[9];
    const float* kW1  = (const float*)d_in[10];
    const float* kb1  = (const float*)d_in[11];
    const float* kW2  = (const float*)d_in[12];
    const float* kb2  = (const float*)d_in[13];
    const float* kW3  = (const float*)d_in[14];
    const float* vW1  = (const float*)d_in[16];
    const float* vb1  = (const float*)d_in[17];
    const float* vW2  = (const float*)d_in[18];
    const float* vb2  = (const float*)d_in[19];
    const float* vW3  = (const float*)d_in[20];
    const float* A    = (const float*)d_in[22];
    const float* Lp   = (const float*)d_in[23];
    const float* Bc   = (const float*)d_in[24];
    float* out = (float*)d_out;

    float *z, *acc, *dzT, *dzV, *Mp;
    __nv_bfloat16 *zk, *h1T, *h1V, *g2T, *g2V, *g1T, *g1V;
    __nv_bfloat16 *Bk1, *Bv1, *Bk2, *Bv2, *Bk2t, *Bv2t, *BkM, *BvM;
    cudaGetSymbolAddress((void**)&z,    g_z);
    cudaGetSymbolAddress((void**)&acc,  g_acc);
    cudaGetSymbolAddress((void**)&dzT,  g_dzT);
    cudaGetSymbolAddress((void**)&dzV,  g_dzV);
    cudaGetSymbolAddress((void**)&zk,   g_zk);
    cudaGetSymbolAddress((void**)&h1T,  g_h1T);
    cudaGetSymbolAddress((void**)&h1V,  g_h1V);
    cudaGetSymbolAddress((void**)&g2T,  g_g2T);
    cudaGetSymbolAddress((void**)&g2V,  g_g2V);
    cudaGetSymbolAddress((void**)&g1T,  g_g1T);
    cudaGetSymbolAddress((void**)&g1V,  g_g1V);
    cudaGetSymbolAddress((void**)&Bk1,  g_Bk1);
    cudaGetSymbolAddress((void**)&Bv1,  g_Bv1);
    cudaGetSymbolAddress((void**)&Bk2,  g_Bk2);
    cudaGetSymbolAddress((void**)&Bv2,  g_Bv2);
    cudaGetSymbolAddress((void**)&Bk2t, g_Bk2t);
    cudaGetSymbolAddress((void**)&Bv2t, g_Bv2t);
    cudaGetSymbolAddress((void**)&BkM,  g_BkM);
    cudaGetSymbolAddress((void**)&BvM,  g_BvM);
    cudaGetSymbolAddress((void**)&Mp,   g_M);

    // dynamic smem per instantiation: (128 + BN) * (K + 8) * 2 bytes
    const int SM1 = (128 + 128) * (64 + 8)  * 2;   //  36,864
    const int SM2 = (128 + 128) * (256 + 8) * 2;   // 135,168
    const int SM4 = (128 + 64)  * (256 + 8) * 2;   // 101,376
    cudaFuncSetAttribute(gemm_mma<64, 128, 0>,
                         cudaFuncAttributeMaxDynamicSharedMemorySize, SM1);
    cudaFuncSetAttribute(gemm_mma<256, 128, 1>,
                         cudaFuncAttributeMaxDynamicSharedMemorySize, SM2);
    cudaFuncSetAttribute(gemm_mma<256, 128, 2>,
                         cudaFuncAttributeMaxDynamicSharedMemorySize, SM2);
    cudaFuncSetAttribute(gemm_mma<256, 64, 3>,
                         cudaFuncAttributeMaxDynamicSharedMemorySize, SM4);

    // ---- prep ----
    build_M_k<<<1, 256>>>(A, Lp, Mp);
    pack_k<<<(HH * 64 + 255) / 256, 256>>>(kW1, Bk1, HH, 64, 64, 0);
    pack_k<<<(HH * 64 + 255) / 256, 256>>>(vW1, Bv1, HH, 64, 32, 0);  // K zero-padded
    pack_k<<<(HH * HH + 255) / 256, 256>>>(kW2, Bk2, HH, HH, HH, 0);
    pack_k<<<(HH * HH + 255) / 256, 256>>>(vW2, Bv2, HH, HH, HH, 0);
    pack_k<<<(HH * HH + 255) / 256, 256>>>(kW2, Bk2t, HH, HH, HH, 1);
    pack_k<<<(HH * HH + 255) / 256, 256>>>(vW2, Bv2t, HH, HH, HH, 1);
    pack_BM_k<<<(64 * HH + 255) / 256, 256>>>(kW1, 64, Mp, BkM);
    pack_BM_k<<<(64 * HH + 255) / 256, 256>>>(vW1, 32, Mp, BvM);

    // ---- s = flow_fwd(h) ----
    cudaMemcpyAsync(z, h, (size_t)BATCH * DIM * sizeof(float),
                    cudaMemcpyDeviceToDevice, 0);
    for (int l = 0; l < NLAYERS; l++)
        flow_layer_k<<<BATCH / 256, 256>>>(z, sW1, sb1, sW2, sb2,
                                           tW1, tb1, tW2, tb2, l, 0);
    f2bf_k<<<BATCH * DIM / 1024, 256>>>(z, zk);

    // ---- RK4 stages ----
    dim3 gBig(BATCH / 128, 2, 2);   // N=256 GEMMs (2 col blocks) x (T,V)
    dim3 gSml(BATCH / 128, 1, 2);   // N=64 GEMM x (T,V)
    for (int st = 0; st < 4; st++) {
        gemm_mma<64, 128, 0><<<gBig, 256, SM1>>>(
            zk, zk, Bk1, Bv1, kb1, vb1, 0, 0, 0, 0, h1T, h1V, HH);
        gemm_mma<256, 128, 1><<<gBig, 256, SM2>>>(
            h1T, h1V, Bk2, Bv2, kb2, vb2, kW3, vW3, 0, 0, g2T, g2V, HH);
        gemm_mma<256, 128, 2><<<gBig, 256, SM2>>>(
            g2T, g2V, Bk2t, Bv2t, 0, 0, 0, 0, h1T, h1V, g1T, g1V, HH);
        gemm_mma<256, 64, 3><<<gSml, 256, SM4>>>(
            g1T, g1V, BkM, BvM, 0, 0, 0, 0, 0, 0, dzT, dzV, DIM);
        rk4_k<<<BATCH * DIM / 256, 256>>>(dzT, dzV, u, Bc, z, acc, zk, out, st);
    }

    // ---- h_next = flow_inv(z_next) in place on out ----
    for (int l = NLAYERS - 1; l >= 0; l--)
        flow_layer_k<<<BATCH / 256, 256>>>(out, sW1, sb1, sW2, sb2,
                                           tW1, tb1, tW2, tb2, l, 1);
}

// round 7
// speedup vs baseline: 2.7376x; 1.2219x over previous
#include <cuda_runtime.h>
#include <cuda_bf16.h>
#include <math.h>
#include <cstdint>

#define BATCH   131072
#define DIM     64
#define QD      32
#define NLAYERS 6
#define HF      128
#define HH      256
#define DTC     0.05f

// ===========================================================================
// Scratch (static __device__ arrays)
// ===========================================================================
__device__ __align__(16) float g_z   [BATCH * DIM];
__device__ __align__(16) float g_acc [BATCH * DIM];
__device__ __align__(16) float g_dzT [BATCH * DIM];
__device__ __align__(16) float g_dzV [BATCH * DIM];
__device__ __align__(16) __nv_bfloat16 g_zk [BATCH * DIM];
__device__ __align__(16) __nv_bfloat16 g_h1T[BATCH * HH];
__device__ __align__(16) __nv_bfloat16 g_h1V[BATCH * HH];
__device__ __align__(16) __nv_bfloat16 g_g2T[BATCH * HH];
__device__ __align__(16) __nv_bfloat16 g_g2V[BATCH * HH];
__device__ __align__(16) __nv_bfloat16 g_g1T[BATCH * HH];
__device__ __align__(16) __nv_bfloat16 g_g1V[BATCH * HH];
// bf16 weight images, plain row-major [N][K]
__device__ __align__(16) __nv_bfloat16 g_Bk1 [HH * 64];
__device__ __align__(16) __nv_bfloat16 g_Bv1 [HH * 64];
__device__ __align__(16) __nv_bfloat16 g_Bk2 [HH * HH];
__device__ __align__(16) __nv_bfloat16 g_Bv2 [HH * HH];
__device__ __align__(16) __nv_bfloat16 g_Bk2t[HH * HH];
__device__ __align__(16) __nv_bfloat16 g_Bv2t[HH * HH];
__device__ __align__(16) __nv_bfloat16 g_BkM [64 * HH];
__device__ __align__(16) __nv_bfloat16 g_BvM [64 * HH];
__device__ float g_M[DIM * DIM];

__device__ __forceinline__ float softplusf(float x) {
    return fmaxf(x, 0.f) + log1pf(expf(-fabsf(x)));
}

__device__ __forceinline__ uint32_t smem_u32(const void* p) {
    uint32_t a;
    asm("{ .reg .u64 t; cvta.to.shared.u64 t, %1; cvt.u32.u64 %0, t; }"
        : "=r"(a) : "l"(p));
    return a;
}

__device__ __forceinline__ uint32_t lds32(uint32_t addr) {
    uint32_t v;
    asm("ld.shared.b32 %0, [%1];" : "=r"(v) : "r"(addr));
    return v;
}

__device__ __forceinline__ void cpasync16(uint32_t dst, const void* src) {
    asm volatile("cp.async.cg.shared.global [%0], [%1], 16;"
                 :: "r"(dst), "l"(src));
}

__device__ __forceinline__ void cp_commit() {
    asm volatile("cp.async.commit_group;");
}

template<int N>
__device__ __forceinline__ void cp_wait() {
    asm volatile("cp.async.wait_group %0;" :: "n"(N));
}

__device__ __forceinline__ void mma16816(float* c, uint32_t a0, uint32_t a1,
                                         uint32_t a2, uint32_t a3,
                                         uint32_t b0, uint32_t b1) {
    asm volatile(
        "mma.sync.aligned.m16n8k16.row.col.f32.bf16.bf16.f32 "
        "{%0,%1,%2,%3},{%4,%5,%6,%7},{%8,%9},{%0,%1,%2,%3};"
        : "+f"(c[0]), "+f"(c[1]), "+f"(c[2]), "+f"(c[3])
        : "r"(a0), "r"(a1), "r"(a2), "r"(a3), "r"(b0), "r"(b1));
}

// ===========================================================================
// Prep kernels
// ===========================================================================
__global__ void build_M_k(const float* __restrict__ A, const float* __restrict__ Lp,
                          float* __restrict__ M) {
    __shared__ float L[DIM * DIM];
    int t = threadIdx.x;
    for (int idx = t; idx < DIM * DIM; idx += 256) {
        int i = idx >> 6, j = idx & 63;
        float v;
        if (i > j)       v = Lp[idx];
        else if (i == j) v = softplusf(Lp[idx]);
        else             v = 0.f;
        L[idx] = v;
    }
    __syncthreads();
    for (int idx = t; idx < DIM * DIM; idx += 256) {
        int i = idx >> 6, j = idx & 63;
        float s = 0.f;
        #pragma unroll 8
        for (int k = 0; k < DIM; k++) s += L[i * DIM + k] * L[j * DIM + k];
        M[idx] = A[i * DIM + j] - A[j * DIM + i] - s;
    }
}

__global__ void pack_k(const float* __restrict__ src, __nv_bfloat16* __restrict__ dst,
                       int R, int K, int srcld, int transpose) {
    int idx = blockIdx.x * 256 + threadIdx.x;
    if (idx >= R * K) return;
    int r = idx / K, k = idx % K;
    float v = transpose ? src[(size_t)k * srcld + r]
                        : ((k < srcld) ? src[(size_t)r * srcld + k] : 0.f);
    dst[idx] = __float2bfloat16(v);
}

__global__ void pack_BM_k(const float* __restrict__ W1, int nc,
                          const float* __restrict__ M, __nv_bfloat16* __restrict__ dst) {
    int idx = blockIdx.x * 256 + threadIdx.x;
    if (idx >= 64 * HH) return;
    int i = idx >> 8, k = idx & 255;
    float s = 0.f;
    for (int n = 0; n < nc; n++) s += W1[k * nc + n] * M[i * 64 + n];
    dst[idx] = __float2bfloat16(s);
}

__global__ void f2bf_k(const float* __restrict__ s, __nv_bfloat16* __restrict__ d) {
    int i = blockIdx.x * 256 + threadIdx.x;
    float4 v = reinterpret_cast<const float4*>(s)[i];
    __nv_bfloat162 a; a.x = __float2bfloat16(v.x); a.y = __float2bfloat16(v.y);
    __nv_bfloat162 b; b.x = __float2bfloat16(v.z); b.y = __float2bfloat16(v.w);
    reinterpret_cast<__nv_bfloat162*>(d)[2 * i]     = a;
    reinterpret_cast<__nv_bfloat162*>(d)[2 * i + 1] = b;
}

// ===========================================================================
// Shared epilogue for both GEMM variants
// ===========================================================================
template<int EPI, int NT>
__device__ __forceinline__ void gemm_epilogue(
    float acc[2][NT][4], size_t row0, int col0, int wm, int wn, int WN,
    int lane, const float* bia, const float* w3, const __nv_bfloat16* aux,
    char* Cc, int Nld) {
    #pragma unroll
    for (int mt = 0; mt < 2; mt++) {
        const size_t r0 = row0 + wm * 32 + mt * 16 + (lane >> 2);
        const size_t r1 = r0 + 8;
        #pragma unroll
        for (int nt = 0; nt < NT; nt++) {
            const int gc = col0 + wn * WN + nt * 8 + (lane & 3) * 2;
            float v0 = acc[mt][nt][0], v1 = acc[mt][nt][1];
            float v2 = acc[mt][nt][2], v3 = acc[mt][nt][3];
            if (EPI == 3) {
                *reinterpret_cast<float2*>((float*)Cc + r0 * Nld + gc) =
                    make_float2(v0, v1);
                *reinterpret_cast<float2*>((float*)Cc + r1 * Nld + gc) =
                    make_float2(v2, v3);
            } else {
                if (EPI == 0) {
                    float b0 = bia[gc], b1 = bia[gc + 1];
                    v0 = softplusf(v0 + b0); v1 = softplusf(v1 + b1);
                    v2 = softplusf(v2 + b0); v3 = softplusf(v3 + b1);
                } else if (EPI == 1) {
                    float b0 = bia[gc], b1 = bia[gc + 1];
                    float s0 = w3[gc], s1 = w3[gc + 1];
                    v0 = s0 / (1.f + expf(-(v0 + b0)));
                    v1 = s1 / (1.f + expf(-(v1 + b1)));
                    v2 = s0 / (1.f + expf(-(v2 + b0)));
                    v3 = s1 / (1.f + expf(-(v3 + b1)));
                } else if (EPI == 2) {
                    __nv_bfloat162 h0 = *reinterpret_cast<const __nv_bfloat162*>(
                        aux + r0 * HH + gc);
                    __nv_bfloat162 h1 = *reinterpret_cast<const __nv_bfloat162*>(
                        aux + r1 * HH + gc);
                    v0 *= (1.f - expf(-__bfloat162float(h0.x)));
                    v1 *= (1.f - expf(-__bfloat162float(h0.y)));
                    v2 *= (1.f - expf(-__bfloat162float(h1.x)));
                    v3 *= (1.f - expf(-__bfloat162float(h1.y)));
                }
                __nv_bfloat162 o0; o0.x = __float2bfloat16(v0); o0.y = __float2bfloat16(v1);
                __nv_bfloat162 o1; o1.x = __float2bfloat16(v2); o1.y = __float2bfloat16(v3);
                *reinterpret_cast<__nv_bfloat162*>(
                    (__nv_bfloat16*)Cc + r0 * Nld + gc) = o0;
                *reinterpret_cast<__nv_bfloat162*>(
                    (__nv_bfloat16*)Cc + r1 * Nld + gc) = o1;
            }
        }
    }
}

// ===========================================================================
// Single-shot warp-MMA GEMM (K=64 only; proven in round 6)
// ===========================================================================
template<int K, int BN, int EPI>
__global__ __launch_bounds__(256)
void gemm_mma(const __nv_bfloat16* __restrict__ A0, const __nv_bfloat16* __restrict__ A1,
              const __nv_bfloat16* __restrict__ B0, const __nv_bfloat16* __restrict__ B1,
              const float* __restrict__ bias0, const float* __restrict__ bias1,
              const float* __restrict__ w30,  const float* __restrict__ w31,
              const __nv_bfloat16* __restrict__ aux0, const __nv_bfloat16* __restrict__ aux1,
              void* __restrict__ C0, void* __restrict__ C1, int Nld) {
    constexpr int LDE = K + 8;
    extern __shared__ __align__(16) char smraw[];
    __nv_bfloat16* smA = reinterpret_cast<__nv_bfloat16*>(smraw);
    __nv_bfloat16* smB = smA + 128 * LDE;

    const int tid = threadIdx.x, wid = tid >> 5, lane = tid & 31;
    const int zi = blockIdx.z;
    const __nv_bfloat16* A   = zi ? A1 : A0;
    const __nv_bfloat16* Bw  = zi ? B1 : B0;
    const float* bia         = zi ? bias1 : bias0;
    const float* w3          = zi ? w31 : w30;
    const __nv_bfloat16* aux = zi ? aux1 : aux0;
    char* Cc                 = (char*)(zi ? C1 : C0);

    const size_t row0 = (size_t)blockIdx.x * 128;
    const int    col0 = blockIdx.y * BN;

    constexpr int ASEG = K / 8;
    #pragma unroll 4
    for (int c = tid; c < 128 * ASEG; c += 256) {
        int r = c / ASEG, s = c % ASEG;
        *reinterpret_cast<uint4*>(smA + r * LDE + s * 8) =
            *reinterpret_cast<const uint4*>(A + (row0 + r) * K + s * 8);
    }
    #pragma unroll 4
    for (int c = tid; c < BN * ASEG; c += 256) {
        int r = c / ASEG, s = c % ASEG;
        *reinterpret_cast<uint4*>(smB + r * LDE + s * 8) =
            *reinterpret_cast<const uint4*>(Bw + (size_t)(col0 + r) * K + s * 8);
    }
    __syncthreads();

    const int wm = wid & 3;
    const int wn = wid >> 2;
    constexpr int WN = BN / 2;
    constexpr int NT = WN / 8;
    const int g = lane >> 2;
    const int j = lane & 3;

    float acc[2][NT][4];
    #pragma unroll
    for (int mt = 0; mt < 2; mt++)
        #pragma unroll
        for (int nt = 0; nt < NT; nt++)
            #pragma unroll
            for (int i = 0; i < 4; i++) acc[mt][nt][i] = 0.f;

    const uint32_t sA = smem_u32(smA), sB = smem_u32(smB);
    uint32_t aBase[2];
    #pragma unroll
    for (int mt = 0; mt < 2; mt++)
        aBase[mt] = sA + (uint32_t)(((wm * 32 + mt * 16 + g) * LDE + 2 * j) * 2);
    uint32_t bBase[NT];
    #pragma unroll
    for (int nt = 0; nt < NT; nt++)
        bBase[nt] = sB + (uint32_t)(((wn * WN + nt * 8 + g) * LDE + 2 * j) * 2);

    constexpr uint32_t ROW8 = (uint32_t)(8 * LDE * 2);

    #pragma unroll 4
    for (int kc = 0; kc < K / 16; kc++) {
        const uint32_t kb = (uint32_t)(kc * 32);
        uint32_t a[2][4];
        #pragma unroll
        for (int mt = 0; mt < 2; mt++) {
            a[mt][0] = lds32(aBase[mt] + kb);
            a[mt][1] = lds32(aBase[mt] + kb + ROW8);
            a[mt][2] = lds32(aBase[mt] + kb + 16);
            a[mt][3] = lds32(aBase[mt] + kb + ROW8 + 16);
        }
        uint32_t b[NT][2];
        #pragma unroll
        for (int nt = 0; nt < NT; nt++) {
            b[nt][0] = lds32(bBase[nt] + kb);
            b[nt][1] = lds32(bBase[nt] + kb + 16);
        }
        #pragma unroll
        for (int mt = 0; mt < 2; mt++)
            #pragma unroll
            for (int nt = 0; nt < NT; nt++)
                mma16816(acc[mt][nt], a[mt][0], a[mt][1], a[mt][2], a[mt][3],
                         b[nt][0], b[nt][1]);
    }

    gemm_epilogue<EPI, NT>(acc, row0, col0, wm, wn, WN, lane, bia, w3, aux, Cc, Nld);
}

// ===========================================================================
// cp.async 3-stage pipelined warp-MMA GEMM (K = 256, BK = 64)
//   smem = 3 * (128 + BN) * 72 * 2 bytes -> 2 CTAs/SM; staging overlaps MMA.
// ===========================================================================
template<int K, int BN, int EPI>
__global__ __launch_bounds__(256, 2)
void gemm_pipe(const __nv_bfloat16* __restrict__ A0, const __nv_bfloat16* __restrict__ A1,
               const __nv_bfloat16* __restrict__ B0, const __nv_bfloat16* __restrict__ B1,
               const float* __restrict__ bias0, const float* __restrict__ bias1,
               const float* __restrict__ w30,  const float* __restrict__ w31,
               const __nv_bfloat16* __restrict__ aux0, const __nv_bfloat16* __restrict__ aux1,
               void* __restrict__ C0, void* __restrict__ C1, int Nld) {
    constexpr int BK   = 64;
    constexpr int LDE  = BK + 8;                 // 72 elems; 144B row ≡ 4 banks mod 32
    constexpr int NSTG = 3;
    constexpr int NCH  = K / BK;                 // 4
    constexpr int STGE = (128 + BN) * LDE;       // elements per stage
    extern __shared__ __align__(16) __nv_bfloat16 sm[];

    const int tid = threadIdx.x, wid = tid >> 5, lane = tid & 31;
    const int zi = blockIdx.z;
    const __nv_bfloat16* A   = zi ? A1 : A0;
    const __nv_bfloat16* Bw  = zi ? B1 : B0;
    const float* bia         = zi ? bias1 : bias0;
    const float* w3          = zi ? w31 : w30;
    const __nv_bfloat16* aux = zi ? aux1 : aux0;
    char* Cc                 = (char*)(zi ? C1 : C0);

    const size_t row0 = (size_t)blockIdx.x * 128;
    const int    col0 = blockIdx.y * BN;
    const uint32_t sm0 = smem_u32(sm);

    // issue async loads of chunk c into stage s
    auto load_chunk = [&](int s, int c) {
        const uint32_t dstS = sm0 + (uint32_t)(s * STGE * 2);
        const int k0 = c * BK;
        #pragma unroll
        for (int t = tid; t < (128 + BN) * 8; t += 256) {
            int r = t >> 3, seg = t & 7;
            if (r < 128) {
                cpasync16(dstS + (uint32_t)((r * LDE + seg * 8) * 2),
                          A + (row0 + r) * K + k0 + seg * 8);
            } else {
                int rb = r - 128;
                cpasync16(dstS + (uint32_t)(((128 + rb) * LDE + seg * 8) * 2),
                          Bw + (size_t)(col0 + rb) * K + k0 + seg * 8);
            }
        }
    };

    const int wm = wid & 3;
    const int wn = wid >> 2;
    constexpr int WN = BN / 2;
    constexpr int NT = WN / 8;
    const int g = lane >> 2;
    const int j = lane & 3;

    float acc[2][NT][4];
    #pragma unroll
    for (int mt = 0; mt < 2; mt++)
        #pragma unroll
        for (int nt = 0; nt < NT; nt++)
            #pragma unroll
            for (int i = 0; i < 4; i++) acc[mt][nt][i] = 0.f;

    // stage-0 relative fragment addresses
    uint32_t aBase[2];
    #pragma unroll
    for (int mt = 0; mt < 2; mt++)
        aBase[mt] = sm0 + (uint32_t)(((wm * 32 + mt * 16 + g) * LDE + 2 * j) * 2);
    uint32_t bBase[NT];
    #pragma unroll
    for (int nt = 0; nt < NT; nt++)
        bBase[nt] = sm0 + (uint32_t)(((128 + wn * WN + nt * 8 + g) * LDE + 2 * j) * 2);
    constexpr uint32_t ROW8 = (uint32_t)(8 * LDE * 2);

    // prologue: 2 committed groups (loads 0 and 1)
    load_chunk(0, 0); cp_commit();
    load_chunk(1, 1); cp_commit();

    for (int c = 0; c < NCH; c++) {
        cp_wait<1>();            // newest group (load c+1) may be in flight; load c done
        __syncthreads();
        const uint32_t soff = (uint32_t)((c % NSTG) * STGE * 2);
        #pragma unroll
        for (int kc = 0; kc < BK / 16; kc++) {
            const uint32_t kb = soff + (uint32_t)(kc * 32);
            uint32_t a[2][4];
            #pragma unroll
            for (int mt = 0; mt < 2; mt++) {
                a[mt][0] = lds32(aBase[mt] + kb);
                a[mt][1] = lds32(aBase[mt] + kb + ROW8);
                a[mt][2] = lds32(aBase[mt] + kb + 16);
                a[mt][3] = lds32(aBase[mt] + kb + ROW8 + 16);
            }
            uint32_t b[NT][2];
            #pragma unroll
            for (int nt = 0; nt < NT; nt++) {
                b[nt][0] = lds32(bBase[nt] + kb);
                b[nt][1] = lds32(bBase[nt] + kb + 16);
            }
            #pragma unroll
            for (int mt = 0; mt < 2; mt++)
                #pragma unroll
                for (int nt = 0; nt < NT; nt++)
                    mma16816(acc[mt][nt], a[mt][0], a[mt][1], a[mt][2], a[mt][3],
                             b[nt][0], b[nt][1]);
        }
        __syncthreads();         // all warps done reading stage (c%NSTG) before reuse
        if (c + 2 < NCH) load_chunk((c + 2) % NSTG, c + 2);
        cp_commit();             // commit every iteration (possibly empty) to keep
                                 // wait_group<1> indexing exact in the tail
    }

    gemm_epilogue<EPI, NT>(acc, row0, col0, wm, wn, WN, lane, bia, w3, aux, Cc, Nld);
}

// ===========================================================================
// RK4 elementwise combine
// ===========================================================================
__global__ __launch_bounds__(256)
void rk4_k(const float* __restrict__ dzT, const float* __restrict__ dzV,
           const float* __restrict__ u, const float* __restrict__ Bc,
           const float* __restrict__ z, float* __restrict__ acc,
           __nv_bfloat16* __restrict__ zk, float* __restrict__ out, int stage) {
    size_t idx = (size_t)blockIdx.x * 256 + threadIdx.x;
    int col = (int)(idx & 63);
    size_t row = idx >> 6;
    float dz = dzT[idx] + dzV[idx];
    if (col >= QD) dz += u[row] * Bc[col - QD];
    float w = (stage == 1 || stage == 2) ? 2.f : 1.f;
    float a = (stage == 0 ? 0.f : acc[idx]) + w * dz;
    acc[idx] = a;
    if (stage < 3) {
        float cn = (stage == 2) ? DTC : 0.5f * DTC;
        zk[idx] = __float2bfloat16(fmaf(cn, dz, z[idx]));
    } else {
        out[idx] = fmaf(DTC / 6.f, a, z[idx]);
    }
}

// ===========================================================================
// Fused RealNVP coupling layer (fp32, proven)
// ===========================================================================
__global__ __launch_bounds__(256)
void flow_layer_k(float* __restrict__ z,
                  const float* __restrict__ sW1, const float* __restrict__ sb1,
                  const float* __restrict__ sW2, const float* __restrict__ sb2,
                  const float* __restrict__ tW1, const float* __restrict__ tb1,
                  const float* __restrict__ tW2, const float* __restrict__ tb2,
                  int layer, int inverse) {
    __shared__ float W1s[HF * QD];
    __shared__ float W2s[QD * HF];
    __shared__ float b1s[HF];
    __shared__ float b2s[QD];

    const int parity = layer & 1;
    const int tid    = threadIdx.x;
    const size_t b   = (size_t)blockIdx.x * 256 + tid;
    float* zrow      = z + b * DIM;
    const int coff   = parity ? QD : 0;
    const int moff   = parity ? 0  : QD;

    float cond[QD];
    #pragma unroll
    for (int i = 0; i < QD; i += 4) {
        float4 v = *reinterpret_cast<const float4*>(zrow + coff + i);
        cond[i] = v.x; cond[i+1] = v.y; cond[i+2] = v.z; cond[i+3] = v.w;
    }

    const float* lsW1 = sW1 + (size_t)layer * HF * QD;
    const float* lsb1 = sb1 + (size_t)layer * HF;
    const float* lsW2 = sW2 + (size_t)layer * QD * HF;
    const float* lsb2 = sb2 + (size_t)layer * QD;
    const float* ltW1 = tW1 + (size_t)layer * HF * QD;
    const float* ltb1 = tb1 + (size_t)layer * HF;
    const float* ltW2 = tW2 + (size_t)layer * QD * HF;
    const float* ltb2 = tb2 + (size_t)layer * QD;

    #pragma unroll
    for (int r = 0; r < 4; r++) {
        int lin = r * 256 + tid;
        *reinterpret_cast<float4*>(&W1s[lin * 4]) =
            *reinterpret_cast<const float4*>(lsW1 + lin * 4);
        *reinterpret_cast<float4*>(&W2s[lin * 4]) =
            *reinterpret_cast<const float4*>(lsW2 + lin * 4);
    }
    if (tid < HF) b1s[tid] = lsb1[tid];
    if (tid < QD) b2s[tid] = lsb2[tid];
    __syncthreads();

    float sacc[QD];
    #pragma unroll
    for (int n = 0; n < QD; n++) sacc[n] = b2s[n];
    #pragma unroll 2
    for (int j = 0; j < HF; j++) {
        float hsum = b1s[j];
        const float4* w4 = reinterpret_cast<const float4*>(&W1s[j * QD]);
        #pragma unroll
        for (int kk = 0; kk < QD / 4; kk++) {
            float4 w = w4[kk];
            hsum = fmaf(cond[kk*4+0], w.x, hsum);
            hsum = fmaf(cond[kk*4+1], w.y, hsum);
            hsum = fmaf(cond[kk*4+2], w.z, hsum);
            hsum = fmaf(cond[kk*4+3], w.w, hsum);
        }
        hsum = fmaxf(hsum, 0.f);
        #pragma unroll
        for (int n = 0; n < QD; n++) sacc[n] = fmaf(hsum, W2s[n * HF + j], sacc[n]);
    }
    __syncthreads();

    #pragma unroll
    for (int r = 0; r < 4; r++) {
        int lin = r * 256 + tid;
        *reinterpret_cast<float4*>(&W1s[lin * 4]) =
            *reinterpret_cast<const float4*>(ltW1 + lin * 4);
        *reinterpret_cast<float4*>(&W2s[lin * 4]) =
            *reinterpret_cast<const float4*>(ltW2 + lin * 4);
    }
    if (tid < HF) b1s[tid] = ltb1[tid];
    if (tid < QD) b2s[tid] = ltb2[tid];
    __syncthreads();

    float tacc[QD];
    #pragma unroll
    for (int n = 0; n < QD; n++) tacc[n] = b2s[n];
    #pragma unroll 2
    for (int j = 0; j < HF; j++) {
        float hsum = b1s[j];
        const float4* w4 = reinterpret_cast<const float4*>(&W1s[j * QD]);
        #pragma unroll
        for (int kk = 0; kk < QD / 4; kk++) {
            float4 w = w4[kk];
            hsum = fmaf(cond[kk*4+0], w.x, hsum);
            hsum = fmaf(cond[kk*4+1], w.y, hsum);
            hsum = fmaf(cond[kk*4+2], w.z, hsum);
            hsum = fmaf(cond[kk*4+3], w.w, hsum);
        }
        hsum = fmaxf(hsum, 0.f);
        #pragma unroll
        for (int n = 0; n < QD; n++) tacc[n] = fmaf(hsum, W2s[n * HF + j], tacc[n]);
    }

    float xo[QD];
    #pragma unroll
    for (int i = 0; i < QD; i += 4) {
        float4 v = *reinterpret_cast<const float4*>(zrow + moff + i);
        xo[i] = v.x; xo[i+1] = v.y; xo[i+2] = v.z; xo[i+3] = v.w;
    }
    #pragma unroll
    for (int n = 0; n < QD; n++) {
        float s = tanhf(sacc[n]);
        float t = tacc[n];
        xo[n] = inverse ? (xo[n] - t) * expf(-s) : fmaf(xo[n], expf(s), t);
    }
    #pragma unroll
    for (int i = 0; i < QD; i += 4) {
        float4 v = make_float4(xo[i], xo[i+1], xo[i+2], xo[i+3]);
        *reinterpret_cast<float4*>(zrow + moff + i) = v;
    }
}

// ===========================================================================
// Host orchestration
// ===========================================================================
extern "C" void kernel_launch(void* const* d_in, const int* in_sizes, int n_in,
                              void* d_out, int out_size) {
    const float* h    = (const float*)d_in[0];
    const float* u    = (const float*)d_in[1];
    const float* sW1  = (const float*)d_in[2];
    const float* sb1  = (const float*)d_in[3];
    const float* sW2  = (const float*)d_in[4];
    const float* sb2  = (const float*)d_in[5];
    const float* tW1  = (const float*)d_in[6];
    const float* tb1  = (const float*)d_in[7];
    const float* tW2  = (const float*)d_in[8];
    const float* tb2  = (const float*)d_in[9];
    const float* kW1  = (const float*)d_in[10];
    const float* kb1  = (const float*)d_in[11];
    const float* kW2  = (const float*)d_in[12];
    const float* kb2  = (const float*)d_in[13];
    const float* kW3  = (const float*)d_in[14];
    const float* vW1  = (const float*)d_in[16];
    const float* vb1  = (const float*)d_in[17];
    const float* vW2  = (const float*)d_in[18];
    const float* vb2  = (const float*)d_in[19];
    const float* vW3  = (const float*)d_in[20];
    const float* A    = (const float*)d_in[22];
    const float* Lp   = (const float*)d_in[23];
    const float* Bc   = (const float*)d_in[24];
    float* out = (float*)d_out;

    float *z, *acc, *dzT, *dzV, *Mp;
    __nv_bfloat16 *zk, *h1T, *h1V, *g2T, *g2V, *g1T, *g1V;
    __nv_bfloat16 *Bk1, *Bv1, *Bk2, *Bv2, *Bk2t, *Bv2t, *BkM, *BvM;
    cudaGetSymbolAddress((void**)&z,    g_z);
    cudaGetSymbolAddress((void**)&acc,  g_acc);
    cudaGetSymbolAddress((void**)&dzT,  g_dzT);
    cudaGetSymbolAddress((void**)&dzV,  g_dzV);
    cudaGetSymbolAddress((void**)&zk,   g_zk);
    cudaGetSymbolAddress((void**)&h1T,  g_h1T);
    cudaGetSymbolAddress((void**)&h1V,  g_h1V);
    cudaGetSymbolAddress((void**)&g2T,  g_g2T);
    cudaGetSymbolAddress((void**)&g2V,  g_g2V);
    cudaGetSymbolAddress((void**)&g1T,  g_g1T);
    cudaGetSymbolAddress((void**)&g1V,  g_g1V);
    cudaGetSymbolAddress((void**)&Bk1,  g_Bk1);
    cudaGetSymbolAddress((void**)&Bv1,  g_Bv1);
    cudaGetSymbolAddress((void**)&Bk2,  g_Bk2);
    cudaGetSymbolAddress((void**)&Bv2,  g_Bv2);
    cudaGetSymbolAddress((void**)&Bk2t, g_Bk2t);
    cudaGetSymbolAddress((void**)&Bv2t, g_Bv2t);
    cudaGetSymbolAddress((void**)&BkM,  g_BkM);
    cudaGetSymbolAddress((void**)&BvM,  g_BvM);
    cudaGetSymbolAddress((void**)&Mp,   g_M);

    const int SM1 = (128 + 128) * (64 + 8) * 2;        // 36,864 (single-shot K=64)
    const int SMP128 = 3 * (128 + 128) * 72 * 2;       // 110,592 (pipe BN=128)
    const int SMP64  = 3 * (128 + 64)  * 72 * 2;       //  82,944 (pipe BN=64)
    cudaFuncSetAttribute(gemm_mma<64, 128, 0>,
                         cudaFuncAttributeMaxDynamicSharedMemorySize, SM1);
    cudaFuncSetAttribute(gemm_pipe<256, 128, 1>,
                         cudaFuncAttributeMaxDynamicSharedMemorySize, SMP128);
    cudaFuncSetAttribute(gemm_pipe<256, 128, 2>,
                         cudaFuncAttributeMaxDynamicSharedMemorySize, SMP128);
    cudaFuncSetAttribute(gemm_pipe<256, 64, 3>,
                         cudaFuncAttributeMaxDynamicSharedMemorySize, SMP64);

    // ---- prep ----
    build_M_k<<<1, 256>>>(A, Lp, Mp);
    pack_k<<<(HH * 64 + 255) / 256, 256>>>(kW1, Bk1, HH, 64, 64, 0);
    pack_k<<<(HH * 64 + 255) / 256, 256>>>(vW1, Bv1, HH, 64, 32, 0);  // K zero-padded
    pack_k<<<(HH * HH + 255) / 256, 256>>>(kW2, Bk2, HH, HH, HH, 0);
    pack_k<<<(HH * HH + 255) / 256, 256>>>(vW2, Bv2, HH, HH, HH, 0);
    pack_k<<<(HH * HH + 255) / 256, 256>>>(kW2, Bk2t, HH, HH, HH, 1);
    pack_k<<<(HH * HH + 255) / 256, 256>>>(vW2, Bv2t, HH, HH, HH, 1);
    pack_BM_k<<<(64 * HH + 255) / 256, 256>>>(kW1, 64, Mp, BkM);
    pack_BM_k<<<(64 * HH + 255) / 256, 256>>>(vW1, 32, Mp, BvM);

    // ---- s = flow_fwd(h) ----
    cudaMemcpyAsync(z, h, (size_t)BATCH * DIM * sizeof(float),
                    cudaMemcpyDeviceToDevice, 0);
    for (int l = 0; l < NLAYERS; l++)
        flow_layer_k<<<BATCH / 256, 256>>>(z, sW1, sb1, sW2, sb2,
                                           tW1, tb1, tW2, tb2, l, 0);
    f2bf_k<<<BATCH * DIM / 1024, 256>>>(z, zk);

    // ---- RK4 stages ----
    dim3 gBig(BATCH / 128, 2, 2);   // N=256 GEMMs (2 col blocks) x (T,V)
    dim3 gSml(BATCH / 128, 1, 2);   // N=64 GEMM x (T,V)
    for (int st = 0; st < 4; st++) {
        gemm_mma<64, 128, 0><<<gBig, 256, SM1>>>(
            zk, zk, Bk1, Bv1, kb1, vb1, 0, 0, 0, 0, h1T, h1V, HH);
        gemm_pipe<256, 128, 1><<<gBig, 256, SMP128>>>(
            h1T, h1V, Bk2, Bv2, kb2, vb2, kW3, vW3, 0, 0, g2T, g2V, HH);
        gemm_pipe<256, 128, 2><<<gBig, 256, SMP128>>>(
            g2T, g2V, Bk2t, Bv2t, 0, 0, 0, 0, h1T, h1V, g1T, g1V, HH);
        gemm_pipe<256, 64, 3><<<gSml, 256, SMP64>>>(
            g1T, g1V, BkM, BvM, 0, 0, 0, 0, 0, 0, dzT, dzV, DIM);
        rk4_k<<<BATCH * DIM / 256, 256>>>(dzT, dzV, u, Bc, z, acc, zk, out, st);
    }

    // ---- h_next = flow_inv(z_next) in place on out ----
    for (int l = NLAYERS - 1; l >= 0; l--)
        flow_layer_k<<<BATCH / 256, 256>>>(out, sW1, sb1, sW2, sb2,
                                           tW1, tb1, tW2, tb2, l, 1);
}

// round 8
// speedup vs baseline: 2.9420x; 1.0747x over previous
#include <cuda_runtime.h>
#include <cuda_bf16.h>
#include <math.h>
#include <cstdint>

#define BATCH   131072
#define DIM     64
#define QD      32
#define NLAYERS 6
#define HF      128
#define HH      256
#define DTC     0.05f

// ===========================================================================
// Scratch (static __device__ arrays)
// ===========================================================================
__device__ __align__(16) float g_z   [BATCH * DIM];
__device__ __align__(16) float g_acc [BATCH * DIM];
__device__ __align__(16) float g_dzT [BATCH * DIM];
__device__ __align__(16) float g_dzV [BATCH * DIM];
__device__ __align__(16) __nv_bfloat16 g_zk [BATCH * DIM];
__device__ __align__(16) __nv_bfloat16 g_h1T[BATCH * HH];
__device__ __align__(16) __nv_bfloat16 g_h1V[BATCH * HH];
__device__ __align__(16) __nv_bfloat16 g_g2T[BATCH * HH];
__device__ __align__(16) __nv_bfloat16 g_g2V[BATCH * HH];
__device__ __align__(16) __nv_bfloat16 g_g1T[BATCH * HH];
__device__ __align__(16) __nv_bfloat16 g_g1V[BATCH * HH];
// bf16 weight images, plain row-major [N][K]
__device__ __align__(16) __nv_bfloat16 g_Bk1 [HH * 64];
__device__ __align__(16) __nv_bfloat16 g_Bv1 [HH * 64];
__device__ __align__(16) __nv_bfloat16 g_Bk2 [HH * HH];
__device__ __align__(16) __nv_bfloat16 g_Bv2 [HH * HH];
__device__ __align__(16) __nv_bfloat16 g_Bk2t[HH * HH];
__device__ __align__(16) __nv_bfloat16 g_Bv2t[HH * HH];
__device__ __align__(16) __nv_bfloat16 g_BkM [64 * HH];
__device__ __align__(16) __nv_bfloat16 g_BvM [64 * HH];
__device__ float g_M[DIM * DIM];
// packed flow weights: per layer [sW1p 4096 | sW2q 4096 | tW1p 4096 | tW2q 4096]
__device__ __align__(16) float g_fpk[NLAYERS * 16384];

typedef unsigned long long ull;

__device__ __forceinline__ float softplusf(float x) {
    return fmaxf(x, 0.f) + log1pf(expf(-fabsf(x)));
}

__device__ __forceinline__ uint32_t smem_u32(const void* p) {
    uint32_t a;
    asm("{ .reg .u64 t; cvta.to.shared.u64 t, %1; cvt.u32.u64 %0, t; }"
        : "=r"(a) : "l"(p));
    return a;
}

__device__ __forceinline__ uint32_t lds32(uint32_t addr) {
    uint32_t v;
    asm("ld.shared.b32 %0, [%1];" : "=r"(v) : "r"(addr));
    return v;
}

__device__ __forceinline__ void ldsv2u64(uint32_t addr, ull& a, ull& b) {
    asm("ld.shared.v2.u64 {%0, %1}, [%2];" : "=l"(a), "=l"(b) : "r"(addr));
}

__device__ __forceinline__ ull fma2(ull a, ull b, ull c) {
    ull d;
    asm("fma.rn.f32x2 %0, %1, %2, %3;" : "=l"(d) : "l"(a), "l"(b), "l"(c));
    return d;
}

__device__ __forceinline__ ull add2(ull a, ull b) {
    ull d;
    asm("add.rn.f32x2 %0, %1, %2;" : "=l"(d) : "l"(a), "l"(b));
    return d;
}

__device__ __forceinline__ ull pack2(float lo, float hi) {
    ull d;
    asm("mov.b64 %0, {%1, %2};" : "=l"(d) : "f"(lo), "f"(hi));
    return d;
}

__device__ __forceinline__ void unpack2(ull v, float& lo, float& hi) {
    asm("mov.b64 {%0, %1}, %2;" : "=f"(lo), "=f"(hi) : "l"(v));
}

__device__ __forceinline__ void cpasync16(uint32_t dst, const void* src) {
    asm volatile("cp.async.cg.shared.global [%0], [%1], 16;"
                 :: "r"(dst), "l"(src));
}

__device__ __forceinline__ void cp_commit() {
    asm volatile("cp.async.commit_group;");
}

template<int N>
__device__ __forceinline__ void cp_wait() {
    asm volatile("cp.async.wait_group %0;" :: "n"(N));
}

__device__ __forceinline__ void mma16816(float* c, uint32_t a0, uint32_t a1,
                                         uint32_t a2, uint32_t a3,
                                         uint32_t b0, uint32_t b1) {
    asm volatile(
        "mma.sync.aligned.m16n8k16.row.col.f32.bf16.bf16.f32 "
        "{%0,%1,%2,%3},{%4,%5,%6,%7},{%8,%9},{%0,%1,%2,%3};"
        : "+f"(c[0]), "+f"(c[1]), "+f"(c[2]), "+f"(c[3])
        : "r"(a0), "r"(a1), "r"(a2), "r"(a3), "r"(b0), "r"(b1));
}

// ===========================================================================
// Prep kernels
// ===========================================================================
__global__ void build_M_k(const float* __restrict__ A, const float* __restrict__ Lp,
                          float* __restrict__ M) {
    __shared__ float L[DIM * DIM];
    int t = threadIdx.x;
    for (int idx = t; idx < DIM * DIM; idx += 256) {
        int i = idx >> 6, j = idx & 63;
        float v;
        if (i > j)       v = Lp[idx];
        else if (i == j) v = softplusf(Lp[idx]);
        else             v = 0.f;
        L[idx] = v;
    }
    __syncthreads();
    for (int idx = t; idx < DIM * DIM; idx += 256) {
        int i = idx >> 6, j = idx & 63;
        float s = 0.f;
        #pragma unroll 8
        for (int k = 0; k < DIM; k++) s += L[i * DIM + k] * L[j * DIM + k];
        M[idx] = A[i * DIM + j] - A[j * DIM + i] - s;
    }
}

// one kernel, tasks on blockIdx.y
__global__ void prep_pack_k(const float* __restrict__ kW1, const float* __restrict__ vW1,
                            const float* __restrict__ kW2, const float* __restrict__ vW2,
                            const float* __restrict__ M,
                            const float* __restrict__ sW1, const float* __restrict__ sW2,
                            const float* __restrict__ tW1, const float* __restrict__ tW2,
                            __nv_bfloat16* __restrict__ Bk1, __nv_bfloat16* __restrict__ Bv1,
                            __nv_bfloat16* __restrict__ Bk2, __nv_bfloat16* __restrict__ Bv2,
                            __nv_bfloat16* __restrict__ Bk2t, __nv_bfloat16* __restrict__ Bv2t,
                            __nv_bfloat16* __restrict__ BkM, __nv_bfloat16* __restrict__ BvM,
                            float* __restrict__ fpk) {
    int idx = blockIdx.x * 256 + threadIdx.x;
    int task = blockIdx.y;
    if (task == 0) {            // Bk1: identity copy [256][64]
        if (idx < HH * 64) Bk1[idx] = __float2bfloat16(kW1[idx]);
    } else if (task == 1) {     // Bv1: [256][64], K zero-padded from 32
        if (idx < HH * 64) {
            int r = idx >> 6, k = idx & 63;
            Bv1[idx] = __float2bfloat16(k < QD ? vW1[r * QD + k] : 0.f);
        }
    } else if (task == 2) {
        if (idx < HH * HH) Bk2[idx] = __float2bfloat16(kW2[idx]);
    } else if (task == 3) {
        if (idx < HH * HH) Bv2[idx] = __float2bfloat16(vW2[idx]);
    } else if (task == 4) {
        if (idx < HH * HH) {
            int r = idx >> 8, k = idx & 255;
            Bk2t[idx] = __float2bfloat16(kW2[k * HH + r]);
        }
    } else if (task == 5) {
        if (idx < HH * HH) {
            int r = idx >> 8, k = idx & 255;
            Bv2t[idx] = __float2bfloat16(vW2[k * HH + r]);
        }
    } else if (task == 6) {     // BkM[i][k] = sum_n kW1[k][n]*M[i][n]
        if (idx < 64 * HH) {
            int i = idx >> 8, k = idx & 255;
            float s = 0.f;
            for (int n = 0; n < 64; n++) s += kW1[k * 64 + n] * M[i * 64 + n];
            BkM[idx] = __float2bfloat16(s);
        }
    } else if (task == 7) {
        if (idx < 64 * HH) {
            int i = idx >> 8, k = idx & 255;
            float s = 0.f;
            for (int n = 0; n < QD; n++) s += vW1[k * QD + n] * M[i * 64 + n];
            BvM[idx] = __float2bfloat16(s);
        }
    } else if (task == 8) {     // flow W1p packing
        if (idx < NLAYERS * 2 * 4096) {
            int l = idx / 8192, rem = idx % 8192;
            int st = rem / 4096, r2 = rem % 4096;
            int j2 = r2 >> 6, k2 = (r2 >> 2) & 15, c = r2 & 3;
            int j = 2 * j2 + (c & 1), k = 2 * k2 + (c >> 1);
            const float* W = st ? tW1 : sW1;
            fpk[l * 16384 + st * 8192 + r2] = W[(l * HF + j) * QD + k];
        }
    } else {                    // task 9: flow W2q packing
        if (idx < NLAYERS * 2 * 4096) {
            int l = idx / 8192, rem = idx % 8192;
            int st = rem / 4096, r2 = rem % 4096;
            int j = r2 >> 5, n4 = (r2 >> 2) & 7, c = r2 & 3;
            int n = 4 * n4 + c;
            const float* W = st ? tW2 : sW2;
            fpk[l * 16384 + st * 8192 + 4096 + r2] = W[(l * QD + n) * HF + j];
        }
    }
}

__global__ void f2bf_k(const float* __restrict__ s, __nv_bfloat16* __restrict__ d) {
    int i = blockIdx.x * 256 + threadIdx.x;
    float4 v = reinterpret_cast<const float4*>(s)[i];
    __nv_bfloat162 a; a.x = __float2bfloat16(v.x); a.y = __float2bfloat16(v.y);
    __nv_bfloat162 b; b.x = __float2bfloat16(v.z); b.y = __float2bfloat16(v.w);
    reinterpret_cast<__nv_bfloat162*>(d)[2 * i]     = a;
    reinterpret_cast<__nv_bfloat162*>(d)[2 * i + 1] = b;
}

// ===========================================================================
// f32x2 RealNVP coupling layer.
//  Weights pre-packed per layer: W1p[j2][k2] float4 = {W1[2j2][2k2],W1[2j2+1][2k2],
//  W1[2j2][2k2+1],W1[2j2+1][2k2+1]}; W2q[j][n4] float4 = {W2[4n4][j]..W2[4n4+3][j]}.
//  Inner loops: ld.shared.v2.u64 + fma.rn.f32x2 (all broadcast reads).
// ===========================================================================
__device__ __forceinline__ void flow_mlp_pass(
    const float* __restrict__ wsrc,       // 8192 floats: W1p | W2q
    const float* __restrict__ b1g, const float* __restrict__ b2g,
    const ull condp[QD], ull acc[16],
    float4* Wp, float* b1s, float* b2s, int tid, uint32_t wbase) {
    // stage (128 threads)
    const float4* src4 = reinterpret_cast<const float4*>(wsrc);
    #pragma unroll
    for (int r = 0; r < 16; r++) Wp[r * 128 + tid] = src4[r * 128 + tid];
    b1s[tid] = b1g[tid];
    if (tid < QD) b2s[tid] = b2g[tid];
    __syncthreads();

    #pragma unroll
    for (int n2 = 0; n2 < 16; n2++) {
        float2 bb = *reinterpret_cast<float2*>(&b2s[2 * n2]);
        acc[n2] = pack2(bb.x, bb.y);
    }

    #pragma unroll 2
    for (int j2 = 0; j2 < 64; j2++) {
        float2 bb = *reinterpret_cast<float2*>(&b1s[2 * j2]);
        ull hA = pack2(bb.x, bb.y), hB = 0, hC = 0, hD = 0;
        const uint32_t a1 = wbase + (uint32_t)(j2 * 256);
        #pragma unroll
        for (int k2 = 0; k2 < 16; k2 += 2) {
            ull w0, w1, w2, w3;
            ldsv2u64(a1 + k2 * 16, w0, w1);
            ldsv2u64(a1 + k2 * 16 + 16, w2, w3);
            hA = fma2(w0, condp[2 * k2],     hA);
            hB = fma2(w1, condp[2 * k2 + 1], hB);
            hC = fma2(w2, condp[2 * k2 + 2], hC);
            hD = fma2(w3, condp[2 * k2 + 3], hD);
        }
        ull h2 = add2(add2(hA, hB), add2(hC, hD));
        float h0, h1;
        unpack2(h2, h0, h1);
        h0 = fmaxf(h0, 0.f); h1 = fmaxf(h1, 0.f);
        ull h00 = pack2(h0, h0), h11 = pack2(h1, h1);
        const uint32_t a2 = wbase + 16384u + (uint32_t)(j2 * 256);
        #pragma unroll
        for (int n4 = 0; n4 < 8; n4++) {
            ull wa, wb;
            ldsv2u64(a2 + n4 * 16, wa, wb);
            acc[2 * n4]     = fma2(wa, h00, acc[2 * n4]);
            acc[2 * n4 + 1] = fma2(wb, h00, acc[2 * n4 + 1]);
        }
        #pragma unroll
        for (int n4 = 0; n4 < 8; n4++) {
            ull wa, wb;
            ldsv2u64(a2 + 128 + n4 * 16, wa, wb);
            acc[2 * n4]     = fma2(wa, h11, acc[2 * n4]);
            acc[2 * n4 + 1] = fma2(wb, h11, acc[2 * n4 + 1]);
        }
    }
}

__global__ __launch_bounds__(128)
void flow2_k(float* __restrict__ z, const float* __restrict__ fpk,
             const float* __restrict__ sb1, const float* __restrict__ sb2,
             const float* __restrict__ tb1, const float* __restrict__ tb2,
             int layer, int inverse) {
    __shared__ __align__(16) float4 Wp[2048];   // W1p [0..1023], W2q [1024..2047]
    __shared__ __align__(16) float b1s[HF];
    __shared__ __align__(16) float b2s[QD];

    const int parity = layer & 1;
    const int tid    = threadIdx.x;
    const size_t b   = (size_t)blockIdx.x * 128 + tid;
    float* zrow      = z + b * DIM;
    const int coff   = parity ? QD : 0;
    const int moff   = parity ? 0  : QD;
    const uint32_t wbase = smem_u32(Wp);

    ull condp[QD];
    #pragma unroll
    for (int i = 0; i < QD; i += 4) {
        float4 v = *reinterpret_cast<const float4*>(zrow + coff + i);
        condp[i]   = pack2(v.x, v.x);
        condp[i+1] = pack2(v.y, v.y);
        condp[i+2] = pack2(v.z, v.z);
        condp[i+3] = pack2(v.w, v.w);
    }

    const float* wl = fpk + (size_t)layer * 16384;

    ull sres[16], tres[16];
    flow_mlp_pass(wl, sb1 + layer * HF, sb2 + layer * QD,
                  condp, sres, Wp, b1s, b2s, tid, wbase);
    __syncthreads();
    flow_mlp_pass(wl + 8192, tb1 + layer * HF, tb2 + layer * QD,
                  condp, tres, Wp, b1s, b2s, tid, wbase);

    float xo[QD];
    #pragma unroll
    for (int i = 0; i < QD; i += 4) {
        float4 v = *reinterpret_cast<const float4*>(zrow + moff + i);
        xo[i] = v.x; xo[i+1] = v.y; xo[i+2] = v.z; xo[i+3] = v.w;
    }
    #pragma unroll
    for (int n2 = 0; n2 < 16; n2++) {
        float s0, s1, t0, t1;
        unpack2(sres[n2], s0, s1);
        unpack2(tres[n2], t0, t1);
        s0 = tanhf(s0); s1 = tanhf(s1);
        if (inverse) {
            xo[2*n2]   = (xo[2*n2]   - t0) * expf(-s0);
            xo[2*n2+1] = (xo[2*n2+1] - t1) * expf(-s1);
        } else {
            xo[2*n2]   = fmaf(xo[2*n2],   expf(s0), t0);
            xo[2*n2+1] = fmaf(xo[2*n2+1], expf(s1), t1);
        }
    }
    #pragma unroll
    for (int i = 0; i < QD; i += 4) {
        *reinterpret_cast<float4*>(zrow + moff + i) =
            make_float4(xo[i], xo[i+1], xo[i+2], xo[i+3]);
    }
}

// ===========================================================================
// Shared GEMM epilogue
// ===========================================================================
template<int EPI, int NT>
__device__ __forceinline__ void gemm_epilogue(
    float acc[2][NT][4], size_t row0, int col0, int wm, int wn, int WN,
    int lane, const float* bia, const float* w3, const __nv_bfloat16* aux,
    char* Cc, int Nld) {
    #pragma unroll
    for (int mt = 0; mt < 2; mt++) {
        const size_t r0 = row0 + wm * 32 + mt * 16 + (lane >> 2);
        const size_t r1 = r0 + 8;
        #pragma unroll
        for (int nt = 0; nt < NT; nt++) {
            const int gc = col0 + wn * WN + nt * 8 + (lane & 3) * 2;
            float v0 = acc[mt][nt][0], v1 = acc[mt][nt][1];
            float v2 = acc[mt][nt][2], v3 = acc[mt][nt][3];
            if (EPI == 3) {
                *reinterpret_cast<float2*>((float*)Cc + r0 * Nld + gc) =
                    make_float2(v0, v1);
                *reinterpret_cast<float2*>((float*)Cc + r1 * Nld + gc) =
                    make_float2(v2, v3);
            } else {
                if (EPI == 0) {
                    float b0 = bia[gc], b1 = bia[gc + 1];
                    v0 = softplusf(v0 + b0); v1 = softplusf(v1 + b1);
                    v2 = softplusf(v2 + b0); v3 = softplusf(v3 + b1);
                } else if (EPI == 1) {
                    float b0 = bia[gc], b1 = bia[gc + 1];
                    float s0 = w3[gc], s1 = w3[gc + 1];
                    v0 = s0 / (1.f + expf(-(v0 + b0)));
                    v1 = s1 / (1.f + expf(-(v1 + b1)));
                    v2 = s0 / (1.f + expf(-(v2 + b0)));
                    v3 = s1 / (1.f + expf(-(v3 + b1)));
                } else if (EPI == 2) {
                    __nv_bfloat162 h0 = *reinterpret_cast<const __nv_bfloat162*>(
                        aux + r0 * HH + gc);
                    __nv_bfloat162 h1 = *reinterpret_cast<const __nv_bfloat162*>(
                        aux + r1 * HH + gc);
                    v0 *= (1.f - expf(-__bfloat162float(h0.x)));
                    v1 *= (1.f - expf(-__bfloat162float(h0.y)));
                    v2 *= (1.f - expf(-__bfloat162float(h1.x)));
                    v3 *= (1.f - expf(-__bfloat162float(h1.y)));
                }
                __nv_bfloat162 o0; o0.x = __float2bfloat16(v0); o0.y = __float2bfloat16(v1);
                __nv_bfloat162 o1; o1.x = __float2bfloat16(v2); o1.y = __float2bfloat16(v3);
                *reinterpret_cast<__nv_bfloat162*>(
                    (__nv_bfloat16*)Cc + r0 * Nld + gc) = o0;
                *reinterpret_cast<__nv_bfloat162*>(
                    (__nv_bfloat16*)Cc + r1 * Nld + gc) = o1;
            }
        }
    }
}

// ===========================================================================
// Single-shot warp-MMA GEMM (K=64)
// ===========================================================================
template<int K, int BN, int EPI>
__global__ __launch_bounds__(256)
void gemm_mma(const __nv_bfloat16* __restrict__ A0, const __nv_bfloat16* __restrict__ A1,
              const __nv_bfloat16* __restrict__ B0, const __nv_bfloat16* __restrict__ B1,
              const float* __restrict__ bias0, const float* __restrict__ bias1,
              const float* __restrict__ w30,  const float* __restrict__ w31,
              const __nv_bfloat16* __restrict__ aux0, const __nv_bfloat16* __restrict__ aux1,
              void* __restrict__ C0, void* __restrict__ C1, int Nld) {
    constexpr int LDE = K + 8;
    extern __shared__ __align__(16) char smraw[];
    __nv_bfloat16* smA = reinterpret_cast<__nv_bfloat16*>(smraw);
    __nv_bfloat16* smB = smA + 128 * LDE;

    const int tid = threadIdx.x, wid = tid >> 5, lane = tid & 31;
    const int zi = blockIdx.z;
    const __nv_bfloat16* A   = zi ? A1 : A0;
    const __nv_bfloat16* Bw  = zi ? B1 : B0;
    const float* bia         = zi ? bias1 : bias0;
    const float* w3          = zi ? w31 : w30;
    const __nv_bfloat16* aux = zi ? aux1 : aux0;
    char* Cc                 = (char*)(zi ? C1 : C0);

    const size_t row0 = (size_t)blockIdx.x * 128;
    const int    col0 = blockIdx.y * BN;

    constexpr int ASEG = K / 8;
    #pragma unroll 4
    for (int c = tid; c < 128 * ASEG; c += 256) {
        int r = c / ASEG, s = c % ASEG;
        *reinterpret_cast<uint4*>(smA + r * LDE + s * 8) =
            *reinterpret_cast<const uint4*>(A + (row0 + r) * K + s * 8);
    }
    #pragma unroll 4
    for (int c = tid; c < BN * ASEG; c += 256) {
        int r = c / ASEG, s = c % ASEG;
        *reinterpret_cast<uint4*>(smB + r * LDE + s * 8) =
            *reinterpret_cast<const uint4*>(Bw + (size_t)(col0 + r) * K + s * 8);
    }
    __syncthreads();

    const int wm = wid & 3;
    const int wn = wid >> 2;
    constexpr int WN = BN / 2;
    constexpr int NT = WN / 8;
    const int g = lane >> 2;
    const int j = lane & 3;

    float acc[2][NT][4];
    #pragma unroll
    for (int mt = 0; mt < 2; mt++)
        #pragma unroll
        for (int nt = 0; nt < NT; nt++)
            #pragma unroll
            for (int i = 0; i < 4; i++) acc[mt][nt][i] = 0.f;

    const uint32_t sA = smem_u32(smA), sB = smem_u32(smB);
    uint32_t aBase[2];
    #pragma unroll
    for (int mt = 0; mt < 2; mt++)
        aBase[mt] = sA + (uint32_t)(((wm * 32 + mt * 16 + g) * LDE + 2 * j) * 2);
    uint32_t bBase[NT];
    #pragma unroll
    for (int nt = 0; nt < NT; nt++)
        bBase[nt] = sB + (uint32_t)(((wn * WN + nt * 8 + g) * LDE + 2 * j) * 2);

    constexpr uint32_t ROW8 = (uint32_t)(8 * LDE * 2);

    #pragma unroll 4
    for (int kc = 0; kc < K / 16; kc++) {
        const uint32_t kb = (uint32_t)(kc * 32);
        uint32_t a[2][4];
        #pragma unroll
        for (int mt = 0; mt < 2; mt++) {
            a[mt][0] = lds32(aBase[mt] + kb);
            a[mt][1] = lds32(aBase[mt] + kb + ROW8);
            a[mt][2] = lds32(aBase[mt] + kb + 16);
            a[mt][3] = lds32(aBase[mt] + kb + ROW8 + 16);
        }
        uint32_t b[NT][2];
        #pragma unroll
        for (int nt = 0; nt < NT; nt++) {
            b[nt][0] = lds32(bBase[nt] + kb);
            b[nt][1] = lds32(bBase[nt] + kb + 16);
        }
        #pragma unroll
        for (int mt = 0; mt < 2; mt++)
            #pragma unroll
            for (int nt = 0; nt < NT; nt++)
                mma16816(acc[mt][nt], a[mt][0], a[mt][1], a[mt][2], a[mt][3],
                         b[nt][0], b[nt][1]);
    }

    gemm_epilogue<EPI, NT>(acc, row0, col0, wm, wn, WN, lane, bia, w3, aux, Cc, Nld);
}

// ===========================================================================
// cp.async 3-stage pipelined warp-MMA GEMM (K = 256, BK = 64)
// ===========================================================================
template<int K, int BN, int EPI>
__global__ __launch_bounds__(256, 2)
void gemm_pipe(const __nv_bfloat16* __restrict__ A0, const __nv_bfloat16* __restrict__ A1,
               const __nv_bfloat16* __restrict__ B0, const __nv_bfloat16* __restrict__ B1,
               const float* __restrict__ bias0, const float* __restrict__ bias1,
               const float* __restrict__ w30,  const float* __restrict__ w31,
               const __nv_bfloat16* __restrict__ aux0, const __nv_bfloat16* __restrict__ aux1,
               void* __restrict__ C0, void* __restrict__ C1, int Nld) {
    constexpr int BK   = 64;
    constexpr int LDE  = BK + 8;
    constexpr int NSTG = 3;
    constexpr int NCH  = K / BK;
    constexpr int STGE = (128 + BN) * LDE;
    extern __shared__ __align__(16) __nv_bfloat16 sm[];

    const int tid = threadIdx.x, wid = tid >> 5, lane = tid & 31;
    const int zi = blockIdx.z;
    const __nv_bfloat16* A   = zi ? A1 : A0;
    const __nv_bfloat16* Bw  = zi ? B1 : B0;
    const float* bia         = zi ? bias1 : bias0;
    const float* w3          = zi ? w31 : w30;
    const __nv_bfloat16* aux = zi ? aux1 : aux0;
    char* Cc                 = (char*)(zi ? C1 : C0);

    const size_t row0 = (size_t)blockIdx.x * 128;
    const int    col0 = blockIdx.y * BN;
    const uint32_t sm0 = smem_u32(sm);

    auto load_chunk = [&](int s, int c) {
        const uint32_t dstS = sm0 + (uint32_t)(s * STGE * 2);
        const int k0 = c * BK;
        #pragma unroll
        for (int t = tid; t < (128 + BN) * 8; t += 256) {
            int r = t >> 3, seg = t & 7;
            if (r < 128) {
                cpasync16(dstS + (uint32_t)((r * LDE + seg * 8) * 2),
                          A + (row0 + r) * K + k0 + seg * 8);
            } else {
                int rb = r - 128;
                cpasync16(dstS + (uint32_t)(((128 + rb) * LDE + seg * 8) * 2),
                          Bw + (size_t)(col0 + rb) * K + k0 + seg * 8);
            }
        }
    };

    const int wm = wid & 3;
    const int wn = wid >> 2;
    constexpr int WN = BN / 2;
    constexpr int NT = WN / 8;
    const int g = lane >> 2;
    const int j = lane & 3;

    float acc[2][NT][4];
    #pragma unroll
    for (int mt = 0; mt < 2; mt++)
        #pragma unroll
        for (int nt = 0; nt < NT; nt++)
            #pragma unroll
            for (int i = 0; i < 4; i++) acc[mt][nt][i] = 0.f;

    uint32_t aBase[2];
    #pragma unroll
    for (int mt = 0; mt < 2; mt++)
        aBase[mt] = sm0 + (uint32_t)(((wm * 32 + mt * 16 + g) * LDE + 2 * j) * 2);
    uint32_t bBase[NT];
    #pragma unroll
    for (int nt = 0; nt < NT; nt++)
        bBase[nt] = sm0 + (uint32_t)(((128 + wn * WN + nt * 8 + g) * LDE + 2 * j) * 2);
    constexpr uint32_t ROW8 = (uint32_t)(8 * LDE * 2);

    load_chunk(0, 0); cp_commit();
    load_chunk(1, 1); cp_commit();

    for (int c = 0; c < NCH; c++) {
        cp_wait<1>();
        __syncthreads();
        const uint32_t soff = (uint32_t)((c % NSTG) * STGE * 2);
        #pragma unroll
        for (int kc = 0; kc < BK / 16; kc++) {
            const uint32_t kb = soff + (uint32_t)(kc * 32);
            uint32_t a[2][4];
            #pragma unroll
            for (int mt = 0; mt < 2; mt++) {
                a[mt][0] = lds32(aBase[mt] + kb);
                a[mt][1] = lds32(aBase[mt] + kb + ROW8);
                a[mt][2] = lds32(aBase[mt] + kb + 16);
                a[mt][3] = lds32(aBase[mt] + kb + ROW8 + 16);
            }
            uint32_t b[NT][2];
            #pragma unroll
            for (int nt = 0; nt < NT; nt++) {
                b[nt][0] = lds32(bBase[nt] + kb);
                b[nt][1] = lds32(bBase[nt] + kb + 16);
            }
            #pragma unroll
            for (int mt = 0; mt < 2; mt++)
                #pragma unroll
                for (int nt = 0; nt < NT; nt++)
                    mma16816(acc[mt][nt], a[mt][0], a[mt][1], a[mt][2], a[mt][3],
                             b[nt][0], b[nt][1]);
        }
        __syncthreads();
        if (c + 2 < NCH) load_chunk((c + 2) % NSTG, c + 2);
        cp_commit();
    }

    gemm_epilogue<EPI, NT>(acc, row0, col0, wm, wn, WN, lane, bia, w3, aux, Cc, Nld);
}

// ===========================================================================
// RK4 elementwise combine
// ===========================================================================
__global__ __launch_bounds__(256)
void rk4_k(const float* __restrict__ dzT, const float* __restrict__ dzV,
           const float* __restrict__ u, const float* __restrict__ Bc,
           const float* __restrict__ z, float* __restrict__ acc,
           __nv_bfloat16* __restrict__ zk, float* __restrict__ out, int stage) {
    size_t idx = (size_t)blockIdx.x * 256 + threadIdx.x;
    int col = (int)(idx & 63);
    size_t row = idx >> 6;
    float dz = dzT[idx] + dzV[idx];
    if (col >= QD) dz += u[row] * Bc[col - QD];
    float w = (stage == 1 || stage == 2) ? 2.f : 1.f;
    float a = (stage == 0 ? 0.f : acc[idx]) + w * dz;
    acc[idx] = a;
    if (stage < 3) {
        float cn = (stage == 2) ? DTC : 0.5f * DTC;
        zk[idx] = __float2bfloat16(fmaf(cn, dz, z[idx]));
    } else {
        out[idx] = fmaf(DTC / 6.f, a, z[idx]);
    }
}

// ===========================================================================
// Host orchestration
// ===========================================================================
extern "C" void kernel_launch(void* const* d_in, const int* in_sizes, int n_in,
                              void* d_out, int out_size) {
    const float* h    = (const float*)d_in[0];
    const float* u    = (const float*)d_in[1];
    const float* sW1  = (const float*)d_in[2];
    const float* sb1  = (const float*)d_in[3];
    const float* sW2  = (const float*)d_in[4];
    const float* sb2  = (const float*)d_in[5];
    const float* tW1  = (const float*)d_in[6];
    const float* tb1  = (const float*)d_in[7];
    const float* tW2  = (const float*)d_in[8];
    const float* tb2  = (const float*)d_in[9];
    const float* kW1  = (const float*)d_in[10];
    const float* kb1  = (const float*)d_in[11];
    const float* kW2  = (const float*)d_in[12];
    const float* kb2  = (const float*)d_in[13];
    const float* kW3  = (const float*)d_in[14];
    const float* vW1  = (const float*)d_in[16];
    const float* vb1  = (const float*)d_in[17];
    const float* vW2  = (const float*)d_in[18];
    const float* vb2  = (const float*)d_in[19];
    const float* vW3  = (const float*)d_in[20];
    const float* A    = (const float*)d_in[22];
    const float* Lp   = (const float*)d_in[23];
    const float* Bc   = (const float*)d_in[24];
    float* out = (float*)d_out;

    float *z, *acc, *dzT, *dzV, *Mp, *fpk;
    __nv_bfloat16 *zk, *h1T, *h1V, *g2T, *g2V, *g1T, *g1V;
    __nv_bfloat16 *Bk1, *Bv1, *Bk2, *Bv2, *Bk2t, *Bv2t, *BkM, *BvM;
    cudaGetSymbolAddress((void**)&z,    g_z);
    cudaGetSymbolAddress((void**)&acc,  g_acc);
    cudaGetSymbolAddress((void**)&dzT,  g_dzT);
    cudaGetSymbolAddress((void**)&dzV,  g_dzV);
    cudaGetSymbolAddress((void**)&zk,   g_zk);
    cudaGetSymbolAddress((void**)&h1T,  g_h1T);
    cudaGetSymbolAddress((void**)&h1V,  g_h1V);
    cudaGetSymbolAddress((void**)&g2T,  g_g2T);
    cudaGetSymbolAddress((void**)&g2V,  g_g2V);
    cudaGetSymbolAddress((void**)&g1T,  g_g1T);
    cudaGetSymbolAddress((void**)&g1V,  g_g1V);
    cudaGetSymbolAddress((void**)&Bk1,  g_Bk1);
    cudaGetSymbolAddress((void**)&Bv1,  g_Bv1);
    cudaGetSymbolAddress((void**)&Bk2,  g_Bk2);
    cudaGetSymbolAddress((void**)&Bv2,  g_Bv2);
    cudaGetSymbolAddress((void**)&Bk2t, g_Bk2t);
    cudaGetSymbolAddress((void**)&Bv2t, g_Bv2t);
    cudaGetSymbolAddress((void**)&BkM,  g_BkM);
    cudaGetSymbolAddress((void**)&BvM,  g_BvM);
    cudaGetSymbolAddress((void**)&Mp,   g_M);
    cudaGetSymbolAddress((void**)&fpk,  g_fpk);

    const int SM1 = (128 + 128) * (64 + 8) * 2;        // 36,864
    const int SMP128 = 3 * (128 + 128) * 72 * 2;       // 110,592
    const int SMP64  = 3 * (128 + 64)  * 72 * 2;       //  82,944
    cudaFuncSetAttribute(gemm_mma<64, 128, 0>,
                         cudaFuncAttributeMaxDynamicSharedMemorySize, SM1);
    cudaFuncSetAttribute(gemm_pipe<256, 128, 1>,
                         cudaFuncAttributeMaxDynamicSharedMemorySize, SMP128);
    cudaFuncSetAttribute(gemm_pipe<256, 128, 2>,
                         cudaFuncAttributeMaxDynamicSharedMemorySize, SMP128);
    cudaFuncSetAttribute(gemm_pipe<256, 64, 3>,
                         cudaFuncAttributeMaxDynamicSharedMemorySize, SMP64);

    // ---- prep: 2 launches ----
    build_M_k<<<1, 256>>>(A, Lp, Mp);
    prep_pack_k<<<dim3(256, 10), 256>>>(kW1, vW1, kW2, vW2, Mp,
                                        sW1, sW2, tW1, tW2,
                                        Bk1, Bv1, Bk2, Bv2, Bk2t, Bv2t,
                                        BkM, BvM, fpk);

    // ---- s = flow_fwd(h) ----
    cudaMemcpyAsync(z, h, (size_t)BATCH * DIM * sizeof(float),
                    cudaMemcpyDeviceToDevice, 0);
    for (int l = 0; l < NLAYERS; l++)
        flow2_k<<<BATCH / 128, 128>>>(z, fpk, sb1, sb2, tb1, tb2, l, 0);
    f2bf_k<<<BATCH * DIM / 1024, 256>>>(z, zk);

    // ---- RK4 stages ----
    dim3 gBig(BATCH / 128, 2, 2);
    dim3 gSml(BATCH / 128, 1, 2);
    for (int st = 0; st < 4; st++) {
        gemm_mma<64, 128, 0><<<gBig, 256, SM1>>>(
            zk, zk, Bk1, Bv1, kb1, vb1, 0, 0, 0, 0, h1T, h1V, HH);
        gemm_pipe<256, 128, 1><<<gBig, 256, SMP128>>>(
            h1T, h1V, Bk2, Bv2, kb2, vb2, kW3, vW3, 0, 0, g2T, g2V, HH);
        gemm_pipe<256, 128, 2><<<gBig, 256, SMP128>>>(
            g2T, g2V, Bk2t, Bv2t, 0, 0, 0, 0, h1T, h1V, g1T, g1V, HH);
        gemm_pipe<256, 64, 3><<<gSml, 256, SMP64>>>(
            g1T, g1V, BkM, BvM, 0, 0, 0, 0, 0, 0, dzT, dzV, DIM);
        rk4_k<<<BATCH * DIM / 256, 256>>>(dzT, dzV, u, Bc, z, acc, zk, out, st);
    }

    // ---- h_next = flow_inv(z_next) in place on out ----
    for (int l = NLAYERS - 1; l >= 0; l--)
        flow2_k<<<BATCH / 128, 128>>>(out, fpk, sb1, sb2, tb1, tb2, l, 1);
}

// round 9
// speedup vs baseline: 3.2052x; 1.0895x over previous
#include <cuda_runtime.h>
#include <cuda_bf16.h>
#include <math.h>
#include <cstdint>

#define BATCH   131072
#define DIM     64
#define QD      32
#define NLAYERS 6
#define HF      128
#define HH      256
#define DTC     0.05f

// ===========================================================================
// Scratch (static __device__ arrays)
// ===========================================================================
__device__ __align__(16) float g_z   [BATCH * DIM];
__device__ __align__(16) float g_acc [BATCH * DIM];
__device__ __align__(16) float g_dzT [BATCH * DIM];
__device__ __align__(16) float g_dzV [BATCH * DIM];
__device__ __align__(16) __nv_bfloat16 g_zk [BATCH * DIM];
__device__ __align__(16) __nv_bfloat16 g_h1T[BATCH * HH];
__device__ __align__(16) __nv_bfloat16 g_h1V[BATCH * HH];
__device__ __align__(16) __nv_bfloat16 g_g2T[BATCH * HH];
__device__ __align__(16) __nv_bfloat16 g_g2V[BATCH * HH];
__device__ __align__(16) __nv_bfloat16 g_g1T[BATCH * HH];
__device__ __align__(16) __nv_bfloat16 g_g1V[BATCH * HH];
// bf16 weight images, plain row-major [N][K]
__device__ __align__(16) __nv_bfloat16 g_Bk1 [HH * 64];
__device__ __align__(16) __nv_bfloat16 g_Bv1 [HH * 64];
__device__ __align__(16) __nv_bfloat16 g_Bk2 [HH * HH];
__device__ __align__(16) __nv_bfloat16 g_Bv2 [HH * HH];
__device__ __align__(16) __nv_bfloat16 g_Bk2t[HH * HH];
__device__ __align__(16) __nv_bfloat16 g_Bv2t[HH * HH];
__device__ __align__(16) __nv_bfloat16 g_BkM [64 * HH];
__device__ __align__(16) __nv_bfloat16 g_BvM [64 * HH];
__device__ float g_M[DIM * DIM];
// flow weights, tf32-rounded, per layer: [sW1 4096 | sW2 4096 | tW1 4096 | tW2 4096]
__device__ __align__(16) float g_fpk[NLAYERS * 16384];

__device__ __forceinline__ float softplusf(float x) {
    return fmaxf(x, 0.f) + log1pf(expf(-fabsf(x)));
}

__device__ __forceinline__ uint32_t smem_u32(const void* p) {
    uint32_t a;
    asm("{ .reg .u64 t; cvta.to.shared.u64 t, %1; cvt.u32.u64 %0, t; }"
        : "=r"(a) : "l"(p));
    return a;
}

__device__ __forceinline__ uint32_t lds32(uint32_t addr) {
    uint32_t v;
    asm("ld.shared.b32 %0, [%1];" : "=r"(v) : "r"(addr));
    return v;
}

__device__ __forceinline__ float tf32r(float x) {
    uint32_t u;
    asm("cvt.rna.tf32.f32 %0, %1;" : "=r"(u) : "f"(x));
    return __uint_as_float(u);
}

__device__ __forceinline__ void cpasync16(uint32_t dst, const void* src) {
    asm volatile("cp.async.cg.shared.global [%0], [%1], 16;"
                 :: "r"(dst), "l"(src));
}

__device__ __forceinline__ void cp_commit() {
    asm volatile("cp.async.commit_group;");
}

template<int N>
__device__ __forceinline__ void cp_wait() {
    asm volatile("cp.async.wait_group %0;" :: "n"(N));
}

__device__ __forceinline__ void mma16816(float* c, uint32_t a0, uint32_t a1,
                                         uint32_t a2, uint32_t a3,
                                         uint32_t b0, uint32_t b1) {
    asm volatile(
        "mma.sync.aligned.m16n8k16.row.col.f32.bf16.bf16.f32 "
        "{%0,%1,%2,%3},{%4,%5,%6,%7},{%8,%9},{%0,%1,%2,%3};"
        : "+f"(c[0]), "+f"(c[1]), "+f"(c[2]), "+f"(c[3])
        : "r"(a0), "r"(a1), "r"(a2), "r"(a3), "r"(b0), "r"(b1));
}

__device__ __forceinline__ void mma_tf32(float* c, uint32_t a0, uint32_t a1,
                                         uint32_t a2, uint32_t a3,
                                         uint32_t b0, uint32_t b1) {
    asm volatile(
        "mma.sync.aligned.m16n8k8.row.col.f32.tf32.tf32.f32 "
        "{%0,%1,%2,%3},{%4,%5,%6,%7},{%8,%9},{%0,%1,%2,%3};"
        : "+f"(c[0]), "+f"(c[1]), "+f"(c[2]), "+f"(c[3])
        : "r"(a0), "r"(a1), "r"(a2), "r"(a3), "r"(b0), "r"(b1));
}

// ===========================================================================
// Prep kernels
// ===========================================================================
__global__ void build_M_k(const float* __restrict__ A, const float* __restrict__ Lp,
                          float* __restrict__ M) {
    __shared__ float L[DIM * DIM];
    int t = threadIdx.x;
    for (int idx = t; idx < DIM * DIM; idx += 256) {
        int i = idx >> 6, j = idx & 63;
        float v;
        if (i > j)       v = Lp[idx];
        else if (i == j) v = softplusf(Lp[idx]);
        else             v = 0.f;
        L[idx] = v;
    }
    __syncthreads();
    for (int idx = t; idx < DIM * DIM; idx += 256) {
        int i = idx >> 6, j = idx & 63;
        float s = 0.f;
        #pragma unroll 8
        for (int k = 0; k < DIM; k++) s += L[i * DIM + k] * L[j * DIM + k];
        M[idx] = A[i * DIM + j] - A[j * DIM + i] - s;
    }
}

// one kernel, tasks on blockIdx.y; grid.x = 384 (task 8 needs 98304 threads)
__global__ void prep_pack_k(const float* __restrict__ kW1, const float* __restrict__ vW1,
                            const float* __restrict__ kW2, const float* __restrict__ vW2,
                            const float* __restrict__ M,
                            const float* __restrict__ sW1, const float* __restrict__ sW2,
                            const float* __restrict__ tW1, const float* __restrict__ tW2,
                            __nv_bfloat16* __restrict__ Bk1, __nv_bfloat16* __restrict__ Bv1,
                            __nv_bfloat16* __restrict__ Bk2, __nv_bfloat16* __restrict__ Bv2,
                            __nv_bfloat16* __restrict__ Bk2t, __nv_bfloat16* __restrict__ Bv2t,
                            __nv_bfloat16* __restrict__ BkM, __nv_bfloat16* __restrict__ BvM,
                            float* __restrict__ fpk) {
    int idx = blockIdx.x * 256 + threadIdx.x;
    int task = blockIdx.y;
    if (task == 0) {
        if (idx < HH * 64) Bk1[idx] = __float2bfloat16(kW1[idx]);
    } else if (task == 1) {
        if (idx < HH * 64) {
            int r = idx >> 6, k = idx & 63;
            Bv1[idx] = __float2bfloat16(k < QD ? vW1[r * QD + k] : 0.f);
        }
    } else if (task == 2) {
        if (idx < HH * HH) Bk2[idx] = __float2bfloat16(kW2[idx]);
    } else if (task == 3) {
        if (idx < HH * HH) Bv2[idx] = __float2bfloat16(vW2[idx]);
    } else if (task == 4) {
        if (idx < HH * HH) {
            int r = idx >> 8, k = idx & 255;
            Bk2t[idx] = __float2bfloat16(kW2[k * HH + r]);
        }
    } else if (task == 5) {
        if (idx < HH * HH) {
            int r = idx >> 8, k = idx & 255;
            Bv2t[idx] = __float2bfloat16(vW2[k * HH + r]);
        }
    } else if (task == 6) {
        if (idx < 64 * HH) {
            int i = idx >> 8, k = idx & 255;
            float s = 0.f;
            for (int n = 0; n < 64; n++) s += kW1[k * 64 + n] * M[i * 64 + n];
            BkM[idx] = __float2bfloat16(s);
        }
    } else if (task == 7) {
        if (idx < 64 * HH) {
            int i = idx >> 8, k = idx & 255;
            float s = 0.f;
            for (int n = 0; n < QD; n++) s += vW1[k * QD + n] * M[i * 64 + n];
            BvM[idx] = __float2bfloat16(s);
        }
    } else {   // task 8: flow weights, tf32-rounded, natural layout
        if (idx < NLAYERS * 16384) {
            int l = idx / 16384, r = idx % 16384;
            int sel = r / 4096, o = r % 4096;
            float v;
            if (sel == 0)      v = sW1[l * 4096 + o];
            else if (sel == 1) v = sW2[l * 4096 + o];
            else if (sel == 2) v = tW1[l * 4096 + o];
            else               v = tW2[l * 4096 + o];
            fpk[idx] = tf32r(v);
        }
    }
}

__global__ void f2bf_k(const float* __restrict__ s, __nv_bfloat16* __restrict__ d) {
    int i = blockIdx.x * 256 + threadIdx.x;
    float4 v = reinterpret_cast<const float4*>(s)[i];
    __nv_bfloat162 a; a.x = __float2bfloat16(v.x); a.y = __float2bfloat16(v.y);
    __nv_bfloat162 b; b.x = __float2bfloat16(v.z); b.y = __float2bfloat16(v.w);
    reinterpret_cast<__nv_bfloat162*>(d)[2 * i]     = a;
    reinterpret_cast<__nv_bfloat162*>(d)[2 * i + 1] = b;
}

// ===========================================================================
// tf32 tensor-core RealNVP coupling layer.
//  128 rows/CTA, 8 warps (4M x 2N). Per MLP (s then t, reusing smem):
//   MMA1 (M128,N128,K32):  hidden = relu(cond @ W1^T + b1), cond split hi/lo
//                          (2 MMAs) for near-fp32 input precision.
//   MMA2 (M128,N32,K128):  pre = hidden @ W2^T   (+ b2 at epilogue)
//  Fragment gathers are plain 4B lds32 (padded strides 36/132 words ≡ 4 banks
//  mod 32 -> conflict-free).
// ===========================================================================
__global__ __launch_bounds__(256)
void flow_mma_k(float* __restrict__ z, const float* __restrict__ fpk,
                const float* __restrict__ sb1, const float* __restrict__ sb2,
                const float* __restrict__ tb1, const float* __restrict__ tb2,
                int layer, int inverse) {
    // smem float offsets
    constexpr int CH   = 0;               // cond_hi  [128][36]
    constexpr int CL   = 4608;            // cond_lo  [128][36]
    constexpr int W1O  = 9216;            // W1       [128][36]
    constexpr int W2O  = 13824;           // W2       [32][132]
    constexpr int HIDO = 18048;           // hidden   [128][132]
    constexpr int B1O  = 34944;           // b1       [128]
    constexpr int B2SO = 35072;           // sb2      [32]
    constexpr int B2TO = 35104;           // tb2      [32]
    extern __shared__ float sm[];

    const int tid = threadIdx.x, wid = tid >> 5, lane = tid & 31;
    const int g = lane >> 2, j = lane & 3;
    const int wm = wid & 3, wn = wid >> 2;
    const int parity = layer & 1;
    const int coff = parity ? QD : 0;
    const int moff = parity ? 0 : QD;
    const size_t row0 = (size_t)blockIdx.x * 128;
    const uint32_t smb = smem_u32(sm);

    // ---- stage cond hi/lo + b2 arrays ----
    for (int idx = tid; idx < 128 * 32; idx += 256) {
        int r = idx >> 5, c = idx & 31;
        float y = z[(row0 + r) * DIM + coff + c];
        float hi = tf32r(y);
        sm[CH + r * 36 + c] = hi;
        sm[CL + r * 36 + c] = tf32r(y - hi);
    }
    if (tid < QD) {
        sm[B2SO + tid] = sb2[layer * QD + tid];
        sm[B2TO + tid] = tb2[layer * QD + tid];
    }

    float res[2][2][2][4];   // [st][mt][nt][frag]

    const float* wl = fpk + (size_t)layer * 16384;
    for (int st = 0; st < 2; st++) {
        // ---- stage W1 [128][32], W2 [32][128], b1 ----
        const float* w1g = wl + st * 8192;
        const float* b1g = (st ? tb1 : sb1) + layer * HF;
        for (int idx = tid; idx < 4096; idx += 256)
            sm[W1O + (idx >> 5) * 36 + (idx & 31)] = w1g[idx];
        for (int idx = tid; idx < 4096; idx += 256)
            sm[W2O + (idx >> 7) * 132 + (idx & 127)] = w1g[4096 + idx];
        if (tid < HF) sm[B1O + tid] = b1g[tid];
        __syncthreads();

        // ---- MMA1: cond(hi+lo) @ W1^T ----
        float acc1[2][8][4];
        #pragma unroll
        for (int mt = 0; mt < 2; mt++)
            #pragma unroll
            for (int nt = 0; nt < 8; nt++)
                #pragma unroll
                for (int i = 0; i < 4; i++) acc1[mt][nt][i] = 0.f;

        uint32_t aH[2], aL[2];
        #pragma unroll
        for (int mt = 0; mt < 2; mt++) {
            int r = wm * 32 + mt * 16 + g;
            aH[mt] = smb + (uint32_t)((CH + r * 36 + j) << 2);
            aL[mt] = smb + (uint32_t)((CL + r * 36 + j) << 2);
        }
        uint32_t bA[8];
        #pragma unroll
        for (int nt = 0; nt < 8; nt++)
            bA[nt] = smb + (uint32_t)((W1O + (wn * 64 + nt * 8 + g) * 36 + j) << 2);

        #pragma unroll
        for (int kc = 0; kc < 4; kc++) {
            const uint32_t ko = (uint32_t)(kc * 32);
            uint32_t ah[2][4], al[2][4];
            #pragma unroll
            for (int mt = 0; mt < 2; mt++) {
                ah[mt][0] = lds32(aH[mt] + ko);
                ah[mt][1] = lds32(aH[mt] + ko + 1152);   // +8 rows (8*36*4)
                ah[mt][2] = lds32(aH[mt] + ko + 16);     // +4 cols
                ah[mt][3] = lds32(aH[mt] + ko + 1168);
                al[mt][0] = lds32(aL[mt] + ko);
                al[mt][1] = lds32(aL[mt] + ko + 1152);
                al[mt][2] = lds32(aL[mt] + ko + 16);
                al[mt][3] = lds32(aL[mt] + ko + 1168);
            }
            #pragma unroll
            for (int nt = 0; nt < 8; nt++) {
                uint32_t b0 = lds32(bA[nt] + ko);
                uint32_t b1 = lds32(bA[nt] + ko + 16);
                #pragma unroll
                for (int mt = 0; mt < 2; mt++) {
                    mma_tf32(acc1[mt][nt], ah[mt][0], ah[mt][1], ah[mt][2], ah[mt][3], b0, b1);
                    mma_tf32(acc1[mt][nt], al[mt][0], al[mt][1], al[mt][2], al[mt][3], b0, b1);
                }
            }
        }

        // ---- bias + relu -> hidden (tf32) ----
        #pragma unroll
        for (int mt = 0; mt < 2; mt++) {
            int r0 = wm * 32 + mt * 16 + g;
            #pragma unroll
            for (int nt = 0; nt < 8; nt++) {
                int c0 = wn * 64 + nt * 8 + 2 * j;
                float b0 = sm[B1O + c0], b1f = sm[B1O + c0 + 1];
                sm[HIDO + r0 * 132 + c0]           = tf32r(fmaxf(acc1[mt][nt][0] + b0, 0.f));
                sm[HIDO + r0 * 132 + c0 + 1]       = tf32r(fmaxf(acc1[mt][nt][1] + b1f, 0.f));
                sm[HIDO + (r0 + 8) * 132 + c0]     = tf32r(fmaxf(acc1[mt][nt][2] + b0, 0.f));
                sm[HIDO + (r0 + 8) * 132 + c0 + 1] = tf32r(fmaxf(acc1[mt][nt][3] + b1f, 0.f));
            }
        }
        __syncthreads();

        // ---- MMA2: hidden @ W2^T ----
        float acc2[2][2][4];
        #pragma unroll
        for (int mt = 0; mt < 2; mt++)
            #pragma unroll
            for (int nt = 0; nt < 2; nt++)
                #pragma unroll
                for (int i = 0; i < 4; i++) acc2[mt][nt][i] = 0.f;

        uint32_t a2[2];
        #pragma unroll
        for (int mt = 0; mt < 2; mt++)
            a2[mt] = smb + (uint32_t)((HIDO + (wm * 32 + mt * 16 + g) * 132 + j) << 2);
        uint32_t b2a[2];
        #pragma unroll
        for (int nt = 0; nt < 2; nt++)
            b2a[nt] = smb + (uint32_t)((W2O + (wn * 16 + nt * 8 + g) * 132 + j) << 2);

        #pragma unroll 4
        for (int kc = 0; kc < 16; kc++) {
            const uint32_t ko = (uint32_t)(kc * 32);
            uint32_t av[2][4];
            #pragma unroll
            for (int mt = 0; mt < 2; mt++) {
                av[mt][0] = lds32(a2[mt] + ko);
                av[mt][1] = lds32(a2[mt] + ko + 4224);   // +8 rows (8*132*4)
                av[mt][2] = lds32(a2[mt] + ko + 16);
                av[mt][3] = lds32(a2[mt] + ko + 4240);
            }
            #pragma unroll
            for (int nt = 0; nt < 2; nt++) {
                uint32_t b0 = lds32(b2a[nt] + ko);
                uint32_t b1 = lds32(b2a[nt] + ko + 16);
                #pragma unroll
                for (int mt = 0; mt < 2; mt++)
                    mma_tf32(acc2[mt][nt], av[mt][0], av[mt][1], av[mt][2], av[mt][3], b0, b1);
            }
        }
        #pragma unroll
        for (int mt = 0; mt < 2; mt++)
            #pragma unroll
            for (int nt = 0; nt < 2; nt++)
                #pragma unroll
                for (int i = 0; i < 4; i++) res[st][mt][nt][i] = acc2[mt][nt][i];
        __syncthreads();   // protect W/hidden restaging next MLP
    }

    // ---- elementwise epilogue: update modified half ----
    #pragma unroll
    for (int mt = 0; mt < 2; mt++) {
        size_t zr0 = (row0 + wm * 32 + mt * 16 + g) * DIM + moff;
        size_t zr1 = zr0 + 8 * DIM;
        #pragma unroll
        for (int nt = 0; nt < 2; nt++) {
            int c0 = wn * 16 + nt * 8 + 2 * j;
            float sb0 = sm[B2SO + c0], sb1v = sm[B2SO + c0 + 1];
            float tb0 = sm[B2TO + c0], tb1v = sm[B2TO + c0 + 1];
            float s0 = tanhf(res[0][mt][nt][0] + sb0);
            float s1 = tanhf(res[0][mt][nt][1] + sb1v);
            float s2 = tanhf(res[0][mt][nt][2] + sb0);
            float s3 = tanhf(res[0][mt][nt][3] + sb1v);
            float t0 = res[1][mt][nt][0] + tb0;
            float t1 = res[1][mt][nt][1] + tb1v;
            float t2 = res[1][mt][nt][2] + tb0;
            float t3 = res[1][mt][nt][3] + tb1v;
            float2 x0 = *reinterpret_cast<float2*>(z + zr0 + c0);
            float2 x1 = *reinterpret_cast<float2*>(z + zr1 + c0);
            if (inverse) {
                x0.x = (x0.x - t0) * expf(-s0);
                x0.y = (x0.y - t1) * expf(-s1);
                x1.x = (x1.x - t2) * expf(-s2);
                x1.y = (x1.y - t3) * expf(-s3);
            } else {
                x0.x = fmaf(x0.x, expf(s0), t0);
                x0.y = fmaf(x0.y, expf(s1), t1);
                x1.x = fmaf(x1.x, expf(s2), t2);
                x1.y = fmaf(x1.y, expf(s3), t3);
            }
            *reinterpret_cast<float2*>(z + zr0 + c0) = x0;
            *reinterpret_cast<float2*>(z + zr1 + c0) = x1;
        }
    }
}

// ===========================================================================
// Shared GEMM epilogue
// ===========================================================================
template<int EPI, int NT>
__device__ __forceinline__ void gemm_epilogue(
    float acc[2][NT][4], size_t row0, int col0, int wm, int wn, int WN,
    int lane, const float* bia, const float* w3, const __nv_bfloat16* aux,
    char* Cc, int Nld) {
    #pragma unroll
    for (int mt = 0; mt < 2; mt++) {
        const size_t r0 = row0 + wm * 32 + mt * 16 + (lane >> 2);
        const size_t r1 = r0 + 8;
        #pragma unroll
        for (int nt = 0; nt < NT; nt++) {
            const int gc = col0 + wn * WN + nt * 8 + (lane & 3) * 2;
            float v0 = acc[mt][nt][0], v1 = acc[mt][nt][1];
            float v2 = acc[mt][nt][2], v3 = acc[mt][nt][3];
            if (EPI == 3) {
                *reinterpret_cast<float2*>((float*)Cc + r0 * Nld + gc) =
                    make_float2(v0, v1);
                *reinterpret_cast<float2*>((float*)Cc + r1 * Nld + gc) =
                    make_float2(v2, v3);
            } else {
                if (EPI == 0) {
                    float b0 = bia[gc], b1 = bia[gc + 1];
                    v0 = softplusf(v0 + b0); v1 = softplusf(v1 + b1);
                    v2 = softplusf(v2 + b0); v3 = softplusf(v3 + b1);
                } else if (EPI == 1) {
                    float b0 = bia[gc], b1 = bia[gc + 1];
                    float s0 = w3[gc], s1 = w3[gc + 1];
                    v0 = s0 / (1.f + expf(-(v0 + b0)));
                    v1 = s1 / (1.f + expf(-(v1 + b1)));
                    v2 = s0 / (1.f + expf(-(v2 + b0)));
                    v3 = s1 / (1.f + expf(-(v3 + b1)));
                } else if (EPI == 2) {
                    __nv_bfloat162 h0 = *reinterpret_cast<const __nv_bfloat162*>(
                        aux + r0 * HH + gc);
                    __nv_bfloat162 h1 = *reinterpret_cast<const __nv_bfloat162*>(
                        aux + r1 * HH + gc);
                    v0 *= (1.f - expf(-__bfloat162float(h0.x)));
                    v1 *= (1.f - expf(-__bfloat162float(h0.y)));
                    v2 *= (1.f - expf(-__bfloat162float(h1.x)));
                    v3 *= (1.f - expf(-__bfloat162float(h1.y)));
                }
                __nv_bfloat162 o0; o0.x = __float2bfloat16(v0); o0.y = __float2bfloat16(v1);
                __nv_bfloat162 o1; o1.x = __float2bfloat16(v2); o1.y = __float2bfloat16(v3);
                *reinterpret_cast<__nv_bfloat162*>(
                    (__nv_bfloat16*)Cc + r0 * Nld + gc) = o0;
                *reinterpret_cast<__nv_bfloat162*>(
                    (__nv_bfloat16*)Cc + r1 * Nld + gc) = o1;
            }
        }
    }
}

// ===========================================================================
// Single-shot warp-MMA GEMM (K=64)
// ===========================================================================
template<int K, int BN, int EPI>
__global__ __launch_bounds__(256)
void gemm_mma(const __nv_bfloat16* __restrict__ A0, const __nv_bfloat16* __restrict__ A1,
              const __nv_bfloat16* __restrict__ B0, const __nv_bfloat16* __restrict__ B1,
              const float* __restrict__ bias0, const float* __restrict__ bias1,
              const float* __restrict__ w30,  const float* __restrict__ w31,
              const __nv_bfloat16* __restrict__ aux0, const __nv_bfloat16* __restrict__ aux1,
              void* __restrict__ C0, void* __restrict__ C1, int Nld) {
    constexpr int LDE = K + 8;
    extern __shared__ __align__(16) char smraw[];
    __nv_bfloat16* smA = reinterpret_cast<__nv_bfloat16*>(smraw);
    __nv_bfloat16* smB = smA + 128 * LDE;

    const int tid = threadIdx.x, wid = tid >> 5, lane = tid & 31;
    const int zi = blockIdx.z;
    const __nv_bfloat16* A   = zi ? A1 : A0;
    const __nv_bfloat16* Bw  = zi ? B1 : B0;
    const float* bia         = zi ? bias1 : bias0;
    const float* w3          = zi ? w31 : w30;
    const __nv_bfloat16* aux = zi ? aux1 : aux0;
    char* Cc                 = (char*)(zi ? C1 : C0);

    const size_t row0 = (size_t)blockIdx.x * 128;
    const int    col0 = blockIdx.y * BN;

    constexpr int ASEG = K / 8;
    #pragma unroll 4
    for (int c = tid; c < 128 * ASEG; c += 256) {
        int r = c / ASEG, s = c % ASEG;
        *reinterpret_cast<uint4*>(smA + r * LDE + s * 8) =
            *reinterpret_cast<const uint4*>(A + (row0 + r) * K + s * 8);
    }
    #pragma unroll 4
    for (int c = tid; c < BN * ASEG; c += 256) {
        int r = c / ASEG, s = c % ASEG;
        *reinterpret_cast<uint4*>(smB + r * LDE + s * 8) =
            *reinterpret_cast<const uint4*>(Bw + (size_t)(col0 + r) * K + s * 8);
    }
    __syncthreads();

    const int wm = wid & 3;
    const int wn = wid >> 2;
    constexpr int WN = BN / 2;
    constexpr int NT = WN / 8;
    const int g = lane >> 2;
    const int j = lane & 3;

    float acc[2][NT][4];
    #pragma unroll
    for (int mt = 0; mt < 2; mt++)
        #pragma unroll
        for (int nt = 0; nt < NT; nt++)
            #pragma unroll
            for (int i = 0; i < 4; i++) acc[mt][nt][i] = 0.f;

    const uint32_t sA = smem_u32(smA), sB = smem_u32(smB);
    uint32_t aBase[2];
    #pragma unroll
    for (int mt = 0; mt < 2; mt++)
        aBase[mt] = sA + (uint32_t)(((wm * 32 + mt * 16 + g) * LDE + 2 * j) * 2);
    uint32_t bBase[NT];
    #pragma unroll
    for (int nt = 0; nt < NT; nt++)
        bBase[nt] = sB + (uint32_t)(((wn * WN + nt * 8 + g) * LDE + 2 * j) * 2);

    constexpr uint32_t ROW8 = (uint32_t)(8 * LDE * 2);

    #pragma unroll 4
    for (int kc = 0; kc < K / 16; kc++) {
        const uint32_t kb = (uint32_t)(kc * 32);
        uint32_t a[2][4];
        #pragma unroll
        for (int mt = 0; mt < 2; mt++) {
            a[mt][0] = lds32(aBase[mt] + kb);
            a[mt][1] = lds32(aBase[mt] + kb + ROW8);
            a[mt][2] = lds32(aBase[mt] + kb + 16);
            a[mt][3] = lds32(aBase[mt] + kb + ROW8 + 16);
        }
        uint32_t b[NT][2];
        #pragma unroll
        for (int nt = 0; nt < NT; nt++) {
            b[nt][0] = lds32(bBase[nt] + kb);
            b[nt][1] = lds32(bBase[nt] + kb + 16);
        }
        #pragma unroll
        for (int mt = 0; mt < 2; mt++)
            #pragma unroll
            for (int nt = 0; nt < NT; nt++)
                mma16816(acc[mt][nt], a[mt][0], a[mt][1], a[mt][2], a[mt][3],
                         b[nt][0], b[nt][1]);
    }

    gemm_epilogue<EPI, NT>(acc, row0, col0, wm, wn, WN, lane, bia, w3, aux, Cc, Nld);
}

// ===========================================================================
// cp.async 3-stage pipelined warp-MMA GEMM (K = 256, BK = 64)
// ===========================================================================
template<int K, int BN, int EPI>
__global__ __launch_bounds__(256, 2)
void gemm_pipe(const __nv_bfloat16* __restrict__ A0, const __nv_bfloat16* __restrict__ A1,
               const __nv_bfloat16* __restrict__ B0, const __nv_bfloat16* __restrict__ B1,
               const float* __restrict__ bias0, const float* __restrict__ bias1,
               const float* __restrict__ w30,  const float* __restrict__ w31,
               const __nv_bfloat16* __restrict__ aux0, const __nv_bfloat16* __restrict__ aux1,
               void* __restrict__ C0, void* __restrict__ C1, int Nld) {
    constexpr int BK   = 64;
    constexpr int LDE  = BK + 8;
    constexpr int NSTG = 3;
    constexpr int NCH  = K / BK;
    constexpr int STGE = (128 + BN) * LDE;
    extern __shared__ __align__(16) __nv_bfloat16 smp[];

    const int tid = threadIdx.x, wid = tid >> 5, lane = tid & 31;
    const int zi = blockIdx.z;
    const __nv_bfloat16* A   = zi ? A1 : A0;
    const __nv_bfloat16* Bw  = zi ? B1 : B0;
    const float* bia         = zi ? bias1 : bias0;
    const float* w3          = zi ? w31 : w30;
    const __nv_bfloat16* aux = zi ? aux1 : aux0;
    char* Cc                 = (char*)(zi ? C1 : C0);

    const size_t row0 = (size_t)blockIdx.x * 128;
    const int    col0 = blockIdx.y * BN;
    const uint32_t sm0 = smem_u32(smp);

    auto load_chunk = [&](int s, int c) {
        const uint32_t dstS = sm0 + (uint32_t)(s * STGE * 2);
        const int k0 = c * BK;
        #pragma unroll
        for (int t = tid; t < (128 + BN) * 8; t += 256) {
            int r = t >> 3, seg = t & 7;
            if (r < 128) {
                cpasync16(dstS + (uint32_t)((r * LDE + seg * 8) * 2),
                          A + (row0 + r) * K + k0 + seg * 8);
            } else {
                int rb = r - 128;
                cpasync16(dstS + (uint32_t)(((128 + rb) * LDE + seg * 8) * 2),
                          Bw + (size_t)(col0 + rb) * K + k0 + seg * 8);
            }
        }
    };

    const int wm = wid & 3;
    const int wn = wid >> 2;
    constexpr int WN = BN / 2;
    constexpr int NT = WN / 8;
    const int g = lane >> 2;
    const int j = lane & 3;

    float acc[2][NT][4];
    #pragma unroll
    for (int mt = 0; mt < 2; mt++)
        #pragma unroll
        for (int nt = 0; nt < NT; nt++)
            #pragma unroll
            for (int i = 0; i < 4; i++) acc[mt][nt][i] = 0.f;

    uint32_t aBase[2];
    #pragma unroll
    for (int mt = 0; mt < 2; mt++)
        aBase[mt] = sm0 + (uint32_t)(((wm * 32 + mt * 16 + g) * LDE + 2 * j) * 2);
    uint32_t bBase[NT];
    #pragma unroll
    for (int nt = 0; nt < NT; nt++)
        bBase[nt] = sm0 + (uint32_t)(((128 + wn * WN + nt * 8 + g) * LDE + 2 * j) * 2);
    constexpr uint32_t ROW8 = (uint32_t)(8 * LDE * 2);

    load_chunk(0, 0); cp_commit();
    load_chunk(1, 1); cp_commit();

    for (int c = 0; c < NCH; c++) {
        cp_wait<1>();
        __syncthreads();
        const uint32_t soff = (uint32_t)((c % NSTG) * STGE * 2);
        #pragma unroll
        for (int kc = 0; kc < BK / 16; kc++) {
            const uint32_t kb = soff + (uint32_t)(kc * 32);
            uint32_t a[2][4];
            #pragma unroll
            for (int mt = 0; mt < 2; mt++) {
                a[mt][0] = lds32(aBase[mt] + kb);
                a[mt][1] = lds32(aBase[mt] + kb + ROW8);
                a[mt][2] = lds32(aBase[mt] + kb + 16);
                a[mt][3] = lds32(aBase[mt] + kb + ROW8 + 16);
            }
            uint32_t b[NT][2];
            #pragma unroll
            for (int nt = 0; nt < NT; nt++) {
                b[nt][0] = lds32(bBase[nt] + kb);
                b[nt][1] = lds32(bBase[nt] + kb + 16);
            }
            #pragma unroll
            for (int mt = 0; mt < 2; mt++)
                #pragma unroll
                for (int nt = 0; nt < NT; nt++)
                    mma16816(acc[mt][nt], a[mt][0], a[mt][1], a[mt][2], a[mt][3],
                             b[nt][0], b[nt][1]);
        }
        __syncthreads();
        if (c + 2 < NCH) load_chunk((c + 2) % NSTG, c + 2);
        cp_commit();
    }

    gemm_epilogue<EPI, NT>(acc, row0, col0, wm, wn, WN, lane, bia, w3, aux, Cc, Nld);
}

// ===========================================================================
// RK4 elementwise combine
// ===========================================================================
__global__ __launch_bounds__(256)
void rk4_k(const float* __restrict__ dzT, const float* __restrict__ dzV,
           const float* __restrict__ u, const float* __restrict__ Bc,
           const float* __restrict__ z, float* __restrict__ acc,
           __nv_bfloat16* __restrict__ zk, float* __restrict__ out, int stage) {
    size_t idx = (size_t)blockIdx.x * 256 + threadIdx.x;
    int col = (int)(idx & 63);
    size_t row = idx >> 6;
    float dz = dzT[idx] + dzV[idx];
    if (col >= QD) dz += u[row] * Bc[col - QD];
    float w = (stage == 1 || stage == 2) ? 2.f : 1.f;
    float a = (stage == 0 ? 0.f : acc[idx]) + w * dz;
    acc[idx] = a;
    if (stage < 3) {
        float cn = (stage == 2) ? DTC : 0.5f * DTC;
        zk[idx] = __float2bfloat16(fmaf(cn, dz, z[idx]));
    } else {
        out[idx] = fmaf(DTC / 6.f, a, z[idx]);
    }
}

// ===========================================================================
// Host orchestration
// ===========================================================================
extern "C" void kernel_launch(void* const* d_in, const int* in_sizes, int n_in,
                              void* d_out, int out_size) {
    const float* h    = (const float*)d_in[0];
    const float* u    = (const float*)d_in[1];
    const float* sW1  = (const float*)d_in[2];
    const float* sb1  = (const float*)d_in[3];
    const float* sW2  = (const float*)d_in[4];
    const float* sb2  = (const float*)d_in[5];
    const float* tW1  = (const float*)d_in[6];
    const float* tb1  = (const float*)d_in[7];
    const float* tW2  = (const float*)d_in[8];
    const float* tb2  = (const float*)d_in[9];
    const float* kW1  = (const float*)d_in[10];
    const float* kb1  = (const float*)d_in[11];
    const float* kW2  = (const float*)d_in[12];
    const float* kb2  = (const float*)d_in[13];
    const float* kW3  = (const float*)d_in[14];
    const float* vW1  = (const float*)d_in[16];
    const float* vb1  = (const float*)d_in[17];
    const float* vW2  = (const float*)d_in[18];
    const float* vb2  = (const float*)d_in[19];
    const float* vW3  = (const float*)d_in[20];
    const float* A    = (const float*)d_in[22];
    const float* Lp   = (const float*)d_in[23];
    const float* Bc   = (const float*)d_in[24];
    float* out = (float*)d_out;

    float *z, *acc, *dzT, *dzV, *Mp, *fpk;
    __nv_bfloat16 *zk, *h1T, *h1V, *g2T, *g2V, *g1T, *g1V;
    __nv_bfloat16 *Bk1, *Bv1, *Bk2, *Bv2, *Bk2t, *Bv2t, *BkM, *BvM;
    cudaGetSymbolAddress((void**)&z,    g_z);
    cudaGetSymbolAddress((void**)&acc,  g_acc);
    cudaGetSymbolAddress((void**)&dzT,  g_dzT);
    cudaGetSymbolAddress((void**)&dzV,  g_dzV);
    cudaGetSymbolAddress((void**)&zk,   g_zk);
    cudaGetSymbolAddress((void**)&h1T,  g_h1T);
    cudaGetSymbolAddress((void**)&h1V,  g_h1V);
    cudaGetSymbolAddress((void**)&g2T,  g_g2T);
    cudaGetSymbolAddress((void**)&g2V,  g_g2V);
    cudaGetSymbolAddress((void**)&g1T,  g_g1T);
    cudaGetSymbolAddress((void**)&g1V,  g_g1V);
    cudaGetSymbolAddress((void**)&Bk1,  g_Bk1);
    cudaGetSymbolAddress((void**)&Bv1,  g_Bv1);
    cudaGetSymbolAddress((void**)&Bk2,  g_Bk2);
    cudaGetSymbolAddress((void**)&Bv2,  g_Bv2);
    cudaGetSymbolAddress((void**)&Bk2t, g_Bk2t);
    cudaGetSymbolAddress((void**)&Bv2t, g_Bv2t);
    cudaGetSymbolAddress((void**)&BkM,  g_BkM);
    cudaGetSymbolAddress((void**)&BvM,  g_BvM);
    cudaGetSymbolAddress((void**)&Mp,   g_M);
    cudaGetSymbolAddress((void**)&fpk,  g_fpk);

    const int SM1 = (128 + 128) * (64 + 8) * 2;        // 36,864
    const int SMP128 = 3 * (128 + 128) * 72 * 2;       // 110,592
    const int SMP64  = 3 * (128 + 64)  * 72 * 2;       //  82,944
    const int SMF    = 35136 * 4;                      // 140,544 (flow_mma_k)
    cudaFuncSetAttribute(gemm_mma<64, 128, 0>,
                         cudaFuncAttributeMaxDynamicSharedMemorySize, SM1);
    cudaFuncSetAttribute(gemm_pipe<256, 128, 1>,
                         cudaFuncAttributeMaxDynamicSharedMemorySize, SMP128);
    cudaFuncSetAttribute(gemm_pipe<256, 128, 2>,
                         cudaFuncAttributeMaxDynamicSharedMemorySize, SMP128);
    cudaFuncSetAttribute(gemm_pipe<256, 64, 3>,
                         cudaFuncAttributeMaxDynamicSharedMemorySize, SMP64);
    cudaFuncSetAttribute(flow_mma_k,
                         cudaFuncAttributeMaxDynamicSharedMemorySize, SMF);

    // ---- prep: 2 launches ----
    build_M_k<<<1, 256>>>(A, Lp, Mp);
    prep_pack_k<<<dim3(384, 9), 256>>>(kW1, vW1, kW2, vW2, Mp,
                                       sW1, sW2, tW1, tW2,
                                       Bk1, Bv1, Bk2, Bv2, Bk2t, Bv2t,
                                       BkM, BvM, fpk);

    // ---- s = flow_fwd(h) ----
    cudaMemcpyAsync(z, h, (size_t)BATCH * DIM * sizeof(float),
                    cudaMemcpyDeviceToDevice, 0);
    for (int l = 0; l < NLAYERS; l++)
        flow_mma_k<<<BATCH / 128, 256, SMF>>>(z, fpk, sb1, sb2, tb1, tb2, l, 0);
    f2bf_k<<<BATCH * DIM / 1024, 256>>>(z, zk);

    // ---- RK4 stages ----
    dim3 gBig(BATCH / 128, 2, 2);
    dim3 gSml(BATCH / 128, 1, 2);
    for (int st = 0; st < 4; st++) {
        gemm_mma<64, 128, 0><<<gBig, 256, SM1>>>(
            zk, zk, Bk1, Bv1, kb1, vb1, 0, 0, 0, 0, h1T, h1V, HH);
        gemm_pipe<256, 128, 1><<<gBig, 256, SMP128>>>(
            h1T, h1V, Bk2, Bv2, kb2, vb2, kW3, vW3, 0, 0, g2T, g2V, HH);
        gemm_pipe<256, 128, 2><<<gBig, 256, SMP128>>>(
            g2T, g2V, Bk2t, Bv2t, 0, 0, 0, 0, h1T, h1V, g1T, g1V, HH);
        gemm_pipe<256, 64, 3><<<gSml, 256, SMP64>>>(
            g1T, g1V, BkM, BvM, 0, 0, 0, 0, 0, 0, dzT, dzV, DIM);
        rk4_k<<<BATCH * DIM / 256, 256>>>(dzT, dzV, u, Bc, z, acc, zk, out, st);
    }

    // ---- h_next = flow_inv(z_next) in place on out ----
    for (int l = NLAYERS - 1; l >= 0; l--)
        flow_mma_k<<<BATCH / 128, 256, SMF>>>(out, fpk, sb1, sb2, tb1, tb2, l, 1);
}

// round 10
// speedup vs baseline: 3.4802x; 1.0858x over previous
#include <cuda_runtime.h>
#include <cuda_bf16.h>
#include <math.h>
#include <cstdint>

#define BATCH   131072
#define DIM     64
#define QD      32
#define NLAYERS 6
#define HF      128
#define HH      256
#define DTC     0.05f

// ===========================================================================
// Scratch (static __device__ arrays)
// ===========================================================================
__device__ __align__(16) float g_z   [BATCH * DIM];
__device__ __align__(16) float g_acc [BATCH * DIM];
__device__ __align__(16) float g_dzT [BATCH * DIM];
__device__ __align__(16) float g_dzV [BATCH * DIM];
__device__ __align__(16) __nv_bfloat16 g_zk [BATCH * DIM];
__device__ __align__(16) __nv_bfloat16 g_h1T[BATCH * HH];
__device__ __align__(16) __nv_bfloat16 g_h1V[BATCH * HH];
__device__ __align__(16) __nv_bfloat16 g_g2T[BATCH * HH];
__device__ __align__(16) __nv_bfloat16 g_g2V[BATCH * HH];
__device__ __align__(16) __nv_bfloat16 g_g1T[BATCH * HH];
__device__ __align__(16) __nv_bfloat16 g_g1V[BATCH * HH];
// bf16 weight images, plain row-major [N][K]
__device__ __align__(16) __nv_bfloat16 g_Bk1 [HH * 64];
__device__ __align__(16) __nv_bfloat16 g_Bv1 [HH * 64];
__device__ __align__(16) __nv_bfloat16 g_Bk2 [HH * HH];
__device__ __align__(16) __nv_bfloat16 g_Bv2 [HH * HH];
__device__ __align__(16) __nv_bfloat16 g_Bk2t[HH * HH];
__device__ __align__(16) __nv_bfloat16 g_Bv2t[HH * HH];
__device__ __align__(16) __nv_bfloat16 g_BkM [64 * HH];
__device__ __align__(16) __nv_bfloat16 g_BvM [64 * HH];
__device__ float g_M[DIM * DIM];
// flow weights, tf32-rounded, per layer: [sW1 4096 | sW2 4096 | tW1 4096 | tW2 4096]
__device__ __align__(16) float g_fpk[NLAYERS * 16384];

__device__ __forceinline__ float softplusf(float x) {
    return fmaxf(x, 0.f) + log1pf(expf(-fabsf(x)));
}

__device__ __forceinline__ uint32_t smem_u32(const void* p) {
    uint32_t a;
    asm("{ .reg .u64 t; cvta.to.shared.u64 t, %1; cvt.u32.u64 %0, t; }"
        : "=r"(a) : "l"(p));
    return a;
}

__device__ __forceinline__ uint32_t lds32(uint32_t addr) {
    uint32_t v;
    asm("ld.shared.b32 %0, [%1];" : "=r"(v) : "r"(addr));
    return v;
}

__device__ __forceinline__ float tf32r(float x) {
    uint32_t u;
    asm("cvt.rna.tf32.f32 %0, %1;" : "=r"(u) : "f"(x));
    return __uint_as_float(u);
}

__device__ __forceinline__ void cpasync16(uint32_t dst, const void* src) {
    asm volatile("cp.async.cg.shared.global [%0], [%1], 16;"
                 :: "r"(dst), "l"(src));
}

__device__ __forceinline__ void cp_commit() {
    asm volatile("cp.async.commit_group;");
}

template<int N>
__device__ __forceinline__ void cp_wait() {
    asm volatile("cp.async.wait_group %0;" :: "n"(N));
}

__device__ __forceinline__ void mma16816(float* c, uint32_t a0, uint32_t a1,
                                         uint32_t a2, uint32_t a3,
                                         uint32_t b0, uint32_t b1) {
    asm volatile(
        "mma.sync.aligned.m16n8k16.row.col.f32.bf16.bf16.f32 "
        "{%0,%1,%2,%3},{%4,%5,%6,%7},{%8,%9},{%0,%1,%2,%3};"
        : "+f"(c[0]), "+f"(c[1]), "+f"(c[2]), "+f"(c[3])
        : "r"(a0), "r"(a1), "r"(a2), "r"(a3), "r"(b0), "r"(b1));
}

__device__ __forceinline__ void mma_tf32(float* c, uint32_t a0, uint32_t a1,
                                         uint32_t a2, uint32_t a3,
                                         uint32_t b0, uint32_t b1) {
    asm volatile(
        "mma.sync.aligned.m16n8k8.row.col.f32.tf32.tf32.f32 "
        "{%0,%1,%2,%3},{%4,%5,%6,%7},{%8,%9},{%0,%1,%2,%3};"
        : "+f"(c[0]), "+f"(c[1]), "+f"(c[2]), "+f"(c[3])
        : "r"(a0), "r"(a1), "r"(a2), "r"(a3), "r"(b0), "r"(b1));
}

// ===========================================================================
// Prep kernels
// ===========================================================================
__global__ void build_M_k(const float* __restrict__ A, const float* __restrict__ Lp,
                          float* __restrict__ M) {
    __shared__ float L[DIM * DIM];
    int t = threadIdx.x;
    for (int idx = t; idx < DIM * DIM; idx += 256) {
        int i = idx >> 6, j = idx & 63;
        float v;
        if (i > j)       v = Lp[idx];
        else if (i == j) v = softplusf(Lp[idx]);
        else             v = 0.f;
        L[idx] = v;
    }
    __syncthreads();
    for (int idx = t; idx < DIM * DIM; idx += 256) {
        int i = idx >> 6, j = idx & 63;
        float s = 0.f;
        #pragma unroll 8
        for (int k = 0; k < DIM; k++) s += L[i * DIM + k] * L[j * DIM + k];
        M[idx] = A[i * DIM + j] - A[j * DIM + i] - s;
    }
}

// one kernel, tasks on blockIdx.y; grid.x = 384 (task 8 needs 98304 threads)
__global__ void prep_pack_k(const float* __restrict__ kW1, const float* __restrict__ vW1,
                            const float* __restrict__ kW2, const float* __restrict__ vW2,
                            const float* __restrict__ M,
                            const float* __restrict__ sW1, const float* __restrict__ sW2,
                            const float* __restrict__ tW1, const float* __restrict__ tW2,
                            __nv_bfloat16* __restrict__ Bk1, __nv_bfloat16* __restrict__ Bv1,
                            __nv_bfloat16* __restrict__ Bk2, __nv_bfloat16* __restrict__ Bv2,
                            __nv_bfloat16* __restrict__ Bk2t, __nv_bfloat16* __restrict__ Bv2t,
                            __nv_bfloat16* __restrict__ BkM, __nv_bfloat16* __restrict__ BvM,
                            float* __restrict__ fpk) {
    int idx = blockIdx.x * 256 + threadIdx.x;
    int task = blockIdx.y;
    if (task == 0) {
        if (idx < HH * 64) Bk1[idx] = __float2bfloat16(kW1[idx]);
    } else if (task == 1) {
        if (idx < HH * 64) {
            int r = idx >> 6, k = idx & 63;
            Bv1[idx] = __float2bfloat16(k < QD ? vW1[r * QD + k] : 0.f);
        }
    } else if (task == 2) {
        if (idx < HH * HH) Bk2[idx] = __float2bfloat16(kW2[idx]);
    } else if (task == 3) {
        if (idx < HH * HH) Bv2[idx] = __float2bfloat16(vW2[idx]);
    } else if (task == 4) {
        if (idx < HH * HH) {
            int r = idx >> 8, k = idx & 255;
            Bk2t[idx] = __float2bfloat16(kW2[k * HH + r]);
        }
    } else if (task == 5) {
        if (idx < HH * HH) {
            int r = idx >> 8, k = idx & 255;
            Bv2t[idx] = __float2bfloat16(vW2[k * HH + r]);
        }
    } else if (task == 6) {
        if (idx < 64 * HH) {
            int i = idx >> 8, k = idx & 255;
            float s = 0.f;
            for (int n = 0; n < 64; n++) s += kW1[k * 64 + n] * M[i * 64 + n];
            BkM[idx] = __float2bfloat16(s);
        }
    } else if (task == 7) {
        if (idx < 64 * HH) {
            int i = idx >> 8, k = idx & 255;
            float s = 0.f;
            for (int n = 0; n < QD; n++) s += vW1[k * QD + n] * M[i * 64 + n];
            BvM[idx] = __float2bfloat16(s);
        }
    } else {   // task 8: flow weights, tf32-rounded, natural layout
        if (idx < NLAYERS * 16384) {
            int l = idx / 16384, r = idx % 16384;
            int sel = r / 4096, o = r % 4096;
            float v;
            if (sel == 0)      v = sW1[l * 4096 + o];
            else if (sel == 1) v = sW2[l * 4096 + o];
            else if (sel == 2) v = tW1[l * 4096 + o];
            else               v = tW2[l * 4096 + o];
            fpk[idx] = tf32r(v);
        }
    }
}

__global__ void f2bf_k(const float* __restrict__ s, __nv_bfloat16* __restrict__ d) {
    int i = blockIdx.x * 256 + threadIdx.x;
    float4 v = reinterpret_cast<const float4*>(s)[i];
    __nv_bfloat162 a; a.x = __float2bfloat16(v.x); a.y = __float2bfloat16(v.y);
    __nv_bfloat162 b; b.x = __float2bfloat16(v.z); b.y = __float2bfloat16(v.w);
    reinterpret_cast<__nv_bfloat162*>(d)[2 * i]     = a;
    reinterpret_cast<__nv_bfloat162*>(d)[2 * i + 1] = b;
}

// ===========================================================================
// tf32 tensor-core RealNVP coupling layer -- 64 rows/CTA (2 CTAs/SM).
//  8 warps as 2M (32-row strips) x 4N. Per MLP (s then t, reusing smem):
//   MMA1 (M64,N128,K32):  hidden = relu(cond @ W1^T + b1), cond split hi/lo.
//   MMA2 (M64,N32,K128):  pre = hidden @ W2^T (+ b2 at epilogue)
//  Padded strides 36 / 132 words (≡ 4 banks mod 32) -> conflict-free gathers.
// ===========================================================================
__global__ __launch_bounds__(256, 2)
void flow_mma_k(float* __restrict__ z, const float* __restrict__ fpk,
                const float* __restrict__ sb1, const float* __restrict__ sb2,
                const float* __restrict__ tb1, const float* __restrict__ tb2,
                int layer, int inverse) {
    // smem float offsets
    constexpr int CH   = 0;               // cond_hi  [64][36]
    constexpr int CL   = 2304;            // cond_lo  [64][36]
    constexpr int W1O  = 4608;            // W1       [128][36]
    constexpr int W2O  = 9216;            // W2       [32][132]
    constexpr int HIDO = 13440;           // hidden   [64][132]
    constexpr int B1O  = 21888;           // b1       [128]
    constexpr int B2SO = 22016;           // sb2      [32]
    constexpr int B2TO = 22048;           // tb2      [32]
    extern __shared__ float sm[];

    const int tid = threadIdx.x, wid = tid >> 5, lane = tid & 31;
    const int g = lane >> 2, j = lane & 3;
    const int wm = wid & 1, wn = wid >> 1;          // 2M x 4N
    const int parity = layer & 1;
    const int coff = parity ? QD : 0;
    const int moff = parity ? 0 : QD;
    const size_t row0 = (size_t)blockIdx.x * 64;
    const uint32_t smb = smem_u32(sm);

    // ---- stage cond hi/lo + b2 arrays ----
    for (int idx = tid; idx < 64 * 32; idx += 256) {
        int r = idx >> 5, c = idx & 31;
        float y = z[(row0 + r) * DIM + coff + c];
        float hi = tf32r(y);
        sm[CH + r * 36 + c] = hi;
        sm[CL + r * 36 + c] = tf32r(y - hi);
    }
    if (tid < QD) {
        sm[B2SO + tid] = sb2[layer * QD + tid];
        sm[B2TO + tid] = tb2[layer * QD + tid];
    }

    float res[2][2][4];   // [st][mt][frag]

    const float* wl = fpk + (size_t)layer * 16384;
    for (int st = 0; st < 2; st++) {
        // ---- stage W1 [128][32], W2 [32][128], b1 ----
        const float* w1g = wl + st * 8192;
        const float* b1g = (st ? tb1 : sb1) + layer * HF;
        for (int idx = tid; idx < 4096; idx += 256)
            sm[W1O + (idx >> 5) * 36 + (idx & 31)] = w1g[idx];
        for (int idx = tid; idx < 4096; idx += 256)
            sm[W2O + (idx >> 7) * 132 + (idx & 127)] = w1g[4096 + idx];
        if (tid < HF) sm[B1O + tid] = b1g[tid];
        __syncthreads();

        // ---- MMA1: cond(hi+lo) @ W1^T ----
        float acc1[2][4][4];
        #pragma unroll
        for (int mt = 0; mt < 2; mt++)
            #pragma unroll
            for (int nt = 0; nt < 4; nt++)
                #pragma unroll
                for (int i = 0; i < 4; i++) acc1[mt][nt][i] = 0.f;

        uint32_t aH[2], aL[2];
        #pragma unroll
        for (int mt = 0; mt < 2; mt++) {
            int r = wm * 32 + mt * 16 + g;
            aH[mt] = smb + (uint32_t)((CH + r * 36 + j) << 2);
            aL[mt] = smb + (uint32_t)((CL + r * 36 + j) << 2);
        }
        uint32_t bA[4];
        #pragma unroll
        for (int nt = 0; nt < 4; nt++)
            bA[nt] = smb + (uint32_t)((W1O + (wn * 32 + nt * 8 + g) * 36 + j) << 2);

        #pragma unroll
        for (int kc = 0; kc < 4; kc++) {
            const uint32_t ko = (uint32_t)(kc * 32);
            uint32_t ah[2][4], al[2][4];
            #pragma unroll
            for (int mt = 0; mt < 2; mt++) {
                ah[mt][0] = lds32(aH[mt] + ko);
                ah[mt][1] = lds32(aH[mt] + ko + 1152);   // +8 rows (8*36*4)
                ah[mt][2] = lds32(aH[mt] + ko + 16);     // +4 cols
                ah[mt][3] = lds32(aH[mt] + ko + 1168);
                al[mt][0] = lds32(aL[mt] + ko);
                al[mt][1] = lds32(aL[mt] + ko + 1152);
                al[mt][2] = lds32(aL[mt] + ko + 16);
                al[mt][3] = lds32(aL[mt] + ko + 1168);
            }
            #pragma unroll
            for (int nt = 0; nt < 4; nt++) {
                uint32_t b0 = lds32(bA[nt] + ko);
                uint32_t b1 = lds32(bA[nt] + ko + 16);
                #pragma unroll
                for (int mt = 0; mt < 2; mt++) {
                    mma_tf32(acc1[mt][nt], ah[mt][0], ah[mt][1], ah[mt][2], ah[mt][3], b0, b1);
                    mma_tf32(acc1[mt][nt], al[mt][0], al[mt][1], al[mt][2], al[mt][3], b0, b1);
                }
            }
        }

        // ---- bias + relu -> hidden (tf32) ----
        #pragma unroll
        for (int mt = 0; mt < 2; mt++) {
            int r0 = wm * 32 + mt * 16 + g;
            #pragma unroll
            for (int nt = 0; nt < 4; nt++) {
                int c0 = wn * 32 + nt * 8 + 2 * j;
                float b0 = sm[B1O + c0], b1f = sm[B1O + c0 + 1];
                sm[HIDO + r0 * 132 + c0]           = tf32r(fmaxf(acc1[mt][nt][0] + b0, 0.f));
                sm[HIDO + r0 * 132 + c0 + 1]       = tf32r(fmaxf(acc1[mt][nt][1] + b1f, 0.f));
                sm[HIDO + (r0 + 8) * 132 + c0]     = tf32r(fmaxf(acc1[mt][nt][2] + b0, 0.f));
                sm[HIDO + (r0 + 8) * 132 + c0 + 1] = tf32r(fmaxf(acc1[mt][nt][3] + b1f, 0.f));
            }
        }
        __syncthreads();

        // ---- MMA2: hidden @ W2^T (each warp: 32 rows x 8 cols) ----
        float acc2[2][4];
        #pragma unroll
        for (int mt = 0; mt < 2; mt++)
            #pragma unroll
            for (int i = 0; i < 4; i++) acc2[mt][i] = 0.f;

        uint32_t a2[2];
        #pragma unroll
        for (int mt = 0; mt < 2; mt++)
            a2[mt] = smb + (uint32_t)((HIDO + (wm * 32 + mt * 16 + g) * 132 + j) << 2);
        uint32_t b2a = smb + (uint32_t)((W2O + (wn * 8 + g) * 132 + j) << 2);

        #pragma unroll 4
        for (int kc = 0; kc < 16; kc++) {
            const uint32_t ko = (uint32_t)(kc * 32);
            uint32_t b0 = lds32(b2a + ko);
            uint32_t b1 = lds32(b2a + ko + 16);
            #pragma unroll
            for (int mt = 0; mt < 2; mt++) {
                uint32_t av0 = lds32(a2[mt] + ko);
                uint32_t av1 = lds32(a2[mt] + ko + 4224);   // +8 rows (8*132*4)
                uint32_t av2 = lds32(a2[mt] + ko + 16);
                uint32_t av3 = lds32(a2[mt] + ko + 4240);
                mma_tf32(acc2[mt], av0, av1, av2, av3, b0, b1);
            }
        }
        #pragma unroll
        for (int mt = 0; mt < 2; mt++)
            #pragma unroll
            for (int i = 0; i < 4; i++) res[st][mt][i] = acc2[mt][i];
        __syncthreads();   // protect W/hidden restaging next MLP
    }

    // ---- elementwise epilogue: update modified half ----
    #pragma unroll
    for (int mt = 0; mt < 2; mt++) {
        size_t zr0 = (row0 + wm * 32 + mt * 16 + g) * DIM + moff;
        size_t zr1 = zr0 + 8 * DIM;
        int c0 = wn * 8 + 2 * j;
        float sb0 = sm[B2SO + c0], sb1v = sm[B2SO + c0 + 1];
        float tb0 = sm[B2TO + c0], tb1v = sm[B2TO + c0 + 1];
        float s0 = tanhf(res[0][mt][0] + sb0);
        float s1 = tanhf(res[0][mt][1] + sb1v);
        float s2 = tanhf(res[0][mt][2] + sb0);
        float s3 = tanhf(res[0][mt][3] + sb1v);
        float t0 = res[1][mt][0] + tb0;
        float t1 = res[1][mt][1] + tb1v;
        float t2 = res[1][mt][2] + tb0;
        float t3 = res[1][mt][3] + tb1v;
        float2 x0 = *reinterpret_cast<float2*>(z + zr0 + c0);
        float2 x1 = *reinterpret_cast<float2*>(z + zr1 + c0);
        if (inverse) {
            x0.x = (x0.x - t0) * expf(-s0);
            x0.y = (x0.y - t1) * expf(-s1);
            x1.x = (x1.x - t2) * expf(-s2);
            x1.y = (x1.y - t3) * expf(-s3);
        } else {
            x0.x = fmaf(x0.x, expf(s0), t0);
            x0.y = fmaf(x0.y, expf(s1), t1);
            x1.x = fmaf(x1.x, expf(s2), t2);
            x1.y = fmaf(x1.y, expf(s3), t3);
        }
        *reinterpret_cast<float2*>(z + zr0 + c0) = x0;
        *reinterpret_cast<float2*>(z + zr1 + c0) = x1;
    }
}

// ===========================================================================
// Shared GEMM epilogue
// ===========================================================================
template<int EPI, int NT>
__device__ __forceinline__ void gemm_epilogue(
    float acc[2][NT][4], size_t row0, int col0, int wm, int wn, int WN,
    int lane, const float* bia, const float* w3, const __nv_bfloat16* aux,
    char* Cc, int Nld) {
    #pragma unroll
    for (int mt = 0; mt < 2; mt++) {
        const size_t r0 = row0 + wm * 32 + mt * 16 + (lane >> 2);
        const size_t r1 = r0 + 8;
        #pragma unroll
        for (int nt = 0; nt < NT; nt++) {
            const int gc = col0 + wn * WN + nt * 8 + (lane & 3) * 2;
            float v0 = acc[mt][nt][0], v1 = acc[mt][nt][1];
            float v2 = acc[mt][nt][2], v3 = acc[mt][nt][3];
            if (EPI == 3) {
                *reinterpret_cast<float2*>((float*)Cc + r0 * Nld + gc) =
                    make_float2(v0, v1);
                *reinterpret_cast<float2*>((float*)Cc + r1 * Nld + gc) =
                    make_float2(v2, v3);
            } else {
                if (EPI == 0) {
                    float b0 = bia[gc], b1 = bia[gc + 1];
                    v0 = softplusf(v0 + b0); v1 = softplusf(v1 + b1);
                    v2 = softplusf(v2 + b0); v3 = softplusf(v3 + b1);
                } else if (EPI == 1) {
                    float b0 = bia[gc], b1 = bia[gc + 1];
                    float s0 = w3[gc], s1 = w3[gc + 1];
                    v0 = s0 / (1.f + expf(-(v0 + b0)));
                    v1 = s1 / (1.f + expf(-(v1 + b1)));
                    v2 = s0 / (1.f + expf(-(v2 + b0)));
                    v3 = s1 / (1.f + expf(-(v3 + b1)));
                } else if (EPI == 2) {
                    __nv_bfloat162 h0 = *reinterpret_cast<const __nv_bfloat162*>(
                        aux + r0 * HH + gc);
                    __nv_bfloat162 h1 = *reinterpret_cast<const __nv_bfloat162*>(
                        aux + r1 * HH + gc);
                    v0 *= (1.f - expf(-__bfloat162float(h0.x)));
                    v1 *= (1.f - expf(-__bfloat162float(h0.y)));
                    v2 *= (1.f - expf(-__bfloat162float(h1.x)));
                    v3 *= (1.f - expf(-__bfloat162float(h1.y)));
                }
                __nv_bfloat162 o0; o0.x = __float2bfloat16(v0); o0.y = __float2bfloat16(v1);
                __nv_bfloat162 o1; o1.x = __float2bfloat16(v2); o1.y = __float2bfloat16(v3);
                *reinterpret_cast<__nv_bfloat162*>(
                    (__nv_bfloat16*)Cc + r0 * Nld + gc) = o0;
                *reinterpret_cast<__nv_bfloat162*>(
                    (__nv_bfloat16*)Cc + r1 * Nld + gc) = o1;
            }
        }
    }
}

// ===========================================================================
// Single-shot warp-MMA GEMM (K=64)
// ===========================================================================
template<int K, int BN, int EPI>
__global__ __launch_bounds__(256)
void gemm_mma(const __nv_bfloat16* __restrict__ A0, const __nv_bfloat16* __restrict__ A1,
              const __nv_bfloat16* __restrict__ B0, const __nv_bfloat16* __restrict__ B1,
              const float* __restrict__ bias0, const float* __restrict__ bias1,
              const float* __restrict__ w30,  const float* __restrict__ w31,
              const __nv_bfloat16* __restrict__ aux0, const __nv_bfloat16* __restrict__ aux1,
              void* __restrict__ C0, void* __restrict__ C1, int Nld) {
    constexpr int LDE = K + 8;
    extern __shared__ __align__(16) char smraw[];
    __nv_bfloat16* smA = reinterpret_cast<__nv_bfloat16*>(smraw);
    __nv_bfloat16* smB = smA + 128 * LDE;

    const int tid = threadIdx.x, wid = tid >> 5, lane = tid & 31;
    const int zi = blockIdx.z;
    const __nv_bfloat16* A   = zi ? A1 : A0;
    const __nv_bfloat16* Bw  = zi ? B1 : B0;
    const float* bia         = zi ? bias1 : bias0;
    const float* w3          = zi ? w31 : w30;
    const __nv_bfloat16* aux = zi ? aux1 : aux0;
    char* Cc                 = (char*)(zi ? C1 : C0);

    const size_t row0 = (size_t)blockIdx.x * 128;
    const int    col0 = blockIdx.y * BN;

    constexpr int ASEG = K / 8;
    #pragma unroll 4
    for (int c = tid; c < 128 * ASEG; c += 256) {
        int r = c / ASEG, s = c % ASEG;
        *reinterpret_cast<uint4*>(smA + r * LDE + s * 8) =
            *reinterpret_cast<const uint4*>(A + (row0 + r) * K + s * 8);
    }
    #pragma unroll 4
    for (int c = tid; c < BN * ASEG; c += 256) {
        int r = c / ASEG, s = c % ASEG;
        *reinterpret_cast<uint4*>(smB + r * LDE + s * 8) =
            *reinterpret_cast<const uint4*>(Bw + (size_t)(col0 + r) * K + s * 8);
    }
    __syncthreads();

    const int wm = wid & 3;
    const int wn = wid >> 2;
    constexpr int WN = BN / 2;
    constexpr int NT = WN / 8;
    const int g = lane >> 2;
    const int j = lane & 3;

    float acc[2][NT][4];
    #pragma unroll
    for (int mt = 0; mt < 2; mt++)
        #pragma unroll
        for (int nt = 0; nt < NT; nt++)
            #pragma unroll
            for (int i = 0; i < 4; i++) acc[mt][nt][i] = 0.f;

    const uint32_t sA = smem_u32(smA), sB = smem_u32(smB);
    uint32_t aBase[2];
    #pragma unroll
    for (int mt = 0; mt < 2; mt++)
        aBase[mt] = sA + (uint32_t)(((wm * 32 + mt * 16 + g) * LDE + 2 * j) * 2);
    uint32_t bBase[NT];
    #pragma unroll
    for (int nt = 0; nt < NT; nt++)
        bBase[nt] = sB + (uint32_t)(((wn * WN + nt * 8 + g) * LDE + 2 * j) * 2);

    constexpr uint32_t ROW8 = (uint32_t)(8 * LDE * 2);

    #pragma unroll 4
    for (int kc = 0; kc < K / 16; kc++) {
        const uint32_t kb = (uint32_t)(kc * 32);
        uint32_t a[2][4];
        #pragma unroll
        for (int mt = 0; mt < 2; mt++) {
            a[mt][0] = lds32(aBase[mt] + kb);
            a[mt][1] = lds32(aBase[mt] + kb + ROW8);
            a[mt][2] = lds32(aBase[mt] + kb + 16);
            a[mt][3] = lds32(aBase[mt] + kb + ROW8 + 16);
        }
        uint32_t b[NT][2];
        #pragma unroll
        for (int nt = 0; nt < NT; nt++) {
            b[nt][0] = lds32(bBase[nt] + kb);
            b[nt][1] = lds32(bBase[nt] + kb + 16);
        }
        #pragma unroll
        for (int mt = 0; mt < 2; mt++)
            #pragma unroll
            for (int nt = 0; nt < NT; nt++)
                mma16816(acc[mt][nt], a[mt][0], a[mt][1], a[mt][2], a[mt][3],
                         b[nt][0], b[nt][1]);
    }

    gemm_epilogue<EPI, NT>(acc, row0, col0, wm, wn, WN, lane, bia, w3, aux, Cc, Nld);
}

// ===========================================================================
// cp.async 3-stage pipelined warp-MMA GEMM (K = 256, BK = 64)
// ===========================================================================
template<int K, int BN, int EPI>
__global__ __launch_bounds__(256, 2)
void gemm_pipe(const __nv_bfloat16* __restrict__ A0, const __nv_bfloat16* __restrict__ A1,
               const __nv_bfloat16* __restrict__ B0, const __nv_bfloat16* __restrict__ B1,
               const float* __restrict__ bias0, const float* __restrict__ bias1,
               const float* __restrict__ w30,  const float* __restrict__ w31,
               const __nv_bfloat16* __restrict__ aux0, const __nv_bfloat16* __restrict__ aux1,
               void* __restrict__ C0, void* __restrict__ C1, int Nld) {
    constexpr int BK   = 64;
    constexpr int LDE  = BK + 8;
    constexpr int NSTG = 3;
    constexpr int NCH  = K / BK;
    constexpr int STGE = (128 + BN) * LDE;
    extern __shared__ __align__(16) __nv_bfloat16 smp[];

    const int tid = threadIdx.x, wid = tid >> 5, lane = tid & 31;
    const int zi = blockIdx.z;
    const __nv_bfloat16* A   = zi ? A1 : A0;
    const __nv_bfloat16* Bw  = zi ? B1 : B0;
    const float* bia         = zi ? bias1 : bias0;
    const float* w3          = zi ? w31 : w30;
    const __nv_bfloat16* aux = zi ? aux1 : aux0;
    char* Cc                 = (char*)(zi ? C1 : C0);

    const size_t row0 = (size_t)blockIdx.x * 128;
    const int    col0 = blockIdx.y * BN;
    const uint32_t sm0 = smem_u32(smp);

    auto load_chunk = [&](int s, int c) {
        const uint32_t dstS = sm0 + (uint32_t)(s * STGE * 2);
        const int k0 = c * BK;
        #pragma unroll
        for (int t = tid; t < (128 + BN) * 8; t += 256) {
            int r = t >> 3, seg = t & 7;
            if (r < 128) {
                cpasync16(dstS + (uint32_t)((r * LDE + seg * 8) * 2),
                          A + (row0 + r) * K + k0 + seg * 8);
            } else {
                int rb = r - 128;
                cpasync16(dstS + (uint32_t)(((128 + rb) * LDE + seg * 8) * 2),
                          Bw + (size_t)(col0 + rb) * K + k0 + seg * 8);
            }
        }
    };

    const int wm = wid & 3;
    const int wn = wid >> 2;
    constexpr int WN = BN / 2;
    constexpr int NT = WN / 8;
    const int g = lane >> 2;
    const int j = lane & 3;

    float acc[2][NT][4];
    #pragma unroll
    for (int mt = 0; mt < 2; mt++)
        #pragma unroll
        for (int nt = 0; nt < NT; nt++)
            #pragma unroll
            for (int i = 0; i < 4; i++) acc[mt][nt][i] = 0.f;

    uint32_t aBase[2];
    #pragma unroll
    for (int mt = 0; mt < 2; mt++)
        aBase[mt] = sm0 + (uint32_t)(((wm * 32 + mt * 16 + g) * LDE + 2 * j) * 2);
    uint32_t bBase[NT];
    #pragma unroll
    for (int nt = 0; nt < NT; nt++)
        bBase[nt] = sm0 + (uint32_t)(((128 + wn * WN + nt * 8 + g) * LDE + 2 * j) * 2);
    constexpr uint32_t ROW8 = (uint32_t)(8 * LDE * 2);

    load_chunk(0, 0); cp_commit();
    load_chunk(1, 1); cp_commit();

    for (int c = 0; c < NCH; c++) {
        cp_wait<1>();
        __syncthreads();
        const uint32_t soff = (uint32_t)((c % NSTG) * STGE * 2);
        #pragma unroll
        for (int kc = 0; kc < BK / 16; kc++) {
            const uint32_t kb = soff + (uint32_t)(kc * 32);
            uint32_t a[2][4];
            #pragma unroll
            for (int mt = 0; mt < 2; mt++) {
                a[mt][0] = lds32(aBase[mt] + kb);
                a[mt][1] = lds32(aBase[mt] + kb + ROW8);
                a[mt][2] = lds32(aBase[mt] + kb + 16);
                a[mt][3] = lds32(aBase[mt] + kb + ROW8 + 16);
            }
            uint32_t b[NT][2];
            #pragma unroll
            for (int nt = 0; nt < NT; nt++) {
                b[nt][0] = lds32(bBase[nt] + kb);
                b[nt][1] = lds32(bBase[nt] + kb + 16);
            }
            #pragma unroll
            for (int mt = 0; mt < 2; mt++)
                #pragma unroll
                for (int nt = 0; nt < NT; nt++)
                    mma16816(acc[mt][nt], a[mt][0], a[mt][1], a[mt][2], a[mt][3],
                             b[nt][0], b[nt][1]);
        }
        __syncthreads();
        if (c + 2 < NCH) load_chunk((c + 2) % NSTG, c + 2);
        cp_commit();
    }

    gemm_epilogue<EPI, NT>(acc, row0, col0, wm, wn, WN, lane, bia, w3, aux, Cc, Nld);
}

// ===========================================================================
// RK4 elementwise combine
// ===========================================================================
__global__ __launch_bounds__(256)
void rk4_k(const float* __restrict__ dzT, const float* __restrict__ dzV,
           const float* __restrict__ u, const float* __restrict__ Bc,
           const float* __restrict__ z, float* __restrict__ acc,
           __nv_bfloat16* __restrict__ zk, float* __restrict__ out, int stage) {
    size_t idx = (size_t)blockIdx.x * 256 + threadIdx.x;
    int col = (int)(idx & 63);
    size_t row = idx >> 6;
    float dz = dzT[idx] + dzV[idx];
    if (col >= QD) dz += u[row] * Bc[col - QD];
    float w = (stage == 1 || stage == 2) ? 2.f : 1.f;
    float a = (stage == 0 ? 0.f : acc[idx]) + w * dz;
    acc[idx] = a;
    if (stage < 3) {
        float cn = (stage == 2) ? DTC : 0.5f * DTC;
        zk[idx] = __float2bfloat16(fmaf(cn, dz, z[idx]));
    } else {
        out[idx] = fmaf(DTC / 6.f, a, z[idx]);
    }
}

// ===========================================================================
// Host orchestration
// ===========================================================================
extern "C" void kernel_launch(void* const* d_in, const int* in_sizes, int n_in,
                              void* d_out, int out_size) {
    const float* h    = (const float*)d_in[0];
    const float* u    = (const float*)d_in[1];
    const float* sW1  = (const float*)d_in[2];
    const float* sb1  = (const float*)d_in[3];
    const float* sW2  = (const float*)d_in[4];
    const float* sb2  = (const float*)d_in[5];
    const float* tW1  = (const float*)d_in[6];
    const float* tb1  = (const float*)d_in[7];
    const float* tW2  = (const float*)d_in[8];
    const float* tb2  = (const float*)d_in[9];
    const float* kW1  = (const float*)d_in[10];
    const float* kb1  = (const float*)d_in[11];
    const float* kW2  = (const float*)d_in[12];
    const float* kb2  = (const float*)d_in[13];
    const float* kW3  = (const float*)d_in[14];
    const float* vW1  = (const float*)d_in[16];
    const float* vb1  = (const float*)d_in[17];
    const float* vW2  = (const float*)d_in[18];
    const float* vb2  = (const float*)d_in[19];
    const float* vW3  = (const float*)d_in[20];
    const float* A    = (const float*)d_in[22];
    const float* Lp   = (const float*)d_in[23];
    const float* Bc   = (const float*)d_in[24];
    float* out = (float*)d_out;

    float *z, *acc, *dzT, *dzV, *Mp, *fpk;
    __nv_bfloat16 *zk, *h1T, *h1V, *g2T, *g2V, *g1T, *g1V;
    __nv_bfloat16 *Bk1, *Bv1, *Bk2, *Bv2, *Bk2t, *Bv2t, *BkM, *BvM;
    cudaGetSymbolAddress((void**)&z,    g_z);
    cudaGetSymbolAddress((void**)&acc,  g_acc);
    cudaGetSymbolAddress((void**)&dzT,  g_dzT);
    cudaGetSymbolAddress((void**)&dzV,  g_dzV);
    cudaGetSymbolAddress((void**)&zk,   g_zk);
    cudaGetSymbolAddress((void**)&h1T,  g_h1T);
    cudaGetSymbolAddress((void**)&h1V,  g_h1V);
    cudaGetSymbolAddress((void**)&g2T,  g_g2T);
    cudaGetSymbolAddress((void**)&g2V,  g_g2V);
    cudaGetSymbolAddress((void**)&g1T,  g_g1T);
    cudaGetSymbolAddress((void**)&g1V,  g_g1V);
    cudaGetSymbolAddress((void**)&Bk1,  g_Bk1);
    cudaGetSymbolAddress((void**)&Bv1,  g_Bv1);
    cudaGetSymbolAddress((void**)&Bk2,  g_Bk2);
    cudaGetSymbolAddress((void**)&Bv2,  g_Bv2);
    cudaGetSymbolAddress((void**)&Bk2t, g_Bk2t);
    cudaGetSymbolAddress((void**)&Bv2t, g_Bv2t);
    cudaGetSymbolAddress((void**)&BkM,  g_BkM);
    cudaGetSymbolAddress((void**)&BvM,  g_BvM);
    cudaGetSymbolAddress((void**)&Mp,   g_M);
    cudaGetSymbolAddress((void**)&fpk,  g_fpk);

    const int SM1 = (128 + 128) * (64 + 8) * 2;        // 36,864
    const int SMP128 = 3 * (128 + 128) * 72 * 2;       // 110,592
    const int SMP64  = 3 * (128 + 64)  * 72 * 2;       //  82,944
    const int SMF    = 22080 * 4;                      //  88,320 (flow_mma_k)
    cudaFuncSetAttribute(gemm_mma<64, 128, 0>,
                         cudaFuncAttributeMaxDynamicSharedMemorySize, SM1);
    cudaFuncSetAttribute(gemm_pipe<256, 128, 1>,
                         cudaFuncAttributeMaxDynamicSharedMemorySize, SMP128);
    cudaFuncSetAttribute(gemm_pipe<256, 128, 2>,
                         cudaFuncAttributeMaxDynamicSharedMemorySize, SMP128);
    cudaFuncSetAttribute(gemm_pipe<256, 64, 3>,
                         cudaFuncAttributeMaxDynamicSharedMemorySize, SMP64);
    cudaFuncSetAttribute(flow_mma_k,
                         cudaFuncAttributeMaxDynamicSharedMemorySize, SMF);

    // ---- prep: 2 launches ----
    build_M_k<<<1, 256>>>(A, Lp, Mp);
    prep_pack_k<<<dim3(384, 9), 256>>>(kW1, vW1, kW2, vW2, Mp,
                                       sW1, sW2, tW1, tW2,
                                       Bk1, Bv1, Bk2, Bv2, Bk2t, Bv2t,
                                       BkM, BvM, fpk);

    // ---- s = flow_fwd(h) ----
    cudaMemcpyAsync(z, h, (size_t)BATCH * DIM * sizeof(float),
                    cudaMemcpyDeviceToDevice, 0);
    for (int l = 0; l < NLAYERS; l++)
        flow_mma_k<<<BATCH / 64, 256, SMF>>>(z, fpk, sb1, sb2, tb1, tb2, l, 0);
    f2bf_k<<<BATCH * DIM / 1024, 256>>>(z, zk);

    // ---- RK4 stages ----
    dim3 gBig(BATCH / 128, 2, 2);
    dim3 gSml(BATCH / 128, 1, 2);
    for (int st = 0; st < 4; st++) {
        gemm_mma<64, 128, 0><<<gBig, 256, SM1>>>(
            zk, zk, Bk1, Bv1, kb1, vb1, 0, 0, 0, 0, h1T, h1V, HH);
        gemm_pipe<256, 128, 1><<<gBig, 256, SMP128>>>(
            h1T, h1V, Bk2, Bv2, kb2, vb2, kW3, vW3, 0, 0, g2T, g2V, HH);
        gemm_pipe<256, 128, 2><<<gBig, 256, SMP128>>>(
            g2T, g2V, Bk2t, Bv2t, 0, 0, 0, 0, h1T, h1V, g1T, g1V, HH);
        gemm_pipe<256, 64, 3><<<gSml, 256, SMP64>>>(
            g1T, g1V, BkM, BvM, 0, 0, 0, 0, 0, 0, dzT, dzV, DIM);
        rk4_k<<<BATCH * DIM / 256, 256>>>(dzT, dzV, u, Bc, z, acc, zk, out, st);
    }

    // ---- h_next = flow_inv(z_next) in place on out ----
    for (int l = NLAYERS - 1; l >= 0; l--)
        flow_mma_k<<<BATCH / 64, 256, SMF>>>(out, fpk, sb1, sb2, tb1, tb2, l, 1);
}

// round 11
// speedup vs baseline: 3.9695x; 1.1406x over previous
#include <cuda_runtime.h>
#include <cuda_bf16.h>
#include <math.h>
#include <cstdint>

#define BATCH   131072
#define DIM     64
#define QD      32
#define NLAYERS 6
#define HF      128
#define HH      256
#define DTC     0.05f

// ===========================================================================
// Scratch (static __device__ arrays)
// ===========================================================================
__device__ __align__(16) float g_z   [BATCH * DIM];
__device__ __align__(16) float g_acc [BATCH * DIM];
__device__ __align__(16) __nv_bfloat16 g_zk [BATCH * DIM];
__device__ __align__(16) __nv_bfloat16 g_h1T[BATCH * HH];
__device__ __align__(16) __nv_bfloat16 g_h1V[BATCH * HH];
__device__ __align__(16) __nv_bfloat16 g_g2T[BATCH * HH];
__device__ __align__(16) __nv_bfloat16 g_g2V[BATCH * HH];
__device__ __align__(16) __nv_bfloat16 g_g1T[BATCH * HH];
__device__ __align__(16) __nv_bfloat16 g_g1V[BATCH * HH];
// bf16 weight images, plain row-major [N][K]
__device__ __align__(16) __nv_bfloat16 g_Bk1  [HH * 64];
__device__ __align__(16) __nv_bfloat16 g_Bv1  [HH * 64];
__device__ __align__(16) __nv_bfloat16 g_Bk2  [HH * HH];
__device__ __align__(16) __nv_bfloat16 g_Bv2  [HH * HH];
__device__ __align__(16) __nv_bfloat16 g_Bk2t [HH * HH];
__device__ __align__(16) __nv_bfloat16 g_Bv2t [HH * HH];
__device__ __align__(16) __nv_bfloat16 g_BMcat[64 * 512];   // [64][512] = (kW1*M^T | vW1*M^T)
__device__ float g_M[DIM * DIM];
// flow weights, tf32-rounded, per layer: [sW1 4096 | sW2 4096 | tW1 4096 | tW2 4096]
__device__ __align__(16) float g_fpk[NLAYERS * 16384];

__device__ __forceinline__ float softplusf(float x) {
    return fmaxf(x, 0.f) + log1pf(expf(-fabsf(x)));
}

__device__ __forceinline__ uint32_t smem_u32(const void* p) {
    uint32_t a;
    asm("{ .reg .u64 t; cvta.to.shared.u64 t, %1; cvt.u32.u64 %0, t; }"
        : "=r"(a) : "l"(p));
    return a;
}

__device__ __forceinline__ uint32_t lds32(uint32_t addr) {
    uint32_t v;
    asm("ld.shared.b32 %0, [%1];" : "=r"(v) : "r"(addr));
    return v;
}

__device__ __forceinline__ float tf32r(float x) {
    uint32_t u;
    asm("cvt.rna.tf32.f32 %0, %1;" : "=r"(u) : "f"(x));
    return __uint_as_float(u);
}

__device__ __forceinline__ void cpasync16(uint32_t dst, const void* src) {
    asm volatile("cp.async.cg.shared.global [%0], [%1], 16;"
                 :: "r"(dst), "l"(src));
}

__device__ __forceinline__ void cp_commit() {
    asm volatile("cp.async.commit_group;");
}

template<int N>
__device__ __forceinline__ void cp_wait() {
    asm volatile("cp.async.wait_group %0;" :: "n"(N));
}

__device__ __forceinline__ void mma16816(float* c, uint32_t a0, uint32_t a1,
                                         uint32_t a2, uint32_t a3,
                                         uint32_t b0, uint32_t b1) {
    asm volatile(
        "mma.sync.aligned.m16n8k16.row.col.f32.bf16.bf16.f32 "
        "{%0,%1,%2,%3},{%4,%5,%6,%7},{%8,%9},{%0,%1,%2,%3};"
        : "+f"(c[0]), "+f"(c[1]), "+f"(c[2]), "+f"(c[3])
        : "r"(a0), "r"(a1), "r"(a2), "r"(a3), "r"(b0), "r"(b1));
}

__device__ __forceinline__ void mma_tf32(float* c, uint32_t a0, uint32_t a1,
                                         uint32_t a2, uint32_t a3,
                                         uint32_t b0, uint32_t b1) {
    asm volatile(
        "mma.sync.aligned.m16n8k8.row.col.f32.tf32.tf32.f32 "
        "{%0,%1,%2,%3},{%4,%5,%6,%7},{%8,%9},{%0,%1,%2,%3};"
        : "+f"(c[0]), "+f"(c[1]), "+f"(c[2]), "+f"(c[3])
        : "r"(a0), "r"(a1), "r"(a2), "r"(a3), "r"(b0), "r"(b1));
}

// ===========================================================================
// Prep kernels
// ===========================================================================
__global__ void build_M_k(const float* __restrict__ A, const float* __restrict__ Lp,
                          float* __restrict__ M) {
    __shared__ float L[DIM * DIM];
    int t = threadIdx.x;
    for (int idx = t; idx < DIM * DIM; idx += 256) {
        int i = idx >> 6, j = idx & 63;
        float v;
        if (i > j)       v = Lp[idx];
        else if (i == j) v = softplusf(Lp[idx]);
        else             v = 0.f;
        L[idx] = v;
    }
    __syncthreads();
    for (int idx = t; idx < DIM * DIM; idx += 256) {
        int i = idx >> 6, j = idx & 63;
        float s = 0.f;
        #pragma unroll 8
        for (int k = 0; k < DIM; k++) s += L[i * DIM + k] * L[j * DIM + k];
        M[idx] = A[i * DIM + j] - A[j * DIM + i] - s;
    }
}

// one kernel, tasks on blockIdx.y; grid.x = 384 (task 8 needs 98304 threads)
__global__ void prep_pack_k(const float* __restrict__ kW1, const float* __restrict__ vW1,
                            const float* __restrict__ kW2, const float* __restrict__ vW2,
                            const float* __restrict__ M,
                            const float* __restrict__ sW1, const float* __restrict__ sW2,
                            const float* __restrict__ tW1, const float* __restrict__ tW2,
                            __nv_bfloat16* __restrict__ Bk1, __nv_bfloat16* __restrict__ Bv1,
                            __nv_bfloat16* __restrict__ Bk2, __nv_bfloat16* __restrict__ Bv2,
                            __nv_bfloat16* __restrict__ Bk2t, __nv_bfloat16* __restrict__ Bv2t,
                            __nv_bfloat16* __restrict__ BMcat,
                            float* __restrict__ fpk) {
    int idx = blockIdx.x * 256 + threadIdx.x;
    int task = blockIdx.y;
    if (task == 0) {
        if (idx < HH * 64) Bk1[idx] = __float2bfloat16(kW1[idx]);
    } else if (task == 1) {
        if (idx < HH * 64) {
            int r = idx >> 6, k = idx & 63;
            Bv1[idx] = __float2bfloat16(k < QD ? vW1[r * QD + k] : 0.f);
        }
    } else if (task == 2) {
        if (idx < HH * HH) Bk2[idx] = __float2bfloat16(kW2[idx]);
    } else if (task == 3) {
        if (idx < HH * HH) Bv2[idx] = __float2bfloat16(vW2[idx]);
    } else if (task == 4) {
        if (idx < HH * HH) {
            int r = idx >> 8, k = idx & 255;
            Bk2t[idx] = __float2bfloat16(kW2[k * HH + r]);
        }
    } else if (task == 5) {
        if (idx < HH * HH) {
            int r = idx >> 8, k = idx & 255;
            Bv2t[idx] = __float2bfloat16(vW2[k * HH + r]);
        }
    } else if (task == 6) {   // BMcat[i][k<256] = sum_n kW1[k][n]*M[i][n]
        if (idx < 64 * HH) {
            int i = idx >> 8, k = idx & 255;
            float s = 0.f;
            for (int n = 0; n < 64; n++) s += kW1[k * 64 + n] * M[i * 64 + n];
            BMcat[i * 512 + k] = __float2bfloat16(s);
        }
    } else if (task == 7) {   // BMcat[i][256+k] = sum_n vW1[k][n]*M[i][n]
        if (idx < 64 * HH) {
            int i = idx >> 8, k = idx & 255;
            float s = 0.f;
            for (int n = 0; n < QD; n++) s += vW1[k * QD + n] * M[i * 64 + n];
            BMcat[i * 512 + 256 + k] = __float2bfloat16(s);
        }
    } else {   // task 8: flow weights, tf32-rounded, natural layout
        if (idx < NLAYERS * 16384) {
            int l = idx / 16384, r = idx % 16384;
            int sel = r / 4096, o = r % 4096;
            float v;
            if (sel == 0)      v = sW1[l * 4096 + o];
            else if (sel == 1) v = sW2[l * 4096 + o];
            else if (sel == 2) v = tW1[l * 4096 + o];
            else               v = tW2[l * 4096 + o];
            fpk[idx] = tf32r(v);
        }
    }
}

__global__ void f2bf_k(const float* __restrict__ s, __nv_bfloat16* __restrict__ d) {
    int i = blockIdx.x * 256 + threadIdx.x;
    float4 v = reinterpret_cast<const float4*>(s)[i];
    __nv_bfloat162 a; a.x = __float2bfloat16(v.x); a.y = __float2bfloat16(v.y);
    __nv_bfloat162 b; b.x = __float2bfloat16(v.z); b.y = __float2bfloat16(v.w);
    reinterpret_cast<__nv_bfloat162*>(d)[2 * i]     = a;
    reinterpret_cast<__nv_bfloat162*>(d)[2 * i + 1] = b;
}

// ===========================================================================
// tf32 tensor-core RealNVP coupling layer -- 64 rows/CTA (2 CTAs/SM),
// cp.async weight double-buffering: W1_t prefetched under MMA2_s, W2_t under
// MMA1_t. Same smem buffers, refilled only when provably idle.
// ===========================================================================
// smem float offsets
#define F_CH   0                 // cond_hi  [64][36]
#define F_CL   2304              // cond_lo  [64][36] (raw cond staged here first)
#define F_W1O  4608              // W1       [128][36]
#define F_W2O  9216              // W2       [32][132]
#define F_HIDO 13440             // hidden   [64][132]
#define F_B1SO 21888             // sb1 [128]
#define F_B1TO 22016             // tb1 [128]
#define F_B2SO 22144             // sb2 [32]
#define F_B2TO 22176             // tb2 [32]
#define F_TOT  22208

__device__ __forceinline__ void flow_stage_w1(uint32_t smb, const float* src, int tid) {
    #pragma unroll
    for (int c = 0; c < 4; c++) {
        int idx = c * 256 + tid;            // 1024 chunks of 16B
        int r = idx >> 3, seg = idx & 7;
        cpasync16(smb + (uint32_t)((F_W1O + r * 36 + seg * 4) << 2), src + idx * 4);
    }
}
__device__ __forceinline__ void flow_stage_w2(uint32_t smb, const float* src, int tid) {
    #pragma unroll
    for (int c = 0; c < 4; c++) {
        int idx = c * 256 + tid;
        int r = idx >> 5, seg = idx & 31;
        cpasync16(smb + (uint32_t)((F_W2O + r * 132 + seg * 4) << 2), src + idx * 4);
    }
}

// MMA1 (cond hi/lo @ W1^T) + bias/relu -> hidden
__device__ __forceinline__ void flow_mma1(float* sm, uint32_t smb,
                                          int wm, int wn, int g, int j, int b1off) {
    float acc1[2][4][4];
    #pragma unroll
    for (int mt = 0; mt < 2; mt++)
        #pragma unroll
        for (int nt = 0; nt < 4; nt++)
            #pragma unroll
            for (int i = 0; i < 4; i++) acc1[mt][nt][i] = 0.f;

    uint32_t aH[2], aL[2];
    #pragma unroll
    for (int mt = 0; mt < 2; mt++) {
        int r = wm * 32 + mt * 16 + g;
        aH[mt] = smb + (uint32_t)((F_CH + r * 36 + j) << 2);
        aL[mt] = smb + (uint32_t)((F_CL + r * 36 + j) << 2);
    }
    uint32_t bA[4];
    #pragma unroll
    for (int nt = 0; nt < 4; nt++)
        bA[nt] = smb + (uint32_t)((F_W1O + (wn * 32 + nt * 8 + g) * 36 + j) << 2);

    #pragma unroll
    for (int kc = 0; kc < 4; kc++) {
        const uint32_t ko = (uint32_t)(kc * 32);
        uint32_t ah[2][4], al[2][4];
        #pragma unroll
        for (int mt = 0; mt < 2; mt++) {
            ah[mt][0] = lds32(aH[mt] + ko);
            ah[mt][1] = lds32(aH[mt] + ko + 1152);
            ah[mt][2] = lds32(aH[mt] + ko + 16);
            ah[mt][3] = lds32(aH[mt] + ko + 1168);
            al[mt][0] = lds32(aL[mt] + ko);
            al[mt][1] = lds32(aL[mt] + ko + 1152);
            al[mt][2] = lds32(aL[mt] + ko + 16);
            al[mt][3] = lds32(aL[mt] + ko + 1168);
        }
        #pragma unroll
        for (int nt = 0; nt < 4; nt++) {
            uint32_t b0 = lds32(bA[nt] + ko);
            uint32_t b1 = lds32(bA[nt] + ko + 16);
            #pragma unroll
            for (int mt = 0; mt < 2; mt++) {
                mma_tf32(acc1[mt][nt], ah[mt][0], ah[mt][1], ah[mt][2], ah[mt][3], b0, b1);
                mma_tf32(acc1[mt][nt], al[mt][0], al[mt][1], al[mt][2], al[mt][3], b0, b1);
            }
        }
    }
    // bias + relu -> hidden (tf32)
    #pragma unroll
    for (int mt = 0; mt < 2; mt++) {
        int r0 = wm * 32 + mt * 16 + g;
        #pragma unroll
        for (int nt = 0; nt < 4; nt++) {
            int c0 = wn * 32 + nt * 8 + 2 * j;
            float b0 = sm[b1off + c0], b1f = sm[b1off + c0 + 1];
            sm[F_HIDO + r0 * 132 + c0]           = tf32r(fmaxf(acc1[mt][nt][0] + b0, 0.f));
            sm[F_HIDO + r0 * 132 + c0 + 1]       = tf32r(fmaxf(acc1[mt][nt][1] + b1f, 0.f));
            sm[F_HIDO + (r0 + 8) * 132 + c0]     = tf32r(fmaxf(acc1[mt][nt][2] + b0, 0.f));
            sm[F_HIDO + (r0 + 8) * 132 + c0 + 1] = tf32r(fmaxf(acc1[mt][nt][3] + b1f, 0.f));
        }
    }
}

// MMA2: hidden @ W2^T (each warp: 32 rows x 8 cols) -> res[2][4]
__device__ __forceinline__ void flow_mma2(uint32_t smb, int wm, int wn, int g, int j,
                                          float res[2][4]) {
    float acc2[2][4];
    #pragma unroll
    for (int mt = 0; mt < 2; mt++)
        #pragma unroll
        for (int i = 0; i < 4; i++) acc2[mt][i] = 0.f;

    uint32_t a2[2];
    #pragma unroll
    for (int mt = 0; mt < 2; mt++)
        a2[mt] = smb + (uint32_t)((F_HIDO + (wm * 32 + mt * 16 + g) * 132 + j) << 2);
    uint32_t b2a = smb + (uint32_t)((F_W2O + (wn * 8 + g) * 132 + j) << 2);

    #pragma unroll 4
    for (int kc = 0; kc < 16; kc++) {
        const uint32_t ko = (uint32_t)(kc * 32);
        uint32_t b0 = lds32(b2a + ko);
        uint32_t b1 = lds32(b2a + ko + 16);
        #pragma unroll
        for (int mt = 0; mt < 2; mt++) {
            uint32_t av0 = lds32(a2[mt] + ko);
            uint32_t av1 = lds32(a2[mt] + ko + 4224);
            uint32_t av2 = lds32(a2[mt] + ko + 16);
            uint32_t av3 = lds32(a2[mt] + ko + 4240);
            mma_tf32(acc2[mt], av0, av1, av2, av3, b0, b1);
        }
    }
    #pragma unroll
    for (int mt = 0; mt < 2; mt++)
        #pragma unroll
        for (int i = 0; i < 4; i++) res[mt][i] = acc2[mt][i];
}

__global__ __launch_bounds__(256, 2)
void flow_mma_k(float* __restrict__ z, const float* __restrict__ fpk,
                const float* __restrict__ sb1, const float* __restrict__ sb2,
                const float* __restrict__ tb1, const float* __restrict__ tb2,
                int layer, int inverse) {
    extern __shared__ float sm[];

    const int tid = threadIdx.x, wid = tid >> 5, lane = tid & 31;
    const int g = lane >> 2, j = lane & 3;
    const int wm = wid & 1, wn = wid >> 1;          // 2M x 4N
    const int parity = layer & 1;
    const int coff = parity ? QD : 0;
    const int moff = parity ? 0 : QD;
    const size_t row0 = (size_t)blockIdx.x * 64;
    const uint32_t smb = smem_u32(sm);
    const float* wl = fpk + (size_t)layer * 16384;

    // ---- G0: cp.async cond(raw -> CL) + W1_s + W2_s ----
    #pragma unroll
    for (int c = 0; c < 2; c++) {            // 512 chunks: cond 64 rows x 8 segs
        int idx = c * 256 + tid;
        int r = idx >> 3, seg = idx & 7;
        cpasync16(smb + (uint32_t)((F_CL + r * 36 + seg * 4) << 2),
                  z + (row0 + r) * DIM + coff + seg * 4);
    }
    flow_stage_w1(smb, wl, tid);
    flow_stage_w2(smb, wl + 4096, tid);
    cp_commit();                              // G0

    // biases (plain loads, tiny)
    if (tid < HF) {
        sm[F_B1SO + tid] = sb1[layer * HF + tid];
        sm[F_B1TO + tid] = tb1[layer * HF + tid];
    }
    if (tid < QD) {
        sm[F_B2SO + tid] = sb2[layer * QD + tid];
        sm[F_B2TO + tid] = tb2[layer * QD + tid];
    }

    cp_wait<0>();
    __syncthreads();

    // ---- split cond hi/lo in place ----
    #pragma unroll
    for (int c = 0; c < 8; c++) {
        int idx = c * 256 + tid;
        int r = idx >> 5, cc = idx & 31;
        float y = sm[F_CL + r * 36 + cc];
        float hi = tf32r(y);
        sm[F_CH + r * 36 + cc] = hi;
        sm[F_CL + r * 36 + cc] = tf32r(y - hi);
    }
    __syncthreads();

    float res_s[2][4], res_t[2][4];

    // ---- s-MLP ----
    flow_mma1(sm, smb, wm, wn, g, j, F_B1SO);
    __syncthreads();                          // hidden_s visible; W1 buf now idle
    flow_stage_w1(smb, wl + 8192, tid);       // prefetch W1_t under MMA2_s
    cp_commit();                              // G1
    flow_mma2(smb, wm, wn, g, j, res_s);
    __syncthreads();                          // all done with W2_s + hidden_s
    flow_stage_w2(smb, wl + 8192 + 4096, tid);// prefetch W2_t under MMA1_t
    cp_commit();                              // G2
    cp_wait<1>();                             // G1 (W1_t) complete
    __syncthreads();

    // ---- t-MLP ----
    flow_mma1(sm, smb, wm, wn, g, j, F_B1TO);
    cp_wait<0>();                             // G2 (W2_t) complete
    __syncthreads();                          // hidden_t + W2_t visible
    flow_mma2(smb, wm, wn, g, j, res_t);

    // ---- elementwise epilogue: update modified half ----
    #pragma unroll
    for (int mt = 0; mt < 2; mt++) {
        size_t zr0 = (row0 + wm * 32 + mt * 16 + g) * DIM + moff;
        size_t zr1 = zr0 + 8 * DIM;
        int c0 = wn * 8 + 2 * j;
        float sb0 = sm[F_B2SO + c0], sb1v = sm[F_B2SO + c0 + 1];
        float tb0 = sm[F_B2TO + c0], tb1v = sm[F_B2TO + c0 + 1];
        float s0 = tanhf(res_s[mt][0] + sb0);
        float s1 = tanhf(res_s[mt][1] + sb1v);
        float s2 = tanhf(res_s[mt][2] + sb0);
        float s3 = tanhf(res_s[mt][3] + sb1v);
        float t0 = res_t[mt][0] + tb0;
        float t1 = res_t[mt][1] + tb1v;
        float t2 = res_t[mt][2] + tb0;
        float t3 = res_t[mt][3] + tb1v;
        float2 x0 = *reinterpret_cast<float2*>(z + zr0 + c0);
        float2 x1 = *reinterpret_cast<float2*>(z + zr1 + c0);
        if (inverse) {
            x0.x = (x0.x - t0) * expf(-s0);
            x0.y = (x0.y - t1) * expf(-s1);
            x1.x = (x1.x - t2) * expf(-s2);
            x1.y = (x1.y - t3) * expf(-s3);
        } else {
            x0.x = fmaf(x0.x, expf(s0), t0);
            x0.y = fmaf(x0.y, expf(s1), t1);
            x1.x = fmaf(x1.x, expf(s2), t2);
            x1.y = fmaf(x1.y, expf(s3), t3);
        }
        *reinterpret_cast<float2*>(z + zr0 + c0) = x0;
        *reinterpret_cast<float2*>(z + zr1 + c0) = x1;
    }
}

// ===========================================================================
// Shared GEMM epilogue (bf16-activation variants)
// ===========================================================================
template<int EPI, int NT>
__device__ __forceinline__ void gemm_epilogue(
    float acc[2][NT][4], size_t row0, int col0, int wm, int wn, int WN,
    int lane, const float* bia, const float* w3, const __nv_bfloat16* aux,
    char* Cc, int Nld) {
    #pragma unroll
    for (int mt = 0; mt < 2; mt++) {
        const size_t r0 = row0 + wm * 32 + mt * 16 + (lane >> 2);
        const size_t r1 = r0 + 8;
        #pragma unroll
        for (int nt = 0; nt < NT; nt++) {
            const int gc = col0 + wn * WN + nt * 8 + (lane & 3) * 2;
            float v0 = acc[mt][nt][0], v1 = acc[mt][nt][1];
            float v2 = acc[mt][nt][2], v3 = acc[mt][nt][3];
            if (EPI == 0) {
                float b0 = bia[gc], b1 = bia[gc + 1];
                v0 = softplusf(v0 + b0); v1 = softplusf(v1 + b1);
                v2 = softplusf(v2 + b0); v3 = softplusf(v3 + b1);
            } else if (EPI == 1) {
                float b0 = bia[gc], b1 = bia[gc + 1];
                float s0 = w3[gc], s1 = w3[gc + 1];
                v0 = s0 / (1.f + expf(-(v0 + b0)));
                v1 = s1 / (1.f + expf(-(v1 + b1)));
                v2 = s0 / (1.f + expf(-(v2 + b0)));
                v3 = s1 / (1.f + expf(-(v3 + b1)));
            } else if (EPI == 2) {
                __nv_bfloat162 h0 = *reinterpret_cast<const __nv_bfloat162*>(
                    aux + r0 * HH + gc);
                __nv_bfloat162 h1 = *reinterpret_cast<const __nv_bfloat162*>(
                    aux + r1 * HH + gc);
                v0 *= (1.f - expf(-__bfloat162float(h0.x)));
                v1 *= (1.f - expf(-__bfloat162float(h0.y)));
                v2 *= (1.f - expf(-__bfloat162float(h1.x)));
                v3 *= (1.f - expf(-__bfloat162float(h1.y)));
            }
            __nv_bfloat162 o0; o0.x = __float2bfloat16(v0); o0.y = __float2bfloat16(v1);
            __nv_bfloat162 o1; o1.x = __float2bfloat16(v2); o1.y = __float2bfloat16(v3);
            *reinterpret_cast<__nv_bfloat162*>(
                (__nv_bfloat16*)Cc + r0 * Nld + gc) = o0;
            *reinterpret_cast<__nv_bfloat162*>(
                (__nv_bfloat16*)Cc + r1 * Nld + gc) = o1;
        }
    }
}

// ===========================================================================
// Single-shot warp-MMA GEMM (K=64)
// ===========================================================================
template<int K, int BN, int EPI>
__global__ __launch_bounds__(256)
void gemm_mma(const __nv_bfloat16* __restrict__ A0, const __nv_bfloat16* __restrict__ A1,
              const __nv_bfloat16* __restrict__ B0, const __nv_bfloat16* __restrict__ B1,
              const float* __restrict__ bias0, const float* __restrict__ bias1,
              const float* __restrict__ w30,  const float* __restrict__ w31,
              const __nv_bfloat16* __restrict__ aux0, const __nv_bfloat16* __restrict__ aux1,
              void* __restrict__ C0, void* __restrict__ C1, int Nld) {
    constexpr int LDE = K + 8;
    extern __shared__ __align__(16) char smraw[];
    __nv_bfloat16* smA = reinterpret_cast<__nv_bfloat16*>(smraw);
    __nv_bfloat16* smB = smA + 128 * LDE;

    const int tid = threadIdx.x, wid = tid >> 5, lane = tid & 31;
    const int zi = blockIdx.z;
    const __nv_bfloat16* A   = zi ? A1 : A0;
    const __nv_bfloat16* Bw  = zi ? B1 : B0;
    const float* bia         = zi ? bias1 : bias0;
    const float* w3          = zi ? w31 : w30;
    const __nv_bfloat16* aux = zi ? aux1 : aux0;
    char* Cc                 = (char*)(zi ? C1 : C0);

    const size_t row0 = (size_t)blockIdx.x * 128;
    const int    col0 = blockIdx.y * BN;

    constexpr int ASEG = K / 8;
    #pragma unroll 4
    for (int c = tid; c < 128 * ASEG; c += 256) {
        int r = c / ASEG, s = c % ASEG;
        *reinterpret_cast<uint4*>(smA + r * LDE + s * 8) =
            *reinterpret_cast<const uint4*>(A + (row0 + r) * K + s * 8);
    }
    #pragma unroll 4
    for (int c = tid; c < BN * ASEG; c += 256) {
        int r = c / ASEG, s = c % ASEG;
        *reinterpret_cast<uint4*>(smB + r * LDE + s * 8) =
            *reinterpret_cast<const uint4*>(Bw + (size_t)(col0 + r) * K + s * 8);
    }
    __syncthreads();

    const int wm = wid & 3;
    const int wn = wid >> 2;
    constexpr int WN = BN / 2;
    constexpr int NT = WN / 8;
    const int g = lane >> 2;
    const int j = lane & 3;

    float acc[2][NT][4];
    #pragma unroll
    for (int mt = 0; mt < 2; mt++)
        #pragma unroll
        for (int nt = 0; nt < NT; nt++)
            #pragma unroll
            for (int i = 0; i < 4; i++) acc[mt][nt][i] = 0.f;

    const uint32_t sA = smem_u32(smA), sB = smem_u32(smB);
    uint32_t aBase[2];
    #pragma unroll
    for (int mt = 0; mt < 2; mt++)
        aBase[mt] = sA + (uint32_t)(((wm * 32 + mt * 16 + g) * LDE + 2 * j) * 2);
    uint32_t bBase[NT];
    #pragma unroll
    for (int nt = 0; nt < NT; nt++)
        bBase[nt] = sB + (uint32_t)(((wn * WN + nt * 8 + g) * LDE + 2 * j) * 2);

    constexpr uint32_t ROW8 = (uint32_t)(8 * LDE * 2);

    #pragma unroll 4
    for (int kc = 0; kc < K / 16; kc++) {
        const uint32_t kb = (uint32_t)(kc * 32);
        uint32_t a[2][4];
        #pragma unroll
        for (int mt = 0; mt < 2; mt++) {
            a[mt][0] = lds32(aBase[mt] + kb);
            a[mt][1] = lds32(aBase[mt] + kb + ROW8);
            a[mt][2] = lds32(aBase[mt] + kb + 16);
            a[mt][3] = lds32(aBase[mt] + kb + ROW8 + 16);
        }
        uint32_t b[NT][2];
        #pragma unroll
        for (int nt = 0; nt < NT; nt++) {
            b[nt][0] = lds32(bBase[nt] + kb);
            b[nt][1] = lds32(bBase[nt] + kb + 16);
        }
        #pragma unroll
        for (int mt = 0; mt < 2; mt++)
            #pragma unroll
            for (int nt = 0; nt < NT; nt++)
                mma16816(acc[mt][nt], a[mt][0], a[mt][1], a[mt][2], a[mt][3],
                         b[nt][0], b[nt][1]);
    }

    gemm_epilogue<EPI, NT>(acc, row0, col0, wm, wn, WN, lane, bia, w3, aux, Cc, Nld);
}

// ===========================================================================
// cp.async 3-stage pipelined warp-MMA GEMM (K = 256, BK = 64, BN = 128)
// ===========================================================================
template<int K, int BN, int EPI>
__global__ __launch_bounds__(256, 2)
void gemm_pipe(const __nv_bfloat16* __restrict__ A0, const __nv_bfloat16* __restrict__ A1,
               const __nv_bfloat16* __restrict__ B0, const __nv_bfloat16* __restrict__ B1,
               const float* __restrict__ bias0, const float* __restrict__ bias1,
               const float* __restrict__ w30,  const float* __restrict__ w31,
               const __nv_bfloat16* __restrict__ aux0, const __nv_bfloat16* __restrict__ aux1,
               void* __restrict__ C0, void* __restrict__ C1, int Nld) {
    constexpr int BK   = 64;
    constexpr int LDE  = BK + 8;
    constexpr int NSTG = 3;
    constexpr int NCH  = K / BK;
    constexpr int STGE = (128 + BN) * LDE;
    extern __shared__ __align__(16) __nv_bfloat16 smp[];

    const int tid = threadIdx.x, wid = tid >> 5, lane = tid & 31;
    const int zi = blockIdx.z;
    const __nv_bfloat16* A   = zi ? A1 : A0;
    const __nv_bfloat16* Bw  = zi ? B1 : B0;
    const float* bia         = zi ? bias1 : bias0;
    const float* w3          = zi ? w31 : w30;
    const __nv_bfloat16* aux = zi ? aux1 : aux0;
    char* Cc                 = (char*)(zi ? C1 : C0);

    const size_t row0 = (size_t)blockIdx.x * 128;
    const int    col0 = blockIdx.y * BN;
    const uint32_t sm0 = smem_u32(smp);

    auto load_chunk = [&](int s, int c) {
        const uint32_t dstS = sm0 + (uint32_t)(s * STGE * 2);
        const int k0 = c * BK;
        #pragma unroll
        for (int t = tid; t < (128 + BN) * 8; t += 256) {
            int r = t >> 3, seg = t & 7;
            if (r < 128) {
                cpasync16(dstS + (uint32_t)((r * LDE + seg * 8) * 2),
                          A + (row0 + r) * K + k0 + seg * 8);
            } else {
                int rb = r - 128;
                cpasync16(dstS + (uint32_t)(((128 + rb) * LDE + seg * 8) * 2),
                          Bw + (size_t)(col0 + rb) * K + k0 + seg * 8);
            }
        }
    };

    const int wm = wid & 3;
    const int wn = wid >> 2;
    constexpr int WN = BN / 2;
    constexpr int NT = WN / 8;
    const int g = lane >> 2;
    const int j = lane & 3;

    float acc[2][NT][4];
    #pragma unroll
    for (int mt = 0; mt < 2; mt++)
        #pragma unroll
        for (int nt = 0; nt < NT; nt++)
            #pragma unroll
            for (int i = 0; i < 4; i++) acc[mt][nt][i] = 0.f;

    uint32_t aBase[2];
    #pragma unroll
    for (int mt = 0; mt < 2; mt++)
        aBase[mt] = sm0 + (uint32_t)(((wm * 32 + mt * 16 + g) * LDE + 2 * j) * 2);
    uint32_t bBase[NT];
    #pragma unroll
    for (int nt = 0; nt < NT; nt++)
        bBase[nt] = sm0 + (uint32_t)(((128 + wn * WN + nt * 8 + g) * LDE + 2 * j) * 2);
    constexpr uint32_t ROW8 = (uint32_t)(8 * LDE * 2);

    load_chunk(0, 0); cp_commit();
    load_chunk(1, 1); cp_commit();

    for (int c = 0; c < NCH; c++) {
        cp_wait<1>();
        __syncthreads();
        const uint32_t soff = (uint32_t)((c % NSTG) * STGE * 2);
        #pragma unroll
        for (int kc = 0; kc < BK / 16; kc++) {
            const uint32_t kb = soff + (uint32_t)(kc * 32);
            uint32_t a[2][4];
            #pragma unroll
            for (int mt = 0; mt < 2; mt++) {
                a[mt][0] = lds32(aBase[mt] + kb);
                a[mt][1] = lds32(aBase[mt] + kb + ROW8);
                a[mt][2] = lds32(aBase[mt] + kb + 16);
                a[mt][3] = lds32(aBase[mt] + kb + ROW8 + 16);
            }
            uint32_t b[NT][2];
            #pragma unroll
            for (int nt = 0; nt < NT; nt++) {
                b[nt][0] = lds32(bBase[nt] + kb);
                b[nt][1] = lds32(bBase[nt] + kb + 16);
            }
            #pragma unroll
            for (int mt = 0; mt < 2; mt++)
                #pragma unroll
                for (int nt = 0; nt < NT; nt++)
                    mma16816(acc[mt][nt], a[mt][0], a[mt][1], a[mt][2], a[mt][3],
                             b[nt][0], b[nt][1]);
        }
        __syncthreads();
        if (c + 2 < NCH) load_chunk((c + 2) % NSTG, c + 2);
        cp_commit();
    }

    gemm_epilogue<EPI, NT>(acc, row0, col0, wm, wn, WN, lane, bia, w3, aux, Cc, Nld);
}

// ===========================================================================
// Fused final GEMM (K=512: [g1T | g1V] @ BMcat^T) + RK4 epilogue.
//   dz = dzT + dzV falls out of the K-concat; epilogue does +u*Bc, acc
//   update, zk (stages 0-2) or out (stage 3). BN = 64 = DIM.
// ===========================================================================
__global__ __launch_bounds__(256, 2)
void gemm_rk4(const __nv_bfloat16* __restrict__ g1T, const __nv_bfloat16* __restrict__ g1V,
              const __nv_bfloat16* __restrict__ Bw,   // BMcat [64][512]
              const float* __restrict__ u, const float* __restrict__ Bc,
              const float* __restrict__ zg, float* __restrict__ accg,
              __nv_bfloat16* __restrict__ zk, float* __restrict__ outg, int stage) {
    constexpr int BK   = 64;
    constexpr int LDE  = BK + 8;
    constexpr int NSTG = 3;
    constexpr int NCH  = 8;              // K = 512
    constexpr int BN   = 64;
    constexpr int STGE = (128 + BN) * LDE;
    extern __shared__ __align__(16) __nv_bfloat16 smp[];

    const int tid = threadIdx.x, wid = tid >> 5, lane = tid & 31;
    const size_t row0 = (size_t)blockIdx.x * 128;
    const uint32_t sm0 = smem_u32(smp);

    auto load_chunk = [&](int s, int c) {
        const uint32_t dstS = sm0 + (uint32_t)(s * STGE * 2);
        const __nv_bfloat16* A = (c < 4) ? g1T : g1V;
        const int k0 = (c & 3) * BK;
        #pragma unroll
        for (int t = tid; t < (128 + BN) * 8; t += 256) {
            int r = t >> 3, seg = t & 7;
            if (r < 128) {
                cpasync16(dstS + (uint32_t)((r * LDE + seg * 8) * 2),
                          A + (row0 + r) * HH + k0 + seg * 8);
            } else {
                int rb = r - 128;
                cpasync16(dstS + (uint32_t)(((128 + rb) * LDE + seg * 8) * 2),
                          Bw + (size_t)rb * 512 + c * BK + seg * 8);
            }
        }
    };

    const int wm = wid & 3;
    const int wn = wid >> 2;
    constexpr int WN = BN / 2;   // 32
    constexpr int NT = WN / 8;   // 4
    const int g = lane >> 2;
    const int j = lane & 3;

    float acc[2][NT][4];
    #pragma unroll
    for (int mt = 0; mt < 2; mt++)
        #pragma unroll
        for (int nt = 0; nt < NT; nt++)
            #pragma unroll
            for (int i = 0; i < 4; i++) acc[mt][nt][i] = 0.f;

    uint32_t aBase[2];
    #pragma unroll
    for (int mt = 0; mt < 2; mt++)
        aBase[mt] = sm0 + (uint32_t)(((wm * 32 + mt * 16 + g) * LDE + 2 * j) * 2);
    uint32_t bBase[NT];
    #pragma unroll
    for (int nt = 0; nt < NT; nt++)
        bBase[nt] = sm0 + (uint32_t)(((128 + wn * WN + nt * 8 + g) * LDE + 2 * j) * 2);
    constexpr uint32_t ROW8 = (uint32_t)(8 * LDE * 2);

    load_chunk(0, 0); cp_commit();
    load_chunk(1, 1); cp_commit();

    for (int c = 0; c < NCH; c++) {
        cp_wait<1>();
        __syncthreads();
        const uint32_t soff = (uint32_t)((c % NSTG) * STGE * 2);
        #pragma unroll
        for (int kc = 0; kc < BK / 16; kc++) {
            const uint32_t kb = soff + (uint32_t)(kc * 32);
            uint32_t a[2][4];
            #pragma unroll
            for (int mt = 0; mt < 2; mt++) {
                a[mt][0] = lds32(aBase[mt] + kb);
                a[mt][1] = lds32(aBase[mt] + kb + ROW8);
                a[mt][2] = lds32(aBase[mt] + kb + 16);
                a[mt][3] = lds32(aBase[mt] + kb + ROW8 + 16);
            }
            uint32_t b[NT][2];
            #pragma unroll
            for (int nt = 0; nt < NT; nt++) {
                b[nt][0] = lds32(bBase[nt] + kb);
                b[nt][1] = lds32(bBase[nt] + kb + 16);
            }
            #pragma unroll
            for (int mt = 0; mt < 2; mt++)
                #pragma unroll
                for (int nt = 0; nt < NT; nt++)
                    mma16816(acc[mt][nt], a[mt][0], a[mt][1], a[mt][2], a[mt][3],
                             b[nt][0], b[nt][1]);
        }
        __syncthreads();
        if (c + 2 < NCH) load_chunk((c + 2) % NSTG, c + 2);
        cp_commit();
    }

    // ---- fused RK4 epilogue ----
    const float wgt = (stage == 1 || stage == 2) ? 2.f : 1.f;
    const float cn  = (stage == 2) ? DTC : 0.5f * DTC;
    #pragma unroll
    for (int mt = 0; mt < 2; mt++) {
        const size_t r0 = row0 + wm * 32 + mt * 16 + (lane >> 2);
        const size_t r1 = r0 + 8;
        const float u0 = u[r0], u1 = u[r1];
        #pragma unroll
        for (int nt = 0; nt < NT; nt++) {
            const int gc = wn * WN + nt * 8 + (lane & 3) * 2;
            float dz0 = acc[mt][nt][0], dz1 = acc[mt][nt][1];
            float dz2 = acc[mt][nt][2], dz3 = acc[mt][nt][3];
            if (gc >= QD) {
                float bc0 = Bc[gc - QD], bc1 = Bc[gc - QD + 1];
                dz0 = fmaf(u0, bc0, dz0); dz1 = fmaf(u0, bc1, dz1);
                dz2 = fmaf(u1, bc0, dz2); dz3 = fmaf(u1, bc1, dz3);
            }
            const size_t i0 = r0 * DIM + gc, i1 = r1 * DIM + gc;
            float2 ap0 = make_float2(0.f, 0.f), ap1 = make_float2(0.f, 0.f);
            if (stage != 0) {
                ap0 = *reinterpret_cast<float2*>(accg + i0);
                ap1 = *reinterpret_cast<float2*>(accg + i1);
            }
            float a0 = fmaf(wgt, dz0, ap0.x), a1 = fmaf(wgt, dz1, ap0.y);
            float a2 = fmaf(wgt, dz2, ap1.x), a3 = fmaf(wgt, dz3, ap1.y);
            *reinterpret_cast<float2*>(accg + i0) = make_float2(a0, a1);
            *reinterpret_cast<float2*>(accg + i1) = make_float2(a2, a3);
            float2 z0 = *reinterpret_cast<const float2*>(zg + i0);
            float2 z1 = *reinterpret_cast<const float2*>(zg + i1);
            if (stage < 3) {
                __nv_bfloat162 o0, o1;
                o0.x = __float2bfloat16(fmaf(cn, dz0, z0.x));
                o0.y = __float2bfloat16(fmaf(cn, dz1, z0.y));
                o1.x = __float2bfloat16(fmaf(cn, dz2, z1.x));
                o1.y = __float2bfloat16(fmaf(cn, dz3, z1.y));
                *reinterpret_cast<__nv_bfloat162*>(zk + i0) = o0;
                *reinterpret_cast<__nv_bfloat162*>(zk + i1) = o1;
            } else {
                *reinterpret_cast<float2*>(outg + i0) =
                    make_float2(fmaf(DTC / 6.f, a0, z0.x), fmaf(DTC / 6.f, a1, z0.y));
                *reinterpret_cast<float2*>(outg + i1) =
                    make_float2(fmaf(DTC / 6.f, a2, z1.x), fmaf(DTC / 6.f, a3, z1.y));
            }
        }
    }
}

// ===========================================================================
// Host orchestration
// ===========================================================================
extern "C" void kernel_launch(void* const* d_in, const int* in_sizes, int n_in,
                              void* d_out, int out_size) {
    const float* h    = (const float*)d_in[0];
    const float* u    = (const float*)d_in[1];
    const float* sW1  = (const float*)d_in[2];
    const float* sb1  = (const float*)d_in[3];
    const float* sW2  = (const float*)d_in[4];
    const float* sb2  = (const float*)d_in[5];
    const float* tW1  = (const float*)d_in[6];
    const float* tb1  = (const float*)d_in[7];
    const float* tW2  = (const float*)d_in[8];
    const float* tb2  = (const float*)d_in[9];
    const float* kW1  = (const float*)d_in[10];
    const float* kb1  = (const float*)d_in[11];
    const float* kW2  = (const float*)d_in[12];
    const float* kb2  = (const float*)d_in[13];
    const float* kW3  = (const float*)d_in[14];
    const float* vW1  = (const float*)d_in[16];
    const float* vb1  = (const float*)d_in[17];
    const float* vW2  = (const float*)d_in[18];
    const float* vb2  = (const float*)d_in[19];
    const float* vW3  = (const float*)d_in[20];
    const float* A    = (const float*)d_in[22];
    const float* Lp   = (const float*)d_in[23];
    const float* Bc   = (const float*)d_in[24];
    float* out = (float*)d_out;

    float *z, *acc, *Mp, *fpk;
    __nv_bfloat16 *zk, *h1T, *h1V, *g2T, *g2V, *g1T, *g1V;
    __nv_bfloat16 *Bk1, *Bv1, *Bk2, *Bv2, *Bk2t, *Bv2t, *BMcat;
    cudaGetSymbolAddress((void**)&z,     g_z);
    cudaGetSymbolAddress((void**)&acc,   g_acc);
    cudaGetSymbolAddress((void**)&zk,    g_zk);
    cudaGetSymbolAddress((void**)&h1T,   g_h1T);
    cudaGetSymbolAddress((void**)&h1V,   g_h1V);
    cudaGetSymbolAddress((void**)&g2T,   g_g2T);
    cudaGetSymbolAddress((void**)&g2V,   g_g2V);
    cudaGetSymbolAddress((void**)&g1T,   g_g1T);
    cudaGetSymbolAddress((void**)&g1V,   g_g1V);
    cudaGetSymbolAddress((void**)&Bk1,   g_Bk1);
    cudaGetSymbolAddress((void**)&Bv1,   g_Bv1);
    cudaGetSymbolAddress((void**)&Bk2,   g_Bk2);
    cudaGetSymbolAddress((void**)&Bv2,   g_Bv2);
    cudaGetSymbolAddress((void**)&Bk2t,  g_Bk2t);
    cudaGetSymbolAddress((void**)&Bv2t,  g_Bv2t);
    cudaGetSymbolAddress((void**)&BMcat, g_BMcat);
    cudaGetSymbolAddress((void**)&Mp,    g_M);
    cudaGetSymbolAddress((void**)&fpk,   g_fpk);

    const int SM1 = (128 + 128) * (64 + 8) * 2;        // 36,864
    const int SMP128 = 3 * (128 + 128) * 72 * 2;       // 110,592
    const int SMP64  = 3 * (128 + 64)  * 72 * 2;       //  82,944
    const int SMF    = F_TOT * 4;                      //  88,832 (flow_mma_k)
    cudaFuncSetAttribute(gemm_mma<64, 128, 0>,
                         cudaFuncAttributeMaxDynamicSharedMemorySize, SM1);
    cudaFuncSetAttribute(gemm_pipe<256, 128, 1>,
                         cudaFuncAttributeMaxDynamicSharedMemorySize, SMP128);
    cudaFuncSetAttribute(gemm_pipe<256, 128, 2>,
                         cudaFuncAttributeMaxDynamicSharedMemorySize, SMP128);
    cudaFuncSetAttribute(gemm_rk4,
                         cudaFuncAttributeMaxDynamicSharedMemorySize, SMP64);
    cudaFuncSetAttribute(flow_mma_k,
                         cudaFuncAttributeMaxDynamicSharedMemorySize, SMF);

    // ---- prep: 2 launches ----
    build_M_k<<<1, 256>>>(A, Lp, Mp);
    prep_pack_k<<<dim3(384, 9), 256>>>(kW1, vW1, kW2, vW2, Mp,
                                       sW1, sW2, tW1, tW2,
                                       Bk1, Bv1, Bk2, Bv2, Bk2t, Bv2t,
                                       BMcat, fpk);

    // ---- s = flow_fwd(h) ----
    cudaMemcpyAsync(z, h, (size_t)BATCH * DIM * sizeof(float),
                    cudaMemcpyDeviceToDevice, 0);
    for (int l = 0; l < NLAYERS; l++)
        flow_mma_k<<<BATCH / 64, 256, SMF>>>(z, fpk, sb1, sb2, tb1, tb2, l, 0);
    f2bf_k<<<BATCH * DIM / 1024, 256>>>(z, zk);

    // ---- RK4 stages ----
    dim3 gBig(BATCH / 128, 2, 2);
    for (int st = 0; st < 4; st++) {
        gemm_mma<64, 128, 0><<<gBig, 256, SM1>>>(
            zk, zk, Bk1, Bv1, kb1, vb1, 0, 0, 0, 0, h1T, h1V, HH);
        gemm_pipe<256, 128, 1><<<gBig, 256, SMP128>>>(
            h1T, h1V, Bk2, Bv2, kb2, vb2, kW3, vW3, 0, 0, g2T, g2V, HH);
        gemm_pipe<256, 128, 2><<<gBig, 256, SMP128>>>(
            g2T, g2V, Bk2t, Bv2t, 0, 0, 0, 0, h1T, h1V, g1T, g1V, HH);
        gemm_rk4<<<BATCH / 128, 256, SMP64>>>(
            g1T, g1V, BMcat, u, Bc, z, acc, zk, out, st);
    }

    // ---- h_next = flow_inv(z_next) in place on out ----
    for (int l = NLAYERS - 1; l >= 0; l--)
        flow_mma_k<<<BATCH / 64, 256, SMF>>>(out, fpk, sb1, sb2, tb1, tb2, l, 1);
}

// round 13
// speedup vs baseline: 3.9942x; 1.0062x over previous
#include <cuda_runtime.h>
#include <cuda_bf16.h>
#include <math.h>
#include <cstdint>

#define BATCH   131072
#define DIM     64
#define QD      32
#define NLAYERS 6
#define HF      128
#define HH      256
#define DTC     0.05f

// ===========================================================================
// Scratch (static __device__ arrays)
// ===========================================================================
__device__ __align__(16) float g_z   [BATCH * DIM];
__device__ __align__(16) float g_acc [BATCH * DIM];
__device__ __align__(16) __nv_bfloat16 g_zk [BATCH * DIM];
__device__ __align__(16) __nv_bfloat16 g_h1T[BATCH * HH];
__device__ __align__(16) __nv_bfloat16 g_h1V[BATCH * HH];
__device__ __align__(16) __nv_bfloat16 g_g2T[BATCH * HH];
__device__ __align__(16) __nv_bfloat16 g_g2V[BATCH * HH];
__device__ __align__(16) __nv_bfloat16 g_g1T[BATCH * HH];
__device__ __align__(16) __nv_bfloat16 g_g1V[BATCH * HH];
// bf16 weight images, plain row-major [N][K]
__device__ __align__(16) __nv_bfloat16 g_Bk1  [HH * 64];
__device__ __align__(16) __nv_bfloat16 g_Bv1  [HH * 64];
__device__ __align__(16) __nv_bfloat16 g_Bk2  [HH * HH];
__device__ __align__(16) __nv_bfloat16 g_Bv2  [HH * HH];
__device__ __align__(16) __nv_bfloat16 g_Bk2t [HH * HH];
__device__ __align__(16) __nv_bfloat16 g_Bv2t [HH * HH];
__device__ __align__(16) __nv_bfloat16 g_BMcat[64 * 512];   // (kW1*M^T | vW1*M^T)
__device__ float g_M[DIM * DIM];
// flow weights, tf32-rounded, per layer: [sW1 4096 | sW2 4096 | tW1 4096 | tW2 4096]
__device__ __align__(16) float g_fpk[NLAYERS * 16384];

__device__ __forceinline__ float softplusf(float x) {
    return fmaxf(x, 0.f) + log1pf(expf(-fabsf(x)));
}

__device__ __forceinline__ uint32_t smem_u32(const void* p) {
    uint32_t a;
    asm("{ .reg .u64 t; cvta.to.shared.u64 t, %1; cvt.u32.u64 %0, t; }"
        : "=r"(a) : "l"(p));
    return a;
}

// VOLATILE: shared loads must not be CSE'd/hoisted across barriers — the
// smem buffers are re-filled with different data at the same addresses.
__device__ __forceinline__ uint32_t lds32(uint32_t addr) {
    uint32_t v;
    asm volatile("ld.shared.b32 %0, [%1];" : "=r"(v) : "r"(addr));
    return v;
}

__device__ __forceinline__ float tf32r(float x) {
    uint32_t u;
    asm("cvt.rna.tf32.f32 %0, %1;" : "=r"(u) : "f"(x));
    return __uint_as_float(u);
}

__device__ __forceinline__ void cpasync16(uint32_t dst, const void* src) {
    asm volatile("cp.async.cg.shared.global [%0], [%1], 16;"
                 :: "r"(dst), "l"(src));
}

__device__ __forceinline__ void cp_commit() {
    asm volatile("cp.async.commit_group;");
}

template<int N>
__device__ __forceinline__ void cp_wait() {
    asm volatile("cp.async.wait_group %0;" :: "n"(N));
}

__device__ __forceinline__ void mma16816(float* c, uint32_t a0, uint32_t a1,
                                         uint32_t a2, uint32_t a3,
                                         uint32_t b0, uint32_t b1) {
    asm volatile(
        "mma.sync.aligned.m16n8k16.row.col.f32.bf16.bf16.f32 "
        "{%0,%1,%2,%3},{%4,%5,%6,%7},{%8,%9},{%0,%1,%2,%3};"
        : "+f"(c[0]), "+f"(c[1]), "+f"(c[2]), "+f"(c[3])
        : "r"(a0), "r"(a1), "r"(a2), "r"(a3), "r"(b0), "r"(b1));
}

__device__ __forceinline__ void mma_tf32(float* c, uint32_t a0, uint32_t a1,
                                         uint32_t a2, uint32_t a3,
                                         uint32_t b0, uint32_t b1) {
    asm volatile(
        "mma.sync.aligned.m16n8k8.row.col.f32.tf32.tf32.f32 "
        "{%0,%1,%2,%3},{%4,%5,%6,%7},{%8,%9},{%0,%1,%2,%3};"
        : "+f"(c[0]), "+f"(c[1]), "+f"(c[2]), "+f"(c[3])
        : "r"(a0), "r"(a1), "r"(a2), "r"(a3), "r"(b0), "r"(b1));
}

// ===========================================================================
// Prep kernels
// ===========================================================================
__global__ void build_M_k(const float* __restrict__ A, const float* __restrict__ Lp,
                          float* __restrict__ M) {
    __shared__ float L[DIM * DIM];
    int t = threadIdx.x;
    for (int idx = t; idx < DIM * DIM; idx += 256) {
        int i = idx >> 6, j = idx & 63;
        float v;
        if (i > j)       v = Lp[idx];
        else if (i == j) v = softplusf(Lp[idx]);
        else             v = 0.f;
        L[idx] = v;
    }
    __syncthreads();
    for (int idx = t; idx < DIM * DIM; idx += 256) {
        int i = idx >> 6, j = idx & 63;
        float s = 0.f;
        #pragma unroll 8
        for (int k = 0; k < DIM; k++) s += L[i * DIM + k] * L[j * DIM + k];
        M[idx] = A[i * DIM + j] - A[j * DIM + i] - s;
    }
}

__global__ void prep_pack_k(const float* __restrict__ kW1, const float* __restrict__ vW1,
                            const float* __restrict__ kW2, const float* __restrict__ vW2,
                            const float* __restrict__ M,
                            const float* __restrict__ sW1, const float* __restrict__ sW2,
                            const float* __restrict__ tW1, const float* __restrict__ tW2,
                            __nv_bfloat16* __restrict__ Bk1, __nv_bfloat16* __restrict__ Bv1,
                            __nv_bfloat16* __restrict__ Bk2, __nv_bfloat16* __restrict__ Bv2,
                            __nv_bfloat16* __restrict__ Bk2t, __nv_bfloat16* __restrict__ Bv2t,
                            __nv_bfloat16* __restrict__ BMcat,
                            float* __restrict__ fpk) {
    int idx = blockIdx.x * 256 + threadIdx.x;
    int task = blockIdx.y;
    if (task == 0) {
        if (idx < HH * 64) Bk1[idx] = __float2bfloat16(kW1[idx]);
    } else if (task == 1) {
        if (idx < HH * 64) {
            int r = idx >> 6, k = idx & 63;
            Bv1[idx] = __float2bfloat16(k < QD ? vW1[r * QD + k] : 0.f);
        }
    } else if (task == 2) {
        if (idx < HH * HH) Bk2[idx] = __float2bfloat16(kW2[idx]);
    } else if (task == 3) {
        if (idx < HH * HH) Bv2[idx] = __float2bfloat16(vW2[idx]);
    } else if (task == 4) {
        if (idx < HH * HH) {
            int r = idx >> 8, k = idx & 255;
            Bk2t[idx] = __float2bfloat16(kW2[k * HH + r]);
        }
    } else if (task == 5) {
        if (idx < HH * HH) {
            int r = idx >> 8, k = idx & 255;
            Bv2t[idx] = __float2bfloat16(vW2[k * HH + r]);
        }
    } else if (task == 6) {
        if (idx < 64 * HH) {
            int i = idx >> 8, k = idx & 255;
            float s = 0.f;
            for (int n = 0; n < 64; n++) s += kW1[k * 64 + n] * M[i * 64 + n];
            BMcat[i * 512 + k] = __float2bfloat16(s);
        }
    } else if (task == 7) {
        if (idx < 64 * HH) {
            int i = idx >> 8, k = idx & 255;
            float s = 0.f;
            for (int n = 0; n < QD; n++) s += vW1[k * QD + n] * M[i * 64 + n];
            BMcat[i * 512 + 256 + k] = __float2bfloat16(s);
        }
    } else {
        if (idx < NLAYERS * 16384) {
            int l = idx / 16384, r = idx % 16384;
            int sel = r / 4096, o = r % 4096;
            float v;
            if (sel == 0)      v = sW1[l * 4096 + o];
            else if (sel == 1) v = sW2[l * 4096 + o];
            else if (sel == 2) v = tW1[l * 4096 + o];
            else               v = tW2[l * 4096 + o];
            fpk[idx] = tf32r(v);
        }
    }
}

// ===========================================================================
// Fully-fused tf32 RealNVP flow: ALL 6 layers in one kernel, 64 rows/CTA,
// z slab resident in smem. cp.async W double-buffer extended cyclically
// across the 12 MLP phases. Phase loop NOT unrolled (I$ + code size).
// ===========================================================================
// smem float offsets
#define F_Z    0                 // z slab   [64][68]
#define F_CH   4352              // cond_hi  [64][36]
#define F_CL   6656              // cond_lo  [64][36]
#define F_W1O  8960              // W1       [128][36]
#define F_W2O  13568             // W2       [32][132]
#define F_HIDO 17792             // hidden   [64][132]
#define F_B1   26240             // sb1 [6][128] | tb1 [6][128]
#define F_B2   27776             // sb2 [6][32]  | tb2 [6][32]
#define F_TOT  28160             // 112,640 bytes

__device__ __forceinline__ void flow_stage_w1(uint32_t smb, const float* src, int tid) {
    #pragma unroll
    for (int c = 0; c < 4; c++) {
        int idx = c * 256 + tid;            // 1024 chunks of 16B
        int r = idx >> 3, seg = idx & 7;
        cpasync16(smb + (uint32_t)((F_W1O + r * 36 + seg * 4) << 2), src + idx * 4);
    }
}
__device__ __forceinline__ void flow_stage_w2(uint32_t smb, const float* src, int tid) {
    #pragma unroll
    for (int c = 0; c < 4; c++) {
        int idx = c * 256 + tid;
        int r = idx >> 5, seg = idx & 31;
        cpasync16(smb + (uint32_t)((F_W2O + r * 132 + seg * 4) << 2), src + idx * 4);
    }
}

// split cond half of resident z into CH/CL (hi/lo tf32)
__device__ __forceinline__ void flow_split(float* sm, int tid, int coff) {
    #pragma unroll
    for (int c = 0; c < 8; c++) {
        int idx = c * 256 + tid;
        int r = idx >> 5, cc = idx & 31;
        float y = sm[F_Z + r * 68 + coff + cc];
        float hi = tf32r(y);
        sm[F_CH + r * 36 + cc] = hi;
        sm[F_CL + r * 36 + cc] = tf32r(y - hi);
    }
}

// MMA1 (cond hi/lo @ W1^T) + bias/relu -> hidden
__device__ __forceinline__ void flow_mma1(float* sm, uint32_t smb,
                                          int wm, int wn, int g, int j, int b1off) {
    float acc1[2][4][4];
    #pragma unroll
    for (int mt = 0; mt < 2; mt++)
        #pragma unroll
        for (int nt = 0; nt < 4; nt++)
            #pragma unroll
            for (int i = 0; i < 4; i++) acc1[mt][nt][i] = 0.f;

    uint32_t aH[2], aL[2];
    #pragma unroll
    for (int mt = 0; mt < 2; mt++) {
        int r = wm * 32 + mt * 16 + g;
        aH[mt] = smb + (uint32_t)((F_CH + r * 36 + j) << 2);
        aL[mt] = smb + (uint32_t)((F_CL + r * 36 + j) << 2);
    }
    uint32_t bA[4];
    #pragma unroll
    for (int nt = 0; nt < 4; nt++)
        bA[nt] = smb + (uint32_t)((F_W1O + (wn * 32 + nt * 8 + g) * 36 + j) << 2);

    #pragma unroll
    for (int kc = 0; kc < 4; kc++) {
        const uint32_t ko = (uint32_t)(kc * 32);
        uint32_t ah[2][4], al[2][4];
        #pragma unroll
        for (int mt = 0; mt < 2; mt++) {
            ah[mt][0] = lds32(aH[mt] + ko);
            ah[mt][1] = lds32(aH[mt] + ko + 1152);
            ah[mt][2] = lds32(aH[mt] + ko + 16);
            ah[mt][3] = lds32(aH[mt] + ko + 1168);
            al[mt][0] = lds32(aL[mt] + ko);
            al[mt][1] = lds32(aL[mt] + ko + 1152);
            al[mt][2] = lds32(aL[mt] + ko + 16);
            al[mt][3] = lds32(aL[mt] + ko + 1168);
        }
        #pragma unroll
        for (int nt = 0; nt < 4; nt++) {
            uint32_t b0 = lds32(bA[nt] + ko);
            uint32_t b1 = lds32(bA[nt] + ko + 16);
            #pragma unroll
            for (int mt = 0; mt < 2; mt++) {
                mma_tf32(acc1[mt][nt], ah[mt][0], ah[mt][1], ah[mt][2], ah[mt][3], b0, b1);
                mma_tf32(acc1[mt][nt], al[mt][0], al[mt][1], al[mt][2], al[mt][3], b0, b1);
            }
        }
    }
    #pragma unroll
    for (int mt = 0; mt < 2; mt++) {
        int r0 = wm * 32 + mt * 16 + g;
        #pragma unroll
        for (int nt = 0; nt < 4; nt++) {
            int c0 = wn * 32 + nt * 8 + 2 * j;
            float b0 = sm[b1off + c0], b1f = sm[b1off + c0 + 1];
            sm[F_HIDO + r0 * 132 + c0]           = tf32r(fmaxf(acc1[mt][nt][0] + b0, 0.f));
            sm[F_HIDO + r0 * 132 + c0 + 1]       = tf32r(fmaxf(acc1[mt][nt][1] + b1f, 0.f));
            sm[F_HIDO + (r0 + 8) * 132 + c0]     = tf32r(fmaxf(acc1[mt][nt][2] + b0, 0.f));
            sm[F_HIDO + (r0 + 8) * 132 + c0 + 1] = tf32r(fmaxf(acc1[mt][nt][3] + b1f, 0.f));
        }
    }
}

// MMA2: hidden @ W2^T (each warp: 32 rows x 8 cols) -> res[2][4]
__device__ __forceinline__ void flow_mma2(uint32_t smb, int wm, int wn, int g, int j,
                                          float res[2][4]) {
    float acc2[2][4];
    #pragma unroll
    for (int mt = 0; mt < 2; mt++)
        #pragma unroll
        for (int i = 0; i < 4; i++) acc2[mt][i] = 0.f;

    uint32_t a2[2];
    #pragma unroll
    for (int mt = 0; mt < 2; mt++)
        a2[mt] = smb + (uint32_t)((F_HIDO + (wm * 32 + mt * 16 + g) * 132 + j) << 2);
    uint32_t b2a = smb + (uint32_t)((F_W2O + (wn * 8 + g) * 132 + j) << 2);

    #pragma unroll 4
    for (int kc = 0; kc < 16; kc++) {
        const uint32_t ko = (uint32_t)(kc * 32);
        uint32_t b0 = lds32(b2a + ko);
        uint32_t b1 = lds32(b2a + ko + 16);
        #pragma unroll
        for (int mt = 0; mt < 2; mt++) {
            uint32_t av0 = lds32(a2[mt] + ko);
            uint32_t av1 = lds32(a2[mt] + ko + 4224);
            uint32_t av2 = lds32(a2[mt] + ko + 16);
            uint32_t av3 = lds32(a2[mt] + ko + 4240);
            mma_tf32(acc2[mt], av0, av1, av2, av3, b0, b1);
        }
    }
    #pragma unroll
    for (int mt = 0; mt < 2; mt++)
        #pragma unroll
        for (int i = 0; i < 4; i++) res[mt][i] = acc2[mt][i];
}

__global__ __launch_bounds__(256, 2)
void flow_fused_k(const float* __restrict__ zin, float* __restrict__ zout,
                  __nv_bfloat16* __restrict__ zkout,
                  const float* __restrict__ fpk,
                  const float* __restrict__ sb1, const float* __restrict__ sb2,
                  const float* __restrict__ tb1, const float* __restrict__ tb2,
                  int inverse) {
    extern __shared__ float sm[];

    const int tid = threadIdx.x, wid = tid >> 5, lane = tid & 31;
    const int g = lane >> 2, j = lane & 3;
    const int wm = wid & 1, wn = wid >> 1;          // 2M x 4N
    const size_t row0 = (size_t)blockIdx.x * 64;
    const uint32_t smb = smem_u32(sm);

    // ---- G0: cp.async z slab + W1(ph0) + W2(ph0) ----
    #pragma unroll
    for (int c = 0; c < 4; c++) {
        int idx = c * 256 + tid;
        int r = idx >> 4, seg = idx & 15;
        cpasync16(smb + (uint32_t)((F_Z + r * 68 + seg * 4) << 2),
                  zin + (row0 + r) * DIM + seg * 4);
    }
    const int layer0 = inverse ? NLAYERS - 1 : 0;
    flow_stage_w1(smb, fpk + layer0 * 16384, tid);
    flow_stage_w2(smb, fpk + layer0 * 16384 + 4096, tid);
    cp_commit();                              // G0

    // biases: all layers, plain loads
    for (int idx = tid; idx < NLAYERS * HF; idx += 256) {
        sm[F_B1 + idx]       = sb1[idx];
        sm[F_B1 + 768 + idx] = tb1[idx];
    }
    if (tid < NLAYERS * QD) {
        sm[F_B2 + tid]       = sb2[tid];
        sm[F_B2 + 192 + tid] = tb2[tid];
    }

    cp_wait<0>();
    __syncthreads();
    flow_split(sm, tid, (layer0 & 1) ? QD : 0);
    __syncthreads();

    float res_s[2][4], res_t[2][4];

    #pragma unroll 1
    for (int p = 0; p < 2 * NLAYERS; p++) {
        const int lidx  = p >> 1, st = p & 1;
        const int layer = inverse ? NLAYERS - 1 - lidx : lidx;
        const int lnext = inverse ? NLAYERS - 1 - ((p + 1) >> 1) : ((p + 1) >> 1);
        const float* wnext = fpk + lnext * 16384 + ((p + 1) & 1) * 8192;
        const int b1off = F_B1 + st * 768 + layer * HF;

        flow_mma1(sm, smb, wm, wn, g, j, b1off);
        __syncthreads();                      // HID visible; W1 buffer free
        if (p + 1 < 2 * NLAYERS) flow_stage_w1(smb, wnext, tid);
        cp_commit();
        cp_wait<1>();                         // W2_p landed (newest = W1_{p+1})
        __syncthreads();
        float rtmp[2][4];
        flow_mma2(smb, wm, wn, g, j, rtmp);
        #pragma unroll
        for (int mt = 0; mt < 2; mt++)
            #pragma unroll
            for (int i = 0; i < 4; i++) {
                if (st == 0) res_s[mt][i] = rtmp[mt][i];
                else         res_t[mt][i] = rtmp[mt][i];
            }
        __syncthreads();                      // HID + W2 buffer free
        if (p + 1 < 2 * NLAYERS) flow_stage_w2(smb, wnext + 4096, tid);
        cp_commit();

        if (st == 1) {
            // ---- layer epilogue: update modified half of resident z ----
            const int moff = (layer & 1) ? 0 : QD;
            const int c0 = wn * 8 + 2 * j;
            float sb0 = sm[F_B2 + layer * QD + c0];
            float sb1v = sm[F_B2 + layer * QD + c0 + 1];
            float tb0 = sm[F_B2 + 192 + layer * QD + c0];
            float tb1v = sm[F_B2 + 192 + layer * QD + c0 + 1];
            #pragma unroll
            for (int mt = 0; mt < 2; mt++) {
                int r0 = wm * 32 + mt * 16 + g;
                float s0 = tanhf(res_s[mt][0] + sb0);
                float s1 = tanhf(res_s[mt][1] + sb1v);
                float s2 = tanhf(res_s[mt][2] + sb0);
                float s3 = tanhf(res_s[mt][3] + sb1v);
                float t0 = res_t[mt][0] + tb0;
                float t1 = res_t[mt][1] + tb1v;
                float t2 = res_t[mt][2] + tb0;
                float t3 = res_t[mt][3] + tb1v;
                float* z0 = &sm[F_Z + r0 * 68 + moff + c0];
                float* z1 = &sm[F_Z + (r0 + 8) * 68 + moff + c0];
                if (inverse) {
                    z0[0] = (z0[0] - t0) * expf(-s0);
                    z0[1] = (z0[1] - t1) * expf(-s1);
                    z1[0] = (z1[0] - t2) * expf(-s2);
                    z1[1] = (z1[1] - t3) * expf(-s3);
                } else {
                    z0[0] = fmaf(z0[0], expf(s0), t0);
                    z0[1] = fmaf(z0[1], expf(s1), t1);
                    z1[0] = fmaf(z1[0], expf(s2), t2);
                    z1[1] = fmaf(z1[1], expf(s3), t3);
                }
            }
        }

        if (p + 1 < 2 * NLAYERS) {
            cp_wait<1>();                     // W1_{p+1} landed (newest = W2_{p+1})
            __syncthreads();                  // also publishes epilogue z writes
            if (st == 1) {
                flow_split(sm, tid, (lnext & 1) ? QD : 0);
                __syncthreads();
            }
        }
    }

    cp_wait<0>();
    __syncthreads();                          // final epilogue z writes visible

    // ---- writeback: z (fp32) and optionally zk (bf16) ----
    #pragma unroll
    for (int c = 0; c < 4; c++) {
        int idx = c * 256 + tid;
        int r = idx >> 4, seg = idx & 15;
        const float* zp = &sm[F_Z + r * 68 + seg * 4];
        float4 v = make_float4(zp[0], zp[1], zp[2], zp[3]);
        *reinterpret_cast<float4*>(zout + (row0 + r) * DIM + seg * 4) = v;
        if (zkout) {
            __nv_bfloat162 a, b;
            a.x = __float2bfloat16(v.x); a.y = __float2bfloat16(v.y);
            b.x = __float2bfloat16(v.z); b.y = __float2bfloat16(v.w);
            *reinterpret_cast<__nv_bfloat162*>(zkout + (row0 + r) * DIM + seg * 4)     = a;
            *reinterpret_cast<__nv_bfloat162*>(zkout + (row0 + r) * DIM + seg * 4 + 2) = b;
        }
    }
}

// ===========================================================================
// Shared GEMM epilogue (bf16-activation variants)
// ===========================================================================
template<int EPI, int NT>
__device__ __forceinline__ void gemm_epilogue(
    float acc[2][NT][4], size_t row0, int col0, int wm, int wn, int WN,
    int lane, const float* bia, const float* w3, const __nv_bfloat16* aux,
    char* Cc, int Nld) {
    #pragma unroll
    for (int mt = 0; mt < 2; mt++) {
        const size_t r0 = row0 + wm * 32 + mt * 16 + (lane >> 2);
        const size_t r1 = r0 + 8;
        #pragma unroll
        for (int nt = 0; nt < NT; nt++) {
            const int gc = col0 + wn * WN + nt * 8 + (lane & 3) * 2;
            float v0 = acc[mt][nt][0], v1 = acc[mt][nt][1];
            float v2 = acc[mt][nt][2], v3 = acc[mt][nt][3];
            if (EPI == 0) {
                float b0 = bia[gc], b1 = bia[gc + 1];
                v0 = softplusf(v0 + b0); v1 = softplusf(v1 + b1);
                v2 = softplusf(v2 + b0); v3 = softplusf(v3 + b1);
            } else if (EPI == 1) {
                float b0 = bia[gc], b1 = bia[gc + 1];
                float s0 = w3[gc], s1 = w3[gc + 1];
                v0 = s0 / (1.f + expf(-(v0 + b0)));
                v1 = s1 / (1.f + expf(-(v1 + b1)));
                v2 = s0 / (1.f + expf(-(v2 + b0)));
                v3 = s1 / (1.f + expf(-(v3 + b1)));
            } else if (EPI == 2) {
                __nv_bfloat162 h0 = *reinterpret_cast<const __nv_bfloat162*>(
                    aux + r0 * HH + gc);
                __nv_bfloat162 h1 = *reinterpret_cast<const __nv_bfloat162*>(
                    aux + r1 * HH + gc);
                v0 *= (1.f - expf(-__bfloat162float(h0.x)));
                v1 *= (1.f - expf(-__bfloat162float(h0.y)));
                v2 *= (1.f - expf(-__bfloat162float(h1.x)));
                v3 *= (1.f - expf(-__bfloat162float(h1.y)));
            }
            __nv_bfloat162 o0; o0.x = __float2bfloat16(v0); o0.y = __float2bfloat16(v1);
            __nv_bfloat162 o1; o1.x = __float2bfloat16(v2); o1.y = __float2bfloat16(v3);
            *reinterpret_cast<__nv_bfloat162*>(
                (__nv_bfloat16*)Cc + r0 * Nld + gc) = o0;
            *reinterpret_cast<__nv_bfloat162*>(
                (__nv_bfloat16*)Cc + r1 * Nld + gc) = o1;
        }
    }
}

// ===========================================================================
// Single-shot warp-MMA GEMM (K=64)
// ===========================================================================
template<int K, int BN, int EPI>
__global__ __launch_bounds__(256)
void gemm_mma(const __nv_bfloat16* __restrict__ A0, const __nv_bfloat16* __restrict__ A1,
              const __nv_bfloat16* __restrict__ B0, const __nv_bfloat16* __restrict__ B1,
              const float* __restrict__ bias0, const float* __restrict__ bias1,
              const float* __restrict__ w30,  const float* __restrict__ w31,
              const __nv_bfloat16* __restrict__ aux0, const __nv_bfloat16* __restrict__ aux1,
              void* __restrict__ C0, void* __restrict__ C1, int Nld) {
    constexpr int LDE = K + 8;
    extern __shared__ __align__(16) char smraw[];
    __nv_bfloat16* smA = reinterpret_cast<__nv_bfloat16*>(smraw);
    __nv_bfloat16* smB = smA + 128 * LDE;

    const int tid = threadIdx.x, wid = tid >> 5, lane = tid & 31;
    const int zi = blockIdx.z;
    const __nv_bfloat16* A   = zi ? A1 : A0;
    const __nv_bfloat16* Bw  = zi ? B1 : B0;
    const float* bia         = zi ? bias1 : bias0;
    const float* w3          = zi ? w31 : w30;
    const __nv_bfloat16* aux = zi ? aux1 : aux0;
    char* Cc                 = (char*)(zi ? C1 : C0);

    const size_t row0 = (size_t)blockIdx.x * 128;
    const int    col0 = blockIdx.y * BN;

    constexpr int ASEG = K / 8;
    #pragma unroll 4
    for (int c = tid; c < 128 * ASEG; c += 256) {
        int r = c / ASEG, s = c % ASEG;
        *reinterpret_cast<uint4*>(smA + r * LDE + s * 8) =
            *reinterpret_cast<const uint4*>(A + (row0 + r) * K + s * 8);
    }
    #pragma unroll 4
    for (int c = tid; c < BN * ASEG; c += 256) {
        int r = c / ASEG, s = c % ASEG;
        *reinterpret_cast<uint4*>(smB + r * LDE + s * 8) =
            *reinterpret_cast<const uint4*>(Bw + (size_t)(col0 + r) * K + s * 8);
    }
    __syncthreads();

    const int wm = wid & 3;
    const int wn = wid >> 2;
    constexpr int WN = BN / 2;
    constexpr int NT = WN / 8;
    const int g = lane >> 2;
    const int j = lane & 3;

    float acc[2][NT][4];
    #pragma unroll
    for (int mt = 0; mt < 2; mt++)
        #pragma unroll
        for (int nt = 0; nt < NT; nt++)
            #pragma unroll
            for (int i = 0; i < 4; i++) acc[mt][nt][i] = 0.f;

    const uint32_t sA = smem_u32(smA), sB = smem_u32(smB);
    uint32_t aBase[2];
    #pragma unroll
    for (int mt = 0; mt < 2; mt++)
        aBase[mt] = sA + (uint32_t)(((wm * 32 + mt * 16 + g) * LDE + 2 * j) * 2);
    uint32_t bBase[NT];
    #pragma unroll
    for (int nt = 0; nt < NT; nt++)
        bBase[nt] = sB + (uint32_t)(((wn * WN + nt * 8 + g) * LDE + 2 * j) * 2);

    constexpr uint32_t ROW8 = (uint32_t)(8 * LDE * 2);

    #pragma unroll 4
    for (int kc = 0; kc < K / 16; kc++) {
        const uint32_t kb = (uint32_t)(kc * 32);
        uint32_t a[2][4];
        #pragma unroll
        for (int mt = 0; mt < 2; mt++) {
            a[mt][0] = lds32(aBase[mt] + kb);
            a[mt][1] = lds32(aBase[mt] + kb + ROW8);
            a[mt][2] = lds32(aBase[mt] + kb + 16);
            a[mt][3] = lds32(aBase[mt] + kb + ROW8 + 16);
        }
        uint32_t b[NT][2];
        #pragma unroll
        for (int nt = 0; nt < NT; nt++) {
            b[nt][0] = lds32(bBase[nt] + kb);
            b[nt][1] = lds32(bBase[nt] + kb + 16);
        }
        #pragma unroll
        for (int mt = 0; mt < 2; mt++)
            #pragma unroll
            for (int nt = 0; nt < NT; nt++)
                mma16816(acc[mt][nt], a[mt][0], a[mt][1], a[mt][2], a[mt][3],
                         b[nt][0], b[nt][1]);
    }

    gemm_epilogue<EPI, NT>(acc, row0, col0, wm, wn, WN, lane, bia, w3, aux, Cc, Nld);
}

// ===========================================================================
// cp.async 3-stage pipelined warp-MMA GEMM (K = 256, BK = 64, BN = 128)
// ===========================================================================
template<int K, int BN, int EPI>
__global__ __launch_bounds__(256, 2)
void gemm_pipe(const __nv_bfloat16* __restrict__ A0, const __nv_bfloat16* __restrict__ A1,
               const __nv_bfloat16* __restrict__ B0, const __nv_bfloat16* __restrict__ B1,
               const float* __restrict__ bias0, const float* __restrict__ bias1,
               const float* __restrict__ w30,  const float* __restrict__ w31,
               const __nv_bfloat16* __restrict__ aux0, const __nv_bfloat16* __restrict__ aux1,
               void* __restrict__ C0, void* __restrict__ C1, int Nld) {
    constexpr int BK   = 64;
    constexpr int LDE  = BK + 8;
    constexpr int NSTG = 3;
    constexpr int NCH  = K / BK;
    constexpr int STGE = (128 + BN) * LDE;
    extern __shared__ __align__(16) __nv_bfloat16 smp[];

    const int tid = threadIdx.x, wid = tid >> 5, lane = tid & 31;
    const int zi = blockIdx.z;
    const __nv_bfloat16* A   = zi ? A1 : A0;
    const __nv_bfloat16* Bw  = zi ? B1 : B0;
    const float* bia         = zi ? bias1 : bias0;
    const float* w3          = zi ? w31 : w30;
    const __nv_bfloat16* aux = zi ? aux1 : aux0;
    char* Cc                 = (char*)(zi ? C1 : C0);

    const size_t row0 = (size_t)blockIdx.x * 128;
    const int    col0 = blockIdx.y * BN;
    const uint32_t sm0 = smem_u32(smp);

    auto load_chunk = [&](int s, int c) {
        const uint32_t dstS = sm0 + (uint32_t)(s * STGE * 2);
        const int k0 = c * BK;
        #pragma unroll
        for (int t = tid; t < (128 + BN) * 8; t += 256) {
            int r = t >> 3, seg = t & 7;
            if (r < 128) {
                cpasync16(dstS + (uint32_t)((r * LDE + seg * 8) * 2),
                          A + (row0 + r) * K + k0 + seg * 8);
            } else {
                int rb = r - 128;
                cpasync16(dstS + (uint32_t)(((128 + rb) * LDE + seg * 8) * 2),
                          Bw + (size_t)(col0 + rb) * K + k0 + seg * 8);
            }
        }
    };

    const int wm = wid & 3;
    const int wn = wid >> 2;
    constexpr int WN = BN / 2;
    constexpr int NT = WN / 8;
    const int g = lane >> 2;
    const int j = lane & 3;

    float acc[2][NT][4];
    #pragma unroll
    for (int mt = 0; mt < 2; mt++)
        #pragma unroll
        for (int nt = 0; nt < NT; nt++)
            #pragma unroll
            for (int i = 0; i < 4; i++) acc[mt][nt][i] = 0.f;

    uint32_t aBase[2];
    #pragma unroll
    for (int mt = 0; mt < 2; mt++)
        aBase[mt] = sm0 + (uint32_t)(((wm * 32 + mt * 16 + g) * LDE + 2 * j) * 2);
    uint32_t bBase[NT];
    #pragma unroll
    for (int nt = 0; nt < NT; nt++)
        bBase[nt] = sm0 + (uint32_t)(((128 + wn * WN + nt * 8 + g) * LDE + 2 * j) * 2);
    constexpr uint32_t ROW8 = (uint32_t)(8 * LDE * 2);

    load_chunk(0, 0); cp_commit();
    load_chunk(1, 1); cp_commit();

    for (int c = 0; c < NCH; c++) {
        cp_wait<1>();
        __syncthreads();
        const uint32_t soff = (uint32_t)((c % NSTG) * STGE * 2);
        #pragma unroll
        for (int kc = 0; kc < BK / 16; kc++) {
            const uint32_t kb = soff + (uint32_t)(kc * 32);
            uint32_t a[2][4];
            #pragma unroll
            for (int mt = 0; mt < 2; mt++) {
                a[mt][0] = lds32(aBase[mt] + kb);
                a[mt][1] = lds32(aBase[mt] + kb + ROW8);
                a[mt][2] = lds32(aBase[mt] + kb + 16);
                a[mt][3] = lds32(aBase[mt] + kb + ROW8 + 16);
            }
            uint32_t b[NT][2];
            #pragma unroll
            for (int nt = 0; nt < NT; nt++) {
                b[nt][0] = lds32(bBase[nt] + kb);
                b[nt][1] = lds32(bBase[nt] + kb + 16);
            }
            #pragma unroll
            for (int mt = 0; mt < 2; mt++)
                #pragma unroll
                for (int nt = 0; nt < NT; nt++)
                    mma16816(acc[mt][nt], a[mt][0], a[mt][1], a[mt][2], a[mt][3],
                             b[nt][0], b[nt][1]);
        }
        __syncthreads();
        if (c + 2 < NCH) load_chunk((c + 2) % NSTG, c + 2);
        cp_commit();
    }

    gemm_epilogue<EPI, NT>(acc, row0, col0, wm, wn, WN, lane, bia, w3, aux, Cc, Nld);
}

// ===========================================================================
// Fused final GEMM (K=512: [g1T | g1V] @ BMcat^T) + RK4 epilogue.
// ===========================================================================
__global__ __launch_bounds__(256, 2)
void gemm_rk4(const __nv_bfloat16* __restrict__ g1T, const __nv_bfloat16* __restrict__ g1V,
              const __nv_bfloat16* __restrict__ Bw,
              const float* __restrict__ u, const float* __restrict__ Bc,
              const float* __restrict__ zg, float* __restrict__ accg,
              __nv_bfloat16* __restrict__ zk, float* __restrict__ outg, int stage) {
    constexpr int BK   = 64;
    constexpr int LDE  = BK + 8;
    constexpr int NSTG = 3;
    constexpr int NCH  = 8;
    constexpr int BN   = 64;
    constexpr int STGE = (128 + BN) * LDE;
    extern __shared__ __align__(16) __nv_bfloat16 smp[];

    const int tid = threadIdx.x, wid = tid >> 5, lane = tid & 31;
    const size_t row0 = (size_t)blockIdx.x * 128;
    const uint32_t sm0 = smem_u32(smp);

    auto load_chunk = [&](int s, int c) {
        const uint32_t dstS = sm0 + (uint32_t)(s * STGE * 2);
        const __nv_bfloat16* A = (c < 4) ? g1T : g1V;
        const int k0 = (c & 3) * BK;
        #pragma unroll
        for (int t = tid; t < (128 + BN) * 8; t += 256) {
            int r = t >> 3, seg = t & 7;
            if (r < 128) {
                cpasync16(dstS + (uint32_t)((r * LDE + seg * 8) * 2),
                          A + (row0 + r) * HH + k0 + seg * 8);
            } else {
                int rb = r - 128;
                cpasync16(dstS + (uint32_t)(((128 + rb) * LDE + seg * 8) * 2),
                          Bw + (size_t)rb * 512 + c * BK + seg * 8);
            }
        }
    };

    const int wm = wid & 3;
    const int wn = wid >> 2;
    constexpr int WN = BN / 2;
    constexpr int NT = WN / 8;
    const int g = lane >> 2;
    const int j = lane & 3;

    float acc[2][NT][4];
    #pragma unroll
    for (int mt = 0; mt < 2; mt++)
        #pragma unroll
        for (int nt = 0; nt < NT; nt++)
            #pragma unroll
            for (int i = 0; i < 4; i++) acc[mt][nt][i] = 0.f;

    uint32_t aBase[2];
    #pragma unroll
    for (int mt = 0; mt < 2; mt++)
        aBase[mt] = sm0 + (uint32_t)(((wm * 32 + mt * 16 + g) * LDE + 2 * j) * 2);
    uint32_t bBase[NT];
    #pragma unroll
    for (int nt = 0; nt < NT; nt++)
        bBase[nt] = sm0 + (uint32_t)(((128 + wn * WN + nt * 8 + g) * LDE + 2 * j) * 2);
    constexpr uint32_t ROW8 = (uint32_t)(8 * LDE * 2);

    load_chunk(0, 0); cp_commit();
    load_chunk(1, 1); cp_commit();

    for (int c = 0; c < NCH; c++) {
        cp_wait<1>();
        __syncthreads();
        const uint32_t soff = (uint32_t)((c % NSTG) * STGE * 2);
        #pragma unroll
        for (int kc = 0; kc < BK / 16; kc++) {
            const uint32_t kb = soff + (uint32_t)(kc * 32);
            uint32_t a[2][4];
            #pragma unroll
            for (int mt = 0; mt < 2; mt++) {
                a[mt][0] = lds32(aBase[mt] + kb);
                a[mt][1] = lds32(aBase[mt] + kb + ROW8);
                a[mt][2] = lds32(aBase[mt] + kb + 16);
                a[mt][3] = lds32(aBase[mt] + kb + ROW8 + 16);
            }
            uint32_t b[NT][2];
            #pragma unroll
            for (int nt = 0; nt < NT; nt++) {
                b[nt][0] = lds32(bBase[nt] + kb);
                b[nt][1] = lds32(bBase[nt] + kb + 16);
            }
            #pragma unroll
            for (int mt = 0; mt < 2; mt++)
                #pragma unroll
                for (int nt = 0; nt < NT; nt++)
                    mma16816(acc[mt][nt], a[mt][0], a[mt][1], a[mt][2], a[mt][3],
                             b[nt][0], b[nt][1]);
        }
        __syncthreads();
        if (c + 2 < NCH) load_chunk((c + 2) % NSTG, c + 2);
        cp_commit();
    }

    // ---- fused RK4 epilogue ----
    const float wgt = (stage == 1 || stage == 2) ? 2.f : 1.f;
    const float cn  = (stage == 2) ? DTC : 0.5f * DTC;
    #pragma unroll
    for (int mt = 0; mt < 2; mt++) {
        const size_t r0 = row0 + wm * 32 + mt * 16 + (lane >> 2);
        const size_t r1 = r0 + 8;
        const float u0 = u[r0], u1 = u[r1];
        #pragma unroll
        for (int nt = 0; nt < NT; nt++) {
            const int gc = wn * WN + nt * 8 + (lane & 3) * 2;
            float dz0 = acc[mt][nt][0], dz1 = acc[mt][nt][1];
            float dz2 = acc[mt][nt][2], dz3 = acc[mt][nt][3];
            if (gc >= QD) {
                float bc0 = Bc[gc - QD], bc1 = Bc[gc - QD + 1];
                dz0 = fmaf(u0, bc0, dz0); dz1 = fmaf(u0, bc1, dz1);
                dz2 = fmaf(u1, bc0, dz2); dz3 = fmaf(u1, bc1, dz3);
            }
            const size_t i0 = r0 * DIM + gc, i1 = r1 * DIM + gc;
            float2 ap0 = make_float2(0.f, 0.f), ap1 = make_float2(0.f, 0.f);
            if (stage != 0) {
                ap0 = *reinterpret_cast<float2*>(accg + i0);
                ap1 = *reinterpret_cast<float2*>(accg + i1);
            }
            float a0 = fmaf(wgt, dz0, ap0.x), a1 = fmaf(wgt, dz1, ap0.y);
            float a2 = fmaf(wgt, dz2, ap1.x), a3 = fmaf(wgt, dz3, ap1.y);
            *reinterpret_cast<float2*>(accg + i0) = make_float2(a0, a1);
            *reinterpret_cast<float2*>(accg + i1) = make_float2(a2, a3);
            float2 z0 = *reinterpret_cast<const float2*>(zg + i0);
            float2 z1 = *reinterpret_cast<const float2*>(zg + i1);
            if (stage < 3) {
                __nv_bfloat162 o0, o1;
                o0.x = __float2bfloat16(fmaf(cn, dz0, z0.x));
                o0.y = __float2bfloat16(fmaf(cn, dz1, z0.y));
                o1.x = __float2bfloat16(fmaf(cn, dz2, z1.x));
                o1.y = __float2bfloat16(fmaf(cn, dz3, z1.y));
                *reinterpret_cast<__nv_bfloat162*>(zk + i0) = o0;
                *reinterpret_cast<__nv_bfloat162*>(zk + i1) = o1;
            } else {
                *reinterpret_cast<float2*>(outg + i0) =
                    make_float2(fmaf(DTC / 6.f, a0, z0.x), fmaf(DTC / 6.f, a1, z0.y));
                *reinterpret_cast<float2*>(outg + i1) =
                    make_float2(fmaf(DTC / 6.f, a2, z1.x), fmaf(DTC / 6.f, a3, z1.y));
            }
        }
    }
}

// ===========================================================================
// Host orchestration
// ===========================================================================
extern "C" void kernel_launch(void* const* d_in, const int* in_sizes, int n_in,
                              void* d_out, int out_size) {
    const float* h    = (const float*)d_in[0];
    const float* u    = (const float*)d_in[1];
    const float* sW1  = (const float*)d_in[2];
    const float* sb1  = (const float*)d_in[3];
    const float* sW2  = (const float*)d_in[4];
    const float* sb2  = (const float*)d_in[5];
    const float* tW1  = (const float*)d_in[6];
    const float* tb1  = (const float*)d_in[7];
    const float* tW2  = (const float*)d_in[8];
    const float* tb2  = (const float*)d_in[9];
    const float* kW1  = (const float*)d_in[10];
    const float* kb1  = (const float*)d_in[11];
    const float* kW2  = (const float*)d_in[12];
    const float* kb2  = (const float*)d_in[13];
    const float* kW3  = (const float*)d_in[14];
    const float* vW1  = (const float*)d_in[16];
    const float* vb1  = (const float*)d_in[17];
    const float* vW2  = (const float*)d_in[18];
    const float* vb2  = (const float*)d_in[19];
    const float* vW3  = (const float*)d_in[20];
    const float* A    = (const float*)d_in[22];
    const float* Lp   = (const float*)d_in[23];
    const float* Bc   = (const float*)d_in[24];
    float* out = (float*)d_out;

    float *z, *acc, *Mp, *fpk;
    __nv_bfloat16 *zk, *h1T, *h1V, *g2T, *g2V, *g1T, *g1V;
    __nv_bfloat16 *Bk1, *Bv1, *Bk2, *Bv2, *Bk2t, *Bv2t, *BMcat;
    cudaGetSymbolAddress((void**)&z,     g_z);
    cudaGetSymbolAddress((void**)&acc,   g_acc);
    cudaGetSymbolAddress((void**)&zk,    g_zk);
    cudaGetSymbolAddress((void**)&h1T,   g_h1T);
    cudaGetSymbolAddress((void**)&h1V,   g_h1V);
    cudaGetSymbolAddress((void**)&g2T,   g_g2T);
    cudaGetSymbolAddress((void**)&g2V,   g_g2V);
    cudaGetSymbolAddress((void**)&g1T,   g_g1T);
    cudaGetSymbolAddress((void**)&g1V,   g_g1V);
    cudaGetSymbolAddress((void**)&Bk1,   g_Bk1);
    cudaGetSymbolAddress((void**)&Bv1,   g_Bv1);
    cudaGetSymbolAddress((void**)&Bk2,   g_Bk2);
    cudaGetSymbolAddress((void**)&Bv2,   g_Bv2);
    cudaGetSymbolAddress((void**)&Bk2t,  g_Bk2t);
    cudaGetSymbolAddress((void**)&Bv2t,  g_Bv2t);
    cudaGetSymbolAddress((void**)&BMcat, g_BMcat);
    cudaGetSymbolAddress((void**)&Mp,    g_M);
    cudaGetSymbolAddress((void**)&fpk,   g_fpk);

    const int SM1 = (128 + 128) * (64 + 8) * 2;        // 36,864
    const int SMP128 = 3 * (128 + 128) * 72 * 2;       // 110,592
    const int SMP64  = 3 * (128 + 64)  * 72 * 2;       //  82,944
    const int SMF    = F_TOT * 4;                      // 112,640 (flow_fused_k)
    cudaFuncSetAttribute(gemm_mma<64, 128, 0>,
                         cudaFuncAttributeMaxDynamicSharedMemorySize, SM1);
    cudaFuncSetAttribute(gemm_pipe<256, 128, 1>,
                         cudaFuncAttributeMaxDynamicSharedMemorySize, SMP128);
    cudaFuncSetAttribute(gemm_pipe<256, 128, 2>,
                         cudaFuncAttributeMaxDynamicSharedMemorySize, SMP128);
    cudaFuncSetAttribute(gemm_rk4,
                         cudaFuncAttributeMaxDynamicSharedMemorySize, SMP64);
    cudaFuncSetAttribute(flow_fused_k,
                         cudaFuncAttributeMaxDynamicSharedMemorySize, SMF);

    // ---- prep: 2 launches ----
    build_M_k<<<1, 256>>>(A, Lp, Mp);
    prep_pack_k<<<dim3(384, 9), 256>>>(kW1, vW1, kW2, vW2, Mp,
                                       sW1, sW2, tW1, tW2,
                                       Bk1, Bv1, Bk2, Bv2, Bk2t, Bv2t,
                                       BMcat, fpk);

    // ---- s = flow_fwd(h): one fused launch (reads h, writes z + zk) ----
    flow_fused_k<<<BATCH / 64, 256, SMF>>>(h, z, zk, fpk, sb1, sb2, tb1, tb2, 0);

    // ---- RK4 stages ----
    dim3 gBig(BATCH / 128, 2, 2);
    for (int st = 0; st < 4; st++) {
        gemm_mma<64, 128, 0><<<gBig, 256, SM1>>>(
            zk, zk, Bk1, Bv1, kb1, vb1, 0, 0, 0, 0, h1T, h1V, HH);
        gemm_pipe<256, 128, 1><<<gBig, 256, SMP128>>>(
            h1T, h1V, Bk2, Bv2, kb2, vb2, kW3, vW3, 0, 0, g2T, g2V, HH);
        gemm_pipe<256, 128, 2><<<gBig, 256, SMP128>>>(
            g2T, g2V, Bk2t, Bv2t, 0, 0, 0, 0, h1T, h1V, g1T, g1V, HH);
        gemm_rk4<<<BATCH / 128, 256, SMP64>>>(
            g1T, g1V, BMcat, u, Bc, z, acc, zk, out, st);
    }

    // ---- h_next = flow_inv(z_next): one fused launch in place on out ----
    flow_fused_k<<<BATCH / 64, 256, SMF>>>(out, out, (__nv_bfloat16*)0,
                                           fpk, sb1, sb2, tb1, tb2, 1);
}

// round 14
// speedup vs baseline: 4.3039x; 1.0776x over previous
#include <cuda_runtime.h>
#include <cuda_bf16.h>
#include <math.h>
#include <cstdint>

#define BATCH   131072
#define DIM     64
#define QD      32
#define NLAYERS 6
#define HF      128
#define HH      256
#define DTC     0.05f

// ===========================================================================
// Scratch (static __device__ arrays)
// ===========================================================================
__device__ __align__(16) float g_z   [BATCH * DIM];
__device__ __align__(16) float g_acc [BATCH * DIM];
__device__ __align__(16) __nv_bfloat16 g_zk [BATCH * DIM];
__device__ __align__(16) __nv_bfloat16 g_h1T[BATCH * HH];
__device__ __align__(16) __nv_bfloat16 g_h1V[BATCH * HH];
__device__ __align__(16) __nv_bfloat16 g_g2T[BATCH * HH];
__device__ __align__(16) __nv_bfloat16 g_g2V[BATCH * HH];
__device__ __align__(16) __nv_bfloat16 g_g1T[BATCH * HH];
__device__ __align__(16) __nv_bfloat16 g_g1V[BATCH * HH];
// bf16 weight images, plain row-major [N][K]
__device__ __align__(16) __nv_bfloat16 g_Bk1  [HH * 64];
__device__ __align__(16) __nv_bfloat16 g_Bv1  [HH * 64];
__device__ __align__(16) __nv_bfloat16 g_Bk2  [HH * HH];
__device__ __align__(16) __nv_bfloat16 g_Bv2  [HH * HH];
__device__ __align__(16) __nv_bfloat16 g_Bk2t [HH * HH];
__device__ __align__(16) __nv_bfloat16 g_Bv2t [HH * HH];
__device__ __align__(16) __nv_bfloat16 g_BMcat[64 * 512];   // (kW1*M^T | vW1*M^T)
__device__ float g_M[DIM * DIM];
// flow weights, tf32-rounded, per layer: [sW1 4096 | sW2 4096 | tW1 4096 | tW2 4096]
__device__ __align__(16) float g_fpk[NLAYERS * 16384];

// exact softplus (prep only -- fp32-sensitive path)
__device__ __forceinline__ float softplusf(float x) {
    return fmaxf(x, 0.f) + log1pf(expf(-fabsf(x)));
}
// fast softplus (GEMM epilogues -- results stored as bf16, MUFU error << 2^-8)
__device__ __forceinline__ float softplus_fast(float x) {
    return fmaxf(x, 0.f) + __logf(1.f + __expf(-fabsf(x)));
}

__device__ __forceinline__ uint32_t smem_u32(const void* p) {
    uint32_t a;
    asm("{ .reg .u64 t; cvta.to.shared.u64 t, %1; cvt.u32.u64 %0, t; }"
        : "=r"(a) : "l"(p));
    return a;
}

// VOLATILE: shared loads must not be CSE'd/hoisted across barriers — the
// smem buffers are re-filled with different data at the same addresses.
__device__ __forceinline__ uint32_t lds32(uint32_t addr) {
    uint32_t v;
    asm volatile("ld.shared.b32 %0, [%1];" : "=r"(v) : "r"(addr));
    return v;
}

__device__ __forceinline__ float tf32r(float x) {
    uint32_t u;
    asm("cvt.rna.tf32.f32 %0, %1;" : "=r"(u) : "f"(x));
    return __uint_as_float(u);
}

__device__ __forceinline__ void cpasync16(uint32_t dst, const void* src) {
    asm volatile("cp.async.cg.shared.global [%0], [%1], 16;"
                 :: "r"(dst), "l"(src));
}

__device__ __forceinline__ void cp_commit() {
    asm volatile("cp.async.commit_group;");
}

template<int N>
__device__ __forceinline__ void cp_wait() {
    asm volatile("cp.async.wait_group %0;" :: "n"(N));
}

__device__ __forceinline__ void mma16816(float* c, uint32_t a0, uint32_t a1,
                                         uint32_t a2, uint32_t a3,
                                         uint32_t b0, uint32_t b1) {
    asm volatile(
        "mma.sync.aligned.m16n8k16.row.col.f32.bf16.bf16.f32 "
        "{%0,%1,%2,%3},{%4,%5,%6,%7},{%8,%9},{%0,%1,%2,%3};"
        : "+f"(c[0]), "+f"(c[1]), "+f"(c[2]), "+f"(c[3])
        : "r"(a0), "r"(a1), "r"(a2), "r"(a3), "r"(b0), "r"(b1));
}

__device__ __forceinline__ void mma_tf32(float* c, uint32_t a0, uint32_t a1,
                                         uint32_t a2, uint32_t a3,
                                         uint32_t b0, uint32_t b1) {
    asm volatile(
        "mma.sync.aligned.m16n8k8.row.col.f32.tf32.tf32.f32 "
        "{%0,%1,%2,%3},{%4,%5,%6,%7},{%8,%9},{%0,%1,%2,%3};"
        : "+f"(c[0]), "+f"(c[1]), "+f"(c[2]), "+f"(c[3])
        : "r"(a0), "r"(a1), "r"(a2), "r"(a3), "r"(b0), "r"(b1));
}

// ===========================================================================
// Prep kernels
// ===========================================================================
__global__ void build_M_k(const float* __restrict__ A, const float* __restrict__ Lp,
                          float* __restrict__ M) {
    __shared__ float L[DIM * DIM];
    int t = threadIdx.x;
    for (int idx = t; idx < DIM * DIM; idx += 256) {
        int i = idx >> 6, j = idx & 63;
        float v;
        if (i > j)       v = Lp[idx];
        else if (i == j) v = softplusf(Lp[idx]);
        else             v = 0.f;
        L[idx] = v;
    }
    __syncthreads();
    for (int idx = t; idx < DIM * DIM; idx += 256) {
        int i = idx >> 6, j = idx & 63;
        float s = 0.f;
        #pragma unroll 8
        for (int k = 0; k < DIM; k++) s += L[i * DIM + k] * L[j * DIM + k];
        M[idx] = A[i * DIM + j] - A[j * DIM + i] - s;
    }
}

__global__ void prep_pack_k(const float* __restrict__ kW1, const float* __restrict__ vW1,
                            const float* __restrict__ kW2, const float* __restrict__ vW2,
                            const float* __restrict__ M,
                            const float* __restrict__ sW1, const float* __restrict__ sW2,
                            const float* __restrict__ tW1, const float* __restrict__ tW2,
                            __nv_bfloat16* __restrict__ Bk1, __nv_bfloat16* __restrict__ Bv1,
                            __nv_bfloat16* __restrict__ Bk2, __nv_bfloat16* __restrict__ Bv2,
                            __nv_bfloat16* __restrict__ Bk2t, __nv_bfloat16* __restrict__ Bv2t,
                            __nv_bfloat16* __restrict__ BMcat,
                            float* __restrict__ fpk) {
    int idx = blockIdx.x * 256 + threadIdx.x;
    int task = blockIdx.y;
    if (task == 0) {
        if (idx < HH * 64) Bk1[idx] = __float2bfloat16(kW1[idx]);
    } else if (task == 1) {
        if (idx < HH * 64) {
            int r = idx >> 6, k = idx & 63;
            Bv1[idx] = __float2bfloat16(k < QD ? vW1[r * QD + k] : 0.f);
        }
    } else if (task == 2) {
        if (idx < HH * HH) Bk2[idx] = __float2bfloat16(kW2[idx]);
    } else if (task == 3) {
        if (idx < HH * HH) Bv2[idx] = __float2bfloat16(vW2[idx]);
    } else if (task == 4) {
        if (idx < HH * HH) {
            int r = idx >> 8, k = idx & 255;
            Bk2t[idx] = __float2bfloat16(kW2[k * HH + r]);
        }
    } else if (task == 5) {
        if (idx < HH * HH) {
            int r = idx >> 8, k = idx & 255;
            Bv2t[idx] = __float2bfloat16(vW2[k * HH + r]);
        }
    } else if (task == 6) {
        if (idx < 64 * HH) {
            int i = idx >> 8, k = idx & 255;
            float s = 0.f;
            for (int n = 0; n < 64; n++) s += kW1[k * 64 + n] * M[i * 64 + n];
            BMcat[i * 512 + k] = __float2bfloat16(s);
        }
    } else if (task == 7) {
        if (idx < 64 * HH) {
            int i = idx >> 8, k = idx & 255;
            float s = 0.f;
            for (int n = 0; n < QD; n++) s += vW1[k * QD + n] * M[i * 64 + n];
            BMcat[i * 512 + 256 + k] = __float2bfloat16(s);
        }
    } else {
        if (idx < NLAYERS * 16384) {
            int l = idx / 16384, r = idx % 16384;
            int sel = r / 4096, o = r % 4096;
            float v;
            if (sel == 0)      v = sW1[l * 4096 + o];
            else if (sel == 1) v = sW2[l * 4096 + o];
            else if (sel == 2) v = tW1[l * 4096 + o];
            else               v = tW2[l * 4096 + o];
            fpk[idx] = tf32r(v);
        }
    }
}

// ===========================================================================
// Fully-fused tf32 RealNVP flow: ALL 6 layers in one kernel, 64 rows/CTA,
// z slab resident in smem. cp.async W double-buffer extended cyclically
// across the 12 MLP phases. Phase loop NOT unrolled (I$ + code size).
// ===========================================================================
// smem float offsets
#define F_Z    0                 // z slab   [64][68]
#define F_CH   4352              // cond_hi  [64][36]
#define F_CL   6656              // cond_lo  [64][36]
#define F_W1O  8960              // W1       [128][36]
#define F_W2O  13568             // W2       [32][132]
#define F_HIDO 17792             // hidden   [64][132]
#define F_B1   26240             // sb1 [6][128] | tb1 [6][128]
#define F_B2   27776             // sb2 [6][32]  | tb2 [6][32]
#define F_TOT  28160             // 112,640 bytes

__device__ __forceinline__ void flow_stage_w1(uint32_t smb, const float* src, int tid) {
    #pragma unroll
    for (int c = 0; c < 4; c++) {
        int idx = c * 256 + tid;            // 1024 chunks of 16B
        int r = idx >> 3, seg = idx & 7;
        cpasync16(smb + (uint32_t)((F_W1O + r * 36 + seg * 4) << 2), src + idx * 4);
    }
}
__device__ __forceinline__ void flow_stage_w2(uint32_t smb, const float* src, int tid) {
    #pragma unroll
    for (int c = 0; c < 4; c++) {
        int idx = c * 256 + tid;
        int r = idx >> 5, seg = idx & 31;
        cpasync16(smb + (uint32_t)((F_W2O + r * 132 + seg * 4) << 2), src + idx * 4);
    }
}

// split cond half of resident z into CH/CL (hi/lo tf32)
__device__ __forceinline__ void flow_split(float* sm, int tid, int coff) {
    #pragma unroll
    for (int c = 0; c < 8; c++) {
        int idx = c * 256 + tid;
        int r = idx >> 5, cc = idx & 31;
        float y = sm[F_Z + r * 68 + coff + cc];
        float hi = tf32r(y);
        sm[F_CH + r * 36 + cc] = hi;
        sm[F_CL + r * 36 + cc] = tf32r(y - hi);
    }
}

// MMA1 (cond hi/lo @ W1^T) + bias/relu -> hidden
__device__ __forceinline__ void flow_mma1(float* sm, uint32_t smb,
                                          int wm, int wn, int g, int j, int b1off) {
    float acc1[2][4][4];
    #pragma unroll
    for (int mt = 0; mt < 2; mt++)
        #pragma unroll
        for (int nt = 0; nt < 4; nt++)
            #pragma unroll
            for (int i = 0; i < 4; i++) acc1[mt][nt][i] = 0.f;

    uint32_t aH[2], aL[2];
    #pragma unroll
    for (int mt = 0; mt < 2; mt++) {
        int r = wm * 32 + mt * 16 + g;
        aH[mt] = smb + (uint32_t)((F_CH + r * 36 + j) << 2);
        aL[mt] = smb + (uint32_t)((F_CL + r * 36 + j) << 2);
    }
    uint32_t bA[4];
    #pragma unroll
    for (int nt = 0; nt < 4; nt++)
        bA[nt] = smb + (uint32_t)((F_W1O + (wn * 32 + nt * 8 + g) * 36 + j) << 2);

    #pragma unroll
    for (int kc = 0; kc < 4; kc++) {
        const uint32_t ko = (uint32_t)(kc * 32);
        uint32_t ah[2][4], al[2][4];
        #pragma unroll
        for (int mt = 0; mt < 2; mt++) {
            ah[mt][0] = lds32(aH[mt] + ko);
            ah[mt][1] = lds32(aH[mt] + ko + 1152);
            ah[mt][2] = lds32(aH[mt] + ko + 16);
            ah[mt][3] = lds32(aH[mt] + ko + 1168);
            al[mt][0] = lds32(aL[mt] + ko);
            al[mt][1] = lds32(aL[mt] + ko + 1152);
            al[mt][2] = lds32(aL[mt] + ko + 16);
            al[mt][3] = lds32(aL[mt] + ko + 1168);
        }
        #pragma unroll
        for (int nt = 0; nt < 4; nt++) {
            uint32_t b0 = lds32(bA[nt] + ko);
            uint32_t b1 = lds32(bA[nt] + ko + 16);
            #pragma unroll
            for (int mt = 0; mt < 2; mt++) {
                mma_tf32(acc1[mt][nt], ah[mt][0], ah[mt][1], ah[mt][2], ah[mt][3], b0, b1);
                mma_tf32(acc1[mt][nt], al[mt][0], al[mt][1], al[mt][2], al[mt][3], b0, b1);
            }
        }
    }
    #pragma unroll
    for (int mt = 0; mt < 2; mt++) {
        int r0 = wm * 32 + mt * 16 + g;
        #pragma unroll
        for (int nt = 0; nt < 4; nt++) {
            int c0 = wn * 32 + nt * 8 + 2 * j;
            float b0 = sm[b1off + c0], b1f = sm[b1off + c0 + 1];
            sm[F_HIDO + r0 * 132 + c0]           = tf32r(fmaxf(acc1[mt][nt][0] + b0, 0.f));
            sm[F_HIDO + r0 * 132 + c0 + 1]       = tf32r(fmaxf(acc1[mt][nt][1] + b1f, 0.f));
            sm[F_HIDO + (r0 + 8) * 132 + c0]     = tf32r(fmaxf(acc1[mt][nt][2] + b0, 0.f));
            sm[F_HIDO + (r0 + 8) * 132 + c0 + 1] = tf32r(fmaxf(acc1[mt][nt][3] + b1f, 0.f));
        }
    }
}

// MMA2: hidden @ W2^T (each warp: 32 rows x 8 cols) -> res[2][4]
__device__ __forceinline__ void flow_mma2(uint32_t smb, int wm, int wn, int g, int j,
                                          float res[2][4]) {
    float acc2[2][4];
    #pragma unroll
    for (int mt = 0; mt < 2; mt++)
        #pragma unroll
        for (int i = 0; i < 4; i++) acc2[mt][i] = 0.f;

    uint32_t a2[2];
    #pragma unroll
    for (int mt = 0; mt < 2; mt++)
        a2[mt] = smb + (uint32_t)((F_HIDO + (wm * 32 + mt * 16 + g) * 132 + j) << 2);
    uint32_t b2a = smb + (uint32_t)((F_W2O + (wn * 8 + g) * 132 + j) << 2);

    #pragma unroll 4
    for (int kc = 0; kc < 16; kc++) {
        const uint32_t ko = (uint32_t)(kc * 32);
        uint32_t b0 = lds32(b2a + ko);
        uint32_t b1 = lds32(b2a + ko + 16);
        #pragma unroll
        for (int mt = 0; mt < 2; mt++) {
            uint32_t av0 = lds32(a2[mt] + ko);
            uint32_t av1 = lds32(a2[mt] + ko + 4224);
            uint32_t av2 = lds32(a2[mt] + ko + 16);
            uint32_t av3 = lds32(a2[mt] + ko + 4240);
            mma_tf32(acc2[mt], av0, av1, av2, av3, b0, b1);
        }
    }
    #pragma unroll
    for (int mt = 0; mt < 2; mt++)
        #pragma unroll
        for (int i = 0; i < 4; i++) res[mt][i] = acc2[mt][i];
}

__global__ __launch_bounds__(256, 2)
void flow_fused_k(const float* __restrict__ zin, float* __restrict__ zout,
                  __nv_bfloat16* __restrict__ zkout,
                  const float* __restrict__ fpk,
                  const float* __restrict__ sb1, const float* __restrict__ sb2,
                  const float* __restrict__ tb1, const float* __restrict__ tb2,
                  int inverse) {
    extern __shared__ float sm[];

    const int tid = threadIdx.x, wid = tid >> 5, lane = tid & 31;
    const int g = lane >> 2, j = lane & 3;
    const int wm = wid & 1, wn = wid >> 1;          // 2M x 4N
    const size_t row0 = (size_t)blockIdx.x * 64;
    const uint32_t smb = smem_u32(sm);

    // ---- G0: cp.async z slab + W1(ph0) + W2(ph0) ----
    #pragma unroll
    for (int c = 0; c < 4; c++) {
        int idx = c * 256 + tid;
        int r = idx >> 4, seg = idx & 15;
        cpasync16(smb + (uint32_t)((F_Z + r * 68 + seg * 4) << 2),
                  zin + (row0 + r) * DIM + seg * 4);
    }
    const int layer0 = inverse ? NLAYERS - 1 : 0;
    flow_stage_w1(smb, fpk + layer0 * 16384, tid);
    flow_stage_w2(smb, fpk + layer0 * 16384 + 4096, tid);
    cp_commit();                              // G0

    // biases: all layers, plain loads
    for (int idx = tid; idx < NLAYERS * HF; idx += 256) {
        sm[F_B1 + idx]       = sb1[idx];
        sm[F_B1 + 768 + idx] = tb1[idx];
    }
    if (tid < NLAYERS * QD) {
        sm[F_B2 + tid]       = sb2[tid];
        sm[F_B2 + 192 + tid] = tb2[tid];
    }

    cp_wait<0>();
    __syncthreads();
    flow_split(sm, tid, (layer0 & 1) ? QD : 0);
    __syncthreads();

    float res_s[2][4], res_t[2][4];

    #pragma unroll 1
    for (int p = 0; p < 2 * NLAYERS; p++) {
        const int lidx  = p >> 1, st = p & 1;
        const int layer = inverse ? NLAYERS - 1 - lidx : lidx;
        const int lnext = inverse ? NLAYERS - 1 - ((p + 1) >> 1) : ((p + 1) >> 1);
        const float* wnext = fpk + lnext * 16384 + ((p + 1) & 1) * 8192;
        const int b1off = F_B1 + st * 768 + layer * HF;

        flow_mma1(sm, smb, wm, wn, g, j, b1off);
        __syncthreads();                      // HID visible; W1 buffer free
        if (p + 1 < 2 * NLAYERS) flow_stage_w1(smb, wnext, tid);
        cp_commit();
        cp_wait<1>();                         // W2_p landed (newest = W1_{p+1})
        __syncthreads();
        float rtmp[2][4];
        flow_mma2(smb, wm, wn, g, j, rtmp);
        #pragma unroll
        for (int mt = 0; mt < 2; mt++)
            #pragma unroll
            for (int i = 0; i < 4; i++) {
                if (st == 0) res_s[mt][i] = rtmp[mt][i];
                else         res_t[mt][i] = rtmp[mt][i];
            }
        __syncthreads();                      // HID + W2 buffer free
        if (p + 1 < 2 * NLAYERS) flow_stage_w2(smb, wnext + 4096, tid);
        cp_commit();

        if (st == 1) {
            // ---- layer epilogue: update modified half of resident z ----
            const int moff = (layer & 1) ? 0 : QD;
            const int c0 = wn * 8 + 2 * j;
            float sb0 = sm[F_B2 + layer * QD + c0];
            float sb1v = sm[F_B2 + layer * QD + c0 + 1];
            float tb0 = sm[F_B2 + 192 + layer * QD + c0];
            float tb1v = sm[F_B2 + 192 + layer * QD + c0 + 1];
            #pragma unroll
            for (int mt = 0; mt < 2; mt++) {
                int r0 = wm * 32 + mt * 16 + g;
                float s0 = tanhf(res_s[mt][0] + sb0);
                float s1 = tanhf(res_s[mt][1] + sb1v);
                float s2 = tanhf(res_s[mt][2] + sb0);
                float s3 = tanhf(res_s[mt][3] + sb1v);
                float t0 = res_t[mt][0] + tb0;
                float t1 = res_t[mt][1] + tb1v;
                float t2 = res_t[mt][2] + tb0;
                float t3 = res_t[mt][3] + tb1v;
                float* z0 = &sm[F_Z + r0 * 68 + moff + c0];
                float* z1 = &sm[F_Z + (r0 + 8) * 68 + moff + c0];
                if (inverse) {
                    z0[0] = (z0[0] - t0) * __expf(-s0);
                    z0[1] = (z0[1] - t1) * __expf(-s1);
                    z1[0] = (z1[0] - t2) * __expf(-s2);
                    z1[1] = (z1[1] - t3) * __expf(-s3);
                } else {
                    z0[0] = fmaf(z0[0], __expf(s0), t0);
                    z0[1] = fmaf(z0[1], __expf(s1), t1);
                    z1[0] = fmaf(z1[0], __expf(s2), t2);
                    z1[1] = fmaf(z1[1], __expf(s3), t3);
                }
            }
        }

        if (p + 1 < 2 * NLAYERS) {
            cp_wait<1>();                     // W1_{p+1} landed (newest = W2_{p+1})
            __syncthreads();                  // also publishes epilogue z writes
            if (st == 1) {
                flow_split(sm, tid, (lnext & 1) ? QD : 0);
                __syncthreads();
            }
        }
    }

    cp_wait<0>();
    __syncthreads();                          // final epilogue z writes visible

    // ---- writeback: z (fp32) and optionally zk (bf16) ----
    #pragma unroll
    for (int c = 0; c < 4; c++) {
        int idx = c * 256 + tid;
        int r = idx >> 4, seg = idx & 15;
        const float* zp = &sm[F_Z + r * 68 + seg * 4];
        float4 v = make_float4(zp[0], zp[1], zp[2], zp[3]);
        *reinterpret_cast<float4*>(zout + (row0 + r) * DIM + seg * 4) = v;
        if (zkout) {
            __nv_bfloat162 a, b;
            a.x = __float2bfloat16(v.x); a.y = __float2bfloat16(v.y);
            b.x = __float2bfloat16(v.z); b.y = __float2bfloat16(v.w);
            *reinterpret_cast<__nv_bfloat162*>(zkout + (row0 + r) * DIM + seg * 4)     = a;
            *reinterpret_cast<__nv_bfloat162*>(zkout + (row0 + r) * DIM + seg * 4 + 2) = b;
        }
    }
}

// ===========================================================================
// Shared GEMM epilogue (bf16-activation variants; fast MUFU transcendentals)
// ===========================================================================
template<int EPI, int NT>
__device__ __forceinline__ void gemm_epilogue(
    float acc[2][NT][4], size_t row0, int col0, int wm, int wn, int WN,
    int lane, const float* bia, const float* w3, const __nv_bfloat16* aux,
    char* Cc, int Nld) {
    #pragma unroll
    for (int mt = 0; mt < 2; mt++) {
        const size_t r0 = row0 + wm * 32 + mt * 16 + (lane >> 2);
        const size_t r1 = r0 + 8;
        #pragma unroll
        for (int nt = 0; nt < NT; nt++) {
            const int gc = col0 + wn * WN + nt * 8 + (lane & 3) * 2;
            float v0 = acc[mt][nt][0], v1 = acc[mt][nt][1];
            float v2 = acc[mt][nt][2], v3 = acc[mt][nt][3];
            if (EPI == 0) {
                float b0 = bia[gc], b1 = bia[gc + 1];
                v0 = softplus_fast(v0 + b0); v1 = softplus_fast(v1 + b1);
                v2 = softplus_fast(v2 + b0); v3 = softplus_fast(v3 + b1);
            } else if (EPI == 1) {
                float b0 = bia[gc], b1 = bia[gc + 1];
                float s0 = w3[gc], s1 = w3[gc + 1];
                v0 = s0 / (1.f + __expf(-(v0 + b0)));
                v1 = s1 / (1.f + __expf(-(v1 + b1)));
                v2 = s0 / (1.f + __expf(-(v2 + b0)));
                v3 = s1 / (1.f + __expf(-(v3 + b1)));
            } else if (EPI == 2) {
                __nv_bfloat162 h0 = *reinterpret_cast<const __nv_bfloat162*>(
                    aux + r0 * HH + gc);
                __nv_bfloat162 h1 = *reinterpret_cast<const __nv_bfloat162*>(
                    aux + r1 * HH + gc);
                v0 *= (1.f - __expf(-__bfloat162float(h0.x)));
                v1 *= (1.f - __expf(-__bfloat162float(h0.y)));
                v2 *= (1.f - __expf(-__bfloat162float(h1.x)));
                v3 *= (1.f - __expf(-__bfloat162float(h1.y)));
            }
            __nv_bfloat162 o0; o0.x = __float2bfloat16(v0); o0.y = __float2bfloat16(v1);
            __nv_bfloat162 o1; o1.x = __float2bfloat16(v2); o1.y = __float2bfloat16(v3);
            *reinterpret_cast<__nv_bfloat162*>(
                (__nv_bfloat16*)Cc + r0 * Nld + gc) = o0;
            *reinterpret_cast<__nv_bfloat162*>(
                (__nv_bfloat16*)Cc + r1 * Nld + gc) = o1;
        }
    }
}

// ===========================================================================
// Single-shot warp-MMA GEMM (K=64)
// ===========================================================================
template<int K, int BN, int EPI>
__global__ __launch_bounds__(256)
void gemm_mma(const __nv_bfloat16* __restrict__ A0, const __nv_bfloat16* __restrict__ A1,
              const __nv_bfloat16* __restrict__ B0, const __nv_bfloat16* __restrict__ B1,
              const float* __restrict__ bias0, const float* __restrict__ bias1,
              const float* __restrict__ w30,  const float* __restrict__ w31,
              const __nv_bfloat16* __restrict__ aux0, const __nv_bfloat16* __restrict__ aux1,
              void* __restrict__ C0, void* __restrict__ C1, int Nld) {
    constexpr int LDE = K + 8;
    extern __shared__ __align__(16) char smraw[];
    __nv_bfloat16* smA = reinterpret_cast<__nv_bfloat16*>(smraw);
    __nv_bfloat16* smB = smA + 128 * LDE;

    const int tid = threadIdx.x, wid = tid >> 5, lane = tid & 31;
    const int zi = blockIdx.z;
    const __nv_bfloat16* A   = zi ? A1 : A0;
    const __nv_bfloat16* Bw  = zi ? B1 : B0;
    const float* bia         = zi ? bias1 : bias0;
    const float* w3          = zi ? w31 : w30;
    const __nv_bfloat16* aux = zi ? aux1 : aux0;
    char* Cc                 = (char*)(zi ? C1 : C0);

    const size_t row0 = (size_t)blockIdx.x * 128;
    const int    col0 = blockIdx.y * BN;

    constexpr int ASEG = K / 8;
    #pragma unroll 4
    for (int c = tid; c < 128 * ASEG; c += 256) {
        int r = c / ASEG, s = c % ASEG;
        *reinterpret_cast<uint4*>(smA + r * LDE + s * 8) =
            *reinterpret_cast<const uint4*>(A + (row0 + r) * K + s * 8);
    }
    #pragma unroll 4
    for (int c = tid; c < BN * ASEG; c += 256) {
        int r = c / ASEG, s = c % ASEG;
        *reinterpret_cast<uint4*>(smB + r * LDE + s * 8) =
            *reinterpret_cast<const uint4*>(Bw + (size_t)(col0 + r) * K + s * 8);
    }
    __syncthreads();

    const int wm = wid & 3;
    const int wn = wid >> 2;
    constexpr int WN = BN / 2;
    constexpr int NT = WN / 8;
    const int g = lane >> 2;
    const int j = lane & 3;

    float acc[2][NT][4];
    #pragma unroll
    for (int mt = 0; mt < 2; mt++)
        #pragma unroll
        for (int nt = 0; nt < NT; nt++)
            #pragma unroll
            for (int i = 0; i < 4; i++) acc[mt][nt][i] = 0.f;

    const uint32_t sA = smem_u32(smA), sB = smem_u32(smB);
    uint32_t aBase[2];
    #pragma unroll
    for (int mt = 0; mt < 2; mt++)
        aBase[mt] = sA + (uint32_t)(((wm * 32 + mt * 16 + g) * LDE + 2 * j) * 2);
    uint32_t bBase[NT];
    #pragma unroll
    for (int nt = 0; nt < NT; nt++)
        bBase[nt] = sB + (uint32_t)(((wn * WN + nt * 8 + g) * LDE + 2 * j) * 2);

    constexpr uint32_t ROW8 = (uint32_t)(8 * LDE * 2);

    #pragma unroll 4
    for (int kc = 0; kc < K / 16; kc++) {
        const uint32_t kb = (uint32_t)(kc * 32);
        uint32_t a[2][4];
        #pragma unroll
        for (int mt = 0; mt < 2; mt++) {
            a[mt][0] = lds32(aBase[mt] + kb);
            a[mt][1] = lds32(aBase[mt] + kb + ROW8);
            a[mt][2] = lds32(aBase[mt] + kb + 16);
            a[mt][3] = lds32(aBase[mt] + kb + ROW8 + 16);
        }
        uint32_t b[NT][2];
        #pragma unroll
        for (int nt = 0; nt < NT; nt++) {
            b[nt][0] = lds32(bBase[nt] + kb);
            b[nt][1] = lds32(bBase[nt] + kb + 16);
        }
        #pragma unroll
        for (int mt = 0; mt < 2; mt++)
            #pragma unroll
            for (int nt = 0; nt < NT; nt++)
                mma16816(acc[mt][nt], a[mt][0], a[mt][1], a[mt][2], a[mt][3],
                         b[nt][0], b[nt][1]);
    }

    gemm_epilogue<EPI, NT>(acc, row0, col0, wm, wn, WN, lane, bia, w3, aux, Cc, Nld);
}

// ===========================================================================
// cp.async 3-stage pipelined warp-MMA GEMM (K = 256, BK = 64, BN = 128)
// ===========================================================================
template<int K, int BN, int EPI>
__global__ __launch_bounds__(256, 2)
void gemm_pipe(const __nv_bfloat16* __restrict__ A0, const __nv_bfloat16* __restrict__ A1,
               const __nv_bfloat16* __restrict__ B0, const __nv_bfloat16* __restrict__ B1,
               const float* __restrict__ bias0, const float* __restrict__ bias1,
               const float* __restrict__ w30,  const float* __restrict__ w31,
               const __nv_bfloat16* __restrict__ aux0, const __nv_bfloat16* __restrict__ aux1,
               void* __restrict__ C0, void* __restrict__ C1, int Nld) {
    constexpr int BK   = 64;
    constexpr int LDE  = BK + 8;
    constexpr int NSTG = 3;
    constexpr int NCH  = K / BK;
    constexpr int STGE = (128 + BN) * LDE;
    extern __shared__ __align__(16) __nv_bfloat16 smp[];

    const int tid = threadIdx.x, wid = tid >> 5, lane = tid & 31;
    const int zi = blockIdx.z;
    const __nv_bfloat16* A   = zi ? A1 : A0;
    const __nv_bfloat16* Bw  = zi ? B1 : B0;
    const float* bia         = zi ? bias1 : bias0;
    const float* w3          = zi ? w31 : w30;
    const __nv_bfloat16* aux = zi ? aux1 : aux0;
    char* Cc                 = (char*)(zi ? C1 : C0);

    const size_t row0 = (size_t)blockIdx.x * 128;
    const int    col0 = blockIdx.y * BN;
    const uint32_t sm0 = smem_u32(smp);

    auto load_chunk = [&](int s, int c) {
        const uint32_t dstS = sm0 + (uint32_t)(s * STGE * 2);
        const int k0 = c * BK;
        #pragma unroll
        for (int t = tid; t < (128 + BN) * 8; t += 256) {
            int r = t >> 3, seg = t & 7;
            if (r < 128) {
                cpasync16(dstS + (uint32_t)((r * LDE + seg * 8) * 2),
                          A + (row0 + r) * K + k0 + seg * 8);
            } else {
                int rb = r - 128;
                cpasync16(dstS + (uint32_t)(((128 + rb) * LDE + seg * 8) * 2),
                          Bw + (size_t)(col0 + rb) * K + k0 + seg * 8);
            }
        }
    };

    const int wm = wid & 3;
    const int wn = wid >> 2;
    constexpr int WN = BN / 2;
    constexpr int NT = WN / 8;
    const int g = lane >> 2;
    const int j = lane & 3;

    float acc[2][NT][4];
    #pragma unroll
    for (int mt = 0; mt < 2; mt++)
        #pragma unroll
        for (int nt = 0; nt < NT; nt++)
            #pragma unroll
            for (int i = 0; i < 4; i++) acc[mt][nt][i] = 0.f;

    uint32_t aBase[2];
    #pragma unroll
    for (int mt = 0; mt < 2; mt++)
        aBase[mt] = sm0 + (uint32_t)(((wm * 32 + mt * 16 + g) * LDE + 2 * j) * 2);
    uint32_t bBase[NT];
    #pragma unroll
    for (int nt = 0; nt < NT; nt++)
        bBase[nt] = sm0 + (uint32_t)(((128 + wn * WN + nt * 8 + g) * LDE + 2 * j) * 2);
    constexpr uint32_t ROW8 = (uint32_t)(8 * LDE * 2);

    load_chunk(0, 0); cp_commit();
    load_chunk(1, 1); cp_commit();

    for (int c = 0; c < NCH; c++) {
        cp_wait<1>();
        __syncthreads();
        const uint32_t soff = (uint32_t)((c % NSTG) * STGE * 2);
        #pragma unroll
        for (int kc = 0; kc < BK / 16; kc++) {
            const uint32_t kb = soff + (uint32_t)(kc * 32);
            uint32_t a[2][4];
            #pragma unroll
            for (int mt = 0; mt < 2; mt++) {
                a[mt][0] = lds32(aBase[mt] + kb);
                a[mt][1] = lds32(aBase[mt] + kb + ROW8);
                a[mt][2] = lds32(aBase[mt] + kb + 16);
                a[mt][3] = lds32(aBase[mt] + kb + ROW8 + 16);
            }
            uint32_t b[NT][2];
            #pragma unroll
            for (int nt = 0; nt < NT; nt++) {
                b[nt][0] = lds32(bBase[nt] + kb);
                b[nt][1] = lds32(bBase[nt] + kb + 16);
            }
            #pragma unroll
            for (int mt = 0; mt < 2; mt++)
                #pragma unroll
                for (int nt = 0; nt < NT; nt++)
                    mma16816(acc[mt][nt], a[mt][0], a[mt][1], a[mt][2], a[mt][3],
                             b[nt][0], b[nt][1]);
        }
        __syncthreads();
        if (c + 2 < NCH) load_chunk((c + 2) % NSTG, c + 2);
        cp_commit();
    }

    gemm_epilogue<EPI, NT>(acc, row0, col0, wm, wn, WN, lane, bia, w3, aux, Cc, Nld);
}

// ===========================================================================
// Fused final GEMM (K=512: [g1T | g1V] @ BMcat^T) + RK4 epilogue.
// ===========================================================================
__global__ __launch_bounds__(256, 2)
void gemm_rk4(const __nv_bfloat16* __restrict__ g1T, const __nv_bfloat16* __restrict__ g1V,
              const __nv_bfloat16* __restrict__ Bw,
              const float* __restrict__ u, const float* __restrict__ Bc,
              const float* __restrict__ zg, float* __restrict__ accg,
              __nv_bfloat16* __restrict__ zk, float* __restrict__ outg, int stage) {
    constexpr int BK   = 64;
    constexpr int LDE  = BK + 8;
    constexpr int NSTG = 3;
    constexpr int NCH  = 8;
    constexpr int BN   = 64;
    constexpr int STGE = (128 + BN) * LDE;
    extern __shared__ __align__(16) __nv_bfloat16 smp[];

    const int tid = threadIdx.x, wid = tid >> 5, lane = tid & 31;
    const size_t row0 = (size_t)blockIdx.x * 128;
    const uint32_t sm0 = smem_u32(smp);

    auto load_chunk = [&](int s, int c) {
        const uint32_t dstS = sm0 + (uint32_t)(s * STGE * 2);
        const __nv_bfloat16* A = (c < 4) ? g1T : g1V;
        const int k0 = (c & 3) * BK;
        #pragma unroll
        for (int t = tid; t < (128 + BN) * 8; t += 256) {
            int r = t >> 3, seg = t & 7;
            if (r < 128) {
                cpasync16(dstS + (uint32_t)((r * LDE + seg * 8) * 2),
                          A + (row0 + r) * HH + k0 + seg * 8);
            } else {
                int rb = r - 128;
                cpasync16(dstS + (uint32_t)(((128 + rb) * LDE + seg * 8) * 2),
                          Bw + (size_t)rb * 512 + c * BK + seg * 8);
            }
        }
    };

    const int wm = wid & 3;
    const int wn = wid >> 2;
    constexpr int WN = BN / 2;
    constexpr int NT = WN / 8;
    const int g = lane >> 2;
    const int j = lane & 3;

    float acc[2][NT][4];
    #pragma unroll
    for (int mt = 0; mt < 2; mt++)
        #pragma unroll
        for (int nt = 0; nt < NT; nt++)
            #pragma unroll
            for (int i = 0; i < 4; i++) acc[mt][nt][i] = 0.f;

    uint32_t aBase[2];
    #pragma unroll
    for (int mt = 0; mt < 2; mt++)
        aBase[mt] = sm0 + (uint32_t)(((wm * 32 + mt * 16 + g) * LDE + 2 * j) * 2);
    uint32_t bBase[NT];
    #pragma unroll
    for (int nt = 0; nt < NT; nt++)
        bBase[nt] = sm0 + (uint32_t)(((128 + wn * WN + nt * 8 + g) * LDE + 2 * j) * 2);
    constexpr uint32_t ROW8 = (uint32_t)(8 * LDE * 2);

    load_chunk(0, 0); cp_commit();
    load_chunk(1, 1); cp_commit();

    for (int c = 0; c < NCH; c++) {
        cp_wait<1>();
        __syncthreads();
        const uint32_t soff = (uint32_t)((c % NSTG) * STGE * 2);
        #pragma unroll
        for (int kc = 0; kc < BK / 16; kc++) {
            const uint32_t kb = soff + (uint32_t)(kc * 32);
            uint32_t a[2][4];
            #pragma unroll
            for (int mt = 0; mt < 2; mt++) {
                a[mt][0] = lds32(aBase[mt] + kb);
                a[mt][1] = lds32(aBase[mt] + kb + ROW8);
                a[mt][2] = lds32(aBase[mt] + kb + 16);
                a[mt][3] = lds32(aBase[mt] + kb + ROW8 + 16);
            }
            uint32_t b[NT][2];
            #pragma unroll
            for (int nt = 0; nt < NT; nt++) {
                b[nt][0] = lds32(bBase[nt] + kb);
                b[nt][1] = lds32(bBase[nt] + kb + 16);
            }
            #pragma unroll
            for (int mt = 0; mt < 2; mt++)
                #pragma unroll
                for (int nt = 0; nt < NT; nt++)
                    mma16816(acc[mt][nt], a[mt][0], a[mt][1], a[mt][2], a[mt][3],
                             b[nt][0], b[nt][1]);
        }
        __syncthreads();
        if (c + 2 < NCH) load_chunk((c + 2) % NSTG, c + 2);
        cp_commit();
    }

    // ---- fused RK4 epilogue ----
    const float wgt = (stage == 1 || stage == 2) ? 2.f : 1.f;
    const float cn  = (stage == 2) ? DTC : 0.5f * DTC;
    #pragma unroll
    for (int mt = 0; mt < 2; mt++) {
        const size_t r0 = row0 + wm * 32 + mt * 16 + (lane >> 2);
        const size_t r1 = r0 + 8;
        const float u0 = u[r0], u1 = u[r1];
        #pragma unroll
        for (int nt = 0; nt < NT; nt++) {
            const int gc = wn * WN + nt * 8 + (lane & 3) * 2;
            float dz0 = acc[mt][nt][0], dz1 = acc[mt][nt][1];
            float dz2 = acc[mt][nt][2], dz3 = acc[mt][nt][3];
            if (gc >= QD) {
                float bc0 = Bc[gc - QD], bc1 = Bc[gc - QD + 1];
                dz0 = fmaf(u0, bc0, dz0); dz1 = fmaf(u0, bc1, dz1);
                dz2 = fmaf(u1, bc0, dz2); dz3 = fmaf(u1, bc1, dz3);
            }
            const size_t i0 = r0 * DIM + gc, i1 = r1 * DIM + gc;
            float2 ap0 = make_float2(0.f, 0.f), ap1 = make_float2(0.f, 0.f);
            if (stage != 0) {
                ap0 = *reinterpret_cast<float2*>(accg + i0);
                ap1 = *reinterpret_cast<float2*>(accg + i1);
            }
            float a0 = fmaf(wgt, dz0, ap0.x), a1 = fmaf(wgt, dz1, ap0.y);
            float a2 = fmaf(wgt, dz2, ap1.x), a3 = fmaf(wgt, dz3, ap1.y);
            *reinterpret_cast<float2*>(accg + i0) = make_float2(a0, a1);
            *reinterpret_cast<float2*>(accg + i1) = make_float2(a2, a3);
            float2 z0 = *reinterpret_cast<const float2*>(zg + i0);
            float2 z1 = *reinterpret_cast<const float2*>(zg + i1);
            if (stage < 3) {
                __nv_bfloat162 o0, o1;
                o0.x = __float2bfloat16(fmaf(cn, dz0, z0.x));
                o0.y = __float2bfloat16(fmaf(cn, dz1, z0.y));
                o1.x = __float2bfloat16(fmaf(cn, dz2, z1.x));
                o1.y = __float2bfloat16(fmaf(cn, dz3, z1.y));
                *reinterpret_cast<__nv_bfloat162*>(zk + i0) = o0;
                *reinterpret_cast<__nv_bfloat162*>(zk + i1) = o1;
            } else {
                *reinterpret_cast<float2*>(outg + i0) =
                    make_float2(fmaf(DTC / 6.f, a0, z0.x), fmaf(DTC / 6.f, a1, z0.y));
                *reinterpret_cast<float2*>(outg + i1) =
                    make_float2(fmaf(DTC / 6.f, a2, z1.x), fmaf(DTC / 6.f, a3, z1.y));
            }
        }
    }
}

// ===========================================================================
// Host orchestration
// ===========================================================================
extern "C" void kernel_launch(void* const* d_in, const int* in_sizes, int n_in,
                              void* d_out, int out_size) {
    const float* h    = (const float*)d_in[0];
    const float* u    = (const float*)d_in[1];
    const float* sW1  = (const float*)d_in[2];
    const float* sb1  = (const float*)d_in[3];
    const float* sW2  = (const float*)d_in[4];
    const float* sb2  = (const float*)d_in[5];
    const float* tW1  = (const float*)d_in[6];
    const float* tb1  = (const float*)d_in[7];
    const float* tW2  = (const float*)d_in[8];
    const float* tb2  = (const float*)d_in[9];
    const float* kW1  = (const float*)d_in[10];
    const float* kb1  = (const float*)d_in[11];
    const float* kW2  = (const float*)d_in[12];
    const float* kb2  = (const float*)d_in[13];
    const float* kW3  = (const float*)d_in[14];
    const float* vW1  = (const float*)d_in[16];
    const float* vb1  = (const float*)d_in[17];
    const float* vW2  = (const float*)d_in[18];
    const float* vb2  = (const float*)d_in[19];
    const float* vW3  = (const float*)d_in[20];
    const float* A    = (const float*)d_in[22];
    const float* Lp   = (const float*)d_in[23];
    const float* Bc   = (const float*)d_in[24];
    float* out = (float*)d_out;

    float *z, *acc, *Mp, *fpk;
    __nv_bfloat16 *zk, *h1T, *h1V, *g2T, *g2V, *g1T, *g1V;
    __nv_bfloat16 *Bk1, *Bv1, *Bk2, *Bv2, *Bk2t, *Bv2t, *BMcat;
    cudaGetSymbolAddress((void**)&z,     g_z);
    cudaGetSymbolAddress((void**)&acc,   g_acc);
    cudaGetSymbolAddress((void**)&zk,    g_zk);
    cudaGetSymbolAddress((void**)&h1T,   g_h1T);
    cudaGetSymbolAddress((void**)&h1V,   g_h1V);
    cudaGetSymbolAddress((void**)&g2T,   g_g2T);
    cudaGetSymbolAddress((void**)&g2V,   g_g2V);
    cudaGetSymbolAddress((void**)&g1T,   g_g1T);
    cudaGetSymbolAddress((void**)&g1V,   g_g1V);
    cudaGetSymbolAddress((void**)&Bk1,   g_Bk1);
    cudaGetSymbolAddress((void**)&Bv1,   g_Bv1);
    cudaGetSymbolAddress((void**)&Bk2,   g_Bk2);
    cudaGetSymbolAddress((void**)&Bv2,   g_Bv2);
    cudaGetSymbolAddress((void**)&Bk2t,  g_Bk2t);
    cudaGetSymbolAddress((void**)&Bv2t,  g_Bv2t);
    cudaGetSymbolAddress((void**)&BMcat, g_BMcat);
    cudaGetSymbolAddress((void**)&Mp,    g_M);
    cudaGetSymbolAddress((void**)&fpk,   g_fpk);

    const int SM1 = (128 + 128) * (64 + 8) * 2;        // 36,864
    const int SMP128 = 3 * (128 + 128) * 72 * 2;       // 110,592
    const int SMP64  = 3 * (128 + 64)  * 72 * 2;       //  82,944
    const int SMF    = F_TOT * 4;                      // 112,640 (flow_fused_k)
    cudaFuncSetAttribute(gemm_mma<64, 128, 0>,
                         cudaFuncAttributeMaxDynamicSharedMemorySize, SM1);
    cudaFuncSetAttribute(gemm_pipe<256, 128, 1>,
                         cudaFuncAttributeMaxDynamicSharedMemorySize, SMP128);
    cudaFuncSetAttribute(gemm_pipe<256, 128, 2>,
                         cudaFuncAttributeMaxDynamicSharedMemorySize, SMP128);
    cudaFuncSetAttribute(gemm_rk4,
                         cudaFuncAttributeMaxDynamicSharedMemorySize, SMP64);
    cudaFuncSetAttribute(flow_fused_k,
                         cudaFuncAttributeMaxDynamicSharedMemorySize, SMF);

    // ---- prep: 2 launches ----
    build_M_k<<<1, 256>>>(A, Lp, Mp);
    prep_pack_k<<<dim3(384, 9), 256>>>(kW1, vW1, kW2, vW2, Mp,
                                       sW1, sW2, tW1, tW2,
                                       Bk1, Bv1, Bk2, Bv2, Bk2t, Bv2t,
                                       BMcat, fpk);

    // ---- s = flow_fwd(h): one fused launch (reads h, writes z + zk) ----
    flow_fused_k<<<BATCH / 64, 256, SMF>>>(h, z, zk, fpk, sb1, sb2, tb1, tb2, 0);

    // ---- RK4 stages ----
    dim3 gBig(BATCH / 128, 2, 2);
    for (int st = 0; st < 4; st++) {
        gemm_mma<64, 128, 0><<<gBig, 256, SM1>>>(
            zk, zk, Bk1, Bv1, kb1, vb1, 0, 0, 0, 0, h1T, h1V, HH);
        gemm_pipe<256, 128, 1><<<gBig, 256, SMP128>>>(
            h1T, h1V, Bk2, Bv2, kb2, vb2, kW3, vW3, 0, 0, g2T, g2V, HH);
        gemm_pipe<256, 128, 2><<<gBig, 256, SMP128>>>(
            g2T, g2V, Bk2t, Bv2t, 0, 0, 0, 0, h1T, h1V, g1T, g1V, HH);
        gemm_rk4<<<BATCH / 128, 256, SMP64>>>(
            g1T, g1V, BMcat, u, Bc, z, acc, zk, out, st);
    }

    // ---- h_next = flow_inv(z_next): one fused launch in place on out ----
    flow_fused_k<<<BATCH / 64, 256, SMF>>>(out, out, (__nv_bfloat16*)0,
                                           fpk, sb1, sb2, tb1, tb2, 1);
}

// round 15
// speedup vs baseline: 4.5141x; 1.0488x over previous
#include <cuda_runtime.h>
#include <cuda_bf16.h>
#include <math.h>
#include <cstdint>

#define BATCH   131072
#define DIM     64
#define QD      32
#define NLAYERS 6
#define HF      128
#define HH      256
#define DTC     0.05f

// ===========================================================================
// Pair-interleaved K layout: within each 16-element k-group, order is
// [k0,k1,k8,k9,k2,k3,k10,k11,k4,k5,k12,k13,k6,k7,k14,k15], so that the mma
// fragment pairs (k=2j,2j+1) and (k=2j+8,2j+9) are adjacent -> one LDS.64.
// ===========================================================================
__host__ __device__ __forceinline__ int ipos(int k) {
    return (k & ~15) | (((k >> 1) & 3) << 2) | ((k & 8) >> 2) | (k & 1);
}

// ===========================================================================
// Scratch (static __device__ arrays)
// ===========================================================================
__device__ __align__(16) float g_z   [BATCH * DIM];
__device__ __align__(16) float g_acc [BATCH * DIM];
__device__ __align__(16) __nv_bfloat16 g_zk [BATCH * DIM];       // k-interleaved
__device__ __align__(16) __nv_bfloat16 g_h1T[BATCH * HH];        // k-interleaved
__device__ __align__(16) __nv_bfloat16 g_h1V[BATCH * HH];
__device__ __align__(16) __nv_bfloat16 g_g2T[BATCH * HH];
__device__ __align__(16) __nv_bfloat16 g_g2V[BATCH * HH];
__device__ __align__(16) __nv_bfloat16 g_g1T[BATCH * HH];
__device__ __align__(16) __nv_bfloat16 g_g1V[BATCH * HH];
// bf16 weight images, row-major [N][K], K pair-interleaved
__device__ __align__(16) __nv_bfloat16 g_Bk1  [HH * 64];
__device__ __align__(16) __nv_bfloat16 g_Bv1  [HH * 64];
__device__ __align__(16) __nv_bfloat16 g_Bk2  [HH * HH];
__device__ __align__(16) __nv_bfloat16 g_Bv2  [HH * HH];
__device__ __align__(16) __nv_bfloat16 g_Bk2t [HH * HH];
__device__ __align__(16) __nv_bfloat16 g_Bv2t [HH * HH];
__device__ __align__(16) __nv_bfloat16 g_BMcat[64 * 512];
__device__ float g_M[DIM * DIM];
// flow weights, tf32-rounded (natural layout -- flow kernel untouched)
__device__ __align__(16) float g_fpk[NLAYERS * 16384];

__device__ __forceinline__ float softplusf(float x) {
    return fmaxf(x, 0.f) + log1pf(expf(-fabsf(x)));
}
__device__ __forceinline__ float softplus_fast(float x) {
    return fmaxf(x, 0.f) + __logf(1.f + __expf(-fabsf(x)));
}

__device__ __forceinline__ uint32_t smem_u32(const void* p) {
    uint32_t a;
    asm("{ .reg .u64 t; cvta.to.shared.u64 t, %1; cvt.u32.u64 %0, t; }"
        : "=r"(a) : "l"(p));
    return a;
}

// VOLATILE shared loads (no CSE across barriers)
__device__ __forceinline__ uint32_t lds32(uint32_t addr) {
    uint32_t v;
    asm volatile("ld.shared.b32 %0, [%1];" : "=r"(v) : "r"(addr));
    return v;
}
__device__ __forceinline__ void lds64(uint32_t addr, uint32_t& x, uint32_t& y) {
    asm volatile("ld.shared.v2.b32 {%0, %1}, [%2];" : "=r"(x), "=r"(y) : "r"(addr));
}

__device__ __forceinline__ float tf32r(float x) {
    uint32_t u;
    asm("cvt.rna.tf32.f32 %0, %1;" : "=r"(u) : "f"(x));
    return __uint_as_float(u);
}

__device__ __forceinline__ void cpasync16(uint32_t dst, const void* src) {
    asm volatile("cp.async.cg.shared.global [%0], [%1], 16;"
                 :: "r"(dst), "l"(src));
}
__device__ __forceinline__ void cp_commit() {
    asm volatile("cp.async.commit_group;");
}
template<int N>
__device__ __forceinline__ void cp_wait() {
    asm volatile("cp.async.wait_group %0;" :: "n"(N));
}

__device__ __forceinline__ void mma16816(float* c, uint32_t a0, uint32_t a1,
                                         uint32_t a2, uint32_t a3,
                                         uint32_t b0, uint32_t b1) {
    asm volatile(
        "mma.sync.aligned.m16n8k16.row.col.f32.bf16.bf16.f32 "
        "{%0,%1,%2,%3},{%4,%5,%6,%7},{%8,%9},{%0,%1,%2,%3};"
        : "+f"(c[0]), "+f"(c[1]), "+f"(c[2]), "+f"(c[3])
        : "r"(a0), "r"(a1), "r"(a2), "r"(a3), "r"(b0), "r"(b1));
}

__device__ __forceinline__ void mma_tf32(float* c, uint32_t a0, uint32_t a1,
                                         uint32_t a2, uint32_t a3,
                                         uint32_t b0, uint32_t b1) {
    asm volatile(
        "mma.sync.aligned.m16n8k8.row.col.f32.tf32.tf32.f32 "
        "{%0,%1,%2,%3},{%4,%5,%6,%7},{%8,%9},{%0,%1,%2,%3};"
        : "+f"(c[0]), "+f"(c[1]), "+f"(c[2]), "+f"(c[3])
        : "r"(a0), "r"(a1), "r"(a2), "r"(a3), "r"(b0), "r"(b1));
}

// ===========================================================================
// Prep kernels
// ===========================================================================
__global__ void build_M_k(const float* __restrict__ A, const float* __restrict__ Lp,
                          float* __restrict__ M) {
    __shared__ float L[DIM * DIM];
    int t = threadIdx.x;
    for (int idx = t; idx < DIM * DIM; idx += 256) {
        int i = idx >> 6, j = idx & 63;
        float v;
        if (i > j)       v = Lp[idx];
        else if (i == j) v = softplusf(Lp[idx]);
        else             v = 0.f;
        L[idx] = v;
    }
    __syncthreads();
    for (int idx = t; idx < DIM * DIM; idx += 256) {
        int i = idx >> 6, j = idx & 63;
        float s = 0.f;
        #pragma unroll 8
        for (int k = 0; k < DIM; k++) s += L[i * DIM + k] * L[j * DIM + k];
        M[idx] = A[i * DIM + j] - A[j * DIM + i] - s;
    }
}

__global__ void prep_pack_k(const float* __restrict__ kW1, const float* __restrict__ vW1,
                            const float* __restrict__ kW2, const float* __restrict__ vW2,
                            const float* __restrict__ M,
                            const float* __restrict__ sW1, const float* __restrict__ sW2,
                            const float* __restrict__ tW1, const float* __restrict__ tW2,
                            __nv_bfloat16* __restrict__ Bk1, __nv_bfloat16* __restrict__ Bv1,
                            __nv_bfloat16* __restrict__ Bk2, __nv_bfloat16* __restrict__ Bv2,
                            __nv_bfloat16* __restrict__ Bk2t, __nv_bfloat16* __restrict__ Bv2t,
                            __nv_bfloat16* __restrict__ BMcat,
                            float* __restrict__ fpk) {
    int idx = blockIdx.x * 256 + threadIdx.x;
    int task = blockIdx.y;
    if (task == 0) {            // Bk1 [256][64] interleaved k
        if (idx < HH * 64) {
            int r = idx >> 6, k = idx & 63;
            Bk1[r * 64 + ipos(k)] = __float2bfloat16(kW1[idx]);
        }
    } else if (task == 1) {     // Bv1, K zero-padded from 32
        if (idx < HH * 64) {
            int r = idx >> 6, k = idx & 63;
            Bv1[r * 64 + ipos(k)] = __float2bfloat16(k < QD ? vW1[r * QD + k] : 0.f);
        }
    } else if (task == 2) {
        if (idx < HH * HH) {
            int r = idx >> 8, k = idx & 255;
            Bk2[r * HH + ipos(k)] = __float2bfloat16(kW2[idx]);
        }
    } else if (task == 3) {
        if (idx < HH * HH) {
            int r = idx >> 8, k = idx & 255;
            Bv2[r * HH + ipos(k)] = __float2bfloat16(vW2[idx]);
        }
    } else if (task == 4) {
        if (idx < HH * HH) {
            int r = idx >> 8, k = idx & 255;
            Bk2t[r * HH + ipos(k)] = __float2bfloat16(kW2[k * HH + r]);
        }
    } else if (task == 5) {
        if (idx < HH * HH) {
            int r = idx >> 8, k = idx & 255;
            Bv2t[r * HH + ipos(k)] = __float2bfloat16(vW2[k * HH + r]);
        }
    } else if (task == 6) {
        if (idx < 64 * HH) {
            int i = idx >> 8, k = idx & 255;
            float s = 0.f;
            for (int n = 0; n < 64; n++) s += kW1[k * 64 + n] * M[i * 64 + n];
            BMcat[i * 512 + ipos(k)] = __float2bfloat16(s);
        }
    } else if (task == 7) {
        if (idx < 64 * HH) {
            int i = idx >> 8, k = idx & 255;
            float s = 0.f;
            for (int n = 0; n < QD; n++) s += vW1[k * QD + n] * M[i * 64 + n];
            BMcat[i * 512 + 256 + ipos(k)] = __float2bfloat16(s);
        }
    } else {                    // flow weights (natural layout)
        if (idx < NLAYERS * 16384) {
            int l = idx / 16384, r = idx % 16384;
            int sel = r / 4096, o = r % 4096;
            float v;
            if (sel == 0)      v = sW1[l * 4096 + o];
            else if (sel == 1) v = sW2[l * 4096 + o];
            else if (sel == 2) v = tW1[l * 4096 + o];
            else               v = tW2[l * 4096 + o];
            fpk[idx] = tf32r(v);
        }
    }
}

// ===========================================================================
// Fully-fused tf32 RealNVP flow (unchanged except zk writeback interleaved)
// ===========================================================================
#define F_Z    0
#define F_CH   4352
#define F_CL   6656
#define F_W1O  8960
#define F_W2O  13568
#define F_HIDO 17792
#define F_B1   26240
#define F_B2   27776
#define F_TOT  28160

__device__ __forceinline__ void flow_stage_w1(uint32_t smb, const float* src, int tid) {
    #pragma unroll
    for (int c = 0; c < 4; c++) {
        int idx = c * 256 + tid;
        int r = idx >> 3, seg = idx & 7;
        cpasync16(smb + (uint32_t)((F_W1O + r * 36 + seg * 4) << 2), src + idx * 4);
    }
}
__device__ __forceinline__ void flow_stage_w2(uint32_t smb, const float* src, int tid) {
    #pragma unroll
    for (int c = 0; c < 4; c++) {
        int idx = c * 256 + tid;
        int r = idx >> 5, seg = idx & 31;
        cpasync16(smb + (uint32_t)((F_W2O + r * 132 + seg * 4) << 2), src + idx * 4);
    }
}

__device__ __forceinline__ void flow_split(float* sm, int tid, int coff) {
    #pragma unroll
    for (int c = 0; c < 8; c++) {
        int idx = c * 256 + tid;
        int r = idx >> 5, cc = idx & 31;
        float y = sm[F_Z + r * 68 + coff + cc];
        float hi = tf32r(y);
        sm[F_CH + r * 36 + cc] = hi;
        sm[F_CL + r * 36 + cc] = tf32r(y - hi);
    }
}

__device__ __forceinline__ void flow_mma1(float* sm, uint32_t smb,
                                          int wm, int wn, int g, int j, int b1off) {
    float acc1[2][4][4];
    #pragma unroll
    for (int mt = 0; mt < 2; mt++)
        #pragma unroll
        for (int nt = 0; nt < 4; nt++)
            #pragma unroll
            for (int i = 0; i < 4; i++) acc1[mt][nt][i] = 0.f;

    uint32_t aH[2], aL[2];
    #pragma unroll
    for (int mt = 0; mt < 2; mt++) {
        int r = wm * 32 + mt * 16 + g;
        aH[mt] = smb + (uint32_t)((F_CH + r * 36 + j) << 2);
        aL[mt] = smb + (uint32_t)((F_CL + r * 36 + j) << 2);
    }
    uint32_t bA[4];
    #pragma unroll
    for (int nt = 0; nt < 4; nt++)
        bA[nt] = smb + (uint32_t)((F_W1O + (wn * 32 + nt * 8 + g) * 36 + j) << 2);

    #pragma unroll
    for (int kc = 0; kc < 4; kc++) {
        const uint32_t ko = (uint32_t)(kc * 32);
        uint32_t ah[2][4], al[2][4];
        #pragma unroll
        for (int mt = 0; mt < 2; mt++) {
            ah[mt][0] = lds32(aH[mt] + ko);
            ah[mt][1] = lds32(aH[mt] + ko + 1152);
            ah[mt][2] = lds32(aH[mt] + ko + 16);
            ah[mt][3] = lds32(aH[mt] + ko + 1168);
            al[mt][0] = lds32(aL[mt] + ko);
            al[mt][1] = lds32(aL[mt] + ko + 1152);
            al[mt][2] = lds32(aL[mt] + ko + 16);
            al[mt][3] = lds32(aL[mt] + ko + 1168);
        }
        #pragma unroll
        for (int nt = 0; nt < 4; nt++) {
            uint32_t b0 = lds32(bA[nt] + ko);
            uint32_t b1 = lds32(bA[nt] + ko + 16);
            #pragma unroll
            for (int mt = 0; mt < 2; mt++) {
                mma_tf32(acc1[mt][nt], ah[mt][0], ah[mt][1], ah[mt][2], ah[mt][3], b0, b1);
                mma_tf32(acc1[mt][nt], al[mt][0], al[mt][1], al[mt][2], al[mt][3], b0, b1);
            }
        }
    }
    #pragma unroll
    for (int mt = 0; mt < 2; mt++) {
        int r0 = wm * 32 + mt * 16 + g;
        #pragma unroll
        for (int nt = 0; nt < 4; nt++) {
            int c0 = wn * 32 + nt * 8 + 2 * j;
            float b0 = sm[b1off + c0], b1f = sm[b1off + c0 + 1];
            sm[F_HIDO + r0 * 132 + c0]           = tf32r(fmaxf(acc1[mt][nt][0] + b0, 0.f));
            sm[F_HIDO + r0 * 132 + c0 + 1]       = tf32r(fmaxf(acc1[mt][nt][1] + b1f, 0.f));
            sm[F_HIDO + (r0 + 8) * 132 + c0]     = tf32r(fmaxf(acc1[mt][nt][2] + b0, 0.f));
            sm[F_HIDO + (r0 + 8) * 132 + c0 + 1] = tf32r(fmaxf(acc1[mt][nt][3] + b1f, 0.f));
        }
    }
}

__device__ __forceinline__ void flow_mma2(uint32_t smb, int wm, int wn, int g, int j,
                                          float res[2][4]) {
    float acc2[2][4];
    #pragma unroll
    for (int mt = 0; mt < 2; mt++)
        #pragma unroll
        for (int i = 0; i < 4; i++) acc2[mt][i] = 0.f;

    uint32_t a2[2];
    #pragma unroll
    for (int mt = 0; mt < 2; mt++)
        a2[mt] = smb + (uint32_t)((F_HIDO + (wm * 32 + mt * 16 + g) * 132 + j) << 2);
    uint32_t b2a = smb + (uint32_t)((F_W2O + (wn * 8 + g) * 132 + j) << 2);

    #pragma unroll 4
    for (int kc = 0; kc < 16; kc++) {
        const uint32_t ko = (uint32_t)(kc * 32);
        uint32_t b0 = lds32(b2a + ko);
        uint32_t b1 = lds32(b2a + ko + 16);
        #pragma unroll
        for (int mt = 0; mt < 2; mt++) {
            uint32_t av0 = lds32(a2[mt] + ko);
            uint32_t av1 = lds32(a2[mt] + ko + 4224);
            uint32_t av2 = lds32(a2[mt] + ko + 16);
            uint32_t av3 = lds32(a2[mt] + ko + 4240);
            mma_tf32(acc2[mt], av0, av1, av2, av3, b0, b1);
        }
    }
    #pragma unroll
    for (int mt = 0; mt < 2; mt++)
        #pragma unroll
        for (int i = 0; i < 4; i++) res[mt][i] = acc2[mt][i];
}

__global__ __launch_bounds__(256, 2)
void flow_fused_k(const float* __restrict__ zin, float* __restrict__ zout,
                  __nv_bfloat16* __restrict__ zkout,
                  const float* __restrict__ fpk,
                  const float* __restrict__ sb1, const float* __restrict__ sb2,
                  const float* __restrict__ tb1, const float* __restrict__ tb2,
                  int inverse) {
    extern __shared__ float sm[];

    const int tid = threadIdx.x, wid = tid >> 5, lane = tid & 31;
    const int g = lane >> 2, j = lane & 3;
    const int wm = wid & 1, wn = wid >> 1;
    const size_t row0 = (size_t)blockIdx.x * 64;
    const uint32_t smb = smem_u32(sm);

    #pragma unroll
    for (int c = 0; c < 4; c++) {
        int idx = c * 256 + tid;
        int r = idx >> 4, seg = idx & 15;
        cpasync16(smb + (uint32_t)((F_Z + r * 68 + seg * 4) << 2),
                  zin + (row0 + r) * DIM + seg * 4);
    }
    const int layer0 = inverse ? NLAYERS - 1 : 0;
    flow_stage_w1(smb, fpk + layer0 * 16384, tid);
    flow_stage_w2(smb, fpk + layer0 * 16384 + 4096, tid);
    cp_commit();

    for (int idx = tid; idx < NLAYERS * HF; idx += 256) {
        sm[F_B1 + idx]       = sb1[idx];
        sm[F_B1 + 768 + idx] = tb1[idx];
    }
    if (tid < NLAYERS * QD) {
        sm[F_B2 + tid]       = sb2[tid];
        sm[F_B2 + 192 + tid] = tb2[tid];
    }

    cp_wait<0>();
    __syncthreads();
    flow_split(sm, tid, (layer0 & 1) ? QD : 0);
    __syncthreads();

    float res_s[2][4], res_t[2][4];

    #pragma unroll 1
    for (int p = 0; p < 2 * NLAYERS; p++) {
        const int lidx  = p >> 1, st = p & 1;
        const int layer = inverse ? NLAYERS - 1 - lidx : lidx;
        const int lnext = inverse ? NLAYERS - 1 - ((p + 1) >> 1) : ((p + 1) >> 1);
        const float* wnext = fpk + lnext * 16384 + ((p + 1) & 1) * 8192;
        const int b1off = F_B1 + st * 768 + layer * HF;

        flow_mma1(sm, smb, wm, wn, g, j, b1off);
        __syncthreads();
        if (p + 1 < 2 * NLAYERS) flow_stage_w1(smb, wnext, tid);
        cp_commit();
        cp_wait<1>();
        __syncthreads();
        float rtmp[2][4];
        flow_mma2(smb, wm, wn, g, j, rtmp);
        #pragma unroll
        for (int mt = 0; mt < 2; mt++)
            #pragma unroll
            for (int i = 0; i < 4; i++) {
                if (st == 0) res_s[mt][i] = rtmp[mt][i];
                else         res_t[mt][i] = rtmp[mt][i];
            }
        __syncthreads();
        if (p + 1 < 2 * NLAYERS) flow_stage_w2(smb, wnext + 4096, tid);
        cp_commit();

        if (st == 1) {
            const int moff = (layer & 1) ? 0 : QD;
            const int c0 = wn * 8 + 2 * j;
            float sb0 = sm[F_B2 + layer * QD + c0];
            float sb1v = sm[F_B2 + layer * QD + c0 + 1];
            float tb0 = sm[F_B2 + 192 + layer * QD + c0];
            float tb1v = sm[F_B2 + 192 + layer * QD + c0 + 1];
            #pragma unroll
            for (int mt = 0; mt < 2; mt++) {
                int r0 = wm * 32 + mt * 16 + g;
                float s0 = tanhf(res_s[mt][0] + sb0);
                float s1 = tanhf(res_s[mt][1] + sb1v);
                float s2 = tanhf(res_s[mt][2] + sb0);
                float s3 = tanhf(res_s[mt][3] + sb1v);
                float t0 = res_t[mt][0] + tb0;
                float t1 = res_t[mt][1] + tb1v;
                float t2 = res_t[mt][2] + tb0;
                float t3 = res_t[mt][3] + tb1v;
                float* z0 = &sm[F_Z + r0 * 68 + moff + c0];
                float* z1 = &sm[F_Z + (r0 + 8) * 68 + moff + c0];
                if (inverse) {
                    z0[0] = (z0[0] - t0) * __expf(-s0);
                    z0[1] = (z0[1] - t1) * __expf(-s1);
                    z1[0] = (z1[0] - t2) * __expf(-s2);
                    z1[1] = (z1[1] - t3) * __expf(-s3);
                } else {
                    z0[0] = fmaf(z0[0], __expf(s0), t0);
                    z0[1] = fmaf(z0[1], __expf(s1), t1);
                    z1[0] = fmaf(z1[0], __expf(s2), t2);
                    z1[1] = fmaf(z1[1], __expf(s3), t3);
                }
            }
        }

        if (p + 1 < 2 * NLAYERS) {
            cp_wait<1>();
            __syncthreads();
            if (st == 1) {
                flow_split(sm, tid, (lnext & 1) ? QD : 0);
                __syncthreads();
            }
        }
    }

    cp_wait<0>();
    __syncthreads();

    // ---- writeback: z (fp32, natural) and zk (bf16, k-interleaved) ----
    #pragma unroll
    for (int c = 0; c < 4; c++) {
        int idx = c * 256 + tid;
        int r = idx >> 4, seg = idx & 15;
        const float* zp = &sm[F_Z + r * 68 + seg * 4];
        float4 v = make_float4(zp[0], zp[1], zp[2], zp[3]);
        *reinterpret_cast<float4*>(zout + (row0 + r) * DIM + seg * 4) = v;
        if (zkout) {
            __nv_bfloat162 a, b;
            a.x = __float2bfloat16(v.x); a.y = __float2bfloat16(v.y);
            b.x = __float2bfloat16(v.z); b.y = __float2bfloat16(v.w);
            int kb = seg * 4;
            *reinterpret_cast<__nv_bfloat162*>(
                zkout + (row0 + r) * DIM + ipos(kb))     = a;
            *reinterpret_cast<__nv_bfloat162*>(
                zkout + (row0 + r) * DIM + ipos(kb + 2)) = b;
        }
    }
}

// ===========================================================================
// Shared GEMM epilogue -- stores to k-interleaved positions (activations
// feed later GEMMs as K-operands); aux (EPI2) read also interleaved.
// ===========================================================================
template<int EPI, int NT>
__device__ __forceinline__ void gemm_epilogue(
    float acc[2][NT][4], size_t row0, int col0, int wm, int wn, int WN,
    int lane, const float* bia, const float* w3, const __nv_bfloat16* aux,
    char* Cc, int Nld) {
    #pragma unroll
    for (int mt = 0; mt < 2; mt++) {
        const size_t r0 = row0 + wm * 32 + mt * 16 + (lane >> 2);
        const size_t r1 = r0 + 8;
        #pragma unroll
        for (int nt = 0; nt < NT; nt++) {
            const int gc = col0 + wn * WN + nt * 8 + (lane & 3) * 2;
            const int gp = ipos(gc);
            float v0 = acc[mt][nt][0], v1 = acc[mt][nt][1];
            float v2 = acc[mt][nt][2], v3 = acc[mt][nt][3];
            if (EPI == 0) {
                float b0 = bia[gc], b1 = bia[gc + 1];
                v0 = softplus_fast(v0 + b0); v1 = softplus_fast(v1 + b1);
                v2 = softplus_fast(v2 + b0); v3 = softplus_fast(v3 + b1);
            } else if (EPI == 1) {
                float b0 = bia[gc], b1 = bia[gc + 1];
                float s0 = w3[gc], s1 = w3[gc + 1];
                v0 = s0 / (1.f + __expf(-(v0 + b0)));
                v1 = s1 / (1.f + __expf(-(v1 + b1)));
                v2 = s0 / (1.f + __expf(-(v2 + b0)));
                v3 = s1 / (1.f + __expf(-(v3 + b1)));
            } else if (EPI == 2) {
                __nv_bfloat162 h0 = *reinterpret_cast<const __nv_bfloat162*>(
                    aux + r0 * HH + gp);
                __nv_bfloat162 h1 = *reinterpret_cast<const __nv_bfloat162*>(
                    aux + r1 * HH + gp);
                v0 *= (1.f - __expf(-__bfloat162float(h0.x)));
                v1 *= (1.f - __expf(-__bfloat162float(h0.y)));
                v2 *= (1.f - __expf(-__bfloat162float(h1.x)));
                v3 *= (1.f - __expf(-__bfloat162float(h1.y)));
            }
            __nv_bfloat162 o0; o0.x = __float2bfloat16(v0); o0.y = __float2bfloat16(v1);
            __nv_bfloat162 o1; o1.x = __float2bfloat16(v2); o1.y = __float2bfloat16(v3);
            *reinterpret_cast<__nv_bfloat162*>(
                (__nv_bfloat16*)Cc + r0 * Nld + gp) = o0;
            *reinterpret_cast<__nv_bfloat162*>(
                (__nv_bfloat16*)Cc + r1 * Nld + gp) = o1;
        }
    }
}

// ===========================================================================
// Single-shot warp-MMA GEMM (K=64), LDE=80, LDS.64 fragment gathers
// ===========================================================================
template<int K, int BN, int EPI>
__global__ __launch_bounds__(256)
void gemm_mma(const __nv_bfloat16* __restrict__ A0, const __nv_bfloat16* __restrict__ A1,
              const __nv_bfloat16* __restrict__ B0, const __nv_bfloat16* __restrict__ B1,
              const float* __restrict__ bias0, const float* __restrict__ bias1,
              const float* __restrict__ w30,  const float* __restrict__ w31,
              const __nv_bfloat16* __restrict__ aux0, const __nv_bfloat16* __restrict__ aux1,
              void* __restrict__ C0, void* __restrict__ C1, int Nld) {
    constexpr int LDE = K + 16;           // row stride 160B = 40 words (≡8 mod 32)
    extern __shared__ __align__(16) char smraw[];
    __nv_bfloat16* smA = reinterpret_cast<__nv_bfloat16*>(smraw);
    __nv_bfloat16* smB = smA + 128 * LDE;

    const int tid = threadIdx.x, wid = tid >> 5, lane = tid & 31;
    const int zi = blockIdx.z;
    const __nv_bfloat16* A   = zi ? A1 : A0;
    const __nv_bfloat16* Bw  = zi ? B1 : B0;
    const float* bia         = zi ? bias1 : bias0;
    const float* w3          = zi ? w31 : w30;
    const __nv_bfloat16* aux = zi ? aux1 : aux0;
    char* Cc                 = (char*)(zi ? C1 : C0);

    const size_t row0 = (size_t)blockIdx.x * 128;
    const int    col0 = blockIdx.y * BN;

    constexpr int ASEG = K / 8;
    #pragma unroll 4
    for (int c = tid; c < 128 * ASEG; c += 256) {
        int r = c / ASEG, s = c % ASEG;
        *reinterpret_cast<uint4*>(smA + r * LDE + s * 8) =
            *reinterpret_cast<const uint4*>(A + (row0 + r) * K + s * 8);
    }
    #pragma unroll 4
    for (int c = tid; c < BN * ASEG; c += 256) {
        int r = c / ASEG, s = c % ASEG;
        *reinterpret_cast<uint4*>(smB + r * LDE + s * 8) =
            *reinterpret_cast<const uint4*>(Bw + (size_t)(col0 + r) * K + s * 8);
    }
    __syncthreads();

    const int wm = wid & 3;
    const int wn = wid >> 2;
    constexpr int WN = BN / 2;
    constexpr int NT = WN / 8;
    const int g = lane >> 2;
    const int j = lane & 3;

    float acc[2][NT][4];
    #pragma unroll
    for (int mt = 0; mt < 2; mt++)
        #pragma unroll
        for (int nt = 0; nt < NT; nt++)
            #pragma unroll
            for (int i = 0; i < 4; i++) acc[mt][nt][i] = 0.f;

    const uint32_t sA = smem_u32(smA), sB = smem_u32(smB);
    uint32_t aBase[2];
    #pragma unroll
    for (int mt = 0; mt < 2; mt++)
        aBase[mt] = sA + (uint32_t)((wm * 32 + mt * 16 + g) * LDE * 2 + j * 8);
    uint32_t bBase[NT];
    #pragma unroll
    for (int nt = 0; nt < NT; nt++)
        bBase[nt] = sB + (uint32_t)((wn * WN + nt * 8 + g) * LDE * 2 + j * 8);

    constexpr uint32_t ROW8 = (uint32_t)(8 * LDE * 2);

    #pragma unroll 4
    for (int kc = 0; kc < K / 16; kc++) {
        const uint32_t kb = (uint32_t)(kc * 32);
        uint32_t a[2][4];
        #pragma unroll
        for (int mt = 0; mt < 2; mt++) {
            lds64(aBase[mt] + kb,        a[mt][0], a[mt][2]);
            lds64(aBase[mt] + kb + ROW8, a[mt][1], a[mt][3]);
        }
        uint32_t b[NT][2];
        #pragma unroll
        for (int nt = 0; nt < NT; nt++)
            lds64(bBase[nt] + kb, b[nt][0], b[nt][1]);
        #pragma unroll
        for (int mt = 0; mt < 2; mt++)
            #pragma unroll
            for (int nt = 0; nt < NT; nt++)
                mma16816(acc[mt][nt], a[mt][0], a[mt][1], a[mt][2], a[mt][3],
                         b[nt][0], b[nt][1]);
    }

    gemm_epilogue<EPI, NT>(acc, row0, col0, wm, wn, WN, lane, bia, w3, aux, Cc, Nld);
}

// ===========================================================================
// cp.async 2-stage pipelined warp-MMA GEMM (K = 256, BK = 64, LDE = 80)
// ===========================================================================
template<int K, int BN, int EPI>
__global__ __launch_bounds__(256, 2)
void gemm_pipe(const __nv_bfloat16* __restrict__ A0, const __nv_bfloat16* __restrict__ A1,
               const __nv_bfloat16* __restrict__ B0, const __nv_bfloat16* __restrict__ B1,
               const float* __restrict__ bias0, const float* __restrict__ bias1,
               const float* __restrict__ w30,  const float* __restrict__ w31,
               const __nv_bfloat16* __restrict__ aux0, const __nv_bfloat16* __restrict__ aux1,
               void* __restrict__ C0, void* __restrict__ C1, int Nld) {
    constexpr int BK   = 64;
    constexpr int LDE  = BK + 16;
    constexpr int NSTG = 2;
    constexpr int NCH  = K / BK;
    constexpr int STGE = (128 + BN) * LDE;
    extern __shared__ __align__(16) __nv_bfloat16 smp[];

    const int tid = threadIdx.x, wid = tid >> 5, lane = tid & 31;
    const int zi = blockIdx.z;
    const __nv_bfloat16* A   = zi ? A1 : A0;
    const __nv_bfloat16* Bw  = zi ? B1 : B0;
    const float* bia         = zi ? bias1 : bias0;
    const float* w3          = zi ? w31 : w30;
    const __nv_bfloat16* aux = zi ? aux1 : aux0;
    char* Cc                 = (char*)(zi ? C1 : C0);

    const size_t row0 = (size_t)blockIdx.x * 128;
    const int    col0 = blockIdx.y * BN;
    const uint32_t sm0 = smem_u32(smp);

    auto load_chunk = [&](int s, int c) {
        const uint32_t dstS = sm0 + (uint32_t)(s * STGE * 2);
        const int k0 = c * BK;
        #pragma unroll
        for (int t = tid; t < (128 + BN) * 8; t += 256) {
            int r = t >> 3, seg = t & 7;
            if (r < 128) {
                cpasync16(dstS + (uint32_t)((r * LDE + seg * 8) * 2),
                          A + (row0 + r) * K + k0 + seg * 8);
            } else {
                int rb = r - 128;
                cpasync16(dstS + (uint32_t)(((128 + rb) * LDE + seg * 8) * 2),
                          Bw + (size_t)(col0 + rb) * K + k0 + seg * 8);
            }
        }
    };

    const int wm = wid & 3;
    const int wn = wid >> 2;
    constexpr int WN = BN / 2;
    constexpr int NT = WN / 8;
    const int g = lane >> 2;
    const int j = lane & 3;

    float acc[2][NT][4];
    #pragma unroll
    for (int mt = 0; mt < 2; mt++)
        #pragma unroll
        for (int nt = 0; nt < NT; nt++)
            #pragma unroll
            for (int i = 0; i < 4; i++) acc[mt][nt][i] = 0.f;

    uint32_t aBase[2];
    #pragma unroll
    for (int mt = 0; mt < 2; mt++)
        aBase[mt] = sm0 + (uint32_t)((wm * 32 + mt * 16 + g) * LDE * 2 + j * 8);
    uint32_t bBase[NT];
    #pragma unroll
    for (int nt = 0; nt < NT; nt++)
        bBase[nt] = sm0 + (uint32_t)((128 + wn * WN + nt * 8 + g) * LDE * 2 + j * 8);
    constexpr uint32_t ROW8 = (uint32_t)(8 * LDE * 2);

    load_chunk(0, 0); cp_commit();
    load_chunk(1, 1); cp_commit();

    for (int c = 0; c < NCH; c++) {
        cp_wait<1>();
        __syncthreads();
        const uint32_t soff = (uint32_t)((c % NSTG) * STGE * 2);
        #pragma unroll
        for (int kc = 0; kc < BK / 16; kc++) {
            const uint32_t kb = soff + (uint32_t)(kc * 32);
            uint32_t a[2][4];
            #pragma unroll
            for (int mt = 0; mt < 2; mt++) {
                lds64(aBase[mt] + kb,        a[mt][0], a[mt][2]);
                lds64(aBase[mt] + kb + ROW8, a[mt][1], a[mt][3]);
            }
            uint32_t b[NT][2];
            #pragma unroll
            for (int nt = 0; nt < NT; nt++)
                lds64(bBase[nt] + kb, b[nt][0], b[nt][1]);
            #pragma unroll
            for (int mt = 0; mt < 2; mt++)
                #pragma unroll
                for (int nt = 0; nt < NT; nt++)
                    mma16816(acc[mt][nt], a[mt][0], a[mt][1], a[mt][2], a[mt][3],
                             b[nt][0], b[nt][1]);
        }
        __syncthreads();
        if (c + 2 < NCH) load_chunk((c + 2) % NSTG, c + 2);
        cp_commit();
    }

    gemm_epilogue<EPI, NT>(acc, row0, col0, wm, wn, WN, lane, bia, w3, aux, Cc, Nld);
}

// ===========================================================================
// Fused final GEMM (K=512: [g1T | g1V] @ BMcat^T) + RK4 epilogue.
// LDE = 80, 3-stage pipeline (smem fits), LDS.64 gathers.
// ===========================================================================
__global__ __launch_bounds__(256, 2)
void gemm_rk4(const __nv_bfloat16* __restrict__ g1T, const __nv_bfloat16* __restrict__ g1V,
              const __nv_bfloat16* __restrict__ Bw,
              const float* __restrict__ u, const float* __restrict__ Bc,
              const float* __restrict__ zg, float* __restrict__ accg,
              __nv_bfloat16* __restrict__ zk, float* __restrict__ outg, int stage) {
    constexpr int BK   = 64;
    constexpr int LDE  = BK + 16;
    constexpr int NSTG = 3;
    constexpr int NCH  = 8;
    constexpr int BN   = 64;
    constexpr int STGE = (128 + BN) * LDE;
    extern __shared__ __align__(16) __nv_bfloat16 smp[];

    const int tid = threadIdx.x, wid = tid >> 5, lane = tid & 31;
    const size_t row0 = (size_t)blockIdx.x * 128;
    const uint32_t sm0 = smem_u32(smp);

    auto load_chunk = [&](int s, int c) {
        const uint32_t dstS = sm0 + (uint32_t)(s * STGE * 2);
        const __nv_bfloat16* A = (c < 4) ? g1T : g1V;
        const int k0 = (c & 3) * BK;
        #pragma unroll
        for (int t = tid; t < (128 + BN) * 8; t += 256) {
            int r = t >> 3, seg = t & 7;
            if (r < 128) {
                cpasync16(dstS + (uint32_t)((r * LDE + seg * 8) * 2),
                          A + (row0 + r) * HH + k0 + seg * 8);
            } else {
                int rb = r - 128;
                cpasync16(dstS + (uint32_t)(((128 + rb) * LDE + seg * 8) * 2),
                          Bw + (size_t)rb * 512 + c * BK + seg * 8);
            }
        }
    };

    const int wm = wid & 3;
    const int wn = wid >> 2;
    constexpr int WN = BN / 2;
    constexpr int NT = WN / 8;
    const int g = lane >> 2;
    const int j = lane & 3;

    float acc[2][NT][4];
    #pragma unroll
    for (int mt = 0; mt < 2; mt++)
        #pragma unroll
        for (int nt = 0; nt < NT; nt++)
            #pragma unroll
            for (int i = 0; i < 4; i++) acc[mt][nt][i] = 0.f;

    uint32_t aBase[2];
    #pragma unroll
    for (int mt = 0; mt < 2; mt++)
        aBase[mt] = sm0 + (uint32_t)((wm * 32 + mt * 16 + g) * LDE * 2 + j * 8);
    uint32_t bBase[NT];
    #pragma unroll
    for (int nt = 0; nt < NT; nt++)
        bBase[nt] = sm0 + (uint32_t)((128 + wn * WN + nt * 8 + g) * LDE * 2 + j * 8);
    constexpr uint32_t ROW8 = (uint32_t)(8 * LDE * 2);

    load_chunk(0, 0); cp_commit();
    load_chunk(1, 1); cp_commit();

    for (int c = 0; c < NCH; c++) {
        cp_wait<1>();
        __syncthreads();
        const uint32_t soff = (uint32_t)((c % NSTG) * STGE * 2);
        #pragma unroll
        for (int kc = 0; kc < BK / 16; kc++) {
            const uint32_t kb = soff + (uint32_t)(kc * 32);
            uint32_t a[2][4];
            #pragma unroll
            for (int mt = 0; mt < 2; mt++) {
                lds64(aBase[mt] + kb,        a[mt][0], a[mt][2]);
                lds64(aBase[mt] + kb + ROW8, a[mt][1], a[mt][3]);
            }
            uint32_t b[NT][2];
            #pragma unroll
            for (int nt = 0; nt < NT; nt++)
                lds64(bBase[nt] + kb, b[nt][0], b[nt][1]);
            #pragma unroll
            for (int mt = 0; mt < 2; mt++)
                #pragma unroll
                for (int nt = 0; nt < NT; nt++)
                    mma16816(acc[mt][nt], a[mt][0], a[mt][1], a[mt][2], a[mt][3],
                             b[nt][0], b[nt][1]);
        }
        __syncthreads();
        if (c + 2 < NCH) load_chunk((c + 2) % NSTG, c + 2);
        cp_commit();
    }

    // ---- fused RK4 epilogue (out/acc natural; zk k-interleaved) ----
    const float wgt = (stage == 1 || stage == 2) ? 2.f : 1.f;
    const float cn  = (stage == 2) ? DTC : 0.5f * DTC;
    #pragma unroll
    for (int mt = 0; mt < 2; mt++) {
        const size_t r0 = row0 + wm * 32 + mt * 16 + (lane >> 2);
        const size_t r1 = r0 + 8;
        const float u0 = u[r0], u1 = u[r1];
        #pragma unroll
        for (int nt = 0; nt < NT; nt++) {
            const int gc = wn * WN + nt * 8 + (lane & 3) * 2;
            float dz0 = acc[mt][nt][0], dz1 = acc[mt][nt][1];
            float dz2 = acc[mt][nt][2], dz3 = acc[mt][nt][3];
            if (gc >= QD) {
                float bc0 = Bc[gc - QD], bc1 = Bc[gc - QD + 1];
                dz0 = fmaf(u0, bc0, dz0); dz1 = fmaf(u0, bc1, dz1);
                dz2 = fmaf(u1, bc0, dz2); dz3 = fmaf(u1, bc1, dz3);
            }
            const size_t i0 = r0 * DIM + gc, i1 = r1 * DIM + gc;
            float2 ap0 = make_float2(0.f, 0.f), ap1 = make_float2(0.f, 0.f);
            if (stage != 0) {
                ap0 = *reinterpret_cast<float2*>(accg + i0);
                ap1 = *reinterpret_cast<float2*>(accg + i1);
            }
            float a0 = fmaf(wgt, dz0, ap0.x), a1 = fmaf(wgt, dz1, ap0.y);
            float a2 = fmaf(wgt, dz2, ap1.x), a3 = fmaf(wgt, dz3, ap1.y);
            *reinterpret_cast<float2*>(accg + i0) = make_float2(a0, a1);
            *reinterpret_cast<float2*>(accg + i1) = make_float2(a2, a3);
            float2 z0 = *reinterpret_cast<const float2*>(zg + i0);
            float2 z1 = *reinterpret_cast<const float2*>(zg + i1);
            if (stage < 3) {
                const int gp = ipos(gc);
                __nv_bfloat162 o0, o1;
                o0.x = __float2bfloat16(fmaf(cn, dz0, z0.x));
                o0.y = __float2bfloat16(fmaf(cn, dz1, z0.y));
                o1.x = __float2bfloat16(fmaf(cn, dz2, z1.x));
                o1.y = __float2bfloat16(fmaf(cn, dz3, z1.y));
                *reinterpret_cast<__nv_bfloat162*>(zk + r0 * DIM + gp) = o0;
                *reinterpret_cast<__nv_bfloat162*>(zk + r1 * DIM + gp) = o1;
            } else {
                *reinterpret_cast<float2*>(outg + i0) =
                    make_float2(fmaf(DTC / 6.f, a0, z0.x), fmaf(DTC / 6.f, a1, z0.y));
                *reinterpret_cast<float2*>(outg + i1) =
                    make_float2(fmaf(DTC / 6.f, a2, z1.x), fmaf(DTC / 6.f, a3, z1.y));
            }
        }
    }
}

// ===========================================================================
// Host orchestration
// ===========================================================================
extern "C" void kernel_launch(void* const* d_in, const int* in_sizes, int n_in,
                              void* d_out, int out_size) {
    const float* h    = (const float*)d_in[0];
    const float* u    = (const float*)d_in[1];
    const float* sW1  = (const float*)d_in[2];
    const float* sb1  = (const float*)d_in[3];
    const float* sW2  = (const float*)d_in[4];
    const float* sb2  = (const float*)d_in[5];
    const float* tW1  = (const float*)d_in[6];
    const float* tb1  = (const float*)d_in[7];
    const float* tW2  = (const float*)d_in[8];
    const float* tb2  = (const float*)d_in[9];
    const float* kW1  = (const float*)d_in[10];
    const float* kb1  = (const float*)d_in[11];
    const float* kW2  = (const float*)d_in[12];
    const float* kb2  = (const float*)d_in[13];
    const float* kW3  = (const float*)d_in[14];
    const float* vW1  = (const float*)d_in[16];
    const float* vb1  = (const float*)d_in[17];
    const float* vW2  = (const float*)d_in[18];
    const float* vb2  = (const float*)d_in[19];
    const float* vW3  = (const float*)d_in[20];
    const float* A    = (const float*)d_in[22];
    const float* Lp   = (const float*)d_in[23];
    const float* Bc   = (const float*)d_in[24];
    float* out = (float*)d_out;

    float *z, *acc, *Mp, *fpk;
    __nv_bfloat16 *zk, *h1T, *h1V, *g2T, *g2V, *g1T, *g1V;
    __nv_bfloat16 *Bk1, *Bv1, *Bk2, *Bv2, *Bk2t, *Bv2t, *BMcat;
    cudaGetSymbolAddress((void**)&z,     g_z);
    cudaGetSymbolAddress((void**)&acc,   g_acc);
    cudaGetSymbolAddress((void**)&zk,    g_zk);
    cudaGetSymbolAddress((void**)&h1T,   g_h1T);
    cudaGetSymbolAddress((void**)&h1V,   g_h1V);
    cudaGetSymbolAddress((void**)&g2T,   g_g2T);
    cudaGetSymbolAddress((void**)&g2V,   g_g2V);
    cudaGetSymbolAddress((void**)&g1T,   g_g1T);
    cudaGetSymbolAddress((void**)&g1V,   g_g1V);
    cudaGetSymbolAddress((void**)&Bk1,   g_Bk1);
    cudaGetSymbolAddress((void**)&Bv1,   g_Bv1);
    cudaGetSymbolAddress((void**)&Bk2,   g_Bk2);
    cudaGetSymbolAddress((void**)&Bv2,   g_Bv2);
    cudaGetSymbolAddress((void**)&Bk2t,  g_Bk2t);
    cudaGetSymbolAddress((void**)&Bv2t,  g_Bv2t);
    cudaGetSymbolAddress((void**)&BMcat, g_BMcat);
    cudaGetSymbolAddress((void**)&Mp,    g_M);
    cudaGetSymbolAddress((void**)&fpk,   g_fpk);

    const int SM1    = (128 + 128) * 80 * 2;           //  40,960
    const int SMP128 = 2 * (128 + 128) * 80 * 2;       //  81,920
    const int SMP64  = 3 * (128 + 64)  * 80 * 2;       //  92,160
    const int SMF    = F_TOT * 4;                      // 112,640
    cudaFuncSetAttribute(gemm_mma<64, 128, 0>,
                         cudaFuncAttributeMaxDynamicSharedMemorySize, SM1);
    cudaFuncSetAttribute(gemm_pipe<256, 128, 1>,
                         cudaFuncAttributeMaxDynamicSharedMemorySize, SMP128);
    cudaFuncSetAttribute(gemm_pipe<256, 128, 2>,
                         cudaFuncAttributeMaxDynamicSharedMemorySize, SMP128);
    cudaFuncSetAttribute(gemm_rk4,
                         cudaFuncAttributeMaxDynamicSharedMemorySize, SMP64);
    cudaFuncSetAttribute(flow_fused_k,
                         cudaFuncAttributeMaxDynamicSharedMemorySize, SMF);

    // ---- prep: 2 launches ----
    build_M_k<<<1, 256>>>(A, Lp, Mp);
    prep_pack_k<<<dim3(384, 9), 256>>>(kW1, vW1, kW2, vW2, Mp,
                                       sW1, sW2, tW1, tW2,
                                       Bk1, Bv1, Bk2, Bv2, Bk2t, Bv2t,
                                       BMcat, fpk);

    // ---- s = flow_fwd(h) ----
    flow_fused_k<<<BATCH / 64, 256, SMF>>>(h, z, zk, fpk, sb1, sb2, tb1, tb2, 0);

    // ---- RK4 stages ----
    dim3 gBig(BATCH / 128, 2, 2);
    for (int st = 0; st < 4; st++) {
        gemm_mma<64, 128, 0><<<gBig, 256, SM1>>>(
            zk, zk, Bk1, Bv1, kb1, vb1, 0, 0, 0, 0, h1T, h1V, HH);
        gemm_pipe<256, 128, 1><<<gBig, 256, SMP128>>>(
            h1T, h1V, Bk2, Bv2, kb2, vb2, kW3, vW3, 0, 0, g2T, g2V, HH);
        gemm_pipe<256, 128, 2><<<gBig, 256, SMP128>>>(
            g2T, g2V, Bk2t, Bv2t, 0, 0, 0, 0, h1T, h1V, g1T, g1V, HH);
        gemm_rk4<<<BATCH / 128, 256, SMP64>>>(
            g1T, g1V, BMcat, u, Bc, z, acc, zk, out, st);
    }

    // ---- h_next = flow_inv(z_next) in place on out ----
    flow_fused_k<<<BATCH / 64, 256, SMF>>>(out, out, (__nv_bfloat16*)0,
                                           fpk, sb1, sb2, tb1, tb2, 1);
}